// round 1
// baseline (speedup 1.0000x reference)
#include <cuda_runtime.h>
#include <math.h>

#define TT  4096   // B*S
#define HH  768
#define SS  512
#define BB  8
#define NHH 12
#define DHH 64
#define II  3072
#define EE  8
#define ENT 8192   // TT * TOPK

// ---------------- scratch (static device allocations; no cudaMalloc) --------
__device__ float g_q[TT * HH];
__device__ float g_k[TT * HH];
__device__ float g_v[TT * HH];
__device__ float g_big[96 * 512 * 512];   // scores, later reused as FFN hidden [ENT, II] (same size)
__device__ float g_ctx[TT * HH];
__device__ float g_preln[TT * HH];
__device__ float g_attnout[TT * HH];
__device__ float g_xl[TT * HH];
__device__ int   g_cnt[EE];
__device__ int   g_off[EE];
__device__ int   g_cur[EE];
__device__ int   g_etok[ENT];
__device__ float g_ew[ENT];
__device__ int   g_ti[TT * 2];
__device__ float g_tw[TT * 2];

// ---------------- 4x4 micro FMA ---------------------------------------------
__device__ __forceinline__ void micro(float (&acc)[4][4], float4 a, float4 b) {
    float av[4] = {a.x, a.y, a.z, a.w};
    float bv[4] = {b.x, b.y, b.z, b.w};
#pragma unroll
    for (int i = 0; i < 4; i++)
#pragma unroll
        for (int j = 0; j < 4; j++) acc[i][j] = fmaf(av[i], bv[j], acc[i][j]);
}

// ================= K1: QKV projection (writes [B,NH,S,DH]) ==================
__global__ void qkv_kernel(const float* __restrict__ X,
                           const float* __restrict__ Wq, const float* __restrict__ bq,
                           const float* __restrict__ Wk, const float* __restrict__ bk,
                           const float* __restrict__ Wv, const float* __restrict__ bv) {
    const float* W    = (blockIdx.z == 0) ? Wq : (blockIdx.z == 1) ? Wk : Wv;
    const float* bias = (blockIdx.z == 0) ? bq : (blockIdx.z == 1) ? bk : bv;
    float*       out  = (blockIdx.z == 0) ? g_q : (blockIdx.z == 1) ? g_k : g_v;

    __shared__ float As[16][68];
    __shared__ float Bs[16][68];
    int tid = threadIdx.x;
    int tx = tid & 15, ty = tid >> 4;
    int m0 = blockIdx.y * 64, n0 = blockIdx.x * 64;
    float acc[4][4] = {};

    for (int k0 = 0; k0 < HH; k0 += 16) {
        {
            int m = tid >> 2, kq = (tid & 3) * 4;
            float4 a = *(const float4*)&X[(size_t)(m0 + m) * HH + k0 + kq];
            As[kq + 0][m] = a.x; As[kq + 1][m] = a.y; As[kq + 2][m] = a.z; As[kq + 3][m] = a.w;
        }
        {
            int kk = tid >> 4, n4 = (tid & 15) * 4;
            *(float4*)&Bs[kk][n4] = *(const float4*)&W[(size_t)(k0 + kk) * HH + n0 + n4];
        }
        __syncthreads();
#pragma unroll
        for (int kk = 0; kk < 16; kk++) {
            float4 a = *(float4*)&As[kk][ty * 4];
            float4 b = *(float4*)&Bs[kk][tx * 4];
            micro(acc, a, b);
        }
        __syncthreads();
    }
#pragma unroll
    for (int i = 0; i < 4; i++) {
        int t = m0 + ty * 4 + i;
        int b = t >> 9, s = t & 511;
#pragma unroll
        for (int j = 0; j < 4; j++) {
            int c = n0 + tx * 4 + j;
            int h = c >> 6, d = c & 63;
            out[(((size_t)(b * NHH + h)) * SS + s) * DHH + d] = acc[i][j] + bias[c];
        }
    }
}

// ================= K2: attention scores (Q @ K^T / 8) =======================
__global__ void scores_kernel() {
    int head = blockIdx.z;
    const float* Q = g_q + (size_t)head * SS * DHH;
    const float* K = g_k + (size_t)head * SS * DHH;
    float* Sc = g_big + (size_t)head * SS * SS;

    __shared__ float Qs[64][68];
    __shared__ float Ks[64][68];
    int tid = threadIdx.x;
    int q0 = blockIdx.y * 64, k0 = blockIdx.x * 64;

#pragma unroll
    for (int i = 0; i < 4; i++) {
        int idx = tid + i * 256;
        int m = idx >> 4, dq = (idx & 15) * 4;
        float4 a = *(const float4*)&Q[(size_t)(q0 + m) * DHH + dq];
        Qs[dq + 0][m] = a.x; Qs[dq + 1][m] = a.y; Qs[dq + 2][m] = a.z; Qs[dq + 3][m] = a.w;
        float4 b = *(const float4*)&K[(size_t)(k0 + m) * DHH + dq];
        Ks[dq + 0][m] = b.x; Ks[dq + 1][m] = b.y; Ks[dq + 2][m] = b.z; Ks[dq + 3][m] = b.w;
    }
    __syncthreads();

    int tx = tid & 15, ty = tid >> 4;
    float acc[4][4] = {};
#pragma unroll 16
    for (int d = 0; d < 64; d++) {
        float4 a = *(float4*)&Qs[d][ty * 4];
        float4 b = *(float4*)&Ks[d][tx * 4];
        micro(acc, a, b);
    }
#pragma unroll
    for (int i = 0; i < 4; i++)
#pragma unroll
        for (int j = 0; j < 4; j++)
            Sc[(size_t)(q0 + ty * 4 + i) * SS + k0 + tx * 4 + j] = acc[i][j] * 0.125f;
}

// ================= K3: row softmax over 512 ==================================
__global__ void softmax_kernel() {
    size_t row = blockIdx.x;
    float* p = g_big + row * SS;
    int tid = threadIdx.x;
    float v0 = p[tid], v1 = p[tid + 256];

    __shared__ float red[256];
    red[tid] = fmaxf(v0, v1);
    __syncthreads();
    for (int s = 128; s > 0; s >>= 1) {
        if (tid < s) red[tid] = fmaxf(red[tid], red[tid + s]);
        __syncthreads();
    }
    float mx = red[0];
    __syncthreads();

    float e0 = expf(v0 - mx), e1 = expf(v1 - mx);
    red[tid] = e0 + e1;
    __syncthreads();
    for (int s = 128; s > 0; s >>= 1) {
        if (tid < s) red[tid] += red[tid + s];
        __syncthreads();
    }
    float inv = 1.0f / red[0];
    p[tid] = e0 * inv;
    p[tid + 256] = e1 * inv;
}

// ================= K4: ctx = probs @ V (writes back to [T,H]) ================
__global__ void ctx_kernel() {
    int head = blockIdx.y;
    const float* P = g_big + (size_t)head * SS * SS;
    const float* V = g_v + (size_t)head * SS * DHH;

    __shared__ float As[16][68];
    __shared__ float Bs[16][68];
    int tid = threadIdx.x;
    int tx = tid & 15, ty = tid >> 4;
    int m0 = blockIdx.x * 64;
    float acc[4][4] = {};

    for (int k0 = 0; k0 < SS; k0 += 16) {
        {
            int m = tid >> 2, kq = (tid & 3) * 4;
            float4 a = *(const float4*)&P[(size_t)(m0 + m) * SS + k0 + kq];
            As[kq + 0][m] = a.x; As[kq + 1][m] = a.y; As[kq + 2][m] = a.z; As[kq + 3][m] = a.w;
        }
        {
            int kk = tid >> 4, n4 = (tid & 15) * 4;
            *(float4*)&Bs[kk][n4] = *(const float4*)&V[(size_t)(k0 + kk) * DHH + n4];
        }
        __syncthreads();
#pragma unroll
        for (int kk = 0; kk < 16; kk++) {
            float4 a = *(float4*)&As[kk][ty * 4];
            float4 b = *(float4*)&Bs[kk][tx * 4];
            micro(acc, a, b);
        }
        __syncthreads();
    }
    int b = head / NHH, h = head % NHH;
#pragma unroll
    for (int i = 0; i < 4; i++) {
        int q = m0 + ty * 4 + i;
        size_t t = (size_t)b * SS + q;
#pragma unroll
        for (int j = 0; j < 4; j++) {
            int d = tx * 4 + j;
            g_ctx[t * HH + h * 64 + d] = acc[i][j];
        }
    }
}

// ================= K5: out-proj + bias + residual ============================
__global__ void proj_kernel(const float* __restrict__ Wo, const float* __restrict__ bo,
                            const float* __restrict__ X) {
    __shared__ float As[16][68];
    __shared__ float Bs[16][68];
    int tid = threadIdx.x;
    int tx = tid & 15, ty = tid >> 4;
    int m0 = blockIdx.y * 64, n0 = blockIdx.x * 64;
    float acc[4][4] = {};

    for (int k0 = 0; k0 < HH; k0 += 16) {
        {
            int m = tid >> 2, kq = (tid & 3) * 4;
            float4 a = *(const float4*)&g_ctx[(size_t)(m0 + m) * HH + k0 + kq];
            As[kq + 0][m] = a.x; As[kq + 1][m] = a.y; As[kq + 2][m] = a.z; As[kq + 3][m] = a.w;
        }
        {
            int kk = tid >> 4, n4 = (tid & 15) * 4;
            *(float4*)&Bs[kk][n4] = *(const float4*)&Wo[(size_t)(k0 + kk) * HH + n0 + n4];
        }
        __syncthreads();
#pragma unroll
        for (int kk = 0; kk < 16; kk++) {
            float4 a = *(float4*)&As[kk][ty * 4];
            float4 b = *(float4*)&Bs[kk][tx * 4];
            micro(acc, a, b);
        }
        __syncthreads();
    }
#pragma unroll
    for (int i = 0; i < 4; i++) {
        size_t t = m0 + ty * 4 + i;
#pragma unroll
        for (int j = 0; j < 4; j++) {
            int c = n0 + tx * 4 + j;
            g_preln[t * HH + c] = acc[i][j] + bo[c] + X[t * HH + c];
        }
    }
}

// ================= K6/K7: LayerNorm ==========================================
// mode 0: in=g_preln, out=g_attnout AND d_out (residual base for MoE)
// mode 1: in=g_attnout, out=g_xl
__global__ void ln_kernel(const float* __restrict__ gamma, const float* __restrict__ beta,
                          float* __restrict__ dout, int mode) {
    size_t row = blockIdx.x;
    const float* in = (mode == 0) ? (g_preln + row * HH) : (g_attnout + row * HH);
    int tid = threadIdx.x;
    float x0 = in[tid], x1 = in[tid + 256], x2 = in[tid + 512];

    __shared__ float red[256];
    red[tid] = x0 + x1 + x2;
    __syncthreads();
    for (int s = 128; s > 0; s >>= 1) {
        if (tid < s) red[tid] += red[tid + s];
        __syncthreads();
    }
    float mean = red[0] * (1.0f / HH);
    __syncthreads();

    float c0 = x0 - mean, c1 = x1 - mean, c2 = x2 - mean;
    red[tid] = c0 * c0 + c1 * c1 + c2 * c2;
    __syncthreads();
    for (int s = 128; s > 0; s >>= 1) {
        if (tid < s) red[tid] += red[tid + s];
        __syncthreads();
    }
    float inv = 1.0f / sqrtf(red[0] * (1.0f / HH) + 1e-12f);

    float y0 = c0 * inv * gamma[tid]       + beta[tid];
    float y1 = c1 * inv * gamma[tid + 256] + beta[tid + 256];
    float y2 = c2 * inv * gamma[tid + 512] + beta[tid + 512];
    if (mode == 0) {
        g_attnout[row * HH + tid]       = y0;
        g_attnout[row * HH + tid + 256] = y1;
        g_attnout[row * HH + tid + 512] = y2;
        dout[row * HH + tid]       = y0;
        dout[row * HH + tid + 256] = y1;
        dout[row * HH + tid + 512] = y2;
    } else {
        g_xl[row * HH + tid]       = y0;
        g_xl[row * HH + tid + 256] = y1;
        g_xl[row * HH + tid + 512] = y2;
    }
}

// ================= K8: reset counters ========================================
__global__ void init_kernel() {
    int i = threadIdx.x;
    if (i < EE) { g_cnt[i] = 0; g_cur[i] = 0; }
}

// ================= K9: router + top-2 ========================================
__global__ void router_kernel(const float* __restrict__ Wr, const float* __restrict__ br,
                              float* __restrict__ logits_out) {
    int warp = threadIdx.x >> 5, lane = threadIdx.x & 31;
    int t = blockIdx.x * 8 + warp;
    const float* x = g_xl + (size_t)t * HH;

    float acc[EE] = {};
    for (int h = lane; h < HH; h += 32) {
        float xv = x[h];
        const float* w = Wr + (size_t)h * EE;
#pragma unroll
        for (int e = 0; e < EE; e++) acc[e] = fmaf(xv, w[e], acc[e]);
    }
#pragma unroll
    for (int e = 0; e < EE; e++)
        for (int o = 16; o > 0; o >>= 1) acc[e] += __shfl_down_sync(0xffffffffu, acc[e], o);

    if (lane == 0) {
        float lg[EE], mx = -1e30f;
#pragma unroll
        for (int e = 0; e < EE; e++) {
            lg[e] = acc[e] + br[e];
            logits_out[(size_t)t * EE + e] = lg[e];
            mx = fmaxf(mx, lg[e]);
        }
        float p[EE], s = 0.0f;
#pragma unroll
        for (int e = 0; e < EE; e++) { p[e] = expf(lg[e] - mx); s += p[e]; }
        float invs = 1.0f / s;
#pragma unroll
        for (int e = 0; e < EE; e++) p[e] *= invs;

        int i1 = 0;
#pragma unroll
        for (int e = 1; e < EE; e++) if (p[e] > p[i1]) i1 = e;
        int i2 = (i1 == 0) ? 1 : 0;
#pragma unroll
        for (int e = 0; e < EE; e++) if (e != i1 && p[e] > p[i2]) i2 = e;

        float w1 = p[i1], w2 = p[i2], inv = 1.0f / (w1 + w2);
        g_ti[t * 2]     = i1;  g_tw[t * 2]     = w1 * inv;
        g_ti[t * 2 + 1] = i2;  g_tw[t * 2 + 1] = w2 * inv;
        atomicAdd(&g_cnt[i1], 1);
        atomicAdd(&g_cnt[i2], 1);
    }
}

// ================= K10: exclusive offsets ====================================
__global__ void offsets_kernel() {
    if (threadIdx.x == 0) {
        int o = 0;
        for (int e = 0; e < EE; e++) { g_off[e] = o; o += g_cnt[e]; }
    }
}

// ================= K11: scatter entries by expert ============================
__global__ void scatter_kernel() {
    int t = blockIdx.x * 256 + threadIdx.x;
    if (t >= TT) return;
#pragma unroll
    for (int s = 0; s < 2; s++) {
        int e = g_ti[t * 2 + s];
        int pos = atomicAdd(&g_cur[e], 1);
        int r = g_off[e] + pos;
        g_etok[r] = t;
        g_ew[r] = g_tw[t * 2 + s];
    }
}

// ================= K12: fused up+gate grouped GEMM ===========================
// h[r, i] = gelu(x@W_up + b_up) * (x@W_new + b_new), rows grouped by expert
__global__ void upgate_kernel(const float* __restrict__ Wu, const float* __restrict__ bu,
                              const float* __restrict__ Wn, const float* __restrict__ bn) {
    int e = blockIdx.y >> 6, lt = blockIdx.y & 63;
    int base = g_off[e] + lt * 64;
    int end = g_off[e] + g_cnt[e];
    if (base >= end) return;

    __shared__ int   stok[64];
    __shared__ float As[16][68];
    __shared__ float Bu[16][68];
    __shared__ float Bn[16][68];

    int tid = threadIdx.x;
    if (tid < 64) stok[tid] = g_etok[min(base + tid, end - 1)];
    __syncthreads();

    const float* WU = Wu + (size_t)e * HH * II;
    const float* WN = Wn + (size_t)e * HH * II;
    int n0 = blockIdx.x * 64;
    int tx = tid & 15, ty = tid >> 4;
    float au[4][4] = {}, ag[4][4] = {};

    for (int k0 = 0; k0 < HH; k0 += 16) {
        {
            int m = tid >> 2, kq = (tid & 3) * 4;
            float4 a = *(const float4*)&g_xl[(size_t)stok[m] * HH + k0 + kq];
            As[kq + 0][m] = a.x; As[kq + 1][m] = a.y; As[kq + 2][m] = a.z; As[kq + 3][m] = a.w;
        }
        {
            int kk = tid >> 4, n4 = (tid & 15) * 4;
            *(float4*)&Bu[kk][n4] = *(const float4*)&WU[(size_t)(k0 + kk) * II + n0 + n4];
            *(float4*)&Bn[kk][n4] = *(const float4*)&WN[(size_t)(k0 + kk) * II + n0 + n4];
        }
        __syncthreads();
#pragma unroll
        for (int kk = 0; kk < 16; kk++) {
            float4 a  = *(float4*)&As[kk][ty * 4];
            float4 b1 = *(float4*)&Bu[kk][tx * 4];
            float4 b2 = *(float4*)&Bn[kk][tx * 4];
            micro(au, a, b1);
            micro(ag, a, b2);
        }
        __syncthreads();
    }
#pragma unroll
    for (int i = 0; i < 4; i++) {
        int r = base + ty * 4 + i;
        if (r >= end) continue;
#pragma unroll
        for (int j = 0; j < 4; j++) {
            int n = n0 + tx * 4 + j;
            float u  = au[i][j] + bu[(size_t)e * II + n];
            float gg = ag[i][j] + bn[(size_t)e * II + n];
            g_big[(size_t)r * II + n] = u * normcdff(u) * gg;   // exact gelu(u) * gate
        }
    }
}

// ================= K13: down grouped GEMM + gated scatter-add ================
__global__ void down_kernel(const float* __restrict__ Wd, const float* __restrict__ bd,
                            float* __restrict__ out) {
    int e = blockIdx.y >> 6, lt = blockIdx.y & 63;
    int base = g_off[e] + lt * 64;
    int end = g_off[e] + g_cnt[e];
    if (base >= end) return;

    __shared__ int   stok[64];
    __shared__ float sw[64];
    __shared__ float As[16][68];
    __shared__ float Bs[16][68];

    int tid = threadIdx.x;
    if (tid < 64) {
        int r = min(base + tid, end - 1);
        stok[tid] = g_etok[r];
        sw[tid] = g_ew[r];
    }
    __syncthreads();

    const float* WD = Wd + (size_t)e * II * HH;
    int n0 = blockIdx.x * 64;
    int tx = tid & 15, ty = tid >> 4;
    float acc[4][4] = {};

    for (int k0 = 0; k0 < II; k0 += 16) {
        {
            int m = tid >> 2, kq = (tid & 3) * 4;
            int rm = min(base + m, end - 1);
            float4 a = *(const float4*)&g_big[(size_t)rm * II + k0 + kq];
            As[kq + 0][m] = a.x; As[kq + 1][m] = a.y; As[kq + 2][m] = a.z; As[kq + 3][m] = a.w;
        }
        {
            int kk = tid >> 4, n4 = (tid & 15) * 4;
            *(float4*)&Bs[kk][n4] = *(const float4*)&WD[(size_t)(k0 + kk) * HH + n0 + n4];
        }
        __syncthreads();
#pragma unroll
        for (int kk = 0; kk < 16; kk++) {
            float4 a = *(float4*)&As[kk][ty * 4];
            float4 b = *(float4*)&Bs[kk][tx * 4];
            micro(acc, a, b);
        }
        __syncthreads();
    }
#pragma unroll
    for (int i = 0; i < 4; i++) {
        int m = ty * 4 + i;
        int r = base + m;
        if (r >= end) continue;
        int t = stok[m];
        float w = sw[m];
#pragma unroll
        for (int j = 0; j < 4; j++) {
            int n = n0 + tx * 4 + j;
            atomicAdd(&out[(size_t)t * HH + n], (acc[i][j] + bd[(size_t)e * HH + n]) * w);
        }
    }
}

// ================= host launcher =============================================
extern "C" void kernel_launch(void* const* d_in, const int* in_sizes, int n_in,
                              void* d_out, int out_size) {
    const float* X        = (const float*)d_in[0];
    const float* Wq       = (const float*)d_in[1];
    const float* bq       = (const float*)d_in[2];
    const float* Wk       = (const float*)d_in[3];
    const float* bk       = (const float*)d_in[4];
    const float* Wv       = (const float*)d_in[5];
    const float* bv       = (const float*)d_in[6];
    const float* Wo       = (const float*)d_in[7];
    const float* bo       = (const float*)d_in[8];
    const float* ln_ag    = (const float*)d_in[9];
    const float* ln_ab    = (const float*)d_in[10];
    const float* ln_fg    = (const float*)d_in[11];
    const float* ln_fb    = (const float*)d_in[12];
    const float* Wr       = (const float*)d_in[13];
    const float* br       = (const float*)d_in[14];
    const float* W_up     = (const float*)d_in[15];
    const float* b_up     = (const float*)d_in[16];
    const float* W_new    = (const float*)d_in[17];
    const float* b_new    = (const float*)d_in[18];
    const float* W_down   = (const float*)d_in[19];
    const float* b_down   = (const float*)d_in[20];

    float* out    = (float*)d_out;                    // layer_output [T, H]
    float* logits = out + (size_t)TT * HH;            // router_logits [T, E]

    init_kernel<<<1, 32>>>();
    qkv_kernel<<<dim3(HH / 64, TT / 64, 3), 256>>>(X, Wq, bq, Wk, bk, Wv, bv);
    scores_kernel<<<dim3(SS / 64, SS / 64, BB * NHH), 256>>>();
    softmax_kernel<<<BB * NHH * SS, 256>>>();
    ctx_kernel<<<dim3(SS / 64, BB * NHH), 256>>>();
    proj_kernel<<<dim3(HH / 64, TT / 64), 256>>>(Wo, bo, X);
    ln_kernel<<<TT, 256>>>(ln_ag, ln_ab, out, 0);     // attention_output -> g_attnout + d_out
    ln_kernel<<<TT, 256>>>(ln_fg, ln_fb, out, 1);     // xl -> g_xl
    router_kernel<<<TT / 8, 256>>>(Wr, br, logits);
    offsets_kernel<<<1, 32>>>();
    scatter_kernel<<<(TT + 255) / 256, 256>>>();
    upgate_kernel<<<dim3(II / 64, EE * 64), 256>>>(W_up, b_up, W_new, b_new);
    down_kernel<<<dim3(HH / 64, EE * 64), 256>>>(W_down, b_down, out);
}

// round 3
// speedup vs baseline: 1.6990x; 1.6990x over previous
#include <cuda_runtime.h>
#include <cuda_fp16.h>
#include <math.h>
#include <stdint.h>

#define TT  4096   // B*S
#define HH  768
#define SS  512
#define BB  8
#define NHH 12
#define DHH 64
#define II  3072
#define EE  8
#define ENT 8192   // TT * TOPK

// ---------------- scratch (static device allocations; no cudaMalloc) --------
__device__ float g_q[TT * HH];
__device__ float g_k[TT * HH];
__device__ float g_v[TT * HH];
__device__ float g_big[(size_t)ENT * II];   // scores (96*512*512 == ENT*II), later gelu(up)
__device__ float g_gt[(size_t)ENT * II];    // gate activations
__device__ float g_ctx[TT * HH];
__device__ float g_preln[TT * HH];
__device__ float g_attnout[TT * HH];
__device__ float g_xl[TT * HH];
__device__ __half g_xlh[TT * HH];
__device__ __half g_xll[TT * HH];
__device__ __half g_wuh[(size_t)EE * II * HH];  // W_up^T  hi [E][I][H]
__device__ __half g_wul[(size_t)EE * II * HH];
__device__ __half g_wnh[(size_t)EE * II * HH];  // W_new^T hi
__device__ __half g_wnl[(size_t)EE * II * HH];
__device__ __half g_wdh[(size_t)EE * HH * II];  // W_down^T hi [E][H][I]
__device__ __half g_wdl[(size_t)EE * HH * II];
__device__ int   g_cnt[EE];
__device__ int   g_off[EE];
__device__ int   g_cur[EE];
__device__ int   g_etok[ENT];
__device__ float g_ew[ENT];
__device__ int   g_ti[TT * 2];
__device__ float g_tw[TT * 2];

// ======================= mma.sync helpers (portable sm_80+) ==================
__device__ __forceinline__ uint32_t smem_u32(const void* p) {
    uint32_t a;
    asm("{ .reg .u64 t; cvta.to.shared.u64 t, %1; cvt.u32.u64 %0, t; }" : "=r"(a) : "l"(p));
    return a;
}
__device__ __forceinline__ void ldsm4(uint32_t& r0, uint32_t& r1, uint32_t& r2, uint32_t& r3,
                                      uint32_t addr) {
    asm volatile("ldmatrix.sync.aligned.m8n8.x4.shared.b16 {%0,%1,%2,%3}, [%4];"
                 : "=r"(r0), "=r"(r1), "=r"(r2), "=r"(r3) : "r"(addr));
}
__device__ __forceinline__ void mma16816(float* c, const uint32_t* a, const uint32_t* b) {
    asm volatile(
        "mma.sync.aligned.m16n8k16.row.col.f32.f16.f16.f32 "
        "{%0,%1,%2,%3}, {%4,%5,%6,%7}, {%8,%9}, {%0,%1,%2,%3};"
        : "+f"(c[0]), "+f"(c[1]), "+f"(c[2]), "+f"(c[3])
        : "r"(a[0]), "r"(a[1]), "r"(a[2]), "r"(a[3]), "r"(b[0]), "r"(b[1]));
}
// xor-swizzled smem byte offset for a [128 rows x 32 halves] tile (row = 64B)
__device__ __forceinline__ uint32_t swoff(int m, int kg) {
    return (uint32_t)(m * 64 + ((kg ^ ((m >> 1) & 3)) << 4));
}

// ---------------- 4x4 micro FMA (attention path) -----------------------------
__device__ __forceinline__ void micro(float (&acc)[4][4], float4 a, float4 b) {
    float av[4] = {a.x, a.y, a.z, a.w};
    float bv[4] = {b.x, b.y, b.z, b.w};
#pragma unroll
    for (int i = 0; i < 4; i++)
#pragma unroll
        for (int j = 0; j < 4; j++) acc[i][j] = fmaf(av[i], bv[j], acc[i][j]);
}

// ============ transpose + fp16 hi/lo split: W[R,C] -> WT_hi/lo[C,R] ==========
__global__ void tsplit(const float* __restrict__ W, __half* __restrict__ Th,
                       __half* __restrict__ Tl, int R, int C) {
    __shared__ float t[32][33];
    int e = blockIdx.z;
    W  += (size_t)e * R * C;
    Th += (size_t)e * R * C;
    Tl += (size_t)e * R * C;
    int r0 = blockIdx.y * 32, c0 = blockIdx.x * 32;
#pragma unroll
    for (int i = threadIdx.y; i < 32; i += 8)
        t[i][threadIdx.x] = W[(size_t)(r0 + i) * C + c0 + threadIdx.x];
    __syncthreads();
#pragma unroll
    for (int i = threadIdx.y; i < 32; i += 8) {
        float v = t[threadIdx.x][i];
        __half h = __float2half_rn(v);
        size_t o = (size_t)(c0 + i) * R + r0 + threadIdx.x;
        Th[o] = h;
        Tl[o] = __float2half_rn(v - __half2float(h));
    }
}

// ================= K1: QKV projection (writes [B,NH,S,DH]) ==================
__global__ void qkv_kernel(const float* __restrict__ X,
                           const float* __restrict__ Wq, const float* __restrict__ bq,
                           const float* __restrict__ Wk, const float* __restrict__ bk,
                           const float* __restrict__ Wv, const float* __restrict__ bv) {
    const float* W    = (blockIdx.z == 0) ? Wq : (blockIdx.z == 1) ? Wk : Wv;
    const float* bias = (blockIdx.z == 0) ? bq : (blockIdx.z == 1) ? bk : bv;
    float*       out  = (blockIdx.z == 0) ? g_q : (blockIdx.z == 1) ? g_k : g_v;

    __shared__ float As[16][68];
    __shared__ float Bs[16][68];
    int tid = threadIdx.x;
    int tx = tid & 15, ty = tid >> 4;
    int m0 = blockIdx.y * 64, n0 = blockIdx.x * 64;
    float acc[4][4] = {};

    for (int k0 = 0; k0 < HH; k0 += 16) {
        {
            int m = tid >> 2, kq = (tid & 3) * 4;
            float4 a = *(const float4*)&X[(size_t)(m0 + m) * HH + k0 + kq];
            As[kq + 0][m] = a.x; As[kq + 1][m] = a.y; As[kq + 2][m] = a.z; As[kq + 3][m] = a.w;
        }
        {
            int kk = tid >> 4, n4 = (tid & 15) * 4;
            *(float4*)&Bs[kk][n4] = *(const float4*)&W[(size_t)(k0 + kk) * HH + n0 + n4];
        }
        __syncthreads();
#pragma unroll
        for (int kk = 0; kk < 16; kk++) {
            float4 a = *(float4*)&As[kk][ty * 4];
            float4 b = *(float4*)&Bs[kk][tx * 4];
            micro(acc, a, b);
        }
        __syncthreads();
    }
#pragma unroll
    for (int i = 0; i < 4; i++) {
        int t = m0 + ty * 4 + i;
        int b = t >> 9, s = t & 511;
#pragma unroll
        for (int j = 0; j < 4; j++) {
            int c = n0 + tx * 4 + j;
            int h = c >> 6, d = c & 63;
            out[(((size_t)(b * NHH + h)) * SS + s) * DHH + d] = acc[i][j] + bias[c];
        }
    }
}

// ================= K2: attention scores (Q @ K^T / 8) =======================
__global__ void scores_kernel() {
    int head = blockIdx.z;
    const float* Q = g_q + (size_t)head * SS * DHH;
    const float* K = g_k + (size_t)head * SS * DHH;
    float* Sc = g_big + (size_t)head * SS * SS;

    __shared__ float Qs[64][68];
    __shared__ float Ks[64][68];
    int tid = threadIdx.x;
    int q0 = blockIdx.y * 64, k0 = blockIdx.x * 64;

#pragma unroll
    for (int i = 0; i < 4; i++) {
        int idx = tid + i * 256;
        int m = idx >> 4, dq = (idx & 15) * 4;
        float4 a = *(const float4*)&Q[(size_t)(q0 + m) * DHH + dq];
        Qs[dq + 0][m] = a.x; Qs[dq + 1][m] = a.y; Qs[dq + 2][m] = a.z; Qs[dq + 3][m] = a.w;
        float4 b = *(const float4*)&K[(size_t)(k0 + m) * DHH + dq];
        Ks[dq + 0][m] = b.x; Ks[dq + 1][m] = b.y; Ks[dq + 2][m] = b.z; Ks[dq + 3][m] = b.w;
    }
    __syncthreads();

    int tx = tid & 15, ty = tid >> 4;
    float acc[4][4] = {};
#pragma unroll 16
    for (int d = 0; d < 64; d++) {
        float4 a = *(float4*)&Qs[d][ty * 4];
        float4 b = *(float4*)&Ks[d][tx * 4];
        micro(acc, a, b);
    }
#pragma unroll
    for (int i = 0; i < 4; i++)
#pragma unroll
        for (int j = 0; j < 4; j++)
            Sc[(size_t)(q0 + ty * 4 + i) * SS + k0 + tx * 4 + j] = acc[i][j] * 0.125f;
}

// ================= K3: row softmax over 512 ==================================
__global__ void softmax_kernel() {
    size_t row = blockIdx.x;
    float* p = g_big + row * SS;
    int tid = threadIdx.x;
    float v0 = p[tid], v1 = p[tid + 256];

    __shared__ float red[256];
    red[tid] = fmaxf(v0, v1);
    __syncthreads();
    for (int s = 128; s > 0; s >>= 1) {
        if (tid < s) red[tid] = fmaxf(red[tid], red[tid + s]);
        __syncthreads();
    }
    float mx = red[0];
    __syncthreads();

    float e0 = expf(v0 - mx), e1 = expf(v1 - mx);
    red[tid] = e0 + e1;
    __syncthreads();
    for (int s = 128; s > 0; s >>= 1) {
        if (tid < s) red[tid] += red[tid + s];
        __syncthreads();
    }
    float inv = 1.0f / red[0];
    p[tid] = e0 * inv;
    p[tid + 256] = e1 * inv;
}

// ================= K4: ctx = probs @ V (writes back to [T,H]) ================
__global__ void ctx_kernel() {
    int head = blockIdx.y;
    const float* P = g_big + (size_t)head * SS * SS;
    const float* V = g_v + (size_t)head * SS * DHH;

    __shared__ float As[16][68];
    __shared__ float Bs[16][68];
    int tid = threadIdx.x;
    int tx = tid & 15, ty = tid >> 4;
    int m0 = blockIdx.x * 64;
    float acc[4][4] = {};

    for (int k0 = 0; k0 < SS; k0 += 16) {
        {
            int m = tid >> 2, kq = (tid & 3) * 4;
            float4 a = *(const float4*)&P[(size_t)(m0 + m) * SS + k0 + kq];
            As[kq + 0][m] = a.x; As[kq + 1][m] = a.y; As[kq + 2][m] = a.z; As[kq + 3][m] = a.w;
        }
        {
            int kk = tid >> 4, n4 = (tid & 15) * 4;
            *(float4*)&Bs[kk][n4] = *(const float4*)&V[(size_t)(k0 + kk) * DHH + n4];
        }
        __syncthreads();
#pragma unroll
        for (int kk = 0; kk < 16; kk++) {
            float4 a = *(float4*)&As[kk][ty * 4];
            float4 b = *(float4*)&Bs[kk][tx * 4];
            micro(acc, a, b);
        }
        __syncthreads();
    }
    int b = head / NHH, h = head % NHH;
#pragma unroll
    for (int i = 0; i < 4; i++) {
        int q = m0 + ty * 4 + i;
        size_t t = (size_t)b * SS + q;
#pragma unroll
        for (int j = 0; j < 4; j++) {
            int d = tx * 4 + j;
            g_ctx[t * HH + h * 64 + d] = acc[i][j];
        }
    }
}

// ================= K5: out-proj + bias + residual ============================
__global__ void proj_kernel(const float* __restrict__ Wo, const float* __restrict__ bo,
                            const float* __restrict__ X) {
    __shared__ float As[16][68];
    __shared__ float Bs[16][68];
    int tid = threadIdx.x;
    int tx = tid & 15, ty = tid >> 4;
    int m0 = blockIdx.y * 64, n0 = blockIdx.x * 64;
    float acc[4][4] = {};

    for (int k0 = 0; k0 < HH; k0 += 16) {
        {
            int m = tid >> 2, kq = (tid & 3) * 4;
            float4 a = *(const float4*)&g_ctx[(size_t)(m0 + m) * HH + k0 + kq];
            As[kq + 0][m] = a.x; As[kq + 1][m] = a.y; As[kq + 2][m] = a.z; As[kq + 3][m] = a.w;
        }
        {
            int kk = tid >> 4, n4 = (tid & 15) * 4;
            *(float4*)&Bs[kk][n4] = *(const float4*)&Wo[(size_t)(k0 + kk) * HH + n0 + n4];
        }
        __syncthreads();
#pragma unroll
        for (int kk = 0; kk < 16; kk++) {
            float4 a = *(float4*)&As[kk][ty * 4];
            float4 b = *(float4*)&Bs[kk][tx * 4];
            micro(acc, a, b);
        }
        __syncthreads();
    }
#pragma unroll
    for (int i = 0; i < 4; i++) {
        size_t t = m0 + ty * 4 + i;
#pragma unroll
        for (int j = 0; j < 4; j++) {
            int c = n0 + tx * 4 + j;
            g_preln[t * HH + c] = acc[i][j] + bo[c] + X[t * HH + c];
        }
    }
}

// ================= K6/K7: LayerNorm ==========================================
__global__ void ln_kernel(const float* __restrict__ gamma, const float* __restrict__ beta,
                          float* __restrict__ dout, int mode) {
    size_t row = blockIdx.x;
    const float* in = (mode == 0) ? (g_preln + row * HH) : (g_attnout + row * HH);
    int tid = threadIdx.x;
    float x0 = in[tid], x1 = in[tid + 256], x2 = in[tid + 512];

    __shared__ float red[256];
    red[tid] = x0 + x1 + x2;
    __syncthreads();
    for (int s = 128; s > 0; s >>= 1) {
        if (tid < s) red[tid] += red[tid + s];
        __syncthreads();
    }
    float mean = red[0] * (1.0f / HH);
    __syncthreads();

    float c0 = x0 - mean, c1 = x1 - mean, c2 = x2 - mean;
    red[tid] = c0 * c0 + c1 * c1 + c2 * c2;
    __syncthreads();
    for (int s = 128; s > 0; s >>= 1) {
        if (tid < s) red[tid] += red[tid + s];
        __syncthreads();
    }
    float inv = 1.0f / sqrtf(red[0] * (1.0f / HH) + 1e-12f);

    float y0 = c0 * inv * gamma[tid]       + beta[tid];
    float y1 = c1 * inv * gamma[tid + 256] + beta[tid + 256];
    float y2 = c2 * inv * gamma[tid + 512] + beta[tid + 512];
    if (mode == 0) {
        g_attnout[row * HH + tid]       = y0;
        g_attnout[row * HH + tid + 256] = y1;
        g_attnout[row * HH + tid + 512] = y2;
        dout[row * HH + tid]       = y0;
        dout[row * HH + tid + 256] = y1;
        dout[row * HH + tid + 512] = y2;
    } else {
        g_xl[row * HH + tid]       = y0;
        g_xl[row * HH + tid + 256] = y1;
        g_xl[row * HH + tid + 512] = y2;
        __half h0 = __float2half_rn(y0), h1 = __float2half_rn(y1), h2 = __float2half_rn(y2);
        g_xlh[row * HH + tid]       = h0;
        g_xlh[row * HH + tid + 256] = h1;
        g_xlh[row * HH + tid + 512] = h2;
        g_xll[row * HH + tid]       = __float2half_rn(y0 - __half2float(h0));
        g_xll[row * HH + tid + 256] = __float2half_rn(y1 - __half2float(h1));
        g_xll[row * HH + tid + 512] = __float2half_rn(y2 - __half2float(h2));
    }
}

// ================= K8: reset counters ========================================
__global__ void init_kernel() {
    int i = threadIdx.x;
    if (i < EE) { g_cnt[i] = 0; g_cur[i] = 0; }
}

// ================= K9: router + top-2 ========================================
__global__ void router_kernel(const float* __restrict__ Wr, const float* __restrict__ br,
                              float* __restrict__ logits_out) {
    int warp = threadIdx.x >> 5, lane = threadIdx.x & 31;
    int t = blockIdx.x * 8 + warp;
    const float* x = g_xl + (size_t)t * HH;

    float acc[EE] = {};
    for (int h = lane; h < HH; h += 32) {
        float xv = x[h];
        const float* w = Wr + (size_t)h * EE;
#pragma unroll
        for (int e = 0; e < EE; e++) acc[e] = fmaf(xv, w[e], acc[e]);
    }
#pragma unroll
    for (int e = 0; e < EE; e++)
        for (int o = 16; o > 0; o >>= 1) acc[e] += __shfl_down_sync(0xffffffffu, acc[e], o);

    if (lane == 0) {
        float lg[EE], mx = -1e30f;
#pragma unroll
        for (int e = 0; e < EE; e++) {
            lg[e] = acc[e] + br[e];
            logits_out[(size_t)t * EE + e] = lg[e];
            mx = fmaxf(mx, lg[e]);
        }
        float p[EE], s = 0.0f;
#pragma unroll
        for (int e = 0; e < EE; e++) { p[e] = expf(lg[e] - mx); s += p[e]; }
        float invs = 1.0f / s;
#pragma unroll
        for (int e = 0; e < EE; e++) p[e] *= invs;

        int i1 = 0;
#pragma unroll
        for (int e = 1; e < EE; e++) if (p[e] > p[i1]) i1 = e;
        int i2 = (i1 == 0) ? 1 : 0;
#pragma unroll
        for (int e = 0; e < EE; e++) if (e != i1 && p[e] > p[i2]) i2 = e;

        float w1 = p[i1], w2 = p[i2], inv = 1.0f / (w1 + w2);
        g_ti[t * 2]     = i1;  g_tw[t * 2]     = w1 * inv;
        g_ti[t * 2 + 1] = i2;  g_tw[t * 2 + 1] = w2 * inv;
        atomicAdd(&g_cnt[i1], 1);
        atomicAdd(&g_cnt[i2], 1);
    }
}

// ================= K10: exclusive offsets ====================================
__global__ void offsets_kernel() {
    if (threadIdx.x == 0) {
        int o = 0;
        for (int e = 0; e < EE; e++) { g_off[e] = o; o += g_cnt[e]; }
    }
}

// ================= K11: scatter entries by expert ============================
__global__ void scatter_kernel() {
    int t = blockIdx.x * 256 + threadIdx.x;
    if (t >= TT) return;
#pragma unroll
    for (int s = 0; s < 2; s++) {
        int e = g_ti[t * 2 + s];
        int pos = atomicAdd(&g_cur[e], 1);
        int r = g_off[e] + pos;
        g_etok[r] = t;
        g_ew[r] = g_tw[t * 2 + s];
    }
}

// ============ K12: fp16x3 mma.sync grouped GEMM: up (z=0) / gate (z=1) ======
// C[128 rows x 128 cols of I] = xl[rows, 768] @ W^T[128, 768]
__global__ void __launch_bounds__(256, 2) ffn_upgate(
    const float* __restrict__ bu, const float* __restrict__ bn) {
    int e = blockIdx.y >> 5, lt = blockIdx.y & 31;
    int base = g_off[e] + lt * 128;
    int end  = g_off[e] + g_cnt[e];
    if (base >= end) return;

    __shared__ __half sAh[128 * 32], sAl[128 * 32], sBh[128 * 32], sBl[128 * 32];
    __shared__ int s_tok[128];

    int tid = threadIdx.x, lane = tid & 31, wid = tid >> 5;
    int wm = wid & 1, wn = wid >> 1;
    bool isUp = (blockIdx.z == 0);

    if (tid < 128) s_tok[tid] = g_etok[min(base + tid, end - 1)];

    const __half* Bhp = (isUp ? g_wuh : g_wnh) + (size_t)e * II * HH;
    const __half* Blp = (isUp ? g_wul : g_wnl) + (size_t)e * II * HH;
    const float*  bias = (isUp ? bu : bn) + (size_t)e * II;
    float* dst = isUp ? g_big : g_gt;
    int n0 = blockIdx.x * 128;

    uint32_t aH = smem_u32(sAh), aL = smem_u32(sAl);
    uint32_t bH = smem_u32(sBh), bL = smem_u32(sBl);

    int j = lane >> 3, rr = lane & 7;
    int amRow = wm * 64 + (j & 1) * 8 + rr;
    int akSel = j >> 1;
    int bnRow = wn * 32 + (j >> 1) * 8 + rr;
    int bkSel = j & 1;

    float C[4][4][4] = {};

    for (int k0 = 0; k0 < HH; k0 += 32) {
        __syncthreads();
#pragma unroll
        for (int i = 0; i < 2; i++) {
            int c = tid + i * 256;
            int m = c >> 2, kc = c & 3;
            uint32_t so = swoff(m, kc);
            int tok = s_tok[m];
            *(uint4*)((char*)sAh + so) = *(const uint4*)(g_xlh + (size_t)tok * HH + k0 + kc * 8);
            *(uint4*)((char*)sAl + so) = *(const uint4*)(g_xll + (size_t)tok * HH + k0 + kc * 8);
            *(uint4*)((char*)sBh + so) = *(const uint4*)(Bhp + (size_t)(n0 + m) * HH + k0 + kc * 8);
            *(uint4*)((char*)sBl + so) = *(const uint4*)(Blp + (size_t)(n0 + m) * HH + k0 + kc * 8);
        }
        __syncthreads();
#pragma unroll
        for (int kk = 0; kk < 2; kk++) {
            uint32_t bh[4][2], bl[4][2];
#pragma unroll
            for (int fp = 0; fp < 2; fp++) {
                int n = bnRow + fp * 16;
                int kg = kk * 2 + bkSel;
                uint32_t o = (uint32_t)(n * 64 + ((kg ^ ((n >> 1) & 3)) << 4));
                ldsm4(bh[fp * 2][0], bh[fp * 2][1], bh[fp * 2 + 1][0], bh[fp * 2 + 1][1], bH + o);
                ldsm4(bl[fp * 2][0], bl[fp * 2][1], bl[fp * 2 + 1][0], bl[fp * 2 + 1][1], bL + o);
            }
#pragma unroll
            for (int fm = 0; fm < 4; fm++) {
                int m = amRow + fm * 16;
                int kg = kk * 2 + akSel;
                uint32_t o = (uint32_t)(m * 64 + ((kg ^ ((m >> 1) & 3)) << 4));
                uint32_t ah[4], al[4];
                ldsm4(ah[0], ah[1], ah[2], ah[3], aH + o);
                ldsm4(al[0], al[1], al[2], al[3], aL + o);
#pragma unroll
                for (int fn = 0; fn < 4; fn++) {
                    mma16816(C[fm][fn], ah, bh[fn]);
                    mma16816(C[fm][fn], ah, bl[fn]);
                    mma16816(C[fm][fn], al, bh[fn]);
                }
            }
        }
    }

    int g = lane >> 2, tig = lane & 3;
#pragma unroll
    for (int fm = 0; fm < 4; fm++) {
        int r0 = base + wm * 64 + fm * 16 + g;
#pragma unroll
        for (int fn = 0; fn < 4; fn++) {
            int col = n0 + wn * 32 + fn * 8 + tig * 2;
            float bb0 = bias[col], bb1 = bias[col + 1];
            if (r0 < end) {
                float u0 = C[fm][fn][0] + bb0, u1 = C[fm][fn][1] + bb1;
                float2 v;
                v.x = isUp ? u0 * normcdff(u0) : u0;
                v.y = isUp ? u1 * normcdff(u1) : u1;
                *(float2*)(dst + (size_t)r0 * II + col) = v;
            }
            if (r0 + 8 < end) {
                float u0 = C[fm][fn][2] + bb0, u1 = C[fm][fn][3] + bb1;
                float2 v;
                v.x = isUp ? u0 * normcdff(u0) : u0;
                v.y = isUp ? u1 * normcdff(u1) : u1;
                *(float2*)(dst + (size_t)(r0 + 8) * II + col) = v;
            }
        }
    }
}

// ============ K13: fp16x3 mma.sync grouped down GEMM + gated scatter-add =====
// C[128 rows x 128 cols of H] = (act*gate)[rows, 3072] @ Wd^T[128, 3072]
__global__ void __launch_bounds__(256, 2) ffn_down(
    const float* __restrict__ bd, float* __restrict__ out) {
    int e = blockIdx.y >> 5, lt = blockIdx.y & 31;
    int base = g_off[e] + lt * 128;
    int end  = g_off[e] + g_cnt[e];
    if (base >= end) return;

    __shared__ __half sAh[128 * 32], sAl[128 * 32], sBh[128 * 32], sBl[128 * 32];
    __shared__ int   s_tok[128];
    __shared__ float s_w[128];

    int tid = threadIdx.x, lane = tid & 31, wid = tid >> 5;
    int wm = wid & 1, wn = wid >> 1;

    if (tid < 128) {
        int r = min(base + tid, end - 1);
        s_tok[tid] = g_etok[r];
        s_w[tid]   = g_ew[r];
    }

    const __half* Bhp = g_wdh + (size_t)e * HH * II;
    const __half* Blp = g_wdl + (size_t)e * HH * II;
    int n0 = blockIdx.x * 128;

    uint32_t aH = smem_u32(sAh), aL = smem_u32(sAl);
    uint32_t bH = smem_u32(sBh), bL = smem_u32(sBl);

    int j = lane >> 3, rr = lane & 7;
    int amRow = wm * 64 + (j & 1) * 8 + rr;
    int akSel = j >> 1;
    int bnRow = wn * 32 + (j >> 1) * 8 + rr;
    int bkSel = j & 1;

    float C[4][4][4] = {};

    for (int k0 = 0; k0 < II; k0 += 32) {
        __syncthreads();
#pragma unroll
        for (int i = 0; i < 4; i++) {
            int c = tid + i * 256;
            int m = c >> 3, q = c & 7;
            int rm = min(base + m, end - 1);
            float4 a  = *(const float4*)(g_big + (size_t)rm * II + k0 + q * 4);
            float4 gt = *(const float4*)(g_gt  + (size_t)rm * II + k0 + q * 4);
            float h0 = a.x * gt.x, h1 = a.y * gt.y, h2 = a.z * gt.z, h3 = a.w * gt.w;
            __half p0 = __float2half_rn(h0), p1 = __float2half_rn(h1);
            __half p2 = __float2half_rn(h2), p3 = __float2half_rn(h3);
            uint32_t so = swoff(m, q >> 1) + (q & 1) * 8;
            ((__half2*)((char*)sAh + so))[0] = __halves2half2(p0, p1);
            ((__half2*)((char*)sAh + so))[1] = __halves2half2(p2, p3);
            ((__half2*)((char*)sAl + so))[0] = __halves2half2(
                __float2half_rn(h0 - __half2float(p0)), __float2half_rn(h1 - __half2float(p1)));
            ((__half2*)((char*)sAl + so))[1] = __halves2half2(
                __float2half_rn(h2 - __half2float(p2)), __float2half_rn(h3 - __half2float(p3)));
        }
#pragma unroll
        for (int i = 0; i < 2; i++) {
            int c = tid + i * 256;
            int m = c >> 2, kc = c & 3;
            uint32_t so = swoff(m, kc);
            *(uint4*)((char*)sBh + so) = *(const uint4*)(Bhp + (size_t)(n0 + m) * II + k0 + kc * 8);
            *(uint4*)((char*)sBl + so) = *(const uint4*)(Blp + (size_t)(n0 + m) * II + k0 + kc * 8);
        }
        __syncthreads();
#pragma unroll
        for (int kk = 0; kk < 2; kk++) {
            uint32_t bh[4][2], bl[4][2];
#pragma unroll
            for (int fp = 0; fp < 2; fp++) {
                int n = bnRow + fp * 16;
                int kg = kk * 2 + bkSel;
                uint32_t o = (uint32_t)(n * 64 + ((kg ^ ((n >> 1) & 3)) << 4));
                ldsm4(bh[fp * 2][0], bh[fp * 2][1], bh[fp * 2 + 1][0], bh[fp * 2 + 1][1], bH + o);
                ldsm4(bl[fp * 2][0], bl[fp * 2][1], bl[fp * 2 + 1][0], bl[fp * 2 + 1][1], bL + o);
            }
#pragma unroll
            for (int fm = 0; fm < 4; fm++) {
                int m = amRow + fm * 16;
                int kg = kk * 2 + akSel;
                uint32_t o = (uint32_t)(m * 64 + ((kg ^ ((m >> 1) & 3)) << 4));
                uint32_t ah[4], al[4];
                ldsm4(ah[0], ah[1], ah[2], ah[3], aH + o);
                ldsm4(al[0], al[1], al[2], al[3], aL + o);
#pragma unroll
                for (int fn = 0; fn < 4; fn++) {
                    mma16816(C[fm][fn], ah, bh[fn]);
                    mma16816(C[fm][fn], ah, bl[fn]);
                    mma16816(C[fm][fn], al, bh[fn]);
                }
            }
        }
    }

    int g = lane >> 2, tig = lane & 3;
    const float* bde = bd + (size_t)e * HH;
#pragma unroll
    for (int fm = 0; fm < 4; fm++) {
        int ml0 = wm * 64 + fm * 16 + g;
        int ml1 = ml0 + 8;
        int t0 = s_tok[ml0], t1 = s_tok[ml1];
        float w0 = s_w[ml0], w1 = s_w[ml1];
        bool v0 = (base + ml0) < end, v1 = (base + ml1) < end;
#pragma unroll
        for (int fn = 0; fn < 4; fn++) {
            int col = n0 + wn * 32 + fn * 8 + tig * 2;
            float bb0 = bde[col], bb1 = bde[col + 1];
            if (v0) {
                atomicAdd(out + (size_t)t0 * HH + col,     (C[fm][fn][0] + bb0) * w0);
                atomicAdd(out + (size_t)t0 * HH + col + 1, (C[fm][fn][1] + bb1) * w0);
            }
            if (v1) {
                atomicAdd(out + (size_t)t1 * HH + col,     (C[fm][fn][2] + bb0) * w1);
                atomicAdd(out + (size_t)t1 * HH + col + 1, (C[fm][fn][3] + bb1) * w1);
            }
        }
    }
}

// ================= host launcher =============================================
extern "C" void kernel_launch(void* const* d_in, const int* in_sizes, int n_in,
                              void* d_out, int out_size) {
    const float* X        = (const float*)d_in[0];
    const float* Wq       = (const float*)d_in[1];
    const float* bq       = (const float*)d_in[2];
    const float* Wk       = (const float*)d_in[3];
    const float* bk       = (const float*)d_in[4];
    const float* Wv       = (const float*)d_in[5];
    const float* bv       = (const float*)d_in[6];
    const float* Wo       = (const float*)d_in[7];
    const float* bo       = (const float*)d_in[8];
    const float* ln_ag    = (const float*)d_in[9];
    const float* ln_ab    = (const float*)d_in[10];
    const float* ln_fg    = (const float*)d_in[11];
    const float* ln_fb    = (const float*)d_in[12];
    const float* Wr       = (const float*)d_in[13];
    const float* br       = (const float*)d_in[14];
    const float* W_up     = (const float*)d_in[15];
    const float* b_up     = (const float*)d_in[16];
    const float* W_new    = (const float*)d_in[17];
    const float* b_new    = (const float*)d_in[18];
    const float* W_down   = (const float*)d_in[19];
    const float* b_down   = (const float*)d_in[20];

    float* out    = (float*)d_out;                    // layer_output [T, H]
    float* logits = out + (size_t)TT * HH;            // router_logits [T, E]

    __half *wuh, *wul, *wnh, *wnl, *wdh, *wdl;
    cudaGetSymbolAddress((void**)&wuh, g_wuh);
    cudaGetSymbolAddress((void**)&wul, g_wul);
    cudaGetSymbolAddress((void**)&wnh, g_wnh);
    cudaGetSymbolAddress((void**)&wnl, g_wnl);
    cudaGetSymbolAddress((void**)&wdh, g_wdh);
    cudaGetSymbolAddress((void**)&wdl, g_wdl);

    // weight transpose + fp16 hi/lo split
    tsplit<<<dim3(II / 32, HH / 32, EE), dim3(32, 8)>>>(W_up,  wuh, wul, HH, II);
    tsplit<<<dim3(II / 32, HH / 32, EE), dim3(32, 8)>>>(W_new, wnh, wnl, HH, II);
    tsplit<<<dim3(HH / 32, II / 32, EE), dim3(32, 8)>>>(W_down, wdh, wdl, II, HH);

    init_kernel<<<1, 32>>>();
    qkv_kernel<<<dim3(HH / 64, TT / 64, 3), 256>>>(X, Wq, bq, Wk, bk, Wv, bv);
    scores_kernel<<<dim3(SS / 64, SS / 64, BB * NHH), 256>>>();
    softmax_kernel<<<BB * NHH * SS, 256>>>();
    ctx_kernel<<<dim3(SS / 64, BB * NHH), 256>>>();
    proj_kernel<<<dim3(HH / 64, TT / 64), 256>>>(Wo, bo, X);
    ln_kernel<<<TT, 256>>>(ln_ag, ln_ab, out, 0);
    ln_kernel<<<TT, 256>>>(ln_fg, ln_fb, out, 1);
    router_kernel<<<TT / 8, 256>>>(Wr, br, logits);
    offsets_kernel<<<1, 32>>>();
    scatter_kernel<<<(TT + 255) / 256, 256>>>();
    ffn_upgate<<<dim3(II / 128, EE * 32, 2), 256>>>(b_up, b_new);
    ffn_down<<<dim3(HH / 128, EE * 32, 1), 256>>>(b_down, out);
}

// round 4
// speedup vs baseline: 2.2786x; 1.3411x over previous
#include <cuda_runtime.h>
#include <cuda_fp16.h>
#include <math.h>
#include <stdint.h>

#define TT  4096   // B*S
#define HH  768
#define SS  512
#define BB  8
#define NHH 12
#define DHH 64
#define II  3072
#define EE  8
#define ENT 8192   // TT * TOPK

// ---------------- scratch (static device allocations; no cudaMalloc) --------
__device__ float g_q[TT * HH];
__device__ float g_k[TT * HH];
__device__ float g_v[TT * HH];
__device__ float g_big[(size_t)ENT * II];   // scores (96*512*512 == ENT*II), later gelu(up)
__device__ float g_ctx[TT * HH];
__device__ float g_preln[TT * HH];
__device__ float g_attnout[TT * HH];
__device__ float g_xl[TT * HH];
__device__ __half g_xlh[TT * HH];           // xl split
__device__ __half g_xll[TT * HH];
__device__ __half g_xsh[TT * HH];           // X split
__device__ __half g_xsl[TT * HH];
__device__ __half g_ch[TT * HH];            // ctx split
__device__ __half g_cl[TT * HH];
__device__ __half g_hh[(size_t)ENT * II];   // FFN hidden h = gelu(u)*gate, hi
__device__ __half g_hl[(size_t)ENT * II];   // lo
__device__ __half g_wqkvh[3 * HH * HH];     // [Wq^T;Wk^T;Wv^T] [2304][768]
__device__ __half g_wqkvl[3 * HH * HH];
__device__ __half g_woh[HH * HH];           // Wo^T
__device__ __half g_wol[HH * HH];
__device__ __half g_wuh[(size_t)EE * II * HH];  // W_up^T  hi [E][I][H]
__device__ __half g_wul[(size_t)EE * II * HH];
__device__ __half g_wnh[(size_t)EE * II * HH];  // W_new^T hi
__device__ __half g_wnl[(size_t)EE * II * HH];
__device__ __half g_wdh[(size_t)EE * HH * II];  // W_down^T hi [E][H][I]
__device__ __half g_wdl[(size_t)EE * HH * II];
__device__ int   g_cnt[EE];
__device__ int   g_off[EE];
__device__ int   g_cur[EE];
__device__ int   g_etok[ENT];
__device__ float g_ew[ENT];
__device__ int   g_ti[TT * 2];
__device__ float g_tw[TT * 2];

// ======================= asm helpers (portable sm_80+) =======================
__device__ __forceinline__ uint32_t smem_u32(const void* p) {
    uint32_t a;
    asm("{ .reg .u64 t; cvta.to.shared.u64 t, %1; cvt.u32.u64 %0, t; }" : "=r"(a) : "l"(p));
    return a;
}
__device__ __forceinline__ void ldsm4(uint32_t& r0, uint32_t& r1, uint32_t& r2, uint32_t& r3,
                                      uint32_t addr) {
    asm volatile("ldmatrix.sync.aligned.m8n8.x4.shared.b16 {%0,%1,%2,%3}, [%4];"
                 : "=r"(r0), "=r"(r1), "=r"(r2), "=r"(r3) : "r"(addr));
}
__device__ __forceinline__ void mma16816(float* c, const uint32_t* a, const uint32_t* b) {
    asm volatile(
        "mma.sync.aligned.m16n8k16.row.col.f32.f16.f16.f32 "
        "{%0,%1,%2,%3}, {%4,%5,%6,%7}, {%8,%9}, {%0,%1,%2,%3};"
        : "+f"(c[0]), "+f"(c[1]), "+f"(c[2]), "+f"(c[3])
        : "r"(a[0]), "r"(a[1]), "r"(a[2]), "r"(a[3]), "r"(b[0]), "r"(b[1]));
}
__device__ __forceinline__ void cpasync16(uint32_t saddr, const void* gaddr) {
    asm volatile("cp.async.cg.shared.global [%0], [%1], 16;" :: "r"(saddr), "l"(gaddr));
}
#define CP_COMMIT() asm volatile("cp.async.commit_group;" ::: "memory")
#define CP_WAIT1()  asm volatile("cp.async.wait_group 1;" ::: "memory")
#define CP_WAIT0()  asm volatile("cp.async.wait_group 0;" ::: "memory")

// xor-swizzled smem byte offset for a [128 rows x 32 halves] tile (row = 64B)
__device__ __forceinline__ uint32_t swoff(int m, int kg) {
    return (uint32_t)(m * 64 + ((kg ^ ((m >> 1) & 3)) << 4));
}

// ---------------- 4x4 micro FMA (attention core) -----------------------------
__device__ __forceinline__ void micro(float (&acc)[4][4], float4 a, float4 b) {
    float av[4] = {a.x, a.y, a.z, a.w};
    float bv[4] = {b.x, b.y, b.z, b.w};
#pragma unroll
    for (int i = 0; i < 4; i++)
#pragma unroll
        for (int j = 0; j < 4; j++) acc[i][j] = fmaf(av[i], bv[j], acc[i][j]);
}

// ============ transpose + fp16 hi/lo split: W[R,C] -> WT_hi/lo[C,R] ==========
__global__ void tsplit(const float* __restrict__ W, __half* __restrict__ Th,
                       __half* __restrict__ Tl, int R, int C) {
    __shared__ float t[32][33];
    int e = blockIdx.z;
    W  += (size_t)e * R * C;
    Th += (size_t)e * R * C;
    Tl += (size_t)e * R * C;
    int r0 = blockIdx.y * 32, c0 = blockIdx.x * 32;
#pragma unroll
    for (int i = threadIdx.y; i < 32; i += 8)
        t[i][threadIdx.x] = W[(size_t)(r0 + i) * C + c0 + threadIdx.x];
    __syncthreads();
#pragma unroll
    for (int i = threadIdx.y; i < 32; i += 8) {
        float v = t[threadIdx.x][i];
        __half h = __float2half_rn(v);
        size_t o = (size_t)(c0 + i) * R + r0 + threadIdx.x;
        Th[o] = h;
        Tl[o] = __float2half_rn(v - __half2float(h));
    }
}

// ============ elementwise fp32 -> fp16 hi/lo split ===========================
__global__ void fsplit(const float* __restrict__ src, __half* __restrict__ h,
                       __half* __restrict__ l) {
    int i = (blockIdx.x * 256 + threadIdx.x) * 4;
    float4 v = *(const float4*)(src + i);
    __half h0 = __float2half_rn(v.x), h1 = __float2half_rn(v.y);
    __half h2 = __float2half_rn(v.z), h3 = __float2half_rn(v.w);
    *(__half2*)(h + i)     = __halves2half2(h0, h1);
    *(__half2*)(h + i + 2) = __halves2half2(h2, h3);
    *(__half2*)(l + i)     = __halves2half2(__float2half_rn(v.x - __half2float(h0)),
                                            __float2half_rn(v.y - __half2float(h1)));
    *(__half2*)(l + i + 2) = __halves2half2(__float2half_rn(v.z - __half2float(h2)),
                                            __float2half_rn(v.w - __half2float(h3)));
}

// ================= unified fp16x3 pipelined HMMA GEMM ========================
// MODE 0: QKV   A=g_xsh/l [t][768]     B=g_wqkvh/l [2304][768]  -> g_q/g_k/g_v
// MODE 1: PROJ  A=g_ch/l  [t][768]     B=g_woh/l   [768][768]   -> g_preln (+bo+X)
// MODE 2: UP    A=g_xlh/l gathered     B=g_wuh/l e [3072][768]  -> g_big = gelu(u)
// MODE 3: GATE  A=g_xlh/l gathered     B=g_wnh/l e [3072][768]  -> g_hh/g_hl = g_big*(C+b)
// MODE 4: DOWN  A=g_hh/l  [r][3072]    B=g_wdh/l e [768][3072]  -> atomicAdd out (gated)
template<int MODE>
__global__ void __launch_bounds__(256, 2) hgemm(
    const float* __restrict__ p0, const float* __restrict__ p1,
    const float* __restrict__ p2, float* __restrict__ pout) {

    constexpr int KD = (MODE == 4) ? II : HH;
    constexpr int NS = KD / 32;

    int e = 0, base = 0, end = 0, m0 = 0;
    if (MODE >= 2) {
        e = blockIdx.y >> 5;
        int lt = blockIdx.y & 31;
        base = g_off[e] + lt * 128;
        end  = g_off[e] + g_cnt[e];
        if (base >= end) return;
    } else {
        m0 = blockIdx.y * 128;
    }
    int n0 = blockIdx.x * 128;

    extern __shared__ char dyn[];
    __shared__ int   s_tok[128];
    __shared__ float s_w[128];

    int tid = threadIdx.x, lane = tid & 31, wid = tid >> 5;
    int wm = wid & 1, wn = wid >> 1;

    if (MODE >= 2 && tid < 128) {
        int r = min(base + tid, end - 1);
        s_tok[tid] = g_etok[r];
        s_w[tid]   = g_ew[r];
    }
    __syncthreads();

    const __half *Bh, *Bl, *Ah, *Al;
    if (MODE == 0)      { Bh = g_wqkvh; Bl = g_wqkvl; Ah = g_xsh; Al = g_xsl; }
    else if (MODE == 1) { Bh = g_woh;   Bl = g_wol;   Ah = g_ch;  Al = g_cl; }
    else if (MODE == 2) { Bh = g_wuh + (size_t)e * II * HH; Bl = g_wul + (size_t)e * II * HH;
                          Ah = g_xlh; Al = g_xll; }
    else if (MODE == 3) { Bh = g_wnh + (size_t)e * II * HH; Bl = g_wnl + (size_t)e * II * HH;
                          Ah = g_xlh; Al = g_xll; }
    else                { Bh = g_wdh + (size_t)e * HH * II; Bl = g_wdl + (size_t)e * HH * II;
                          Ah = g_hh;  Al = g_hl; }

    uint32_t sbase = smem_u32(dyn);

    auto issue = [&](int slab, int st) {
        int k0 = slab * 32;
        uint32_t sb = sbase + st * 32768;
#pragma unroll
        for (int i = 0; i < 2; i++) {
            int c = tid + i * 256;
            int m = c >> 2, kc = c & 3;
            uint32_t so = sb + swoff(m, kc);
            int koff = k0 + kc * 8;
            size_t aoff;
            if (MODE < 2)       aoff = (size_t)(m0 + m) * KD;
            else if (MODE <= 3) aoff = (size_t)s_tok[m] * KD;
            else                aoff = (size_t)min(base + m, end - 1) * KD;
            cpasync16(so,         Ah + aoff + koff);
            cpasync16(so + 8192,  Al + aoff + koff);
            size_t boff = (size_t)(n0 + m) * KD + koff;
            cpasync16(so + 16384, Bh + boff);
            cpasync16(so + 24576, Bl + boff);
        }
    };

    int j = lane >> 3, rr = lane & 7;
    int amRow = wm * 64 + (j & 1) * 8 + rr;
    int akSel = j >> 1;
    int bnRow = wn * 32 + (j >> 1) * 8 + rr;
    int bkSel = j & 1;
    float C[4][4][4] = {};

    issue(0, 0);
    CP_COMMIT();
    for (int s = 0; s < NS; s++) {
        int st = s & 1;
        if (s + 1 < NS) {
            issue(s + 1, st ^ 1);
            CP_COMMIT();
            CP_WAIT1();
        } else {
            CP_WAIT0();
        }
        __syncthreads();
        uint32_t aH = sbase + st * 32768, aL = aH + 8192;
        uint32_t bH = aH + 16384, bL = aH + 24576;
#pragma unroll
        for (int kk = 0; kk < 2; kk++) {
            uint32_t bh[4][2], bl[4][2];
#pragma unroll
            for (int fp = 0; fp < 2; fp++) {
                int n = bnRow + fp * 16;
                int kg = kk * 2 + bkSel;
                uint32_t o = (uint32_t)(n * 64 + ((kg ^ ((n >> 1) & 3)) << 4));
                ldsm4(bh[fp * 2][0], bh[fp * 2][1], bh[fp * 2 + 1][0], bh[fp * 2 + 1][1], bH + o);
                ldsm4(bl[fp * 2][0], bl[fp * 2][1], bl[fp * 2 + 1][0], bl[fp * 2 + 1][1], bL + o);
            }
#pragma unroll
            for (int fm = 0; fm < 4; fm++) {
                int m = amRow + fm * 16;
                int kg = kk * 2 + akSel;
                uint32_t o = (uint32_t)(m * 64 + ((kg ^ ((m >> 1) & 3)) << 4));
                uint32_t ah[4], al[4];
                ldsm4(ah[0], ah[1], ah[2], ah[3], aH + o);
                ldsm4(al[0], al[1], al[2], al[3], aL + o);
#pragma unroll
                for (int fn = 0; fn < 4; fn++) {
                    mma16816(C[fm][fn], ah, bh[fn]);
                    mma16816(C[fm][fn], ah, bl[fn]);
                    mma16816(C[fm][fn], al, bh[fn]);
                }
            }
        }
        __syncthreads();
    }

    // ----------------------------- epilogue ---------------------------------
    int g = lane >> 2, tig = lane & 3;

    // MODE 0 per-CTA constants (whole 128-col tile lies in one of q/k/v)
    float* qkvout = nullptr;
    const float* mbias = nullptr;
    int hcol0 = 0;
    if (MODE == 0) {
        int which = n0 / HH;
        qkvout = (which == 0) ? g_q : (which == 1) ? g_k : g_v;
        mbias  = (which == 0) ? p0 : (which == 1) ? p1 : p2;
        hcol0  = n0 - which * HH;
    }

#pragma unroll
    for (int fm = 0; fm < 4; fm++) {
        int rowl0 = wm * 64 + fm * 16 + g;
#pragma unroll
        for (int fn = 0; fn < 4; fn++) {
            int coll = wn * 32 + fn * 8 + tig * 2;
#pragma unroll
            for (int hf = 0; hf < 2; hf++) {
                int ml = rowl0 + hf * 8;
                float c0 = C[fm][fn][hf * 2], c1 = C[fm][fn][hf * 2 + 1];
                if (MODE == 0) {
                    int t = m0 + ml;
                    int hcol = hcol0 + coll;
                    int h = hcol >> 6, d = hcol & 63;
                    int b = t >> 9, sI = t & 511;
                    float2 v = {c0 + mbias[hcol], c1 + mbias[hcol + 1]};
                    *(float2*)(qkvout + (((size_t)(b * NHH + h)) * SS + sI) * DHH + d) = v;
                } else if (MODE == 1) {
                    size_t t = m0 + ml;
                    int col = n0 + coll;
                    float2 xr = *(const float2*)(p1 + t * HH + col);
                    float2 v = {c0 + p0[col] + xr.x, c1 + p0[col + 1] + xr.y};
                    *(float2*)(g_preln + t * HH + col) = v;
                } else if (MODE == 2) {
                    int r = base + ml;
                    if (r < end) {
                        int col = n0 + coll;
                        const float* eb = p0 + (size_t)e * II;
                        float u0 = c0 + eb[col], u1 = c1 + eb[col + 1];
                        float2 v = {u0 * normcdff(u0), u1 * normcdff(u1)};
                        *(float2*)(g_big + (size_t)r * II + col) = v;
                    }
                } else if (MODE == 3) {
                    int r = base + ml;
                    if (r < end) {
                        int col = n0 + coll;
                        const float* eb = p0 + (size_t)e * II;
                        float2 gu = *(const float2*)(g_big + (size_t)r * II + col);
                        float h0 = gu.x * (c0 + eb[col]);
                        float h1 = gu.y * (c1 + eb[col + 1]);
                        __half p0h = __float2half_rn(h0), p1h = __float2half_rn(h1);
                        *(__half2*)(g_hh + (size_t)r * II + col) = __halves2half2(p0h, p1h);
                        *(__half2*)(g_hl + (size_t)r * II + col) = __halves2half2(
                            __float2half_rn(h0 - __half2float(p0h)),
                            __float2half_rn(h1 - __half2float(p1h)));
                    }
                } else {
                    if (base + ml < end) {
                        int col = n0 + coll;
                        int t = s_tok[ml];
                        float w = s_w[ml];
                        const float* eb = p0 + (size_t)e * HH;
                        atomicAdd(pout + (size_t)t * HH + col,     (c0 + eb[col]) * w);
                        atomicAdd(pout + (size_t)t * HH + col + 1, (c1 + eb[col + 1]) * w);
                    }
                }
            }
        }
    }
}

// ================= K2: attention scores (Q @ K^T / 8) =======================
__global__ void scores_kernel() {
    int head = blockIdx.z;
    const float* Q = g_q + (size_t)head * SS * DHH;
    const float* K = g_k + (size_t)head * SS * DHH;
    float* Sc = g_big + (size_t)head * SS * SS;

    __shared__ float Qs[64][68];
    __shared__ float Ks[64][68];
    int tid = threadIdx.x;
    int q0 = blockIdx.y * 64, k0 = blockIdx.x * 64;

#pragma unroll
    for (int i = 0; i < 4; i++) {
        int idx = tid + i * 256;
        int m = idx >> 4, dq = (idx & 15) * 4;
        float4 a = *(const float4*)&Q[(size_t)(q0 + m) * DHH + dq];
        Qs[dq + 0][m] = a.x; Qs[dq + 1][m] = a.y; Qs[dq + 2][m] = a.z; Qs[dq + 3][m] = a.w;
        float4 b = *(const float4*)&K[(size_t)(k0 + m) * DHH + dq];
        Ks[dq + 0][m] = b.x; Ks[dq + 1][m] = b.y; Ks[dq + 2][m] = b.z; Ks[dq + 3][m] = b.w;
    }
    __syncthreads();

    int tx = tid & 15, ty = tid >> 4;
    float acc[4][4] = {};
#pragma unroll 16
    for (int d = 0; d < 64; d++) {
        float4 a = *(float4*)&Qs[d][ty * 4];
        float4 b = *(float4*)&Ks[d][tx * 4];
        micro(acc, a, b);
    }
#pragma unroll
    for (int i = 0; i < 4; i++)
#pragma unroll
        for (int j = 0; j < 4; j++)
            Sc[(size_t)(q0 + ty * 4 + i) * SS + k0 + tx * 4 + j] = acc[i][j] * 0.125f;
}

// ================= K3: row softmax over 512 ==================================
__global__ void softmax_kernel() {
    size_t row = blockIdx.x;
    float* p = g_big + row * SS;
    int tid = threadIdx.x;
    float v0 = p[tid], v1 = p[tid + 256];

    __shared__ float red[256];
    red[tid] = fmaxf(v0, v1);
    __syncthreads();
    for (int s = 128; s > 0; s >>= 1) {
        if (tid < s) red[tid] = fmaxf(red[tid], red[tid + s]);
        __syncthreads();
    }
    float mx = red[0];
    __syncthreads();

    float e0 = expf(v0 - mx), e1 = expf(v1 - mx);
    red[tid] = e0 + e1;
    __syncthreads();
    for (int s = 128; s > 0; s >>= 1) {
        if (tid < s) red[tid] += red[tid + s];
        __syncthreads();
    }
    float inv = 1.0f / red[0];
    p[tid] = e0 * inv;
    p[tid + 256] = e1 * inv;
}

// ================= K4: ctx = probs @ V (writes back to [T,H]) ================
__global__ void ctx_kernel() {
    int head = blockIdx.y;
    const float* P = g_big + (size_t)head * SS * SS;
    const float* V = g_v + (size_t)head * SS * DHH;

    __shared__ float As[16][68];
    __shared__ float Bs[16][68];
    int tid = threadIdx.x;
    int tx = tid & 15, ty = tid >> 4;
    int m0 = blockIdx.x * 64;
    float acc[4][4] = {};

    for (int k0 = 0; k0 < SS; k0 += 16) {
        {
            int m = tid >> 2, kq = (tid & 3) * 4;
            float4 a = *(const float4*)&P[(size_t)(m0 + m) * SS + k0 + kq];
            As[kq + 0][m] = a.x; As[kq + 1][m] = a.y; As[kq + 2][m] = a.z; As[kq + 3][m] = a.w;
        }
        {
            int kk = tid >> 4, n4 = (tid & 15) * 4;
            *(float4*)&Bs[kk][n4] = *(const float4*)&V[(size_t)(k0 + kk) * DHH + n4];
        }
        __syncthreads();
#pragma unroll
        for (int kk = 0; kk < 16; kk++) {
            float4 a = *(float4*)&As[kk][ty * 4];
            float4 b = *(float4*)&Bs[kk][tx * 4];
            micro(acc, a, b);
        }
        __syncthreads();
    }
    int b = head / NHH, h = head % NHH;
#pragma unroll
    for (int i = 0; i < 4; i++) {
        int q = m0 + ty * 4 + i;
        size_t t = (size_t)b * SS + q;
#pragma unroll
        for (int j = 0; j < 4; j++) {
            int d = tx * 4 + j;
            g_ctx[t * HH + h * 64 + d] = acc[i][j];
        }
    }
}

// ================= LayerNorm ==================================================
__global__ void ln_kernel(const float* __restrict__ gamma, const float* __restrict__ beta,
                          float* __restrict__ dout, int mode) {
    size_t row = blockIdx.x;
    const float* in = (mode == 0) ? (g_preln + row * HH) : (g_attnout + row * HH);
    int tid = threadIdx.x;
    float x0 = in[tid], x1 = in[tid + 256], x2 = in[tid + 512];

    __shared__ float red[256];
    red[tid] = x0 + x1 + x2;
    __syncthreads();
    for (int s = 128; s > 0; s >>= 1) {
        if (tid < s) red[tid] += red[tid + s];
        __syncthreads();
    }
    float mean = red[0] * (1.0f / HH);
    __syncthreads();

    float c0 = x0 - mean, c1 = x1 - mean, c2 = x2 - mean;
    red[tid] = c0 * c0 + c1 * c1 + c2 * c2;
    __syncthreads();
    for (int s = 128; s > 0; s >>= 1) {
        if (tid < s) red[tid] += red[tid + s];
        __syncthreads();
    }
    float inv = 1.0f / sqrtf(red[0] * (1.0f / HH) + 1e-12f);

    float y0 = c0 * inv * gamma[tid]       + beta[tid];
    float y1 = c1 * inv * gamma[tid + 256] + beta[tid + 256];
    float y2 = c2 * inv * gamma[tid + 512] + beta[tid + 512];
    if (mode == 0) {
        g_attnout[row * HH + tid]       = y0;
        g_attnout[row * HH + tid + 256] = y1;
        g_attnout[row * HH + tid + 512] = y2;
        dout[row * HH + tid]       = y0;
        dout[row * HH + tid + 256] = y1;
        dout[row * HH + tid + 512] = y2;
    } else {
        g_xl[row * HH + tid]       = y0;
        g_xl[row * HH + tid + 256] = y1;
        g_xl[row * HH + tid + 512] = y2;
        __half h0 = __float2half_rn(y0), h1 = __float2half_rn(y1), h2 = __float2half_rn(y2);
        g_xlh[row * HH + tid]       = h0;
        g_xlh[row * HH + tid + 256] = h1;
        g_xlh[row * HH + tid + 512] = h2;
        g_xll[row * HH + tid]       = __float2half_rn(y0 - __half2float(h0));
        g_xll[row * HH + tid + 256] = __float2half_rn(y1 - __half2float(h1));
        g_xll[row * HH + tid + 512] = __float2half_rn(y2 - __half2float(h2));
    }
}

// ================= counters / router / scatter ===============================
__global__ void init_kernel() {
    int i = threadIdx.x;
    if (i < EE) { g_cnt[i] = 0; g_cur[i] = 0; }
}

__global__ void router_kernel(const float* __restrict__ Wr, const float* __restrict__ br,
                              float* __restrict__ logits_out) {
    int warp = threadIdx.x >> 5, lane = threadIdx.x & 31;
    int t = blockIdx.x * 8 + warp;
    const float* x = g_xl + (size_t)t * HH;

    float acc[EE] = {};
    for (int h = lane; h < HH; h += 32) {
        float xv = x[h];
        const float* w = Wr + (size_t)h * EE;
#pragma unroll
        for (int e = 0; e < EE; e++) acc[e] = fmaf(xv, w[e], acc[e]);
    }
#pragma unroll
    for (int e = 0; e < EE; e++)
        for (int o = 16; o > 0; o >>= 1) acc[e] += __shfl_down_sync(0xffffffffu, acc[e], o);

    if (lane == 0) {
        float lg[EE], mx = -1e30f;
#pragma unroll
        for (int e = 0; e < EE; e++) {
            lg[e] = acc[e] + br[e];
            logits_out[(size_t)t * EE + e] = lg[e];
            mx = fmaxf(mx, lg[e]);
        }
        float p[EE], s = 0.0f;
#pragma unroll
        for (int e = 0; e < EE; e++) { p[e] = expf(lg[e] - mx); s += p[e]; }
        float invs = 1.0f / s;
#pragma unroll
        for (int e = 0; e < EE; e++) p[e] *= invs;

        int i1 = 0;
#pragma unroll
        for (int e = 1; e < EE; e++) if (p[e] > p[i1]) i1 = e;
        int i2 = (i1 == 0) ? 1 : 0;
#pragma unroll
        for (int e = 0; e < EE; e++) if (e != i1 && p[e] > p[i2]) i2 = e;

        float w1 = p[i1], w2 = p[i2], inv = 1.0f / (w1 + w2);
        g_ti[t * 2]     = i1;  g_tw[t * 2]     = w1 * inv;
        g_ti[t * 2 + 1] = i2;  g_tw[t * 2 + 1] = w2 * inv;
        atomicAdd(&g_cnt[i1], 1);
        atomicAdd(&g_cnt[i2], 1);
    }
}

__global__ void offsets_kernel() {
    if (threadIdx.x == 0) {
        int o = 0;
        for (int e = 0; e < EE; e++) { g_off[e] = o; o += g_cnt[e]; }
    }
}

__global__ void scatter_kernel() {
    int t = blockIdx.x * 256 + threadIdx.x;
    if (t >= TT) return;
#pragma unroll
    for (int s = 0; s < 2; s++) {
        int e = g_ti[t * 2 + s];
        int pos = atomicAdd(&g_cur[e], 1);
        int r = g_off[e] + pos;
        g_etok[r] = t;
        g_ew[r] = g_tw[t * 2 + s];
    }
}

// ================= host launcher =============================================
#define HG_SMEM 65536

extern "C" void kernel_launch(void* const* d_in, const int* in_sizes, int n_in,
                              void* d_out, int out_size) {
    const float* X        = (const float*)d_in[0];
    const float* Wq       = (const float*)d_in[1];
    const float* bq       = (const float*)d_in[2];
    const float* Wk       = (const float*)d_in[3];
    const float* bk       = (const float*)d_in[4];
    const float* Wv       = (const float*)d_in[5];
    const float* bv       = (const float*)d_in[6];
    const float* Wo       = (const float*)d_in[7];
    const float* bo       = (const float*)d_in[8];
    const float* ln_ag    = (const float*)d_in[9];
    const float* ln_ab    = (const float*)d_in[10];
    const float* ln_fg    = (const float*)d_in[11];
    const float* ln_fb    = (const float*)d_in[12];
    const float* Wr       = (const float*)d_in[13];
    const float* br       = (const float*)d_in[14];
    const float* W_up     = (const float*)d_in[15];
    const float* b_up     = (const float*)d_in[16];
    const float* W_new    = (const float*)d_in[17];
    const float* b_new    = (const float*)d_in[18];
    const float* W_down   = (const float*)d_in[19];
    const float* b_down   = (const float*)d_in[20];

    float* out    = (float*)d_out;                    // layer_output [T, H]
    float* logits = out + (size_t)TT * HH;            // router_logits [T, E]

    static int attr_done = 0;
    if (!attr_done) {
        cudaFuncSetAttribute(hgemm<0>, cudaFuncAttributeMaxDynamicSharedMemorySize, HG_SMEM);
        cudaFuncSetAttribute(hgemm<1>, cudaFuncAttributeMaxDynamicSharedMemorySize, HG_SMEM);
        cudaFuncSetAttribute(hgemm<2>, cudaFuncAttributeMaxDynamicSharedMemorySize, HG_SMEM);
        cudaFuncSetAttribute(hgemm<3>, cudaFuncAttributeMaxDynamicSharedMemorySize, HG_SMEM);
        cudaFuncSetAttribute(hgemm<4>, cudaFuncAttributeMaxDynamicSharedMemorySize, HG_SMEM);
        attr_done = 1;
    }

    __half *wqkvh, *wqkvl, *woh, *wol, *wuh, *wul, *wnh, *wnl, *wdh, *wdl;
    __half *xsh, *xsl, *ch, *cl;
    float *ctxp;
    cudaGetSymbolAddress((void**)&wqkvh, g_wqkvh);
    cudaGetSymbolAddress((void**)&wqkvl, g_wqkvl);
    cudaGetSymbolAddress((void**)&woh, g_woh);
    cudaGetSymbolAddress((void**)&wol, g_wol);
    cudaGetSymbolAddress((void**)&wuh, g_wuh);
    cudaGetSymbolAddress((void**)&wul, g_wul);
    cudaGetSymbolAddress((void**)&wnh, g_wnh);
    cudaGetSymbolAddress((void**)&wnl, g_wnl);
    cudaGetSymbolAddress((void**)&wdh, g_wdh);
    cudaGetSymbolAddress((void**)&wdl, g_wdl);
    cudaGetSymbolAddress((void**)&xsh, g_xsh);
    cudaGetSymbolAddress((void**)&xsl, g_xsl);
    cudaGetSymbolAddress((void**)&ch, g_ch);
    cudaGetSymbolAddress((void**)&cl, g_cl);
    cudaGetSymbolAddress((void**)&ctxp, g_ctx);

    // weight prep: transpose + fp16 hi/lo split
    tsplit<<<dim3(HH / 32, HH / 32, 1), dim3(32, 8)>>>(Wq, wqkvh,              wqkvl,              HH, HH);
    tsplit<<<dim3(HH / 32, HH / 32, 1), dim3(32, 8)>>>(Wk, wqkvh + HH * HH,    wqkvl + HH * HH,    HH, HH);
    tsplit<<<dim3(HH / 32, HH / 32, 1), dim3(32, 8)>>>(Wv, wqkvh + 2 * HH * HH, wqkvl + 2 * HH * HH, HH, HH);
    tsplit<<<dim3(HH / 32, HH / 32, 1), dim3(32, 8)>>>(Wo, woh, wol, HH, HH);
    tsplit<<<dim3(II / 32, HH / 32, EE), dim3(32, 8)>>>(W_up,  wuh, wul, HH, II);
    tsplit<<<dim3(II / 32, HH / 32, EE), dim3(32, 8)>>>(W_new, wnh, wnl, HH, II);
    tsplit<<<dim3(HH / 32, II / 32, EE), dim3(32, 8)>>>(W_down, wdh, wdl, II, HH);

    init_kernel<<<1, 32>>>();
    fsplit<<<TT * HH / 1024, 256>>>(X, xsh, xsl);

    // QKV (fused) -> attention core -> proj
    hgemm<0><<<dim3(3 * HH / 128, TT / 128), 256, HG_SMEM>>>(bq, bk, bv, nullptr);
    scores_kernel<<<dim3(SS / 64, SS / 64, BB * NHH), 256>>>();
    softmax_kernel<<<BB * NHH * SS, 256>>>();
    ctx_kernel<<<dim3(SS / 64, BB * NHH), 256>>>();
    fsplit<<<TT * HH / 1024, 256>>>(ctxp, ch, cl);
    hgemm<1><<<dim3(HH / 128, TT / 128), 256, HG_SMEM>>>(bo, X, nullptr, nullptr);

    ln_kernel<<<TT, 256>>>(ln_ag, ln_ab, out, 0);
    ln_kernel<<<TT, 256>>>(ln_fg, ln_fb, out, 1);
    router_kernel<<<TT / 8, 256>>>(Wr, br, logits);
    offsets_kernel<<<1, 32>>>();
    scatter_kernel<<<(TT + 255) / 256, 256>>>();

    // MoE FFN
    hgemm<2><<<dim3(II / 128, EE * 32), 256, HG_SMEM>>>(b_up, nullptr, nullptr, nullptr);
    hgemm<3><<<dim3(II / 128, EE * 32), 256, HG_SMEM>>>(b_new, nullptr, nullptr, nullptr);
    hgemm<4><<<dim3(HH / 128, EE * 32), 256, HG_SMEM>>>(b_down, nullptr, nullptr, out);
}

// round 5
// speedup vs baseline: 2.6937x; 1.1822x over previous
#include <cuda_runtime.h>
#include <cuda_fp16.h>
#include <math.h>
#include <stdint.h>

#define TT  4096   // B*S
#define HH  768
#define SS  512
#define BB  8
#define NHH 12
#define DHH 64
#define II  3072
#define EE  8
#define ENT 8192   // TT * TOPK

// ---------------- scratch (static device allocations; no cudaMalloc) --------
__device__ float g_preln[TT * HH];
__device__ float g_attnout[TT * HH];
__device__ float g_xl[TT * HH];
__device__ __half g_xlh[TT * HH];           // xl split
__device__ __half g_xll[TT * HH];
__device__ __half g_xsh[TT * HH];           // X split
__device__ __half g_xsl[TT * HH];
__device__ __half g_qh[TT * HH];            // Q split, [B*NH][S][DH]
__device__ __half g_ql[TT * HH];
__device__ __half g_kh[TT * HH];
__device__ __half g_kl[TT * HH];
__device__ __half g_vh[TT * HH];
__device__ __half g_vl[TT * HH];
__device__ __half g_ch[TT * HH];            // ctx split [T][H]
__device__ __half g_cl[TT * HH];
__device__ __half g_hh[(size_t)ENT * II];   // FFN hidden h = gelu(u)*gate, hi
__device__ __half g_hl[(size_t)ENT * II];   // lo
__device__ __half g_wqkvh[3 * HH * HH];     // [Wq^T;Wk^T;Wv^T] [2304][768]
__device__ __half g_wqkvl[3 * HH * HH];
__device__ __half g_woh[HH * HH];           // Wo^T
__device__ __half g_wol[HH * HH];
__device__ __half g_wuh[(size_t)EE * II * HH];  // W_up^T  hi [E][I][H]
__device__ __half g_wul[(size_t)EE * II * HH];
__device__ __half g_wnh[(size_t)EE * II * HH];  // W_new^T hi
__device__ __half g_wnl[(size_t)EE * II * HH];
__device__ __half g_wdh[(size_t)EE * HH * II];  // W_down^T hi [E][H][I]
__device__ __half g_wdl[(size_t)EE * HH * II];
__device__ int   g_cnt[EE];
__device__ int   g_off[EE];
__device__ int   g_cur[EE];
__device__ int   g_etok[ENT];
__device__ float g_ew[ENT];
__device__ int   g_ti[TT * 2];
__device__ float g_tw[TT * 2];

// ======================= asm helpers (portable sm_80+) =======================
__device__ __forceinline__ uint32_t smem_u32(const void* p) {
    uint32_t a;
    asm("{ .reg .u64 t; cvta.to.shared.u64 t, %1; cvt.u32.u64 %0, t; }" : "=r"(a) : "l"(p));
    return a;
}
__device__ __forceinline__ void ldsm4(uint32_t& r0, uint32_t& r1, uint32_t& r2, uint32_t& r3,
                                      uint32_t addr) {
    asm volatile("ldmatrix.sync.aligned.m8n8.x4.shared.b16 {%0,%1,%2,%3}, [%4];"
                 : "=r"(r0), "=r"(r1), "=r"(r2), "=r"(r3) : "r"(addr));
}
__device__ __forceinline__ void ldsm4t(uint32_t& r0, uint32_t& r1, uint32_t& r2, uint32_t& r3,
                                       uint32_t addr) {
    asm volatile("ldmatrix.sync.aligned.m8n8.x4.trans.shared.b16 {%0,%1,%2,%3}, [%4];"
                 : "=r"(r0), "=r"(r1), "=r"(r2), "=r"(r3) : "r"(addr));
}
__device__ __forceinline__ void mma16816(float* c, const uint32_t* a, const uint32_t* b) {
    asm volatile(
        "mma.sync.aligned.m16n8k16.row.col.f32.f16.f16.f32 "
        "{%0,%1,%2,%3}, {%4,%5,%6,%7}, {%8,%9}, {%0,%1,%2,%3};"
        : "+f"(c[0]), "+f"(c[1]), "+f"(c[2]), "+f"(c[3])
        : "r"(a[0]), "r"(a[1]), "r"(a[2]), "r"(a[3]), "r"(b[0]), "r"(b[1]));
}
__device__ __forceinline__ void cpasync16(uint32_t saddr, const void* gaddr) {
    asm volatile("cp.async.cg.shared.global [%0], [%1], 16;" :: "r"(saddr), "l"(gaddr));
}
#define CP_COMMIT() asm volatile("cp.async.commit_group;" ::: "memory")
#define CP_WAIT1()  asm volatile("cp.async.wait_group 1;" ::: "memory")
#define CP_WAIT0()  asm volatile("cp.async.wait_group 0;" ::: "memory")

// xor-swizzled smem byte offset for a [rows x 32 halves] tile (row = 64B)
__device__ __forceinline__ uint32_t swoff(int m, int kg) {
    return (uint32_t)(m * 64 + ((kg ^ ((m >> 1) & 3)) << 4));
}
// xor-swizzled smem byte offset for a [rows x 64 halves] tile (row = 128B, 8 chunks)
__device__ __forceinline__ uint32_t fswz(int m, int c) {
    return (uint32_t)(m * 128 + ((c ^ (m & 7)) << 4));
}
__device__ __forceinline__ uint32_t packsplit(float v0, float v1, uint32_t& lo) {
    __half h0 = __float2half_rn(v0), h1 = __float2half_rn(v1);
    __half2 l = __halves2half2(__float2half_rn(v0 - __half2float(h0)),
                               __float2half_rn(v1 - __half2float(h1)));
    lo = *(uint32_t*)&l;
    __half2 h = __halves2half2(h0, h1);
    return *(uint32_t*)&h;
}

// ============ transpose + fp16 hi/lo split: W[R,C] -> WT_hi/lo[C,R] ==========
__global__ void tsplit(const float* __restrict__ W, __half* __restrict__ Th,
                       __half* __restrict__ Tl, int R, int C) {
    __shared__ float t[32][33];
    int e = blockIdx.z;
    W  += (size_t)e * R * C;
    Th += (size_t)e * R * C;
    Tl += (size_t)e * R * C;
    int r0 = blockIdx.y * 32, c0 = blockIdx.x * 32;
#pragma unroll
    for (int i = threadIdx.y; i < 32; i += 8)
        t[i][threadIdx.x] = W[(size_t)(r0 + i) * C + c0 + threadIdx.x];
    __syncthreads();
#pragma unroll
    for (int i = threadIdx.y; i < 32; i += 8) {
        float v = t[threadIdx.x][i];
        __half h = __float2half_rn(v);
        size_t o = (size_t)(c0 + i) * R + r0 + threadIdx.x;
        Th[o] = h;
        Tl[o] = __float2half_rn(v - __half2float(h));
    }
}

// ============ elementwise fp32 -> fp16 hi/lo split ===========================
__global__ void fsplit(const float* __restrict__ src, __half* __restrict__ h,
                       __half* __restrict__ l) {
    int i = (blockIdx.x * 256 + threadIdx.x) * 4;
    float4 v = *(const float4*)(src + i);
    uint32_t lo0, lo1;
    uint32_t h0 = packsplit(v.x, v.y, lo0);
    uint32_t h1 = packsplit(v.z, v.w, lo1);
    *(uint32_t*)(h + i)     = h0;
    *(uint32_t*)(h + i + 2) = h1;
    *(uint32_t*)(l + i)     = lo0;
    *(uint32_t*)(l + i + 2) = lo1;
}

// ================= unified fp16x3 pipelined HMMA GEMM ========================
// MODE 0: QKV   A=g_xsh/l [t][768]   B=g_wqkvh/l [2304][768] -> g_qh..g_vl split
// MODE 1: PROJ  A=g_ch/l  [t][768]   B=g_woh/l   [768][768]  -> g_preln (+bo+X)
// MODE 2: DOWN  A=g_hh/l  [r][3072]  B=g_wdh/l e [768][3072] -> atomicAdd out
template<int MODE>
__global__ void __launch_bounds__(256, 2) hgemm(
    const float* __restrict__ p0, const float* __restrict__ p1,
    const float* __restrict__ p2, float* __restrict__ pout) {

    constexpr int KD = (MODE == 2) ? II : HH;
    constexpr int NS = KD / 32;

    int e = 0, base = 0, end = 0, m0 = 0;
    if (MODE == 2) {
        e = blockIdx.y >> 5;
        int lt = blockIdx.y & 31;
        base = g_off[e] + lt * 128;
        end  = g_off[e] + g_cnt[e];
        if (base >= end) return;
    } else {
        m0 = blockIdx.y * 128;
    }
    int n0 = blockIdx.x * 128;

    extern __shared__ char dyn[];
    __shared__ int   s_tok[128];
    __shared__ float s_w[128];

    int tid = threadIdx.x, lane = tid & 31, wid = tid >> 5;
    int wm = wid & 1, wn = wid >> 1;

    if (MODE == 2 && tid < 128) {
        int r = min(base + tid, end - 1);
        s_tok[tid] = g_etok[r];
        s_w[tid]   = g_ew[r];
    }
    __syncthreads();

    const __half *Bh, *Bl, *Ah, *Al;
    if (MODE == 0)      { Bh = g_wqkvh; Bl = g_wqkvl; Ah = g_xsh; Al = g_xsl; }
    else if (MODE == 1) { Bh = g_woh;   Bl = g_wol;   Ah = g_ch;  Al = g_cl; }
    else                { Bh = g_wdh + (size_t)e * HH * II; Bl = g_wdl + (size_t)e * HH * II;
                          Ah = g_hh;  Al = g_hl; }

    uint32_t sbase = smem_u32(dyn);

    auto issue = [&](int slab, int st) {
        int k0 = slab * 32;
        uint32_t sb = sbase + st * 32768;
#pragma unroll
        for (int i = 0; i < 2; i++) {
            int c = tid + i * 256;
            int m = c >> 2, kc = c & 3;
            uint32_t so = sb + swoff(m, kc);
            int koff = k0 + kc * 8;
            size_t aoff;
            if (MODE < 2) aoff = (size_t)(m0 + m) * KD;
            else          aoff = (size_t)min(base + m, end - 1) * KD;
            cpasync16(so,         Ah + aoff + koff);
            cpasync16(so + 8192,  Al + aoff + koff);
            size_t boff = (size_t)(n0 + m) * KD + koff;
            cpasync16(so + 16384, Bh + boff);
            cpasync16(so + 24576, Bl + boff);
        }
    };

    int j = lane >> 3, rr = lane & 7;
    int amRow = wm * 64 + (j & 1) * 8 + rr;
    int akSel = j >> 1;
    int bnRow = wn * 32 + (j >> 1) * 8 + rr;
    int bkSel = j & 1;
    float C[4][4][4] = {};

    issue(0, 0);
    CP_COMMIT();
    for (int s = 0; s < NS; s++) {
        int st = s & 1;
        if (s + 1 < NS) {
            issue(s + 1, st ^ 1);
            CP_COMMIT();
            CP_WAIT1();
        } else {
            CP_WAIT0();
        }
        __syncthreads();
        uint32_t aH = sbase + st * 32768, aL = aH + 8192;
        uint32_t bH = aH + 16384, bL = aH + 24576;
#pragma unroll
        for (int kk = 0; kk < 2; kk++) {
            uint32_t bh[4][2], bl[4][2];
#pragma unroll
            for (int fp = 0; fp < 2; fp++) {
                int n = bnRow + fp * 16;
                int kg = kk * 2 + bkSel;
                uint32_t o = (uint32_t)(n * 64 + ((kg ^ ((n >> 1) & 3)) << 4));
                ldsm4(bh[fp * 2][0], bh[fp * 2][1], bh[fp * 2 + 1][0], bh[fp * 2 + 1][1], bH + o);
                ldsm4(bl[fp * 2][0], bl[fp * 2][1], bl[fp * 2 + 1][0], bl[fp * 2 + 1][1], bL + o);
            }
#pragma unroll
            for (int fm = 0; fm < 4; fm++) {
                int m = amRow + fm * 16;
                int kg = kk * 2 + akSel;
                uint32_t o = (uint32_t)(m * 64 + ((kg ^ ((m >> 1) & 3)) << 4));
                uint32_t ah[4], al[4];
                ldsm4(ah[0], ah[1], ah[2], ah[3], aH + o);
                ldsm4(al[0], al[1], al[2], al[3], aL + o);
#pragma unroll
                for (int fn = 0; fn < 4; fn++) {
                    mma16816(C[fm][fn], ah, bh[fn]);
                    mma16816(C[fm][fn], ah, bl[fn]);
                    mma16816(C[fm][fn], al, bh[fn]);
                }
            }
        }
        __syncthreads();
    }

    // ----------------------------- epilogue ---------------------------------
    int g = lane >> 2, tig = lane & 3;

    __half *qh_out = nullptr, *ql_out = nullptr;
    const float* mbias = nullptr;
    int hcol0 = 0;
    if (MODE == 0) {
        int which = n0 / HH;
        qh_out = (which == 0) ? g_qh : (which == 1) ? g_kh : g_vh;
        ql_out = (which == 0) ? g_ql : (which == 1) ? g_kl : g_vl;
        mbias  = (which == 0) ? p0 : (which == 1) ? p1 : p2;
        hcol0  = n0 - which * HH;
    }

#pragma unroll
    for (int fm = 0; fm < 4; fm++) {
        int rowl0 = wm * 64 + fm * 16 + g;
#pragma unroll
        for (int fn = 0; fn < 4; fn++) {
            int coll = wn * 32 + fn * 8 + tig * 2;
#pragma unroll
            for (int hf = 0; hf < 2; hf++) {
                int ml = rowl0 + hf * 8;
                float c0 = C[fm][fn][hf * 2], c1 = C[fm][fn][hf * 2 + 1];
                if (MODE == 0) {
                    int t = m0 + ml;
                    int hcol = hcol0 + coll;
                    int h = hcol >> 6, d = hcol & 63;
                    int b = t >> 9, sI = t & 511;
                    size_t o = (((size_t)(b * NHH + h)) * SS + sI) * DHH + d;
                    uint32_t lo;
                    uint32_t hi = packsplit(c0 + mbias[hcol], c1 + mbias[hcol + 1], lo);
                    *(uint32_t*)(qh_out + o) = hi;
                    *(uint32_t*)(ql_out + o) = lo;
                } else if (MODE == 1) {
                    size_t t = m0 + ml;
                    int col = n0 + coll;
                    float2 xr = *(const float2*)(p1 + t * HH + col);
                    float2 v = {c0 + p0[col] + xr.x, c1 + p0[col + 1] + xr.y};
                    *(float2*)(g_preln + t * HH + col) = v;
                } else {
                    if (base + ml < end) {
                        int col = n0 + coll;
                        int t = s_tok[ml];
                        float w = s_w[ml];
                        const float* eb = p0 + (size_t)e * HH;
                        atomicAdd(pout + (size_t)t * HH + col,     (c0 + eb[col]) * w);
                        atomicAdd(pout + (size_t)t * HH + col + 1, (c1 + eb[col + 1]) * w);
                    }
                }
            }
        }
    }
}

// ============ fused up+gate pipelined HMMA grouped GEMM ======================
// h[r, i] = gelu(xl@Wu + bu) * (xl@Wn + bn)  -> g_hh/g_hl (fp16 split)
#define UPG_SMEM (2 * 49152)
__global__ void __launch_bounds__(256, 1) ffn_upgate(
    const float* __restrict__ bu_, const float* __restrict__ bn_) {
    int e = blockIdx.y >> 5, lt = blockIdx.y & 31;
    int base = g_off[e] + lt * 128;
    int end  = g_off[e] + g_cnt[e];
    if (base >= end) return;

    extern __shared__ char dyn[];
    __shared__ int s_tok[128];

    int tid = threadIdx.x, lane = tid & 31, wid = tid >> 5;
    int wm = wid & 1, wn = wid >> 1;

    if (tid < 128) s_tok[tid] = g_etok[min(base + tid, end - 1)];
    __syncthreads();

    const __half* Buh = g_wuh + (size_t)e * II * HH;
    const __half* Bul = g_wul + (size_t)e * II * HH;
    const __half* Bnh = g_wnh + (size_t)e * II * HH;
    const __half* Bnl = g_wnl + (size_t)e * II * HH;
    int n0 = blockIdx.x * 128;
    uint32_t sbase = smem_u32(dyn);

    auto issue = [&](int slab, int st) {
        int k0 = slab * 32;
        uint32_t sb = sbase + st * 49152;
#pragma unroll
        for (int i = 0; i < 2; i++) {
            int c = tid + i * 256;
            int m = c >> 2, kc = c & 3;
            uint32_t so = sb + swoff(m, kc);
            int koff = k0 + kc * 8;
            size_t aoff = (size_t)s_tok[m] * HH + koff;
            cpasync16(so,         g_xlh + aoff);
            cpasync16(so + 8192,  g_xll + aoff);
            size_t boff = (size_t)(n0 + m) * HH + koff;
            cpasync16(so + 16384, Buh + boff);
            cpasync16(so + 24576, Bul + boff);
            cpasync16(so + 32768, Bnh + boff);
            cpasync16(so + 40960, Bnl + boff);
        }
    };

    int j = lane >> 3, rr = lane & 7;
    int amRow = wm * 64 + (j & 1) * 8 + rr;
    int akSel = j >> 1;
    int bnRow = wn * 32 + (j >> 1) * 8 + rr;
    int bkSel = j & 1;
    float Cu[4][4][4] = {}, Cn[4][4][4] = {};

    issue(0, 0);
    CP_COMMIT();
    for (int s = 0; s < HH / 32; s++) {
        int st = s & 1;
        if (s + 1 < HH / 32) {
            issue(s + 1, st ^ 1);
            CP_COMMIT();
            CP_WAIT1();
        } else {
            CP_WAIT0();
        }
        __syncthreads();
        uint32_t aH = sbase + st * 49152, aL = aH + 8192;
        uint32_t uH = aH + 16384, uL = aH + 24576;
        uint32_t nH = aH + 32768, nL = aH + 40960;
#pragma unroll
        for (int kk = 0; kk < 2; kk++) {
            uint32_t buh[4][2], bul[4][2], bnh[4][2], bnl[4][2];
#pragma unroll
            for (int fp = 0; fp < 2; fp++) {
                int n = bnRow + fp * 16;
                int kg = kk * 2 + bkSel;
                uint32_t o = (uint32_t)(n * 64 + ((kg ^ ((n >> 1) & 3)) << 4));
                ldsm4(buh[fp * 2][0], buh[fp * 2][1], buh[fp * 2 + 1][0], buh[fp * 2 + 1][1], uH + o);
                ldsm4(bul[fp * 2][0], bul[fp * 2][1], bul[fp * 2 + 1][0], bul[fp * 2 + 1][1], uL + o);
                ldsm4(bnh[fp * 2][0], bnh[fp * 2][1], bnh[fp * 2 + 1][0], bnh[fp * 2 + 1][1], nH + o);
                ldsm4(bnl[fp * 2][0], bnl[fp * 2][1], bnl[fp * 2 + 1][0], bnl[fp * 2 + 1][1], nL + o);
            }
#pragma unroll
            for (int fm = 0; fm < 4; fm++) {
                int m = amRow + fm * 16;
                int kg = kk * 2 + akSel;
                uint32_t o = (uint32_t)(m * 64 + ((kg ^ ((m >> 1) & 3)) << 4));
                uint32_t ah[4], al[4];
                ldsm4(ah[0], ah[1], ah[2], ah[3], aH + o);
                ldsm4(al[0], al[1], al[2], al[3], aL + o);
#pragma unroll
                for (int fn = 0; fn < 4; fn++) {
                    mma16816(Cu[fm][fn], ah, buh[fn]);
                    mma16816(Cu[fm][fn], ah, bul[fn]);
                    mma16816(Cu[fm][fn], al, buh[fn]);
                    mma16816(Cn[fm][fn], ah, bnh[fn]);
                    mma16816(Cn[fm][fn], ah, bnl[fn]);
                    mma16816(Cn[fm][fn], al, bnh[fn]);
                }
            }
        }
        __syncthreads();
    }

    int g = lane >> 2, tig = lane & 3;
    const float* bu = bu_ + (size_t)e * II;
    const float* bn = bn_ + (size_t)e * II;
#pragma unroll
    for (int fm = 0; fm < 4; fm++) {
        int rowl0 = wm * 64 + fm * 16 + g;
#pragma unroll
        for (int fn = 0; fn < 4; fn++) {
            int col = n0 + wn * 32 + fn * 8 + tig * 2;
            float bu0 = bu[col], bu1 = bu[col + 1];
            float bn0 = bn[col], bn1 = bn[col + 1];
#pragma unroll
            for (int hf = 0; hf < 2; hf++) {
                int r = base + rowl0 + hf * 8;
                if (r < end) {
                    float u0 = Cu[fm][fn][hf * 2] + bu0, u1 = Cu[fm][fn][hf * 2 + 1] + bu1;
                    float h0 = u0 * normcdff(u0) * (Cn[fm][fn][hf * 2] + bn0);
                    float h1 = u1 * normcdff(u1) * (Cn[fm][fn][hf * 2 + 1] + bn1);
                    uint32_t lo;
                    uint32_t hi = packsplit(h0, h1, lo);
                    *(uint32_t*)(g_hh + (size_t)r * II + col) = hi;
                    *(uint32_t*)(g_hl + (size_t)r * II + col) = lo;
                }
            }
        }
    }
}

// ================= flash attention (fp16x3 HMMA, online softmax) =============
// grid (S/128, B*NH); 8 warps, each warp owns 16 q-rows. Writes ctx split.
#define FL_SMEM (32768 + 2 * 65536)
__global__ void __launch_bounds__(256, 1) flash_attn() {
    int q0 = blockIdx.x * 128;
    int head = blockIdx.y;
    int b = head / NHH, h_ = head % NHH;

    extern __shared__ char dyn[];
    uint32_t sb = smem_u32(dyn);
    const uint32_t QH = 0, QL = 16384;
    // stage s: 32768 + s*65536: KH, KL, VH, VL (16 KB each)

    const __half* Qh = g_qh + (size_t)head * SS * DHH;
    const __half* Ql = g_ql + (size_t)head * SS * DHH;
    const __half* Kh = g_kh + (size_t)head * SS * DHH;
    const __half* Kl = g_kl + (size_t)head * SS * DHH;
    const __half* Vh = g_vh + (size_t)head * SS * DHH;
    const __half* Vl = g_vl + (size_t)head * SS * DHH;

    int tid = threadIdx.x, lane = tid & 31, wid = tid >> 5;
    int j = lane >> 3, rr = lane & 7;
    int g = lane >> 2, tig = lane & 3;

    // [128][64] half tile loader (1024 16B-chunks)
    auto load_tile = [&](uint32_t dst, const __half* src, int row0) {
#pragma unroll
        for (int i = 0; i < 4; i++) {
            int idx = tid + i * 256;
            int m = idx >> 3, c = idx & 7;
            cpasync16(sb + dst + fswz(m, c), src + (size_t)(row0 + m) * DHH + c * 8);
        }
    };

    // Q + tile 0 (group A)
    load_tile(QH, Qh, q0);
    load_tile(QL, Ql, q0);
    load_tile(32768, Kh, 0);
    load_tile(32768 + 16384, Kl, 0);
    load_tile(32768 + 32768, Vh, 0);
    load_tile(32768 + 49152, Vl, 0);
    CP_COMMIT();

    float O[8][4] = {};
    float rm0 = -1e30f, rm1 = -1e30f, l0 = 0.0f, l1 = 0.0f;

    for (int kt = 0; kt < 4; kt++) {
        int st = kt & 1;
        if (kt + 1 < 4) {
            uint32_t nb = 32768 + (st ^ 1) * 65536;
            load_tile(nb,         Kh, (kt + 1) * 128);
            load_tile(nb + 16384, Kl, (kt + 1) * 128);
            load_tile(nb + 32768, Vh, (kt + 1) * 128);
            load_tile(nb + 49152, Vl, (kt + 1) * 128);
            CP_COMMIT();
            CP_WAIT1();
        } else {
            CP_WAIT0();
        }
        __syncthreads();

        uint32_t kH = sb + 32768 + st * 65536, kL = kH + 16384;
        uint32_t vH = kH + 32768, vL = kH + 49152;
        uint32_t qHb = sb + QH, qLb = sb + QL;

        // ---- S = Q @ K^T (fp32 acc) ----
        float S[16][4] = {};
#pragma unroll
        for (int ks = 0; ks < 4; ks++) {
            int am = wid * 16 + (j & 1) * 8 + rr;
            int ac = 2 * ks + (j >> 1);
            uint32_t ao = fswz(am, ac) - (uint32_t)(am & 7) * 0; // fswz handles swizzle
            uint32_t ah[4], al[4];
            ldsm4(ah[0], ah[1], ah[2], ah[3], qHb + fswz(am, ac));
            ldsm4(al[0], al[1], al[2], al[3], qLb + fswz(am, ac));
            (void)ao;
#pragma unroll
            for (int fnp = 0; fnp < 8; fnp++) {
                int bn = fnp * 16 + (j >> 1) * 8 + rr;
                int bc = 2 * ks + (j & 1);
                uint32_t bo = fswz(bn, bc);
                uint32_t bh[4], bl[4];
                ldsm4(bh[0], bh[1], bh[2], bh[3], kH + bo);
                ldsm4(bl[0], bl[1], bl[2], bl[3], kL + bo);
                mma16816(S[2 * fnp],     ah, bh);
                mma16816(S[2 * fnp],     ah, bl);
                mma16816(S[2 * fnp],     al, bh);
                mma16816(S[2 * fnp + 1], ah, bh + 2);
                mma16816(S[2 * fnp + 1], ah, bl + 2);
                mma16816(S[2 * fnp + 1], al, bh + 2);
            }
        }

        // ---- online softmax (rows g and g+8 of this warp's 16) ----
        float mx0 = -1e30f, mx1 = -1e30f;
#pragma unroll
        for (int fn = 0; fn < 16; fn++) {
            mx0 = fmaxf(mx0, fmaxf(S[fn][0], S[fn][1]));
            mx1 = fmaxf(mx1, fmaxf(S[fn][2], S[fn][3]));
        }
        mx0 = fmaxf(mx0, __shfl_xor_sync(~0u, mx0, 1));
        mx0 = fmaxf(mx0, __shfl_xor_sync(~0u, mx0, 2));
        mx1 = fmaxf(mx1, __shfl_xor_sync(~0u, mx1, 1));
        mx1 = fmaxf(mx1, __shfl_xor_sync(~0u, mx1, 2));
        float nm0 = fmaxf(rm0, mx0 * 0.125f);
        float nm1 = fmaxf(rm1, mx1 * 0.125f);
        float al0 = __expf(rm0 - nm0);
        float al1 = __expf(rm1 - nm1);
        rm0 = nm0; rm1 = nm1;
        float sum0 = 0.0f, sum1 = 0.0f;
#pragma unroll
        for (int fn = 0; fn < 16; fn++) {
            float p0 = __expf(fmaf(S[fn][0], 0.125f, -nm0));
            float p1 = __expf(fmaf(S[fn][1], 0.125f, -nm0));
            float p2 = __expf(fmaf(S[fn][2], 0.125f, -nm1));
            float p3 = __expf(fmaf(S[fn][3], 0.125f, -nm1));
            S[fn][0] = p0; S[fn][1] = p1; S[fn][2] = p2; S[fn][3] = p3;
            sum0 += p0 + p1; sum1 += p2 + p3;
        }
        sum0 += __shfl_xor_sync(~0u, sum0, 1);
        sum0 += __shfl_xor_sync(~0u, sum0, 2);
        sum1 += __shfl_xor_sync(~0u, sum1, 1);
        sum1 += __shfl_xor_sync(~0u, sum1, 2);
        l0 = l0 * al0 + sum0;
        l1 = l1 * al1 + sum1;
#pragma unroll
        for (int fo = 0; fo < 8; fo++) {
            O[fo][0] *= al0; O[fo][1] *= al0;
            O[fo][2] *= al1; O[fo][3] *= al1;
        }

        // ---- O += P @ V ----
#pragma unroll
        for (int kp = 0; kp < 8; kp++) {
            uint32_t aph[4], apl[4];
            aph[0] = packsplit(S[2 * kp][0],     S[2 * kp][1],     apl[0]);
            aph[1] = packsplit(S[2 * kp][2],     S[2 * kp][3],     apl[1]);
            aph[2] = packsplit(S[2 * kp + 1][0], S[2 * kp + 1][1], apl[2]);
            aph[3] = packsplit(S[2 * kp + 1][2], S[2 * kp + 1][3], apl[3]);
#pragma unroll
            for (int dg = 0; dg < 4; dg++) {
                int vrow = kp * 16 + (j & 1) * 8 + rr;
                int vc = dg * 2 + (j >> 1);
                uint32_t vo = fswz(vrow, vc);
                uint32_t vh[4], vl[4];
                ldsm4t(vh[0], vh[1], vh[2], vh[3], vH + vo);
                ldsm4t(vl[0], vl[1], vl[2], vl[3], vL + vo);
#pragma unroll
                for (int hg = 0; hg < 2; hg++) {
                    int fo = dg * 2 + hg;
                    mma16816(O[fo], aph, vh + hg * 2);
                    mma16816(O[fo], apl, vh + hg * 2);
                    mma16816(O[fo], aph, vl + hg * 2);
                }
            }
        }
        __syncthreads();
    }

    // ---- epilogue: ctx split [T][H] ----
    float inv0 = 1.0f / l0, inv1 = 1.0f / l1;
    int qr0 = q0 + wid * 16 + g;
    size_t t0 = (size_t)b * SS + qr0;
    size_t t1 = t0 + 8;
#pragma unroll
    for (int fo = 0; fo < 8; fo++) {
        int d = fo * 8 + tig * 2;
        int col = h_ * 64 + d;
        uint32_t lo;
        uint32_t hi = packsplit(O[fo][0] * inv0, O[fo][1] * inv0, lo);
        *(uint32_t*)(g_ch + t0 * HH + col) = hi;
        *(uint32_t*)(g_cl + t0 * HH + col) = lo;
        hi = packsplit(O[fo][2] * inv1, O[fo][3] * inv1, lo);
        *(uint32_t*)(g_ch + t1 * HH + col) = hi;
        *(uint32_t*)(g_cl + t1 * HH + col) = lo;
    }
}

// ================= LayerNorm ==================================================
__global__ void ln_kernel(const float* __restrict__ gamma, const float* __restrict__ beta,
                          float* __restrict__ dout, int mode) {
    size_t row = blockIdx.x;
    const float* in = (mode == 0) ? (g_preln + row * HH) : (g_attnout + row * HH);
    int tid = threadIdx.x;
    float x0 = in[tid], x1 = in[tid + 256], x2 = in[tid + 512];

    __shared__ float red[256];
    red[tid] = x0 + x1 + x2;
    __syncthreads();
    for (int s = 128; s > 0; s >>= 1) {
        if (tid < s) red[tid] += red[tid + s];
        __syncthreads();
    }
    float mean = red[0] * (1.0f / HH);
    __syncthreads();

    float c0 = x0 - mean, c1 = x1 - mean, c2 = x2 - mean;
    red[tid] = c0 * c0 + c1 * c1 + c2 * c2;
    __syncthreads();
    for (int s = 128; s > 0; s >>= 1) {
        if (tid < s) red[tid] += red[tid + s];
        __syncthreads();
    }
    float inv = 1.0f / sqrtf(red[0] * (1.0f / HH) + 1e-12f);

    float y0 = c0 * inv * gamma[tid]       + beta[tid];
    float y1 = c1 * inv * gamma[tid + 256] + beta[tid + 256];
    float y2 = c2 * inv * gamma[tid + 512] + beta[tid + 512];
    if (mode == 0) {
        g_attnout[row * HH + tid]       = y0;
        g_attnout[row * HH + tid + 256] = y1;
        g_attnout[row * HH + tid + 512] = y2;
        dout[row * HH + tid]       = y0;
        dout[row * HH + tid + 256] = y1;
        dout[row * HH + tid + 512] = y2;
    } else {
        g_xl[row * HH + tid]       = y0;
        g_xl[row * HH + tid + 256] = y1;
        g_xl[row * HH + tid + 512] = y2;
        __half h0 = __float2half_rn(y0), h1 = __float2half_rn(y1), h2 = __float2half_rn(y2);
        g_xlh[row * HH + tid]       = h0;
        g_xlh[row * HH + tid + 256] = h1;
        g_xlh[row * HH + tid + 512] = h2;
        g_xll[row * HH + tid]       = __float2half_rn(y0 - __half2float(h0));
        g_xll[row * HH + tid + 256] = __float2half_rn(y1 - __half2float(h1));
        g_xll[row * HH + tid + 512] = __float2half_rn(y2 - __half2float(h2));
    }
}

// ================= counters / router / scatter ===============================
__global__ void init_kernel() {
    int i = threadIdx.x;
    if (i < EE) { g_cnt[i] = 0; g_cur[i] = 0; }
}

__global__ void router_kernel(const float* __restrict__ Wr, const float* __restrict__ br,
                              float* __restrict__ logits_out) {
    int warp = threadIdx.x >> 5, lane = threadIdx.x & 31;
    int t = blockIdx.x * 8 + warp;
    const float* x = g_xl + (size_t)t * HH;

    float acc[EE] = {};
    for (int h = lane; h < HH; h += 32) {
        float xv = x[h];
        const float* w = Wr + (size_t)h * EE;
#pragma unroll
        for (int e = 0; e < EE; e++) acc[e] = fmaf(xv, w[e], acc[e]);
    }
#pragma unroll
    for (int e = 0; e < EE; e++)
        for (int o = 16; o > 0; o >>= 1) acc[e] += __shfl_down_sync(0xffffffffu, acc[e], o);

    if (lane == 0) {
        float lg[EE], mx = -1e30f;
#pragma unroll
        for (int e = 0; e < EE; e++) {
            lg[e] = acc[e] + br[e];
            logits_out[(size_t)t * EE + e] = lg[e];
            mx = fmaxf(mx, lg[e]);
        }
        float p[EE], s = 0.0f;
#pragma unroll
        for (int e = 0; e < EE; e++) { p[e] = expf(lg[e] - mx); s += p[e]; }
        float invs = 1.0f / s;
#pragma unroll
        for (int e = 0; e < EE; e++) p[e] *= invs;

        int i1 = 0;
#pragma unroll
        for (int e = 1; e < EE; e++) if (p[e] > p[i1]) i1 = e;
        int i2 = (i1 == 0) ? 1 : 0;
#pragma unroll
        for (int e = 0; e < EE; e++) if (e != i1 && p[e] > p[i2]) i2 = e;

        float w1 = p[i1], w2 = p[i2], inv = 1.0f / (w1 + w2);
        g_ti[t * 2]     = i1;  g_tw[t * 2]     = w1 * inv;
        g_ti[t * 2 + 1] = i2;  g_tw[t * 2 + 1] = w2 * inv;
        atomicAdd(&g_cnt[i1], 1);
        atomicAdd(&g_cnt[i2], 1);
    }
}

__global__ void offsets_kernel() {
    if (threadIdx.x == 0) {
        int o = 0;
        for (int e = 0; e < EE; e++) { g_off[e] = o; o += g_cnt[e]; }
    }
}

__global__ void scatter_kernel() {
    int t = blockIdx.x * 256 + threadIdx.x;
    if (t >= TT) return;
#pragma unroll
    for (int s = 0; s < 2; s++) {
        int e = g_ti[t * 2 + s];
        int pos = atomicAdd(&g_cur[e], 1);
        int r = g_off[e] + pos;
        g_etok[r] = t;
        g_ew[r] = g_tw[t * 2 + s];
    }
}

// ================= host launcher =============================================
#define HG_SMEM 65536

extern "C" void kernel_launch(void* const* d_in, const int* in_sizes, int n_in,
                              void* d_out, int out_size) {
    const float* X        = (const float*)d_in[0];
    const float* Wq       = (const float*)d_in[1];
    const float* bq       = (const float*)d_in[2];
    const float* Wk       = (const float*)d_in[3];
    const float* bk       = (const float*)d_in[4];
    const float* Wv       = (const float*)d_in[5];
    const float* bv       = (const float*)d_in[6];
    const float* Wo       = (const float*)d_in[7];
    const float* bo       = (const float*)d_in[8];
    const float* ln_ag    = (const float*)d_in[9];
    const float* ln_ab    = (const float*)d_in[10];
    const float* ln_fg    = (const float*)d_in[11];
    const float* ln_fb    = (const float*)d_in[12];
    const float* Wr       = (const float*)d_in[13];
    const float* br       = (const float*)d_in[14];
    const float* W_up     = (const float*)d_in[15];
    const float* b_up     = (const float*)d_in[16];
    const float* W_new    = (const float*)d_in[17];
    const float* b_new    = (const float*)d_in[18];
    const float* W_down   = (const float*)d_in[19];
    const float* b_down   = (const float*)d_in[20];

    float* out    = (float*)d_out;                    // layer_output [T, H]
    float* logits = out + (size_t)TT * HH;            // router_logits [T, E]

    static int attr_done = 0;
    if (!attr_done) {
        cudaFuncSetAttribute(hgemm<0>, cudaFuncAttributeMaxDynamicSharedMemorySize, HG_SMEM);
        cudaFuncSetAttribute(hgemm<1>, cudaFuncAttributeMaxDynamicSharedMemorySize, HG_SMEM);
        cudaFuncSetAttribute(hgemm<2>, cudaFuncAttributeMaxDynamicSharedMemorySize, HG_SMEM);
        cudaFuncSetAttribute(ffn_upgate, cudaFuncAttributeMaxDynamicSharedMemorySize, UPG_SMEM);
        cudaFuncSetAttribute(flash_attn, cudaFuncAttributeMaxDynamicSharedMemorySize, FL_SMEM);
        attr_done = 1;
    }

    __half *wqkvh, *wqkvl, *woh, *wol, *wuh, *wul, *wnh, *wnl, *wdh, *wdl, *xsh, *xsl;
    cudaGetSymbolAddress((void**)&wqkvh, g_wqkvh);
    cudaGetSymbolAddress((void**)&wqkvl, g_wqkvl);
    cudaGetSymbolAddress((void**)&woh, g_woh);
    cudaGetSymbolAddress((void**)&wol, g_wol);
    cudaGetSymbolAddress((void**)&wuh, g_wuh);
    cudaGetSymbolAddress((void**)&wul, g_wul);
    cudaGetSymbolAddress((void**)&wnh, g_wnh);
    cudaGetSymbolAddress((void**)&wnl, g_wnl);
    cudaGetSymbolAddress((void**)&wdh, g_wdh);
    cudaGetSymbolAddress((void**)&wdl, g_wdl);
    cudaGetSymbolAddress((void**)&xsh, g_xsh);
    cudaGetSymbolAddress((void**)&xsl, g_xsl);

    // weight prep: transpose + fp16 hi/lo split
    tsplit<<<dim3(HH / 32, HH / 32, 1), dim3(32, 8)>>>(Wq, wqkvh,               wqkvl,               HH, HH);
    tsplit<<<dim3(HH / 32, HH / 32, 1), dim3(32, 8)>>>(Wk, wqkvh + HH * HH,     wqkvl + HH * HH,     HH, HH);
    tsplit<<<dim3(HH / 32, HH / 32, 1), dim3(32, 8)>>>(Wv, wqkvh + 2 * HH * HH, wqkvl + 2 * HH * HH, HH, HH);
    tsplit<<<dim3(HH / 32, HH / 32, 1), dim3(32, 8)>>>(Wo, woh, wol, HH, HH);
    tsplit<<<dim3(II / 32, HH / 32, EE), dim3(32, 8)>>>(W_up,  wuh, wul, HH, II);
    tsplit<<<dim3(II / 32, HH / 32, EE), dim3(32, 8)>>>(W_new, wnh, wnl, HH, II);
    tsplit<<<dim3(HH / 32, II / 32, EE), dim3(32, 8)>>>(W_down, wdh, wdl, II, HH);

    init_kernel<<<1, 32>>>();
    fsplit<<<TT * HH / 1024, 256>>>(X, xsh, xsl);

    // QKV (fused, emits fp16 splits) -> flash attention -> proj
    hgemm<0><<<dim3(3 * HH / 128, TT / 128), 256, HG_SMEM>>>(bq, bk, bv, nullptr);
    flash_attn<<<dim3(SS / 128, BB * NHH), 256, FL_SMEM>>>();
    hgemm<1><<<dim3(HH / 128, TT / 128), 256, HG_SMEM>>>(bo, X, nullptr, nullptr);

    ln_kernel<<<TT, 256>>>(ln_ag, ln_ab, out, 0);
    ln_kernel<<<TT, 256>>>(ln_fg, ln_fb, out, 1);
    router_kernel<<<TT / 8, 256>>>(Wr, br, logits);
    offsets_kernel<<<1, 32>>>();
    scatter_kernel<<<(TT + 255) / 256, 256>>>();

    // MoE FFN: fused up+gate, then down
    ffn_upgate<<<dim3(II / 128, EE * 32), 256, UPG_SMEM>>>(b_up, b_new);
    hgemm<2><<<dim3(HH / 128, EE * 32), 256, HG_SMEM>>>(b_down, nullptr, nullptr, out);
}

// round 6
// speedup vs baseline: 2.6996x; 1.0022x over previous
#include <cuda_runtime.h>
#include <cuda_fp16.h>
#include <math.h>
#include <stdint.h>

#define TT  4096   // B*S
#define HH  768
#define SS  512
#define BB  8
#define NHH 12
#define DHH 64
#define II  3072
#define EE  8
#define ENT 8192   // TT * TOPK

// ---------------- scratch (static device allocations; no cudaMalloc) --------
__device__ float g_preln[TT * HH];
__device__ float g_attnout[TT * HH];
__device__ float g_xl[TT * HH];
__device__ __half g_xlh[TT * HH];           // xl split
__device__ __half g_xll[TT * HH];
__device__ __half g_xsh[TT * HH];           // X split
__device__ __half g_xsl[TT * HH];
__device__ __half g_qh[TT * HH];            // Q split, [B*NH][S][DH]
__device__ __half g_ql[TT * HH];
__device__ __half g_kh[TT * HH];
__device__ __half g_kl[TT * HH];
__device__ __half g_vh[TT * HH];
__device__ __half g_vl[TT * HH];
__device__ __half g_ch[TT * HH];            // ctx split [T][H]
__device__ __half g_cl[TT * HH];
__device__ __half g_hh[(size_t)ENT * II];   // FFN hidden h = gelu(u)*gate, hi
__device__ __half g_hl[(size_t)ENT * II];   // lo
__device__ __half g_wqkvh[3 * HH * HH];     // [Wq^T;Wk^T;Wv^T] [2304][768]
__device__ __half g_wqkvl[3 * HH * HH];
__device__ __half g_woh[HH * HH];           // Wo^T
__device__ __half g_wol[HH * HH];
__device__ __half g_wuh[(size_t)EE * II * HH];  // W_up^T  hi [E][I][H]
__device__ __half g_wul[(size_t)EE * II * HH];
__device__ __half g_wnh[(size_t)EE * II * HH];  // W_new^T hi
__device__ __half g_wnl[(size_t)EE * II * HH];
__device__ __half g_wdh[(size_t)EE * HH * II];  // W_down^T hi [E][H][I]
__device__ __half g_wdl[(size_t)EE * HH * II];
__device__ int   g_cnt[EE];
__device__ int   g_off[EE];
__device__ int   g_cur[EE];
__device__ int   g_etok[ENT];
__device__ float g_ew[ENT];
__device__ int   g_ti[TT * 2];
__device__ float g_tw[TT * 2];

// ======================= asm helpers (portable sm_80+) =======================
__device__ __forceinline__ uint32_t smem_u32(const void* p) {
    uint32_t a;
    asm("{ .reg .u64 t; cvta.to.shared.u64 t, %1; cvt.u32.u64 %0, t; }" : "=r"(a) : "l"(p));
    return a;
}
__device__ __forceinline__ void ldsm4(uint32_t& r0, uint32_t& r1, uint32_t& r2, uint32_t& r3,
                                      uint32_t addr) {
    asm volatile("ldmatrix.sync.aligned.m8n8.x4.shared.b16 {%0,%1,%2,%3}, [%4];"
                 : "=r"(r0), "=r"(r1), "=r"(r2), "=r"(r3) : "r"(addr));
}
__device__ __forceinline__ void ldsm4t(uint32_t& r0, uint32_t& r1, uint32_t& r2, uint32_t& r3,
                                       uint32_t addr) {
    asm volatile("ldmatrix.sync.aligned.m8n8.x4.trans.shared.b16 {%0,%1,%2,%3}, [%4];"
                 : "=r"(r0), "=r"(r1), "=r"(r2), "=r"(r3) : "r"(addr));
}
__device__ __forceinline__ void mma16816(float* c, const uint32_t* a, const uint32_t* b) {
    asm volatile(
        "mma.sync.aligned.m16n8k16.row.col.f32.f16.f16.f32 "
        "{%0,%1,%2,%3}, {%4,%5,%6,%7}, {%8,%9}, {%0,%1,%2,%3};"
        : "+f"(c[0]), "+f"(c[1]), "+f"(c[2]), "+f"(c[3])
        : "r"(a[0]), "r"(a[1]), "r"(a[2]), "r"(a[3]), "r"(b[0]), "r"(b[1]));
}
__device__ __forceinline__ void cpasync16(uint32_t saddr, const void* gaddr) {
    asm volatile("cp.async.cg.shared.global [%0], [%1], 16;" :: "r"(saddr), "l"(gaddr));
}
#define CP_COMMIT() asm volatile("cp.async.commit_group;" ::: "memory")
#define CP_WAIT1()  asm volatile("cp.async.wait_group 1;" ::: "memory")
#define CP_WAIT0()  asm volatile("cp.async.wait_group 0;" ::: "memory")

// xor-swizzled smem byte offset for a [rows x 32 halves] tile (row = 64B)
__device__ __forceinline__ uint32_t swoff(int m, int kg) {
    return (uint32_t)(m * 64 + ((kg ^ ((m >> 1) & 3)) << 4));
}
// xor-swizzled smem byte offset for a [rows x 64 halves] tile (row = 128B, 8 chunks)
__device__ __forceinline__ uint32_t fswz(int m, int c) {
    return (uint32_t)(m * 128 + ((c ^ (m & 7)) << 4));
}
__device__ __forceinline__ uint32_t packsplit(float v0, float v1, uint32_t& lo) {
    __half h0 = __float2half_rn(v0), h1 = __float2half_rn(v1);
    __half2 l = __halves2half2(__float2half_rn(v0 - __half2float(h0)),
                               __float2half_rn(v1 - __half2float(h1)));
    lo = *(uint32_t*)&l;
    __half2 h = __halves2half2(h0, h1);
    return *(uint32_t*)&h;
}

// ============ transpose + fp16 hi/lo split: W[R,C] -> WT_hi/lo[C,R] ==========
__global__ void tsplit(const float* __restrict__ W, __half* __restrict__ Th,
                       __half* __restrict__ Tl, int R, int C) {
    __shared__ float t[32][33];
    int e = blockIdx.z;
    W  += (size_t)e * R * C;
    Th += (size_t)e * R * C;
    Tl += (size_t)e * R * C;
    int r0 = blockIdx.y * 32, c0 = blockIdx.x * 32;
#pragma unroll
    for (int i = threadIdx.y; i < 32; i += 8)
        t[i][threadIdx.x] = W[(size_t)(r0 + i) * C + c0 + threadIdx.x];
    __syncthreads();
#pragma unroll
    for (int i = threadIdx.y; i < 32; i += 8) {
        float v = t[threadIdx.x][i];
        __half h = __float2half_rn(v);
        size_t o = (size_t)(c0 + i) * R + r0 + threadIdx.x;
        Th[o] = h;
        Tl[o] = __float2half_rn(v - __half2float(h));
    }
}

// ============ elementwise fp32 -> fp16 hi/lo split ===========================
__global__ void fsplit(const float* __restrict__ src, __half* __restrict__ h,
                       __half* __restrict__ l) {
    int i = (blockIdx.x * 256 + threadIdx.x) * 4;
    float4 v = *(const float4*)(src + i);
    uint32_t lo0, lo1;
    uint32_t h0 = packsplit(v.x, v.y, lo0);
    uint32_t h1 = packsplit(v.z, v.w, lo1);
    *(uint32_t*)(h + i)     = h0;
    *(uint32_t*)(h + i + 2) = h1;
    *(uint32_t*)(l + i)     = lo0;
    *(uint32_t*)(l + i + 2) = lo1;
}

// ================= unified fp16x3 pipelined HMMA GEMM ========================
// MODE 0: QKV   A=g_xsh/l [t][768]   B=g_wqkvh/l [2304][768] -> g_qh..g_vl split
// MODE 1: PROJ  A=g_ch/l  [t][768]   B=g_woh/l   [768][768]  -> g_preln (+bo+X)
// MODE 2: DOWN  A=g_hh/l  [r][3072]  B=g_wdh/l e [768][3072] -> atomicAdd out
//   MODE 2 grid: x = row-group (L2 weight reuse across concurrent CTAs),
//                y = e * 6 + n-tile
template<int MODE>
__global__ void __launch_bounds__(256, 2) hgemm(
    const float* __restrict__ p0, const float* __restrict__ p1,
    const float* __restrict__ p2, float* __restrict__ pout) {

    constexpr int KD = (MODE == 2) ? II : HH;
    constexpr int NS = KD / 32;

    int e = 0, base = 0, end = 0, m0 = 0, n0;
    if (MODE == 2) {
        e = blockIdx.y / 6;
        n0 = (blockIdx.y % 6) * 128;
        base = g_off[e] + blockIdx.x * 128;
        end  = g_off[e] + g_cnt[e];
        if (base >= end) return;
    } else {
        m0 = blockIdx.y * 128;
        n0 = blockIdx.x * 128;
    }

    extern __shared__ char dyn[];
    __shared__ int   s_tok[128];
    __shared__ float s_w[128];

    int tid = threadIdx.x, lane = tid & 31, wid = tid >> 5;
    int wm = wid & 1, wn = wid >> 1;

    if (MODE == 2 && tid < 128) {
        int r = min(base + tid, end - 1);
        s_tok[tid] = g_etok[r];
        s_w[tid]   = g_ew[r];
    }
    __syncthreads();

    const __half *Bh, *Bl, *Ah, *Al;
    if (MODE == 0)      { Bh = g_wqkvh; Bl = g_wqkvl; Ah = g_xsh; Al = g_xsl; }
    else if (MODE == 1) { Bh = g_woh;   Bl = g_wol;   Ah = g_ch;  Al = g_cl; }
    else                { Bh = g_wdh + (size_t)e * HH * II; Bl = g_wdl + (size_t)e * HH * II;
                          Ah = g_hh;  Al = g_hl; }

    uint32_t sbase = smem_u32(dyn);

    auto issue = [&](int slab, int st) {
        int k0 = slab * 32;
        uint32_t sb = sbase + st * 32768;
#pragma unroll
        for (int i = 0; i < 2; i++) {
            int c = tid + i * 256;
            int m = c >> 2, kc = c & 3;
            uint32_t so = sb + swoff(m, kc);
            int koff = k0 + kc * 8;
            size_t aoff;
            if (MODE < 2) aoff = (size_t)(m0 + m) * KD;
            else          aoff = (size_t)min(base + m, end - 1) * KD;
            cpasync16(so,         Ah + aoff + koff);
            cpasync16(so + 8192,  Al + aoff + koff);
            size_t boff = (size_t)(n0 + m) * KD + koff;
            cpasync16(so + 16384, Bh + boff);
            cpasync16(so + 24576, Bl + boff);
        }
    };

    int j = lane >> 3, rr = lane & 7;
    int amRow = wm * 64 + (j & 1) * 8 + rr;
    int akSel = j >> 1;
    int bnRow = wn * 32 + (j >> 1) * 8 + rr;
    int bkSel = j & 1;
    float C[4][4][4] = {};

    issue(0, 0);
    CP_COMMIT();
    for (int s = 0; s < NS; s++) {
        int st = s & 1;
        if (s + 1 < NS) {
            issue(s + 1, st ^ 1);
            CP_COMMIT();
            CP_WAIT1();
        } else {
            CP_WAIT0();
        }
        __syncthreads();
        uint32_t aH = sbase + st * 32768, aL = aH + 8192;
        uint32_t bH = aH + 16384, bL = aH + 24576;
#pragma unroll
        for (int kk = 0; kk < 2; kk++) {
            uint32_t bh[4][2], bl[4][2];
#pragma unroll
            for (int fp = 0; fp < 2; fp++) {
                int n = bnRow + fp * 16;
                int kg = kk * 2 + bkSel;
                uint32_t o = (uint32_t)(n * 64 + ((kg ^ ((n >> 1) & 3)) << 4));
                ldsm4(bh[fp * 2][0], bh[fp * 2][1], bh[fp * 2 + 1][0], bh[fp * 2 + 1][1], bH + o);
                ldsm4(bl[fp * 2][0], bl[fp * 2][1], bl[fp * 2 + 1][0], bl[fp * 2 + 1][1], bL + o);
            }
#pragma unroll
            for (int fm = 0; fm < 4; fm++) {
                int m = amRow + fm * 16;
                int kg = kk * 2 + akSel;
                uint32_t o = (uint32_t)(m * 64 + ((kg ^ ((m >> 1) & 3)) << 4));
                uint32_t ah[4], al[4];
                ldsm4(ah[0], ah[1], ah[2], ah[3], aH + o);
                ldsm4(al[0], al[1], al[2], al[3], aL + o);
#pragma unroll
                for (int fn = 0; fn < 4; fn++) {
                    mma16816(C[fm][fn], ah, bh[fn]);
                    mma16816(C[fm][fn], ah, bl[fn]);
                    mma16816(C[fm][fn], al, bh[fn]);
                }
            }
        }
        __syncthreads();
    }

    // ----------------------------- epilogue ---------------------------------
    int g = lane >> 2, tig = lane & 3;

    __half *qh_out = nullptr, *ql_out = nullptr;
    const float* mbias = nullptr;
    int hcol0 = 0;
    if (MODE == 0) {
        int which = n0 / HH;
        qh_out = (which == 0) ? g_qh : (which == 1) ? g_kh : g_vh;
        ql_out = (which == 0) ? g_ql : (which == 1) ? g_kl : g_vl;
        mbias  = (which == 0) ? p0 : (which == 1) ? p1 : p2;
        hcol0  = n0 - which * HH;
    }

#pragma unroll
    for (int fm = 0; fm < 4; fm++) {
        int rowl0 = wm * 64 + fm * 16 + g;
#pragma unroll
        for (int fn = 0; fn < 4; fn++) {
            int coll = wn * 32 + fn * 8 + tig * 2;
#pragma unroll
            for (int hf = 0; hf < 2; hf++) {
                int ml = rowl0 + hf * 8;
                float c0 = C[fm][fn][hf * 2], c1 = C[fm][fn][hf * 2 + 1];
                if (MODE == 0) {
                    int t = m0 + ml;
                    int hcol = hcol0 + coll;
                    int h = hcol >> 6, d = hcol & 63;
                    int b = t >> 9, sI = t & 511;
                    size_t o = (((size_t)(b * NHH + h)) * SS + sI) * DHH + d;
                    uint32_t lo;
                    uint32_t hi = packsplit(c0 + mbias[hcol], c1 + mbias[hcol + 1], lo);
                    *(uint32_t*)(qh_out + o) = hi;
                    *(uint32_t*)(ql_out + o) = lo;
                } else if (MODE == 1) {
                    size_t t = m0 + ml;
                    int col = n0 + coll;
                    float2 xr = *(const float2*)(p1 + t * HH + col);
                    float2 v = {c0 + p0[col] + xr.x, c1 + p0[col + 1] + xr.y};
                    *(float2*)(g_preln + t * HH + col) = v;
                } else {
                    if (base + ml < end) {
                        int col = n0 + coll;
                        int t = s_tok[ml];
                        float w = s_w[ml];
                        const float* eb = p0 + (size_t)e * HH;
                        atomicAdd(pout + (size_t)t * HH + col,     (c0 + eb[col]) * w);
                        atomicAdd(pout + (size_t)t * HH + col + 1, (c1 + eb[col + 1]) * w);
                    }
                }
            }
        }
    }
}

// ============ fused up+gate pipelined HMMA grouped GEMM ======================
// h[r, i] = gelu(xl@Wu + bu) * (xl@Wn + bn)  -> g_hh/g_hl (fp16 split)
// grid: x = row-group (fast; shares weight slice via L2), y = e * 24 + n-tile
#define UPG_SMEM (2 * 49152)
__global__ void __launch_bounds__(256, 1) ffn_upgate(
    const float* __restrict__ bu_, const float* __restrict__ bn_) {
    int e = blockIdx.y / 24;
    int n0 = (blockIdx.y % 24) * 128;
    int base = g_off[e] + blockIdx.x * 128;
    int end  = g_off[e] + g_cnt[e];
    if (base >= end) return;

    extern __shared__ char dyn[];
    __shared__ int s_tok[128];

    int tid = threadIdx.x, lane = tid & 31, wid = tid >> 5;
    int wm = wid & 1, wn = wid >> 1;

    if (tid < 128) s_tok[tid] = g_etok[min(base + tid, end - 1)];
    __syncthreads();

    const __half* Buh = g_wuh + (size_t)e * II * HH;
    const __half* Bul = g_wul + (size_t)e * II * HH;
    const __half* Bnh = g_wnh + (size_t)e * II * HH;
    const __half* Bnl = g_wnl + (size_t)e * II * HH;
    uint32_t sbase = smem_u32(dyn);

    auto issue = [&](int slab, int st) {
        int k0 = slab * 32;
        uint32_t sb = sbase + st * 49152;
#pragma unroll
        for (int i = 0; i < 2; i++) {
            int c = tid + i * 256;
            int m = c >> 2, kc = c & 3;
            uint32_t so = sb + swoff(m, kc);
            int koff = k0 + kc * 8;
            size_t aoff = (size_t)s_tok[m] * HH + koff;
            cpasync16(so,         g_xlh + aoff);
            cpasync16(so + 8192,  g_xll + aoff);
            size_t boff = (size_t)(n0 + m) * HH + koff;
            cpasync16(so + 16384, Buh + boff);
            cpasync16(so + 24576, Bul + boff);
            cpasync16(so + 32768, Bnh + boff);
            cpasync16(so + 40960, Bnl + boff);
        }
    };

    int j = lane >> 3, rr = lane & 7;
    int amRow = wm * 64 + (j & 1) * 8 + rr;
    int akSel = j >> 1;
    int bnRow = wn * 32 + (j >> 1) * 8 + rr;
    int bkSel = j & 1;
    float Cu[4][4][4] = {}, Cn[4][4][4] = {};

    issue(0, 0);
    CP_COMMIT();
    for (int s = 0; s < HH / 32; s++) {
        int st = s & 1;
        if (s + 1 < HH / 32) {
            issue(s + 1, st ^ 1);
            CP_COMMIT();
            CP_WAIT1();
        } else {
            CP_WAIT0();
        }
        __syncthreads();
        uint32_t aH = sbase + st * 49152, aL = aH + 8192;
        uint32_t uH = aH + 16384, uL = aH + 24576;
        uint32_t nH = aH + 32768, nL = aH + 40960;
#pragma unroll
        for (int kk = 0; kk < 2; kk++) {
            uint32_t buh[4][2], bul[4][2], bnh[4][2], bnl[4][2];
#pragma unroll
            for (int fp = 0; fp < 2; fp++) {
                int n = bnRow + fp * 16;
                int kg = kk * 2 + bkSel;
                uint32_t o = (uint32_t)(n * 64 + ((kg ^ ((n >> 1) & 3)) << 4));
                ldsm4(buh[fp * 2][0], buh[fp * 2][1], buh[fp * 2 + 1][0], buh[fp * 2 + 1][1], uH + o);
                ldsm4(bul[fp * 2][0], bul[fp * 2][1], bul[fp * 2 + 1][0], bul[fp * 2 + 1][1], uL + o);
                ldsm4(bnh[fp * 2][0], bnh[fp * 2][1], bnh[fp * 2 + 1][0], bnh[fp * 2 + 1][1], nH + o);
                ldsm4(bnl[fp * 2][0], bnl[fp * 2][1], bnl[fp * 2 + 1][0], bnl[fp * 2 + 1][1], nL + o);
            }
#pragma unroll
            for (int fm = 0; fm < 4; fm++) {
                int m = amRow + fm * 16;
                int kg = kk * 2 + akSel;
                uint32_t o = (uint32_t)(m * 64 + ((kg ^ ((m >> 1) & 3)) << 4));
                uint32_t ah[4], al[4];
                ldsm4(ah[0], ah[1], ah[2], ah[3], aH + o);
                ldsm4(al[0], al[1], al[2], al[3], aL + o);
#pragma unroll
                for (int fn = 0; fn < 4; fn++) {
                    mma16816(Cu[fm][fn], ah, buh[fn]);
                    mma16816(Cu[fm][fn], ah, bul[fn]);
                    mma16816(Cu[fm][fn], al, buh[fn]);
                    mma16816(Cn[fm][fn], ah, bnh[fn]);
                    mma16816(Cn[fm][fn], ah, bnl[fn]);
                    mma16816(Cn[fm][fn], al, bnh[fn]);
                }
            }
        }
        __syncthreads();
    }

    int g = lane >> 2, tig = lane & 3;
    const float* bu = bu_ + (size_t)e * II;
    const float* bn = bn_ + (size_t)e * II;
#pragma unroll
    for (int fm = 0; fm < 4; fm++) {
        int rowl0 = wm * 64 + fm * 16 + g;
#pragma unroll
        for (int fn = 0; fn < 4; fn++) {
            int col = n0 + wn * 32 + fn * 8 + tig * 2;
            float bu0 = bu[col], bu1 = bu[col + 1];
            float bn0 = bn[col], bn1 = bn[col + 1];
#pragma unroll
            for (int hf = 0; hf < 2; hf++) {
                int r = base + rowl0 + hf * 8;
                if (r < end) {
                    float u0 = Cu[fm][fn][hf * 2] + bu0, u1 = Cu[fm][fn][hf * 2 + 1] + bu1;
                    float h0 = u0 * normcdff(u0) * (Cn[fm][fn][hf * 2] + bn0);
                    float h1 = u1 * normcdff(u1) * (Cn[fm][fn][hf * 2 + 1] + bn1);
                    uint32_t lo;
                    uint32_t hi = packsplit(h0, h1, lo);
                    *(uint32_t*)(g_hh + (size_t)r * II + col) = hi;
                    *(uint32_t*)(g_hl + (size_t)r * II + col) = lo;
                }
            }
        }
    }
}

// ================= flash attention (fp16x3 HMMA, online softmax) =============
// grid (S/128, B*NH); 8 warps, each warp owns 16 q-rows. Writes ctx split.
#define FL_SMEM (32768 + 2 * 65536)
__global__ void __launch_bounds__(256, 1) flash_attn() {
    int q0 = blockIdx.x * 128;
    int head = blockIdx.y;
    int b = head / NHH, h_ = head % NHH;

    extern __shared__ char dyn[];
    uint32_t sb = smem_u32(dyn);
    const uint32_t QH = 0, QL = 16384;

    const __half* Qh = g_qh + (size_t)head * SS * DHH;
    const __half* Ql = g_ql + (size_t)head * SS * DHH;
    const __half* Kh = g_kh + (size_t)head * SS * DHH;
    const __half* Kl = g_kl + (size_t)head * SS * DHH;
    const __half* Vh = g_vh + (size_t)head * SS * DHH;
    const __half* Vl = g_vl + (size_t)head * SS * DHH;

    int tid = threadIdx.x, lane = tid & 31, wid = tid >> 5;
    int j = lane >> 3, rr = lane & 7;
    int g = lane >> 2, tig = lane & 3;

    auto load_tile = [&](uint32_t dst, const __half* src, int row0) {
#pragma unroll
        for (int i = 0; i < 4; i++) {
            int idx = tid + i * 256;
            int m = idx >> 3, c = idx & 7;
            cpasync16(sb + dst + fswz(m, c), src + (size_t)(row0 + m) * DHH + c * 8);
        }
    };

    load_tile(QH, Qh, q0);
    load_tile(QL, Ql, q0);
    load_tile(32768, Kh, 0);
    load_tile(32768 + 16384, Kl, 0);
    load_tile(32768 + 32768, Vh, 0);
    load_tile(32768 + 49152, Vl, 0);
    CP_COMMIT();

    float O[8][4] = {};
    float rm0 = -1e30f, rm1 = -1e30f, l0 = 0.0f, l1 = 0.0f;

    for (int kt = 0; kt < 4; kt++) {
        int st = kt & 1;
        if (kt + 1 < 4) {
            uint32_t nb = 32768 + (st ^ 1) * 65536;
            load_tile(nb,         Kh, (kt + 1) * 128);
            load_tile(nb + 16384, Kl, (kt + 1) * 128);
            load_tile(nb + 32768, Vh, (kt + 1) * 128);
            load_tile(nb + 49152, Vl, (kt + 1) * 128);
            CP_COMMIT();
            CP_WAIT1();
        } else {
            CP_WAIT0();
        }
        __syncthreads();

        uint32_t kH = sb + 32768 + st * 65536, kL = kH + 16384;
        uint32_t vH = kH + 32768, vL = kH + 49152;
        uint32_t qHb = sb + QH, qLb = sb + QL;

        // ---- S = Q @ K^T (fp32 acc) ----
        float S[16][4] = {};
#pragma unroll
        for (int ks = 0; ks < 4; ks++) {
            int am = wid * 16 + (j & 1) * 8 + rr;
            int ac = 2 * ks + (j >> 1);
            uint32_t ah[4], al[4];
            ldsm4(ah[0], ah[1], ah[2], ah[3], qHb + fswz(am, ac));
            ldsm4(al[0], al[1], al[2], al[3], qLb + fswz(am, ac));
#pragma unroll
            for (int fnp = 0; fnp < 8; fnp++) {
                int bn = fnp * 16 + (j >> 1) * 8 + rr;
                int bc = 2 * ks + (j & 1);
                uint32_t bo = fswz(bn, bc);
                uint32_t bh[4], bl[4];
                ldsm4(bh[0], bh[1], bh[2], bh[3], kH + bo);
                ldsm4(bl[0], bl[1], bl[2], bl[3], kL + bo);
                mma16816(S[2 * fnp],     ah, bh);
                mma16816(S[2 * fnp],     ah, bl);
                mma16816(S[2 * fnp],     al, bh);
                mma16816(S[2 * fnp + 1], ah, bh + 2);
                mma16816(S[2 * fnp + 1], ah, bl + 2);
                mma16816(S[2 * fnp + 1], al, bh + 2);
            }
        }

        // ---- online softmax ----
        float mx0 = -1e30f, mx1 = -1e30f;
#pragma unroll
        for (int fn = 0; fn < 16; fn++) {
            mx0 = fmaxf(mx0, fmaxf(S[fn][0], S[fn][1]));
            mx1 = fmaxf(mx1, fmaxf(S[fn][2], S[fn][3]));
        }
        mx0 = fmaxf(mx0, __shfl_xor_sync(~0u, mx0, 1));
        mx0 = fmaxf(mx0, __shfl_xor_sync(~0u, mx0, 2));
        mx1 = fmaxf(mx1, __shfl_xor_sync(~0u, mx1, 1));
        mx1 = fmaxf(mx1, __shfl_xor_sync(~0u, mx1, 2));
        float nm0 = fmaxf(rm0, mx0 * 0.125f);
        float nm1 = fmaxf(rm1, mx1 * 0.125f);
        float al0 = __expf(rm0 - nm0);
        float al1 = __expf(rm1 - nm1);
        rm0 = nm0; rm1 = nm1;
        float sum0 = 0.0f, sum1 = 0.0f;
#pragma unroll
        for (int fn = 0; fn < 16; fn++) {
            float p0 = __expf(fmaf(S[fn][0], 0.125f, -nm0));
            float p1 = __expf(fmaf(S[fn][1], 0.125f, -nm0));
            float p2 = __expf(fmaf(S[fn][2], 0.125f, -nm1));
            float p3 = __expf(fmaf(S[fn][3], 0.125f, -nm1));
            S[fn][0] = p0; S[fn][1] = p1; S[fn][2] = p2; S[fn][3] = p3;
            sum0 += p0 + p1; sum1 += p2 + p3;
        }
        sum0 += __shfl_xor_sync(~0u, sum0, 1);
        sum0 += __shfl_xor_sync(~0u, sum0, 2);
        sum1 += __shfl_xor_sync(~0u, sum1, 1);
        sum1 += __shfl_xor_sync(~0u, sum1, 2);
        l0 = l0 * al0 + sum0;
        l1 = l1 * al1 + sum1;
#pragma unroll
        for (int fo = 0; fo < 8; fo++) {
            O[fo][0] *= al0; O[fo][1] *= al0;
            O[fo][2] *= al1; O[fo][3] *= al1;
        }

        // ---- O += P @ V ----
#pragma unroll
        for (int kp = 0; kp < 8; kp++) {
            uint32_t aph[4], apl[4];
            aph[0] = packsplit(S[2 * kp][0],     S[2 * kp][1],     apl[0]);
            aph[1] = packsplit(S[2 * kp][2],     S[2 * kp][3],     apl[1]);
            aph[2] = packsplit(S[2 * kp + 1][0], S[2 * kp + 1][1], apl[2]);
            aph[3] = packsplit(S[2 * kp + 1][2], S[2 * kp + 1][3], apl[3]);
#pragma unroll
            for (int dg = 0; dg < 4; dg++) {
                int vrow = kp * 16 + (j & 1) * 8 + rr;
                int vc = dg * 2 + (j >> 1);
                uint32_t vo = fswz(vrow, vc);
                uint32_t vh[4], vl[4];
                ldsm4t(vh[0], vh[1], vh[2], vh[3], vH + vo);
                ldsm4t(vl[0], vl[1], vl[2], vl[3], vL + vo);
#pragma unroll
                for (int hg = 0; hg < 2; hg++) {
                    int fo = dg * 2 + hg;
                    mma16816(O[fo], aph, vh + hg * 2);
                    mma16816(O[fo], apl, vh + hg * 2);
                    mma16816(O[fo], aph, vl + hg * 2);
                }
            }
        }
        __syncthreads();
    }

    float inv0 = 1.0f / l0, inv1 = 1.0f / l1;
    int qr0 = q0 + wid * 16 + g;
    size_t t0 = (size_t)b * SS + qr0;
    size_t t1 = t0 + 8;
#pragma unroll
    for (int fo = 0; fo < 8; fo++) {
        int d = fo * 8 + tig * 2;
        int col = h_ * 64 + d;
        uint32_t lo;
        uint32_t hi = packsplit(O[fo][0] * inv0, O[fo][1] * inv0, lo);
        *(uint32_t*)(g_ch + t0 * HH + col) = hi;
        *(uint32_t*)(g_cl + t0 * HH + col) = lo;
        hi = packsplit(O[fo][2] * inv1, O[fo][3] * inv1, lo);
        *(uint32_t*)(g_ch + t1 * HH + col) = hi;
        *(uint32_t*)(g_cl + t1 * HH + col) = lo;
    }
}

// ================= LayerNorm ==================================================
__global__ void ln_kernel(const float* __restrict__ gamma, const float* __restrict__ beta,
                          float* __restrict__ dout, int mode) {
    size_t row = blockIdx.x;
    const float* in = (mode == 0) ? (g_preln + row * HH) : (g_attnout + row * HH);
    int tid = threadIdx.x;
    float x0 = in[tid], x1 = in[tid + 256], x2 = in[tid + 512];

    __shared__ float red[256];
    red[tid] = x0 + x1 + x2;
    __syncthreads();
    for (int s = 128; s > 0; s >>= 1) {
        if (tid < s) red[tid] += red[tid + s];
        __syncthreads();
    }
    float mean = red[0] * (1.0f / HH);
    __syncthreads();

    float c0 = x0 - mean, c1 = x1 - mean, c2 = x2 - mean;
    red[tid] = c0 * c0 + c1 * c1 + c2 * c2;
    __syncthreads();
    for (int s = 128; s > 0; s >>= 1) {
        if (tid < s) red[tid] += red[tid + s];
        __syncthreads();
    }
    float inv = 1.0f / sqrtf(red[0] * (1.0f / HH) + 1e-12f);

    float y0 = c0 * inv * gamma[tid]       + beta[tid];
    float y1 = c1 * inv * gamma[tid + 256] + beta[tid + 256];
    float y2 = c2 * inv * gamma[tid + 512] + beta[tid + 512];
    if (mode == 0) {
        g_attnout[row * HH + tid]       = y0;
        g_attnout[row * HH + tid + 256] = y1;
        g_attnout[row * HH + tid + 512] = y2;
        dout[row * HH + tid]       = y0;
        dout[row * HH + tid + 256] = y1;
        dout[row * HH + tid + 512] = y2;
    } else {
        g_xl[row * HH + tid]       = y0;
        g_xl[row * HH + tid + 256] = y1;
        g_xl[row * HH + tid + 512] = y2;
        __half h0 = __float2half_rn(y0), h1 = __float2half_rn(y1), h2 = __float2half_rn(y2);
        g_xlh[row * HH + tid]       = h0;
        g_xlh[row * HH + tid + 256] = h1;
        g_xlh[row * HH + tid + 512] = h2;
        g_xll[row * HH + tid]       = __float2half_rn(y0 - __half2float(h0));
        g_xll[row * HH + tid + 256] = __float2half_rn(y1 - __half2float(h1));
        g_xll[row * HH + tid + 512] = __float2half_rn(y2 - __half2float(h2));
    }
}

// ================= counters / router / scatter ===============================
__global__ void init_kernel() {
    int i = threadIdx.x;
    if (i < EE) { g_cnt[i] = 0; g_cur[i] = 0; }
}

__global__ void router_kernel(const float* __restrict__ Wr, const float* __restrict__ br,
                              float* __restrict__ logits_out) {
    int warp = threadIdx.x >> 5, lane = threadIdx.x & 31;
    int t = blockIdx.x * 8 + warp;
    const float* x = g_xl + (size_t)t * HH;

    float acc[EE] = {};
    for (int h = lane; h < HH; h += 32) {
        float xv = x[h];
        const float* w = Wr + (size_t)h * EE;
#pragma unroll
        for (int e = 0; e < EE; e++) acc[e] = fmaf(xv, w[e], acc[e]);
    }
#pragma unroll
    for (int e = 0; e < EE; e++)
        for (int o = 16; o > 0; o >>= 1) acc[e] += __shfl_down_sync(0xffffffffu, acc[e], o);

    if (lane == 0) {
        float lg[EE], mx = -1e30f;
#pragma unroll
        for (int e = 0; e < EE; e++) {
            lg[e] = acc[e] + br[e];
            logits_out[(size_t)t * EE + e] = lg[e];
            mx = fmaxf(mx, lg[e]);
        }
        float p[EE], s = 0.0f;
#pragma unroll
        for (int e = 0; e < EE; e++) { p[e] = expf(lg[e] - mx); s += p[e]; }
        float invs = 1.0f / s;
#pragma unroll
        for (int e = 0; e < EE; e++) p[e] *= invs;

        int i1 = 0;
#pragma unroll
        for (int e = 1; e < EE; e++) if (p[e] > p[i1]) i1 = e;
        int i2 = (i1 == 0) ? 1 : 0;
#pragma unroll
        for (int e = 0; e < EE; e++) if (e != i1 && p[e] > p[i2]) i2 = e;

        float w1 = p[i1], w2 = p[i2], inv = 1.0f / (w1 + w2);
        g_ti[t * 2]     = i1;  g_tw[t * 2]     = w1 * inv;
        g_ti[t * 2 + 1] = i2;  g_tw[t * 2 + 1] = w2 * inv;
        atomicAdd(&g_cnt[i1], 1);
        atomicAdd(&g_cnt[i2], 1);
    }
}

__global__ void offsets_kernel() {
    if (threadIdx.x == 0) {
        int o = 0;
        for (int e = 0; e < EE; e++) { g_off[e] = o; o += g_cnt[e]; }
    }
}

__global__ void scatter_kernel() {
    int t = blockIdx.x * 256 + threadIdx.x;
    if (t >= TT) return;
#pragma unroll
    for (int s = 0; s < 2; s++) {
        int e = g_ti[t * 2 + s];
        int pos = atomicAdd(&g_cur[e], 1);
        int r = g_off[e] + pos;
        g_etok[r] = t;
        g_ew[r] = g_tw[t * 2 + s];
    }
}

// ================= host launcher =============================================
#define HG_SMEM 65536

extern "C" void kernel_launch(void* const* d_in, const int* in_sizes, int n_in,
                              void* d_out, int out_size) {
    const float* X        = (const float*)d_in[0];
    const float* Wq       = (const float*)d_in[1];
    const float* bq       = (const float*)d_in[2];
    const float* Wk       = (const float*)d_in[3];
    const float* bk       = (const float*)d_in[4];
    const float* Wv       = (const float*)d_in[5];
    const float* bv       = (const float*)d_in[6];
    const float* Wo       = (const float*)d_in[7];
    const float* bo       = (const float*)d_in[8];
    const float* ln_ag    = (const float*)d_in[9];
    const float* ln_ab    = (const float*)d_in[10];
    const float* ln_fg    = (const float*)d_in[11];
    const float* ln_fb    = (const float*)d_in[12];
    const float* Wr       = (const float*)d_in[13];
    const float* br       = (const float*)d_in[14];
    const float* W_up     = (const float*)d_in[15];
    const float* b_up     = (const float*)d_in[16];
    const float* W_new    = (const float*)d_in[17];
    const float* b_new    = (const float*)d_in[18];
    const float* W_down   = (const float*)d_in[19];
    const float* b_down   = (const float*)d_in[20];

    float* out    = (float*)d_out;                    // layer_output [T, H]
    float* logits = out + (size_t)TT * HH;            // router_logits [T, E]

    static int attr_done = 0;
    if (!attr_done) {
        cudaFuncSetAttribute(hgemm<0>, cudaFuncAttributeMaxDynamicSharedMemorySize, HG_SMEM);
        cudaFuncSetAttribute(hgemm<1>, cudaFuncAttributeMaxDynamicSharedMemorySize, HG_SMEM);
        cudaFuncSetAttribute(hgemm<2>, cudaFuncAttributeMaxDynamicSharedMemorySize, HG_SMEM);
        cudaFuncSetAttribute(ffn_upgate, cudaFuncAttributeMaxDynamicSharedMemorySize, UPG_SMEM);
        cudaFuncSetAttribute(flash_attn, cudaFuncAttributeMaxDynamicSharedMemorySize, FL_SMEM);
        attr_done = 1;
    }

    __half *wqkvh, *wqkvl, *woh, *wol, *wuh, *wul, *wnh, *wnl, *wdh, *wdl, *xsh, *xsl;
    cudaGetSymbolAddress((void**)&wqkvh, g_wqkvh);
    cudaGetSymbolAddress((void**)&wqkvl, g_wqkvl);
    cudaGetSymbolAddress((void**)&woh, g_woh);
    cudaGetSymbolAddress((void**)&wol, g_wol);
    cudaGetSymbolAddress((void**)&wuh, g_wuh);
    cudaGetSymbolAddress((void**)&wul, g_wul);
    cudaGetSymbolAddress((void**)&wnh, g_wnh);
    cudaGetSymbolAddress((void**)&wnl, g_wnl);
    cudaGetSymbolAddress((void**)&wdh, g_wdh);
    cudaGetSymbolAddress((void**)&wdl, g_wdl);
    cudaGetSymbolAddress((void**)&xsh, g_xsh);
    cudaGetSymbolAddress((void**)&xsl, g_xsl);

    // weight prep: transpose + fp16 hi/lo split
    tsplit<<<dim3(HH / 32, HH / 32, 1), dim3(32, 8)>>>(Wq, wqkvh,               wqkvl,               HH, HH);
    tsplit<<<dim3(HH / 32, HH / 32, 1), dim3(32, 8)>>>(Wk, wqkvh + HH * HH,     wqkvl + HH * HH,     HH, HH);
    tsplit<<<dim3(HH / 32, HH / 32, 1), dim3(32, 8)>>>(Wv, wqkvh + 2 * HH * HH, wqkvl + 2 * HH * HH, HH, HH);
    tsplit<<<dim3(HH / 32, HH / 32, 1), dim3(32, 8)>>>(Wo, woh, wol, HH, HH);
    tsplit<<<dim3(II / 32, HH / 32, EE), dim3(32, 8)>>>(W_up,  wuh, wul, HH, II);
    tsplit<<<dim3(II / 32, HH / 32, EE), dim3(32, 8)>>>(W_new, wnh, wnl, HH, II);
    tsplit<<<dim3(HH / 32, II / 32, EE), dim3(32, 8)>>>(W_down, wdh, wdl, II, HH);

    init_kernel<<<1, 32>>>();
    fsplit<<<TT * HH / 1024, 256>>>(X, xsh, xsl);

    // QKV (fused, emits fp16 splits) -> flash attention -> proj
    hgemm<0><<<dim3(3 * HH / 128, TT / 128), 256, HG_SMEM>>>(bq, bk, bv, nullptr);
    flash_attn<<<dim3(SS / 128, BB * NHH), 256, FL_SMEM>>>();
    hgemm<1><<<dim3(HH / 128, TT / 128), 256, HG_SMEM>>>(bo, X, nullptr, nullptr);

    ln_kernel<<<TT, 256>>>(ln_ag, ln_ab, out, 0);
    ln_kernel<<<TT, 256>>>(ln_fg, ln_fb, out, 1);
    router_kernel<<<TT / 8, 256>>>(Wr, br, logits);
    offsets_kernel<<<1, 32>>>();
    scatter_kernel<<<(TT + 255) / 256, 256>>>();

    // MoE FFN: fused up+gate, then down (row-group = blockIdx.x for L2 reuse)
    ffn_upgate<<<dim3(32, EE * 24), 256, UPG_SMEM>>>(b_up, b_new);
    hgemm<2><<<dim3(32, EE * 6), 256, HG_SMEM>>>(b_down, nullptr, nullptr, out);
}

// round 7
// speedup vs baseline: 2.9734x; 1.1014x over previous
#include <cuda_runtime.h>
#include <cuda_fp16.h>
#include <math.h>
#include <stdint.h>

#define TT  4096   // B*S
#define HH  768
#define SS  512
#define BB  8
#define NHH 12
#define DHH 64
#define II  3072
#define EE  8
#define ENT 8192   // TT * TOPK

// ---------------- scratch (static device allocations; no cudaMalloc) --------
__device__ float g_preln[TT * HH];
__device__ float g_attnout[TT * HH];
__device__ float g_xl[TT * HH];
__device__ __half g_xlh[TT * HH];           // xl split
__device__ __half g_xll[TT * HH];
__device__ __half g_xsh[TT * HH];           // X split
__device__ __half g_xsl[TT * HH];
__device__ __half g_qh[TT * HH];            // Q split, [B*NH][S][DH]
__device__ __half g_ql[TT * HH];
__device__ __half g_kh[TT * HH];
__device__ __half g_kl[TT * HH];
__device__ __half g_vh[TT * HH];
__device__ __half g_vl[TT * HH];
__device__ __half g_ch[TT * HH];            // ctx split [T][H]
__device__ __half g_cl[TT * HH];
__device__ __half g_hh[(size_t)ENT * II];   // FFN hidden h = gelu(u)*gate, hi
__device__ __half g_hl[(size_t)ENT * II];   // lo
__device__ __half g_wqkvh[3 * HH * HH];     // [Wq;Wk;Wv] each [768 k][768 n] (ORIGINAL layout)
__device__ __half g_wqkvl[3 * HH * HH];
__device__ __half g_woh[HH * HH];           // Wo [768 k][768 n]
__device__ __half g_wol[HH * HH];
__device__ __half g_wuh[(size_t)EE * HH * II];  // W_up  hi [E][H k][I n]
__device__ __half g_wul[(size_t)EE * HH * II];
__device__ __half g_wnh[(size_t)EE * HH * II];  // W_new hi
__device__ __half g_wnl[(size_t)EE * HH * II];
__device__ __half g_wdh[(size_t)EE * II * HH];  // W_down hi [E][I k][H n]
__device__ __half g_wdl[(size_t)EE * II * HH];
__device__ int   g_cnt[EE];
__device__ int   g_off[EE];
__device__ int   g_cur[EE];
__device__ int   g_etok[ENT];
__device__ float g_ew[ENT];
__device__ int   g_ti[TT * 2];
__device__ float g_tw[TT * 2];

// ======================= asm helpers (portable sm_80+) =======================
__device__ __forceinline__ uint32_t smem_u32(const void* p) {
    uint32_t a;
    asm("{ .reg .u64 t; cvta.to.shared.u64 t, %1; cvt.u32.u64 %0, t; }" : "=r"(a) : "l"(p));
    return a;
}
__device__ __forceinline__ void ldsm4(uint32_t& r0, uint32_t& r1, uint32_t& r2, uint32_t& r3,
                                      uint32_t addr) {
    asm volatile("ldmatrix.sync.aligned.m8n8.x4.shared.b16 {%0,%1,%2,%3}, [%4];"
                 : "=r"(r0), "=r"(r1), "=r"(r2), "=r"(r3) : "r"(addr));
}
__device__ __forceinline__ void ldsm4t(uint32_t& r0, uint32_t& r1, uint32_t& r2, uint32_t& r3,
                                       uint32_t addr) {
    asm volatile("ldmatrix.sync.aligned.m8n8.x4.trans.shared.b16 {%0,%1,%2,%3}, [%4];"
                 : "=r"(r0), "=r"(r1), "=r"(r2), "=r"(r3) : "r"(addr));
}
__device__ __forceinline__ void mma16816(float* c, const uint32_t* a, const uint32_t* b) {
    asm volatile(
        "mma.sync.aligned.m16n8k16.row.col.f32.f16.f16.f32 "
        "{%0,%1,%2,%3}, {%4,%5,%6,%7}, {%8,%9}, {%0,%1,%2,%3};"
        : "+f"(c[0]), "+f"(c[1]), "+f"(c[2]), "+f"(c[3])
        : "r"(a[0]), "r"(a[1]), "r"(a[2]), "r"(a[3]), "r"(b[0]), "r"(b[1]));
}
__device__ __forceinline__ void cpasync16(uint32_t saddr, const void* gaddr) {
    asm volatile("cp.async.cg.shared.global [%0], [%1], 16;" :: "r"(saddr), "l"(gaddr));
}
#define CP_COMMIT() asm volatile("cp.async.commit_group;" ::: "memory")
#define CP_WAIT1()  asm volatile("cp.async.wait_group 1;" ::: "memory")
#define CP_WAIT0()  asm volatile("cp.async.wait_group 0;" ::: "memory")

// xor-swizzled smem byte offset for a [rows x 32 halves] tile (row = 64B)
__device__ __forceinline__ uint32_t swoff(int m, int kg) {
    return (uint32_t)(m * 64 + ((kg ^ ((m >> 1) & 3)) << 4));
}
// xor-swizzled smem byte offset for a [rows x 64 halves] tile (row = 128B, 8 chunks)
__device__ __forceinline__ uint32_t fswz(int m, int c) {
    return (uint32_t)(m * 128 + ((c ^ (m & 7)) << 4));
}
// xor-swizzled smem byte offset for a [32 k x 128 halves] B tile (row = 256B, 16 chunks)
__device__ __forceinline__ uint32_t bswz(int k, int c) {
    return (uint32_t)(k * 256 + ((c ^ (k & 7)) << 4));
}
__device__ __forceinline__ uint32_t packsplit(float v0, float v1, uint32_t& lo) {
    __half h0 = __float2half_rn(v0), h1 = __float2half_rn(v1);
    __half2 l = __halves2half2(__float2half_rn(v0 - __half2float(h0)),
                               __float2half_rn(v1 - __half2float(h1)));
    lo = *(uint32_t*)&l;
    __half2 h = __halves2half2(h0, h1);
    return *(uint32_t*)&h;
}

// ============ elementwise fp32 -> fp16 hi/lo split (pure streaming) ==========
__global__ void fsplit(const float* __restrict__ src, __half* __restrict__ h,
                       __half* __restrict__ l) {
    size_t i = ((size_t)blockIdx.x * 256 + threadIdx.x) * 4;
    float4 v = *(const float4*)(src + i);
    uint32_t lo0, lo1;
    uint32_t h0 = packsplit(v.x, v.y, lo0);
    uint32_t h1 = packsplit(v.z, v.w, lo1);
    *(uint32_t*)(h + i)     = h0;
    *(uint32_t*)(h + i + 2) = h1;
    *(uint32_t*)(l + i)     = lo0;
    *(uint32_t*)(l + i + 2) = lo1;
}

// ================= unified fp16x3 pipelined HMMA GEMM ========================
// B operand is [K][N] row-major (ORIGINAL weight layout), loaded via ldsm4t.
// MODE 0: QKV   A=g_xsh/l [t][768]   B=g_wqkvh/l 3x[768][768] -> g_qh..g_vl split
// MODE 1: PROJ  A=g_ch/l  [t][768]   B=g_woh/l   [768][768]   -> g_preln (+bo+X)
// MODE 2: DOWN  A=g_hh/l  [r][3072]  B=g_wdh/l e [3072][768]  -> atomicAdd out
template<int MODE>
__global__ void __launch_bounds__(256, 2) hgemm(
    const float* __restrict__ p0, const float* __restrict__ p1,
    const float* __restrict__ p2, float* __restrict__ pout) {

    constexpr int KD = (MODE == 2) ? II : HH;   // A K-dim
    constexpr int NS = KD / 32;

    int e = 0, base = 0, end = 0, m0 = 0, n0;
    if (MODE == 2) {
        e = blockIdx.y / 6;
        n0 = (blockIdx.y % 6) * 128;
        base = g_off[e] + blockIdx.x * 128;
        end  = g_off[e] + g_cnt[e];
        if (base >= end) return;
    } else {
        m0 = blockIdx.y * 128;
        n0 = blockIdx.x * 128;
    }

    extern __shared__ char dyn[];
    __shared__ int   s_tok[128];
    __shared__ float s_w[128];

    int tid = threadIdx.x, lane = tid & 31, wid = tid >> 5;
    int wm = wid & 1, wn = wid >> 1;

    if (MODE == 2 && tid < 128) {
        int r = min(base + tid, end - 1);
        s_tok[tid] = g_etok[r];
        s_w[tid]   = g_ew[r];
    }
    __syncthreads();

    // B pointers + column base within B's N dim (stride HH for all modes)
    const __half *Bh, *Bl, *Ah, *Al;
    int nb;
    if (MODE == 0) {
        int which = n0 / HH;
        Bh = g_wqkvh + (size_t)which * HH * HH;
        Bl = g_wqkvl + (size_t)which * HH * HH;
        Ah = g_xsh; Al = g_xsl;
        nb = n0 - which * HH;
    } else if (MODE == 1) {
        Bh = g_woh; Bl = g_wol; Ah = g_ch; Al = g_cl; nb = n0;
    } else {
        Bh = g_wdh + (size_t)e * II * HH; Bl = g_wdl + (size_t)e * II * HH;
        Ah = g_hh;  Al = g_hl; nb = n0;
    }

    uint32_t sbase = smem_u32(dyn);

    auto issue = [&](int slab, int st) {
        int k0 = slab * 32;
        uint32_t sb = sbase + st * 32768;
#pragma unroll
        for (int i = 0; i < 2; i++) {
            int c = tid + i * 256;
            // A tile [128 m][32 k]
            {
                int m = c >> 2, kc = c & 3;
                uint32_t so = sb + swoff(m, kc);
                int koff = k0 + kc * 8;
                size_t aoff;
                if (MODE < 2) aoff = (size_t)(m0 + m) * KD;
                else          aoff = (size_t)min(base + m, end - 1) * KD;
                cpasync16(so,        Ah + aoff + koff);
                cpasync16(so + 8192, Al + aoff + koff);
            }
            // B tile [32 k][128 n] from [K][N] gmem
            {
                int k = c >> 4, cb = c & 15;
                uint32_t bo = sb + 16384 + bswz(k, cb);
                size_t go = (size_t)(k0 + k) * HH + nb + cb * 8;
                cpasync16(bo,        Bh + go);
                cpasync16(bo + 8192, Bl + go);
            }
        }
    };

    int j = lane >> 3, rr = lane & 7;
    int amRow = wm * 64 + (j & 1) * 8 + rr;
    int akSel = j >> 1;
    float C[4][4][4] = {};

    issue(0, 0);
    CP_COMMIT();
    for (int s = 0; s < NS; s++) {
        int st = s & 1;
        if (s + 1 < NS) {
            issue(s + 1, st ^ 1);
            CP_COMMIT();
            CP_WAIT1();
        } else {
            CP_WAIT0();
        }
        __syncthreads();
        uint32_t aH = sbase + st * 32768, aL = aH + 8192;
        uint32_t bH = aH + 16384, bL = aH + 24576;
#pragma unroll
        for (int kk = 0; kk < 2; kk++) {
            uint32_t bh[4][2], bl[4][2];
#pragma unroll
            for (int f16 = 0; f16 < 2; f16++) {
                int krow = kk * 16 + (j & 1) * 8 + rr;
                int cc = wn * 4 + f16 * 2 + (j >> 1);
                uint32_t o = bswz(krow, cc);
                ldsm4t(bh[f16 * 2][0], bh[f16 * 2][1], bh[f16 * 2 + 1][0], bh[f16 * 2 + 1][1], bH + o);
                ldsm4t(bl[f16 * 2][0], bl[f16 * 2][1], bl[f16 * 2 + 1][0], bl[f16 * 2 + 1][1], bL + o);
            }
#pragma unroll
            for (int fm = 0; fm < 4; fm++) {
                int m = amRow + fm * 16;
                int kg = kk * 2 + akSel;
                uint32_t o = (uint32_t)(m * 64 + ((kg ^ ((m >> 1) & 3)) << 4));
                uint32_t ah[4], al[4];
                ldsm4(ah[0], ah[1], ah[2], ah[3], aH + o);
                ldsm4(al[0], al[1], al[2], al[3], aL + o);
#pragma unroll
                for (int fn = 0; fn < 4; fn++) {
                    mma16816(C[fm][fn], ah, bh[fn]);
                    mma16816(C[fm][fn], ah, bl[fn]);
                    mma16816(C[fm][fn], al, bh[fn]);
                }
            }
        }
        __syncthreads();
    }

    // ----------------------------- epilogue ---------------------------------
    int g = lane >> 2, tig = lane & 3;

    __half *qh_out = nullptr, *ql_out = nullptr;
    const float* mbias = nullptr;
    int hcol0 = 0;
    if (MODE == 0) {
        int which = n0 / HH;
        qh_out = (which == 0) ? g_qh : (which == 1) ? g_kh : g_vh;
        ql_out = (which == 0) ? g_ql : (which == 1) ? g_kl : g_vl;
        mbias  = (which == 0) ? p0 : (which == 1) ? p1 : p2;
        hcol0  = n0 - which * HH;
    }

#pragma unroll
    for (int fm = 0; fm < 4; fm++) {
        int rowl0 = wm * 64 + fm * 16 + g;
#pragma unroll
        for (int fn = 0; fn < 4; fn++) {
            int coll = wn * 32 + fn * 8 + tig * 2;
#pragma unroll
            for (int hf = 0; hf < 2; hf++) {
                int ml = rowl0 + hf * 8;
                float c0 = C[fm][fn][hf * 2], c1 = C[fm][fn][hf * 2 + 1];
                if (MODE == 0) {
                    int t = m0 + ml;
                    int hcol = hcol0 + coll;
                    int h = hcol >> 6, d = hcol & 63;
                    int b = t >> 9, sI = t & 511;
                    size_t o = (((size_t)(b * NHH + h)) * SS + sI) * DHH + d;
                    uint32_t lo;
                    uint32_t hi = packsplit(c0 + mbias[hcol], c1 + mbias[hcol + 1], lo);
                    *(uint32_t*)(qh_out + o) = hi;
                    *(uint32_t*)(ql_out + o) = lo;
                } else if (MODE == 1) {
                    size_t t = m0 + ml;
                    int col = n0 + coll;
                    float2 xr = *(const float2*)(p1 + t * HH + col);
                    float2 v = {c0 + p0[col] + xr.x, c1 + p0[col + 1] + xr.y};
                    *(float2*)(g_preln + t * HH + col) = v;
                } else {
                    if (base + ml < end) {
                        int col = n0 + coll;
                        int t = s_tok[ml];
                        float w = s_w[ml];
                        const float* eb = p0 + (size_t)e * HH;
                        atomicAdd(pout + (size_t)t * HH + col,     (c0 + eb[col]) * w);
                        atomicAdd(pout + (size_t)t * HH + col + 1, (c1 + eb[col + 1]) * w);
                    }
                }
            }
        }
    }
}

// ============ fused up+gate pipelined HMMA grouped GEMM ======================
// h[r, i] = gelu(xl@Wu + bu) * (xl@Wn + bn)  -> g_hh/g_hl (fp16 split)
// B matrices in ORIGINAL [H k][I n] layout.
#define UPG_SMEM (2 * 49152)
__global__ void __launch_bounds__(256, 1) ffn_upgate(
    const float* __restrict__ bu_, const float* __restrict__ bn_) {
    int e = blockIdx.y / 24;
    int n0 = (blockIdx.y % 24) * 128;
    int base = g_off[e] + blockIdx.x * 128;
    int end  = g_off[e] + g_cnt[e];
    if (base >= end) return;

    extern __shared__ char dyn[];
    __shared__ int s_tok[128];

    int tid = threadIdx.x, lane = tid & 31, wid = tid >> 5;
    int wm = wid & 1, wn = wid >> 1;

    if (tid < 128) s_tok[tid] = g_etok[min(base + tid, end - 1)];
    __syncthreads();

    const __half* Buh = g_wuh + (size_t)e * HH * II;
    const __half* Bul = g_wul + (size_t)e * HH * II;
    const __half* Bnh = g_wnh + (size_t)e * HH * II;
    const __half* Bnl = g_wnl + (size_t)e * HH * II;
    uint32_t sbase = smem_u32(dyn);

    auto issue = [&](int slab, int st) {
        int k0 = slab * 32;
        uint32_t sb = sbase + st * 49152;
#pragma unroll
        for (int i = 0; i < 2; i++) {
            int c = tid + i * 256;
            {
                int m = c >> 2, kc = c & 3;
                uint32_t so = sb + swoff(m, kc);
                size_t aoff = (size_t)s_tok[m] * HH + k0 + kc * 8;
                cpasync16(so,        g_xlh + aoff);
                cpasync16(so + 8192, g_xll + aoff);
            }
            {
                int k = c >> 4, cb = c & 15;
                uint32_t bo = sb + 16384 + bswz(k, cb);
                size_t go = (size_t)(k0 + k) * II + n0 + cb * 8;
                cpasync16(bo,         Buh + go);
                cpasync16(bo + 8192,  Bul + go);
                cpasync16(bo + 16384, Bnh + go);
                cpasync16(bo + 24576, Bnl + go);
            }
        }
    };

    int j = lane >> 3, rr = lane & 7;
    int amRow = wm * 64 + (j & 1) * 8 + rr;
    int akSel = j >> 1;
    float Cu[4][4][4] = {}, Cn[4][4][4] = {};

    issue(0, 0);
    CP_COMMIT();
    for (int s = 0; s < HH / 32; s++) {
        int st = s & 1;
        if (s + 1 < HH / 32) {
            issue(s + 1, st ^ 1);
            CP_COMMIT();
            CP_WAIT1();
        } else {
            CP_WAIT0();
        }
        __syncthreads();
        uint32_t aH = sbase + st * 49152, aL = aH + 8192;
        uint32_t uH = aH + 16384, uL = aH + 24576;
        uint32_t nH = aH + 32768, nL = aH + 40960;
#pragma unroll
        for (int kk = 0; kk < 2; kk++) {
            uint32_t buh[4][2], bul[4][2], bnh[4][2], bnl[4][2];
#pragma unroll
            for (int f16 = 0; f16 < 2; f16++) {
                int krow = kk * 16 + (j & 1) * 8 + rr;
                int cc = wn * 4 + f16 * 2 + (j >> 1);
                uint32_t o = bswz(krow, cc);
                ldsm4t(buh[f16 * 2][0], buh[f16 * 2][1], buh[f16 * 2 + 1][0], buh[f16 * 2 + 1][1], uH + o);
                ldsm4t(bul[f16 * 2][0], bul[f16 * 2][1], bul[f16 * 2 + 1][0], bul[f16 * 2 + 1][1], uL + o);
                ldsm4t(bnh[f16 * 2][0], bnh[f16 * 2][1], bnh[f16 * 2 + 1][0], bnh[f16 * 2 + 1][1], nH + o);
                ldsm4t(bnl[f16 * 2][0], bnl[f16 * 2][1], bnl[f16 * 2 + 1][0], bnl[f16 * 2 + 1][1], nL + o);
            }
#pragma unroll
            for (int fm = 0; fm < 4; fm++) {
                int m = amRow + fm * 16;
                int kg = kk * 2 + akSel;
                uint32_t o = (uint32_t)(m * 64 + ((kg ^ ((m >> 1) & 3)) << 4));
                uint32_t ah[4], al[4];
                ldsm4(ah[0], ah[1], ah[2], ah[3], aH + o);
                ldsm4(al[0], al[1], al[2], al[3], aL + o);
#pragma unroll
                for (int fn = 0; fn < 4; fn++) {
                    mma16816(Cu[fm][fn], ah, buh[fn]);
                    mma16816(Cu[fm][fn], ah, bul[fn]);
                    mma16816(Cu[fm][fn], al, buh[fn]);
                    mma16816(Cn[fm][fn], ah, bnh[fn]);
                    mma16816(Cn[fm][fn], ah, bnl[fn]);
                    mma16816(Cn[fm][fn], al, bnh[fn]);
                }
            }
        }
        __syncthreads();
    }

    int g = lane >> 2, tig = lane & 3;
    const float* bu = bu_ + (size_t)e * II;
    const float* bn = bn_ + (size_t)e * II;
#pragma unroll
    for (int fm = 0; fm < 4; fm++) {
        int rowl0 = wm * 64 + fm * 16 + g;
#pragma unroll
        for (int fn = 0; fn < 4; fn++) {
            int col = n0 + wn * 32 + fn * 8 + tig * 2;
            float bu0 = bu[col], bu1 = bu[col + 1];
            float bn0 = bn[col], bn1 = bn[col + 1];
#pragma unroll
            for (int hf = 0; hf < 2; hf++) {
                int r = base + rowl0 + hf * 8;
                if (r < end) {
                    float u0 = Cu[fm][fn][hf * 2] + bu0, u1 = Cu[fm][fn][hf * 2 + 1] + bu1;
                    float h0 = u0 * normcdff(u0) * (Cn[fm][fn][hf * 2] + bn0);
                    float h1 = u1 * normcdff(u1) * (Cn[fm][fn][hf * 2 + 1] + bn1);
                    uint32_t lo;
                    uint32_t hi = packsplit(h0, h1, lo);
                    *(uint32_t*)(g_hh + (size_t)r * II + col) = hi;
                    *(uint32_t*)(g_hl + (size_t)r * II + col) = lo;
                }
            }
        }
    }
}

// ================= flash attention (fp16x3 HMMA, online softmax) =============
#define FL_SMEM (32768 + 2 * 65536)
__global__ void __launch_bounds__(256, 1) flash_attn() {
    int q0 = blockIdx.x * 128;
    int head = blockIdx.y;
    int b = head / NHH, h_ = head % NHH;

    extern __shared__ char dyn[];
    uint32_t sb = smem_u32(dyn);
    const uint32_t QH = 0, QL = 16384;

    const __half* Qh = g_qh + (size_t)head * SS * DHH;
    const __half* Ql = g_ql + (size_t)head * SS * DHH;
    const __half* Kh = g_kh + (size_t)head * SS * DHH;
    const __half* Kl = g_kl + (size_t)head * SS * DHH;
    const __half* Vh = g_vh + (size_t)head * SS * DHH;
    const __half* Vl = g_vl + (size_t)head * SS * DHH;

    int tid = threadIdx.x, lane = tid & 31, wid = tid >> 5;
    int j = lane >> 3, rr = lane & 7;
    int g = lane >> 2, tig = lane & 3;

    auto load_tile = [&](uint32_t dst, const __half* src, int row0) {
#pragma unroll
        for (int i = 0; i < 4; i++) {
            int idx = tid + i * 256;
            int m = idx >> 3, c = idx & 7;
            cpasync16(sb + dst + fswz(m, c), src + (size_t)(row0 + m) * DHH + c * 8);
        }
    };

    load_tile(QH, Qh, q0);
    load_tile(QL, Ql, q0);
    load_tile(32768, Kh, 0);
    load_tile(32768 + 16384, Kl, 0);
    load_tile(32768 + 32768, Vh, 0);
    load_tile(32768 + 49152, Vl, 0);
    CP_COMMIT();

    float O[8][4] = {};
    float rm0 = -1e30f, rm1 = -1e30f, l0 = 0.0f, l1 = 0.0f;

    for (int kt = 0; kt < 4; kt++) {
        int st = kt & 1;
        if (kt + 1 < 4) {
            uint32_t nb = 32768 + (st ^ 1) * 65536;
            load_tile(nb,         Kh, (kt + 1) * 128);
            load_tile(nb + 16384, Kl, (kt + 1) * 128);
            load_tile(nb + 32768, Vh, (kt + 1) * 128);
            load_tile(nb + 49152, Vl, (kt + 1) * 128);
            CP_COMMIT();
            CP_WAIT1();
        } else {
            CP_WAIT0();
        }
        __syncthreads();

        uint32_t kH = sb + 32768 + st * 65536, kL = kH + 16384;
        uint32_t vH = kH + 32768, vL = kH + 49152;
        uint32_t qHb = sb + QH, qLb = sb + QL;

        float S[16][4] = {};
#pragma unroll
        for (int ks = 0; ks < 4; ks++) {
            int am = wid * 16 + (j & 1) * 8 + rr;
            int ac = 2 * ks + (j >> 1);
            uint32_t ah[4], al[4];
            ldsm4(ah[0], ah[1], ah[2], ah[3], qHb + fswz(am, ac));
            ldsm4(al[0], al[1], al[2], al[3], qLb + fswz(am, ac));
#pragma unroll
            for (int fnp = 0; fnp < 8; fnp++) {
                int bn = fnp * 16 + (j >> 1) * 8 + rr;
                int bc = 2 * ks + (j & 1);
                uint32_t bo = fswz(bn, bc);
                uint32_t bh[4], bl[4];
                ldsm4(bh[0], bh[1], bh[2], bh[3], kH + bo);
                ldsm4(bl[0], bl[1], bl[2], bl[3], kL + bo);
                mma16816(S[2 * fnp],     ah, bh);
                mma16816(S[2 * fnp],     ah, bl);
                mma16816(S[2 * fnp],     al, bh);
                mma16816(S[2 * fnp + 1], ah, bh + 2);
                mma16816(S[2 * fnp + 1], ah, bl + 2);
                mma16816(S[2 * fnp + 1], al, bh + 2);
            }
        }

        float mx0 = -1e30f, mx1 = -1e30f;
#pragma unroll
        for (int fn = 0; fn < 16; fn++) {
            mx0 = fmaxf(mx0, fmaxf(S[fn][0], S[fn][1]));
            mx1 = fmaxf(mx1, fmaxf(S[fn][2], S[fn][3]));
        }
        mx0 = fmaxf(mx0, __shfl_xor_sync(~0u, mx0, 1));
        mx0 = fmaxf(mx0, __shfl_xor_sync(~0u, mx0, 2));
        mx1 = fmaxf(mx1, __shfl_xor_sync(~0u, mx1, 1));
        mx1 = fmaxf(mx1, __shfl_xor_sync(~0u, mx1, 2));
        float nm0 = fmaxf(rm0, mx0 * 0.125f);
        float nm1 = fmaxf(rm1, mx1 * 0.125f);
        float al0 = __expf(rm0 - nm0);
        float al1 = __expf(rm1 - nm1);
        rm0 = nm0; rm1 = nm1;
        float sum0 = 0.0f, sum1 = 0.0f;
#pragma unroll
        for (int fn = 0; fn < 16; fn++) {
            float p0 = __expf(fmaf(S[fn][0], 0.125f, -nm0));
            float p1 = __expf(fmaf(S[fn][1], 0.125f, -nm0));
            float p2 = __expf(fmaf(S[fn][2], 0.125f, -nm1));
            float p3 = __expf(fmaf(S[fn][3], 0.125f, -nm1));
            S[fn][0] = p0; S[fn][1] = p1; S[fn][2] = p2; S[fn][3] = p3;
            sum0 += p0 + p1; sum1 += p2 + p3;
        }
        sum0 += __shfl_xor_sync(~0u, sum0, 1);
        sum0 += __shfl_xor_sync(~0u, sum0, 2);
        sum1 += __shfl_xor_sync(~0u, sum1, 1);
        sum1 += __shfl_xor_sync(~0u, sum1, 2);
        l0 = l0 * al0 + sum0;
        l1 = l1 * al1 + sum1;
#pragma unroll
        for (int fo = 0; fo < 8; fo++) {
            O[fo][0] *= al0; O[fo][1] *= al0;
            O[fo][2] *= al1; O[fo][3] *= al1;
        }

#pragma unroll
        for (int kp = 0; kp < 8; kp++) {
            uint32_t aph[4], apl[4];
            aph[0] = packsplit(S[2 * kp][0],     S[2 * kp][1],     apl[0]);
            aph[1] = packsplit(S[2 * kp][2],     S[2 * kp][3],     apl[1]);
            aph[2] = packsplit(S[2 * kp + 1][0], S[2 * kp + 1][1], apl[2]);
            aph[3] = packsplit(S[2 * kp + 1][2], S[2 * kp + 1][3], apl[3]);
#pragma unroll
            for (int dg = 0; dg < 4; dg++) {
                int vrow = kp * 16 + (j & 1) * 8 + rr;
                int vc = dg * 2 + (j >> 1);
                uint32_t vo = fswz(vrow, vc);
                uint32_t vh[4], vl[4];
                ldsm4t(vh[0], vh[1], vh[2], vh[3], vH + vo);
                ldsm4t(vl[0], vl[1], vl[2], vl[3], vL + vo);
#pragma unroll
                for (int hg = 0; hg < 2; hg++) {
                    int fo = dg * 2 + hg;
                    mma16816(O[fo], aph, vh + hg * 2);
                    mma16816(O[fo], apl, vh + hg * 2);
                    mma16816(O[fo], aph, vl + hg * 2);
                }
            }
        }
        __syncthreads();
    }

    float inv0 = 1.0f / l0, inv1 = 1.0f / l1;
    int qr0 = q0 + wid * 16 + g;
    size_t t0 = (size_t)b * SS + qr0;
    size_t t1 = t0 + 8;
#pragma unroll
    for (int fo = 0; fo < 8; fo++) {
        int d = fo * 8 + tig * 2;
        int col = h_ * 64 + d;
        uint32_t lo;
        uint32_t hi = packsplit(O[fo][0] * inv0, O[fo][1] * inv0, lo);
        *(uint32_t*)(g_ch + t0 * HH + col) = hi;
        *(uint32_t*)(g_cl + t0 * HH + col) = lo;
        hi = packsplit(O[fo][2] * inv1, O[fo][3] * inv1, lo);
        *(uint32_t*)(g_ch + t1 * HH + col) = hi;
        *(uint32_t*)(g_cl + t1 * HH + col) = lo;
    }
}

// ================= LayerNorm ==================================================
__global__ void ln_kernel(const float* __restrict__ gamma, const float* __restrict__ beta,
                          float* __restrict__ dout, int mode) {
    size_t row = blockIdx.x;
    const float* in = (mode == 0) ? (g_preln + row * HH) : (g_attnout + row * HH);
    int tid = threadIdx.x;
    float x0 = in[tid], x1 = in[tid + 256], x2 = in[tid + 512];

    __shared__ float red[256];
    red[tid] = x0 + x1 + x2;
    __syncthreads();
    for (int s = 128; s > 0; s >>= 1) {
        if (tid < s) red[tid] += red[tid + s];
        __syncthreads();
    }
    float mean = red[0] * (1.0f / HH);
    __syncthreads();

    float c0 = x0 - mean, c1 = x1 - mean, c2 = x2 - mean;
    red[tid] = c0 * c0 + c1 * c1 + c2 * c2;
    __syncthreads();
    for (int s = 128; s > 0; s >>= 1) {
        if (tid < s) red[tid] += red[tid + s];
        __syncthreads();
    }
    float inv = 1.0f / sqrtf(red[0] * (1.0f / HH) + 1e-12f);

    float y0 = c0 * inv * gamma[tid]       + beta[tid];
    float y1 = c1 * inv * gamma[tid + 256] + beta[tid + 256];
    float y2 = c2 * inv * gamma[tid + 512] + beta[tid + 512];
    if (mode == 0) {
        g_attnout[row * HH + tid]       = y0;
        g_attnout[row * HH + tid + 256] = y1;
        g_attnout[row * HH + tid + 512] = y2;
        dout[row * HH + tid]       = y0;
        dout[row * HH + tid + 256] = y1;
        dout[row * HH + tid + 512] = y2;
    } else {
        g_xl[row * HH + tid]       = y0;
        g_xl[row * HH + tid + 256] = y1;
        g_xl[row * HH + tid + 512] = y2;
        __half h0 = __float2half_rn(y0), h1 = __float2half_rn(y1), h2 = __float2half_rn(y2);
        g_xlh[row * HH + tid]       = h0;
        g_xlh[row * HH + tid + 256] = h1;
        g_xlh[row * HH + tid + 512] = h2;
        g_xll[row * HH + tid]       = __float2half_rn(y0 - __half2float(h0));
        g_xll[row * HH + tid + 256] = __float2half_rn(y1 - __half2float(h1));
        g_xll[row * HH + tid + 512] = __float2half_rn(y2 - __half2float(h2));
    }
}

// ================= counters / router / scatter ===============================
__global__ void init_kernel() {
    int i = threadIdx.x;
    if (i < EE) { g_cnt[i] = 0; g_cur[i] = 0; }
}

__global__ void router_kernel(const float* __restrict__ Wr, const float* __restrict__ br,
                              float* __restrict__ logits_out) {
    int warp = threadIdx.x >> 5, lane = threadIdx.x & 31;
    int t = blockIdx.x * 8 + warp;
    const float* x = g_xl + (size_t)t * HH;

    float acc[EE] = {};
    for (int h = lane; h < HH; h += 32) {
        float xv = x[h];
        const float* w = Wr + (size_t)h * EE;
#pragma unroll
        for (int e = 0; e < EE; e++) acc[e] = fmaf(xv, w[e], acc[e]);
    }
#pragma unroll
    for (int e = 0; e < EE; e++)
        for (int o = 16; o > 0; o >>= 1) acc[e] += __shfl_down_sync(0xffffffffu, acc[e], o);

    if (lane == 0) {
        float lg[EE], mx = -1e30f;
#pragma unroll
        for (int e = 0; e < EE; e++) {
            lg[e] = acc[e] + br[e];
            logits_out[(size_t)t * EE + e] = lg[e];
            mx = fmaxf(mx, lg[e]);
        }
        float p[EE], s = 0.0f;
#pragma unroll
        for (int e = 0; e < EE; e++) { p[e] = expf(lg[e] - mx); s += p[e]; }
        float invs = 1.0f / s;
#pragma unroll
        for (int e = 0; e < EE; e++) p[e] *= invs;

        int i1 = 0;
#pragma unroll
        for (int e = 1; e < EE; e++) if (p[e] > p[i1]) i1 = e;
        int i2 = (i1 == 0) ? 1 : 0;
#pragma unroll
        for (int e = 0; e < EE; e++) if (e != i1 && p[e] > p[i2]) i2 = e;

        float w1 = p[i1], w2 = p[i2], inv = 1.0f / (w1 + w2);
        g_ti[t * 2]     = i1;  g_tw[t * 2]     = w1 * inv;
        g_ti[t * 2 + 1] = i2;  g_tw[t * 2 + 1] = w2 * inv;
        atomicAdd(&g_cnt[i1], 1);
        atomicAdd(&g_cnt[i2], 1);
    }
}

__global__ void offsets_kernel() {
    if (threadIdx.x == 0) {
        int o = 0;
        for (int e = 0; e < EE; e++) { g_off[e] = o; o += g_cnt[e]; }
    }
}

__global__ void scatter_kernel() {
    int t = blockIdx.x * 256 + threadIdx.x;
    if (t >= TT) return;
#pragma unroll
    for (int s = 0; s < 2; s++) {
        int e = g_ti[t * 2 + s];
        int pos = atomicAdd(&g_cur[e], 1);
        int r = g_off[e] + pos;
        g_etok[r] = t;
        g_ew[r] = g_tw[t * 2 + s];
    }
}

// ================= host launcher =============================================
#define HG_SMEM 65536

extern "C" void kernel_launch(void* const* d_in, const int* in_sizes, int n_in,
                              void* d_out, int out_size) {
    const float* X        = (const float*)d_in[0];
    const float* Wq       = (const float*)d_in[1];
    const float* bq       = (const float*)d_in[2];
    const float* Wk       = (const float*)d_in[3];
    const float* bk       = (const float*)d_in[4];
    const float* Wv       = (const float*)d_in[5];
    const float* bv       = (const float*)d_in[6];
    const float* Wo       = (const float*)d_in[7];
    const float* bo       = (const float*)d_in[8];
    const float* ln_ag    = (const float*)d_in[9];
    const float* ln_ab    = (const float*)d_in[10];
    const float* ln_fg    = (const float*)d_in[11];
    const float* ln_fb    = (const float*)d_in[12];
    const float* Wr       = (const float*)d_in[13];
    const float* br       = (const float*)d_in[14];
    const float* W_up     = (const float*)d_in[15];
    const float* b_up     = (const float*)d_in[16];
    const float* W_new    = (const float*)d_in[17];
    const float* b_new    = (const float*)d_in[18];
    const float* W_down   = (const float*)d_in[19];
    const float* b_down   = (const float*)d_in[20];

    float* out    = (float*)d_out;                    // layer_output [T, H]
    float* logits = out + (size_t)TT * HH;            // router_logits [T, E]

    static int attr_done = 0;
    if (!attr_done) {
        cudaFuncSetAttribute(hgemm<0>, cudaFuncAttributeMaxDynamicSharedMemorySize, HG_SMEM);
        cudaFuncSetAttribute(hgemm<1>, cudaFuncAttributeMaxDynamicSharedMemorySize, HG_SMEM);
        cudaFuncSetAttribute(hgemm<2>, cudaFuncAttributeMaxDynamicSharedMemorySize, HG_SMEM);
        cudaFuncSetAttribute(ffn_upgate, cudaFuncAttributeMaxDynamicSharedMemorySize, UPG_SMEM);
        cudaFuncSetAttribute(flash_attn, cudaFuncAttributeMaxDynamicSharedMemorySize, FL_SMEM);
        attr_done = 1;
    }

    __half *wqkvh, *wqkvl, *woh, *wol, *wuh, *wul, *wnh, *wnl, *wdh, *wdl, *xsh, *xsl;
    cudaGetSymbolAddress((void**)&wqkvh, g_wqkvh);
    cudaGetSymbolAddress((void**)&wqkvl, g_wqkvl);
    cudaGetSymbolAddress((void**)&woh, g_woh);
    cudaGetSymbolAddress((void**)&wol, g_wol);
    cudaGetSymbolAddress((void**)&wuh, g_wuh);
    cudaGetSymbolAddress((void**)&wul, g_wul);
    cudaGetSymbolAddress((void**)&wnh, g_wnh);
    cudaGetSymbolAddress((void**)&wnl, g_wnl);
    cudaGetSymbolAddress((void**)&wdh, g_wdh);
    cudaGetSymbolAddress((void**)&wdl, g_wdl);
    cudaGetSymbolAddress((void**)&xsh, g_xsh);
    cudaGetSymbolAddress((void**)&xsl, g_xsl);

    // weight prep: pure elementwise fp16 hi/lo split (NO transpose)
    fsplit<<<HH * HH / 1024, 256>>>(Wq, wqkvh,               wqkvl);
    fsplit<<<HH * HH / 1024, 256>>>(Wk, wqkvh + HH * HH,     wqkvl + HH * HH);
    fsplit<<<HH * HH / 1024, 256>>>(Wv, wqkvh + 2 * HH * HH, wqkvl + 2 * HH * HH);
    fsplit<<<HH * HH / 1024, 256>>>(Wo, woh, wol);
    fsplit<<<EE * HH * II / 1024, 256>>>(W_up,  wuh, wul);
    fsplit<<<EE * HH * II / 1024, 256>>>(W_new, wnh, wnl);
    fsplit<<<EE * II * HH / 1024, 256>>>(W_down, wdh, wdl);

    init_kernel<<<1, 32>>>();
    fsplit<<<TT * HH / 1024, 256>>>(X, xsh, xsl);

    // QKV (fused, emits fp16 splits) -> flash attention -> proj
    hgemm<0><<<dim3(3 * HH / 128, TT / 128), 256, HG_SMEM>>>(bq, bk, bv, nullptr);
    flash_attn<<<dim3(SS / 128, BB * NHH), 256, FL_SMEM>>>();
    hgemm<1><<<dim3(HH / 128, TT / 128), 256, HG_SMEM>>>(bo, X, nullptr, nullptr);

    ln_kernel<<<TT, 256>>>(ln_ag, ln_ab, out, 0);
    ln_kernel<<<TT, 256>>>(ln_fg, ln_fb, out, 1);
    router_kernel<<<TT / 8, 256>>>(Wr, br, logits);
    offsets_kernel<<<1, 32>>>();
    scatter_kernel<<<(TT + 255) / 256, 256>>>();

    // MoE FFN: fused up+gate, then down
    ffn_upgate<<<dim3(32, EE * 24), 256, UPG_SMEM>>>(b_up, b_new);
    hgemm<2><<<dim3(32, EE * 6), 256, HG_SMEM>>>(b_down, nullptr, nullptr, out);
}

// round 8
// speedup vs baseline: 3.0187x; 1.0153x over previous
#include <cuda_runtime.h>
#include <cuda_fp16.h>
#include <math.h>
#include <stdint.h>

#define TT  4096   // B*S
#define HH  768
#define SS  512
#define BB  8
#define NHH 12
#define DHH 64
#define II  3072
#define EE  8
#define ENT 8192   // TT * TOPK

// ---------------- scratch (static device allocations; no cudaMalloc) --------
__device__ float g_preln[TT * HH];
__device__ float g_attnout[TT * HH];
__device__ float g_xl[TT * HH];
__device__ __half g_xlh[TT * HH];           // xl split
__device__ __half g_xll[TT * HH];
__device__ __half g_xsh[TT * HH];           // X split
__device__ __half g_xsl[TT * HH];
__device__ __half g_qh[TT * HH];            // Q split, [B*NH][S][DH]
__device__ __half g_ql[TT * HH];
__device__ __half g_kh[TT * HH];
__device__ __half g_kl[TT * HH];
__device__ __half g_vh[TT * HH];
__device__ __half g_vl[TT * HH];
__device__ __half g_ch[TT * HH];            // ctx split [T][H]
__device__ __half g_cl[TT * HH];
__device__ __half g_hh[(size_t)ENT * II];   // FFN hidden h = gelu(u)*gate, hi
__device__ __half g_hl[(size_t)ENT * II];   // lo
__device__ __half g_wqkvh[3 * HH * HH];     // [Wq;Wk;Wv] each [768 k][768 n] (ORIGINAL layout)
__device__ __half g_wqkvl[3 * HH * HH];
__device__ __half g_woh[HH * HH];           // Wo [768 k][768 n]
__device__ __half g_wol[HH * HH];
__device__ __half g_wuh[(size_t)EE * HH * II];  // W_up  hi [E][H k][I n]
__device__ __half g_wul[(size_t)EE * HH * II];
__device__ __half g_wnh[(size_t)EE * HH * II];  // W_new hi
__device__ __half g_wnl[(size_t)EE * HH * II];
__device__ __half g_wdh[(size_t)EE * II * HH];  // W_down hi [E][I k][H n]
__device__ __half g_wdl[(size_t)EE * II * HH];
__device__ int   g_cnt[EE];
__device__ int   g_off[EE];
__device__ int   g_cur[EE];
__device__ int   g_etok[ENT];
__device__ float g_ew[ENT];
__device__ int   g_ti[TT * 2];
__device__ float g_tw[TT * 2];

// ======================= asm helpers (portable sm_80+) =======================
__device__ __forceinline__ uint32_t smem_u32(const void* p) {
    uint32_t a;
    asm("{ .reg .u64 t; cvta.to.shared.u64 t, %1; cvt.u32.u64 %0, t; }" : "=r"(a) : "l"(p));
    return a;
}
__device__ __forceinline__ void ldsm4(uint32_t& r0, uint32_t& r1, uint32_t& r2, uint32_t& r3,
                                      uint32_t addr) {
    asm volatile("ldmatrix.sync.aligned.m8n8.x4.shared.b16 {%0,%1,%2,%3}, [%4];"
                 : "=r"(r0), "=r"(r1), "=r"(r2), "=r"(r3) : "r"(addr));
}
__device__ __forceinline__ void ldsm4t(uint32_t& r0, uint32_t& r1, uint32_t& r2, uint32_t& r3,
                                       uint32_t addr) {
    asm volatile("ldmatrix.sync.aligned.m8n8.x4.trans.shared.b16 {%0,%1,%2,%3}, [%4];"
                 : "=r"(r0), "=r"(r1), "=r"(r2), "=r"(r3) : "r"(addr));
}
__device__ __forceinline__ void mma16816(float* c, const uint32_t* a, const uint32_t* b) {
    asm volatile(
        "mma.sync.aligned.m16n8k16.row.col.f32.f16.f16.f32 "
        "{%0,%1,%2,%3}, {%4,%5,%6,%7}, {%8,%9}, {%0,%1,%2,%3};"
        : "+f"(c[0]), "+f"(c[1]), "+f"(c[2]), "+f"(c[3])
        : "r"(a[0]), "r"(a[1]), "r"(a[2]), "r"(a[3]), "r"(b[0]), "r"(b[1]));
}
__device__ __forceinline__ void cpasync16(uint32_t saddr, const void* gaddr) {
    asm volatile("cp.async.cg.shared.global [%0], [%1], 16;" :: "r"(saddr), "l"(gaddr));
}
#define CP_COMMIT() asm volatile("cp.async.commit_group;" ::: "memory")
#define CP_WAIT1()  asm volatile("cp.async.wait_group 1;" ::: "memory")
#define CP_WAIT0()  asm volatile("cp.async.wait_group 0;" ::: "memory")

// xor-swizzled smem byte offset for a [rows x 32 halves] tile (row = 64B)
__device__ __forceinline__ uint32_t swoff(int m, int kg) {
    return (uint32_t)(m * 64 + ((kg ^ ((m >> 1) & 3)) << 4));
}
// xor-swizzled smem byte offset for a [rows x 64 halves] tile (row = 128B, 8 chunks)
__device__ __forceinline__ uint32_t fswz(int m, int c) {
    return (uint32_t)(m * 128 + ((c ^ (m & 7)) << 4));
}
// xor-swizzled smem byte offset for a [32 k x 128 halves] B tile (row = 256B, 16 chunks)
__device__ __forceinline__ uint32_t bswz(int k, int c) {
    return (uint32_t)(k * 256 + ((c ^ (k & 7)) << 4));
}
__device__ __forceinline__ uint32_t packsplit(float v0, float v1, uint32_t& lo) {
    __half h0 = __float2half_rn(v0), h1 = __float2half_rn(v1);
    __half2 l = __halves2half2(__float2half_rn(v0 - __half2float(h0)),
                               __float2half_rn(v1 - __half2float(h1)));
    lo = *(uint32_t*)&l;
    __half2 h = __halves2half2(h0, h1);
    return *(uint32_t*)&h;
}

// ============ elementwise fp32 -> fp16 hi/lo split (pure streaming) ==========
__global__ void fsplit(const float* __restrict__ src, __half* __restrict__ h,
                       __half* __restrict__ l) {
    size_t i = ((size_t)blockIdx.x * 256 + threadIdx.x) * 4;
    float4 v = *(const float4*)(src + i);
    uint32_t lo0, lo1;
    uint32_t h0 = packsplit(v.x, v.y, lo0);
    uint32_t h1 = packsplit(v.z, v.w, lo1);
    *(uint32_t*)(h + i)     = h0;
    *(uint32_t*)(h + i + 2) = h1;
    *(uint32_t*)(l + i)     = lo0;
    *(uint32_t*)(l + i + 2) = lo1;
}

// ================= unified fp16x3 pipelined HMMA GEMM ========================
// B operand is [K][N] row-major (ORIGINAL weight layout), loaded via ldsm4t.
// MODE 0: QKV   A=g_xsh/l [t][768]   B=g_wqkvh/l 3x[768][768] -> g_qh..g_vl split
// MODE 1: PROJ  A=g_ch/l  [t][768]   B=g_woh/l   [768][768]   -> g_preln (+bo+X)
// MODE 2: DOWN  A=g_hh/l  [r][3072]  B=g_wdh/l e [3072][768]  -> atomicAdd out
template<int MODE>
__global__ void __launch_bounds__(256, 2) hgemm(
    const float* __restrict__ p0, const float* __restrict__ p1,
    const float* __restrict__ p2, float* __restrict__ pout) {

    constexpr int KD = (MODE == 2) ? II : HH;   // A K-dim
    constexpr int NS = KD / 32;

    int e = 0, base = 0, end = 0, m0 = 0, n0;
    if (MODE == 2) {
        e = blockIdx.y / 6;
        n0 = (blockIdx.y % 6) * 128;
        base = g_off[e] + blockIdx.x * 128;
        end  = g_off[e] + g_cnt[e];
        if (base >= end) return;
    } else {
        m0 = blockIdx.y * 128;
        n0 = blockIdx.x * 128;
    }

    extern __shared__ char dyn[];
    __shared__ int   s_tok[128];
    __shared__ float s_w[128];

    int tid = threadIdx.x, lane = tid & 31, wid = tid >> 5;
    int wm = wid & 1, wn = wid >> 1;

    if (MODE == 2 && tid < 128) {
        int r = min(base + tid, end - 1);
        s_tok[tid] = g_etok[r];
        s_w[tid]   = g_ew[r];
    }
    __syncthreads();

    const __half *Bh, *Bl, *Ah, *Al;
    int nb;
    if (MODE == 0) {
        int which = n0 / HH;
        Bh = g_wqkvh + (size_t)which * HH * HH;
        Bl = g_wqkvl + (size_t)which * HH * HH;
        Ah = g_xsh; Al = g_xsl;
        nb = n0 - which * HH;
    } else if (MODE == 1) {
        Bh = g_woh; Bl = g_wol; Ah = g_ch; Al = g_cl; nb = n0;
    } else {
        Bh = g_wdh + (size_t)e * II * HH; Bl = g_wdl + (size_t)e * II * HH;
        Ah = g_hh;  Al = g_hl; nb = n0;
    }

    uint32_t sbase = smem_u32(dyn);

    auto issue = [&](int slab, int st) {
        int k0 = slab * 32;
        uint32_t sb = sbase + st * 32768;
#pragma unroll
        for (int i = 0; i < 2; i++) {
            int c = tid + i * 256;
            {
                int m = c >> 2, kc = c & 3;
                uint32_t so = sb + swoff(m, kc);
                int koff = k0 + kc * 8;
                size_t aoff;
                if (MODE < 2) aoff = (size_t)(m0 + m) * KD;
                else          aoff = (size_t)min(base + m, end - 1) * KD;
                cpasync16(so,        Ah + aoff + koff);
                cpasync16(so + 8192, Al + aoff + koff);
            }
            {
                int k = c >> 4, cb = c & 15;
                uint32_t bo = sb + 16384 + bswz(k, cb);
                size_t go = (size_t)(k0 + k) * HH + nb + cb * 8;
                cpasync16(bo,        Bh + go);
                cpasync16(bo + 8192, Bl + go);
            }
        }
    };

    int j = lane >> 3, rr = lane & 7;
    int amRow = wm * 64 + (j & 1) * 8 + rr;
    int akSel = j >> 1;
    float C[4][4][4] = {};

    issue(0, 0);
    CP_COMMIT();
    for (int s = 0; s < NS; s++) {
        int st = s & 1;
        if (s + 1 < NS) {
            issue(s + 1, st ^ 1);
            CP_COMMIT();
            CP_WAIT1();
        } else {
            CP_WAIT0();
        }
        __syncthreads();
        uint32_t aH = sbase + st * 32768, aL = aH + 8192;
        uint32_t bH = aH + 16384, bL = aH + 24576;
#pragma unroll
        for (int kk = 0; kk < 2; kk++) {
            uint32_t bh[4][2], bl[4][2];
#pragma unroll
            for (int f16 = 0; f16 < 2; f16++) {
                int krow = kk * 16 + (j & 1) * 8 + rr;
                int cc = wn * 4 + f16 * 2 + (j >> 1);
                uint32_t o = bswz(krow, cc);
                ldsm4t(bh[f16 * 2][0], bh[f16 * 2][1], bh[f16 * 2 + 1][0], bh[f16 * 2 + 1][1], bH + o);
                ldsm4t(bl[f16 * 2][0], bl[f16 * 2][1], bl[f16 * 2 + 1][0], bl[f16 * 2 + 1][1], bL + o);
            }
#pragma unroll
            for (int fm = 0; fm < 4; fm++) {
                int m = amRow + fm * 16;
                int kg = kk * 2 + akSel;
                uint32_t o = (uint32_t)(m * 64 + ((kg ^ ((m >> 1) & 3)) << 4));
                uint32_t ah[4], al[4];
                ldsm4(ah[0], ah[1], ah[2], ah[3], aH + o);
                ldsm4(al[0], al[1], al[2], al[3], aL + o);
#pragma unroll
                for (int fn = 0; fn < 4; fn++) {
                    mma16816(C[fm][fn], ah, bh[fn]);
                    mma16816(C[fm][fn], ah, bl[fn]);
                    mma16816(C[fm][fn], al, bh[fn]);
                }
            }
        }
        __syncthreads();
    }

    int g = lane >> 2, tig = lane & 3;

    __half *qh_out = nullptr, *ql_out = nullptr;
    const float* mbias = nullptr;
    int hcol0 = 0;
    if (MODE == 0) {
        int which = n0 / HH;
        qh_out = (which == 0) ? g_qh : (which == 1) ? g_kh : g_vh;
        ql_out = (which == 0) ? g_ql : (which == 1) ? g_kl : g_vl;
        mbias  = (which == 0) ? p0 : (which == 1) ? p1 : p2;
        hcol0  = n0 - which * HH;
    }

#pragma unroll
    for (int fm = 0; fm < 4; fm++) {
        int rowl0 = wm * 64 + fm * 16 + g;
#pragma unroll
        for (int fn = 0; fn < 4; fn++) {
            int coll = wn * 32 + fn * 8 + tig * 2;
#pragma unroll
            for (int hf = 0; hf < 2; hf++) {
                int ml = rowl0 + hf * 8;
                float c0 = C[fm][fn][hf * 2], c1 = C[fm][fn][hf * 2 + 1];
                if (MODE == 0) {
                    int t = m0 + ml;
                    int hcol = hcol0 + coll;
                    int h = hcol >> 6, d = hcol & 63;
                    int b = t >> 9, sI = t & 511;
                    size_t o = (((size_t)(b * NHH + h)) * SS + sI) * DHH + d;
                    uint32_t lo;
                    uint32_t hi = packsplit(c0 + mbias[hcol], c1 + mbias[hcol + 1], lo);
                    *(uint32_t*)(qh_out + o) = hi;
                    *(uint32_t*)(ql_out + o) = lo;
                } else if (MODE == 1) {
                    size_t t = m0 + ml;
                    int col = n0 + coll;
                    float2 xr = *(const float2*)(p1 + t * HH + col);
                    float2 v = {c0 + p0[col] + xr.x, c1 + p0[col + 1] + xr.y};
                    *(float2*)(g_preln + t * HH + col) = v;
                } else {
                    if (base + ml < end) {
                        int col = n0 + coll;
                        int t = s_tok[ml];
                        float w = s_w[ml];
                        const float* eb = p0 + (size_t)e * HH;
                        atomicAdd(pout + (size_t)t * HH + col,     (c0 + eb[col]) * w);
                        atomicAdd(pout + (size_t)t * HH + col + 1, (c1 + eb[col + 1]) * w);
                    }
                }
            }
        }
    }
}

// ============ fused up+gate pipelined HMMA grouped GEMM ======================
#define UPG_SMEM (2 * 49152)
__global__ void __launch_bounds__(256, 1) ffn_upgate(
    const float* __restrict__ bu_, const float* __restrict__ bn_) {
    int e = blockIdx.y / 24;
    int n0 = (blockIdx.y % 24) * 128;
    int base = g_off[e] + blockIdx.x * 128;
    int end  = g_off[e] + g_cnt[e];
    if (base >= end) return;

    extern __shared__ char dyn[];
    __shared__ int s_tok[128];

    int tid = threadIdx.x, lane = tid & 31, wid = tid >> 5;
    int wm = wid & 1, wn = wid >> 1;

    if (tid < 128) s_tok[tid] = g_etok[min(base + tid, end - 1)];
    __syncthreads();

    const __half* Buh = g_wuh + (size_t)e * HH * II;
    const __half* Bul = g_wul + (size_t)e * HH * II;
    const __half* Bnh = g_wnh + (size_t)e * HH * II;
    const __half* Bnl = g_wnl + (size_t)e * HH * II;
    uint32_t sbase = smem_u32(dyn);

    auto issue = [&](int slab, int st) {
        int k0 = slab * 32;
        uint32_t sb = sbase + st * 49152;
#pragma unroll
        for (int i = 0; i < 2; i++) {
            int c = tid + i * 256;
            {
                int m = c >> 2, kc = c & 3;
                uint32_t so = sb + swoff(m, kc);
                size_t aoff = (size_t)s_tok[m] * HH + k0 + kc * 8;
                cpasync16(so,        g_xlh + aoff);
                cpasync16(so + 8192, g_xll + aoff);
            }
            {
                int k = c >> 4, cb = c & 15;
                uint32_t bo = sb + 16384 + bswz(k, cb);
                size_t go = (size_t)(k0 + k) * II + n0 + cb * 8;
                cpasync16(bo,         Buh + go);
                cpasync16(bo + 8192,  Bul + go);
                cpasync16(bo + 16384, Bnh + go);
                cpasync16(bo + 24576, Bnl + go);
            }
        }
    };

    int j = lane >> 3, rr = lane & 7;
    int amRow = wm * 64 + (j & 1) * 8 + rr;
    int akSel = j >> 1;
    float Cu[4][4][4] = {}, Cn[4][4][4] = {};

    issue(0, 0);
    CP_COMMIT();
    for (int s = 0; s < HH / 32; s++) {
        int st = s & 1;
        if (s + 1 < HH / 32) {
            issue(s + 1, st ^ 1);
            CP_COMMIT();
            CP_WAIT1();
        } else {
            CP_WAIT0();
        }
        __syncthreads();
        uint32_t aH = sbase + st * 49152, aL = aH + 8192;
        uint32_t uH = aH + 16384, uL = aH + 24576;
        uint32_t nH = aH + 32768, nL = aH + 40960;
#pragma unroll
        for (int kk = 0; kk < 2; kk++) {
            uint32_t buh[4][2], bul[4][2], bnh[4][2], bnl[4][2];
#pragma unroll
            for (int f16 = 0; f16 < 2; f16++) {
                int krow = kk * 16 + (j & 1) * 8 + rr;
                int cc = wn * 4 + f16 * 2 + (j >> 1);
                uint32_t o = bswz(krow, cc);
                ldsm4t(buh[f16 * 2][0], buh[f16 * 2][1], buh[f16 * 2 + 1][0], buh[f16 * 2 + 1][1], uH + o);
                ldsm4t(bul[f16 * 2][0], bul[f16 * 2][1], bul[f16 * 2 + 1][0], bul[f16 * 2 + 1][1], uL + o);
                ldsm4t(bnh[f16 * 2][0], bnh[f16 * 2][1], bnh[f16 * 2 + 1][0], bnh[f16 * 2 + 1][1], nH + o);
                ldsm4t(bnl[f16 * 2][0], bnl[f16 * 2][1], bnl[f16 * 2 + 1][0], bnl[f16 * 2 + 1][1], nL + o);
            }
#pragma unroll
            for (int fm = 0; fm < 4; fm++) {
                int m = amRow + fm * 16;
                int kg = kk * 2 + akSel;
                uint32_t o = (uint32_t)(m * 64 + ((kg ^ ((m >> 1) & 3)) << 4));
                uint32_t ah[4], al[4];
                ldsm4(ah[0], ah[1], ah[2], ah[3], aH + o);
                ldsm4(al[0], al[1], al[2], al[3], aL + o);
#pragma unroll
                for (int fn = 0; fn < 4; fn++) {
                    mma16816(Cu[fm][fn], ah, buh[fn]);
                    mma16816(Cu[fm][fn], ah, bul[fn]);
                    mma16816(Cu[fm][fn], al, buh[fn]);
                    mma16816(Cn[fm][fn], ah, bnh[fn]);
                    mma16816(Cn[fm][fn], ah, bnl[fn]);
                    mma16816(Cn[fm][fn], al, bnh[fn]);
                }
            }
        }
        __syncthreads();
    }

    int g = lane >> 2, tig = lane & 3;
    const float* bu = bu_ + (size_t)e * II;
    const float* bn = bn_ + (size_t)e * II;
#pragma unroll
    for (int fm = 0; fm < 4; fm++) {
        int rowl0 = wm * 64 + fm * 16 + g;
#pragma unroll
        for (int fn = 0; fn < 4; fn++) {
            int col = n0 + wn * 32 + fn * 8 + tig * 2;
            float bu0 = bu[col], bu1 = bu[col + 1];
            float bn0 = bn[col], bn1 = bn[col + 1];
#pragma unroll
            for (int hf = 0; hf < 2; hf++) {
                int r = base + rowl0 + hf * 8;
                if (r < end) {
                    float u0 = Cu[fm][fn][hf * 2] + bu0, u1 = Cu[fm][fn][hf * 2 + 1] + bu1;
                    float h0 = u0 * normcdff(u0) * (Cn[fm][fn][hf * 2] + bn0);
                    float h1 = u1 * normcdff(u1) * (Cn[fm][fn][hf * 2 + 1] + bn1);
                    uint32_t lo;
                    uint32_t hi = packsplit(h0, h1, lo);
                    *(uint32_t*)(g_hh + (size_t)r * II + col) = hi;
                    *(uint32_t*)(g_hl + (size_t)r * II + col) = lo;
                }
            }
        }
    }
}

// ================= flash attention (fp16x3 HMMA, online softmax) =============
#define FL_SMEM (32768 + 2 * 65536)
__global__ void __launch_bounds__(256, 1) flash_attn() {
    int q0 = blockIdx.x * 128;
    int head = blockIdx.y;
    int b = head / NHH, h_ = head % NHH;

    extern __shared__ char dyn[];
    uint32_t sb = smem_u32(dyn);
    const uint32_t QH = 0, QL = 16384;

    const __half* Qh = g_qh + (size_t)head * SS * DHH;
    const __half* Ql = g_ql + (size_t)head * SS * DHH;
    const __half* Kh = g_kh + (size_t)head * SS * DHH;
    const __half* Kl = g_kl + (size_t)head * SS * DHH;
    const __half* Vh = g_vh + (size_t)head * SS * DHH;
    const __half* Vl = g_vl + (size_t)head * SS * DHH;

    int tid = threadIdx.x, lane = tid & 31, wid = tid >> 5;
    int j = lane >> 3, rr = lane & 7;
    int g = lane >> 2, tig = lane & 3;

    auto load_tile = [&](uint32_t dst, const __half* src, int row0) {
#pragma unroll
        for (int i = 0; i < 4; i++) {
            int idx = tid + i * 256;
            int m = idx >> 3, c = idx & 7;
            cpasync16(sb + dst + fswz(m, c), src + (size_t)(row0 + m) * DHH + c * 8);
        }
    };

    load_tile(QH, Qh, q0);
    load_tile(QL, Ql, q0);
    load_tile(32768, Kh, 0);
    load_tile(32768 + 16384, Kl, 0);
    load_tile(32768 + 32768, Vh, 0);
    load_tile(32768 + 49152, Vl, 0);
    CP_COMMIT();

    float O[8][4] = {};
    float rm0 = -1e30f, rm1 = -1e30f, l0 = 0.0f, l1 = 0.0f;

    for (int kt = 0; kt < 4; kt++) {
        int st = kt & 1;
        if (kt + 1 < 4) {
            uint32_t nb = 32768 + (st ^ 1) * 65536;
            load_tile(nb,         Kh, (kt + 1) * 128);
            load_tile(nb + 16384, Kl, (kt + 1) * 128);
            load_tile(nb + 32768, Vh, (kt + 1) * 128);
            load_tile(nb + 49152, Vl, (kt + 1) * 128);
            CP_COMMIT();
            CP_WAIT1();
        } else {
            CP_WAIT0();
        }
        __syncthreads();

        uint32_t kH = sb + 32768 + st * 65536, kL = kH + 16384;
        uint32_t vH = kH + 32768, vL = kH + 49152;
        uint32_t qHb = sb + QH, qLb = sb + QL;

        float S[16][4] = {};
#pragma unroll
        for (int ks = 0; ks < 4; ks++) {
            int am = wid * 16 + (j & 1) * 8 + rr;
            int ac = 2 * ks + (j >> 1);
            uint32_t ah[4], al[4];
            ldsm4(ah[0], ah[1], ah[2], ah[3], qHb + fswz(am, ac));
            ldsm4(al[0], al[1], al[2], al[3], qLb + fswz(am, ac));
#pragma unroll
            for (int fnp = 0; fnp < 8; fnp++) {
                int bn = fnp * 16 + (j >> 1) * 8 + rr;
                int bc = 2 * ks + (j & 1);
                uint32_t bo = fswz(bn, bc);
                uint32_t bh[4], bl[4];
                ldsm4(bh[0], bh[1], bh[2], bh[3], kH + bo);
                ldsm4(bl[0], bl[1], bl[2], bl[3], kL + bo);
                mma16816(S[2 * fnp],     ah, bh);
                mma16816(S[2 * fnp],     ah, bl);
                mma16816(S[2 * fnp],     al, bh);
                mma16816(S[2 * fnp + 1], ah, bh + 2);
                mma16816(S[2 * fnp + 1], ah, bl + 2);
                mma16816(S[2 * fnp + 1], al, bh + 2);
            }
        }

        float mx0 = -1e30f, mx1 = -1e30f;
#pragma unroll
        for (int fn = 0; fn < 16; fn++) {
            mx0 = fmaxf(mx0, fmaxf(S[fn][0], S[fn][1]));
            mx1 = fmaxf(mx1, fmaxf(S[fn][2], S[fn][3]));
        }
        mx0 = fmaxf(mx0, __shfl_xor_sync(~0u, mx0, 1));
        mx0 = fmaxf(mx0, __shfl_xor_sync(~0u, mx0, 2));
        mx1 = fmaxf(mx1, __shfl_xor_sync(~0u, mx1, 1));
        mx1 = fmaxf(mx1, __shfl_xor_sync(~0u, mx1, 2));
        float nm0 = fmaxf(rm0, mx0 * 0.125f);
        float nm1 = fmaxf(rm1, mx1 * 0.125f);
        float al0 = __expf(rm0 - nm0);
        float al1 = __expf(rm1 - nm1);
        rm0 = nm0; rm1 = nm1;
        float sum0 = 0.0f, sum1 = 0.0f;
#pragma unroll
        for (int fn = 0; fn < 16; fn++) {
            float p0 = __expf(fmaf(S[fn][0], 0.125f, -nm0));
            float p1 = __expf(fmaf(S[fn][1], 0.125f, -nm0));
            float p2 = __expf(fmaf(S[fn][2], 0.125f, -nm1));
            float p3 = __expf(fmaf(S[fn][3], 0.125f, -nm1));
            S[fn][0] = p0; S[fn][1] = p1; S[fn][2] = p2; S[fn][3] = p3;
            sum0 += p0 + p1; sum1 += p2 + p3;
        }
        sum0 += __shfl_xor_sync(~0u, sum0, 1);
        sum0 += __shfl_xor_sync(~0u, sum0, 2);
        sum1 += __shfl_xor_sync(~0u, sum1, 1);
        sum1 += __shfl_xor_sync(~0u, sum1, 2);
        l0 = l0 * al0 + sum0;
        l1 = l1 * al1 + sum1;
#pragma unroll
        for (int fo = 0; fo < 8; fo++) {
            O[fo][0] *= al0; O[fo][1] *= al0;
            O[fo][2] *= al1; O[fo][3] *= al1;
        }

#pragma unroll
        for (int kp = 0; kp < 8; kp++) {
            uint32_t aph[4], apl[4];
            aph[0] = packsplit(S[2 * kp][0],     S[2 * kp][1],     apl[0]);
            aph[1] = packsplit(S[2 * kp][2],     S[2 * kp][3],     apl[1]);
            aph[2] = packsplit(S[2 * kp + 1][0], S[2 * kp + 1][1], apl[2]);
            aph[3] = packsplit(S[2 * kp + 1][2], S[2 * kp + 1][3], apl[3]);
#pragma unroll
            for (int dg = 0; dg < 4; dg++) {
                int vrow = kp * 16 + (j & 1) * 8 + rr;
                int vc = dg * 2 + (j >> 1);
                uint32_t vo = fswz(vrow, vc);
                uint32_t vh[4], vl[4];
                ldsm4t(vh[0], vh[1], vh[2], vh[3], vH + vo);
                ldsm4t(vl[0], vl[1], vl[2], vl[3], vL + vo);
#pragma unroll
                for (int hg = 0; hg < 2; hg++) {
                    int fo = dg * 2 + hg;
                    mma16816(O[fo], aph, vh + hg * 2);
                    mma16816(O[fo], apl, vh + hg * 2);
                    mma16816(O[fo], aph, vl + hg * 2);
                }
            }
        }
        __syncthreads();
    }

    float inv0 = 1.0f / l0, inv1 = 1.0f / l1;
    int qr0 = q0 + wid * 16 + g;
    size_t t0 = (size_t)b * SS + qr0;
    size_t t1 = t0 + 8;
#pragma unroll
    for (int fo = 0; fo < 8; fo++) {
        int d = fo * 8 + tig * 2;
        int col = h_ * 64 + d;
        uint32_t lo;
        uint32_t hi = packsplit(O[fo][0] * inv0, O[fo][1] * inv0, lo);
        *(uint32_t*)(g_ch + t0 * HH + col) = hi;
        *(uint32_t*)(g_cl + t0 * HH + col) = lo;
        hi = packsplit(O[fo][2] * inv1, O[fo][3] * inv1, lo);
        *(uint32_t*)(g_ch + t1 * HH + col) = hi;
        *(uint32_t*)(g_cl + t1 * HH + col) = lo;
    }
}

// ================= LayerNorm ==================================================
__global__ void ln_kernel(const float* __restrict__ gamma, const float* __restrict__ beta,
                          float* __restrict__ dout, int mode) {
    size_t row = blockIdx.x;
    const float* in = (mode == 0) ? (g_preln + row * HH) : (g_attnout + row * HH);
    int tid = threadIdx.x;
    float x0 = in[tid], x1 = in[tid + 256], x2 = in[tid + 512];

    __shared__ float red[256];
    red[tid] = x0 + x1 + x2;
    __syncthreads();
    for (int s = 128; s > 0; s >>= 1) {
        if (tid < s) red[tid] += red[tid + s];
        __syncthreads();
    }
    float mean = red[0] * (1.0f / HH);
    __syncthreads();

    float c0 = x0 - mean, c1 = x1 - mean, c2 = x2 - mean;
    red[tid] = c0 * c0 + c1 * c1 + c2 * c2;
    __syncthreads();
    for (int s = 128; s > 0; s >>= 1) {
        if (tid < s) red[tid] += red[tid + s];
        __syncthreads();
    }
    float inv = 1.0f / sqrtf(red[0] * (1.0f / HH) + 1e-12f);

    float y0 = c0 * inv * gamma[tid]       + beta[tid];
    float y1 = c1 * inv * gamma[tid + 256] + beta[tid + 256];
    float y2 = c2 * inv * gamma[tid + 512] + beta[tid + 512];
    if (mode == 0) {
        g_attnout[row * HH + tid]       = y0;
        g_attnout[row * HH + tid + 256] = y1;
        g_attnout[row * HH + tid + 512] = y2;
        dout[row * HH + tid]       = y0;
        dout[row * HH + tid + 256] = y1;
        dout[row * HH + tid + 512] = y2;
    } else {
        g_xl[row * HH + tid]       = y0;
        g_xl[row * HH + tid + 256] = y1;
        g_xl[row * HH + tid + 512] = y2;
        __half h0 = __float2half_rn(y0), h1 = __float2half_rn(y1), h2 = __float2half_rn(y2);
        g_xlh[row * HH + tid]       = h0;
        g_xlh[row * HH + tid + 256] = h1;
        g_xlh[row * HH + tid + 512] = h2;
        g_xll[row * HH + tid]       = __float2half_rn(y0 - __half2float(h0));
        g_xll[row * HH + tid + 256] = __float2half_rn(y1 - __half2float(h1));
        g_xll[row * HH + tid + 512] = __float2half_rn(y2 - __half2float(h2));
    }
}

// ================= counters / router / scatter ===============================
__global__ void init_kernel() {
    int i = threadIdx.x;
    if (i < EE) { g_cnt[i] = 0; g_cur[i] = 0; }
}

__global__ void router_kernel(const float* __restrict__ Wr, const float* __restrict__ br,
                              float* __restrict__ logits_out) {
    int warp = threadIdx.x >> 5, lane = threadIdx.x & 31;
    int t = blockIdx.x * 8 + warp;
    const float* x = g_xl + (size_t)t * HH;

    float acc[EE] = {};
    for (int h = lane; h < HH; h += 32) {
        float xv = x[h];
        const float* w = Wr + (size_t)h * EE;
#pragma unroll
        for (int e = 0; e < EE; e++) acc[e] = fmaf(xv, w[e], acc[e]);
    }
#pragma unroll
    for (int e = 0; e < EE; e++)
        for (int o = 16; o > 0; o >>= 1) acc[e] += __shfl_down_sync(0xffffffffu, acc[e], o);

    if (lane == 0) {
        float lg[EE], mx = -1e30f;
#pragma unroll
        for (int e = 0; e < EE; e++) {
            lg[e] = acc[e] + br[e];
            logits_out[(size_t)t * EE + e] = lg[e];
            mx = fmaxf(mx, lg[e]);
        }
        float p[EE], s = 0.0f;
#pragma unroll
        for (int e = 0; e < EE; e++) { p[e] = expf(lg[e] - mx); s += p[e]; }
        float invs = 1.0f / s;
#pragma unroll
        for (int e = 0; e < EE; e++) p[e] *= invs;

        int i1 = 0;
#pragma unroll
        for (int e = 1; e < EE; e++) if (p[e] > p[i1]) i1 = e;
        int i2 = (i1 == 0) ? 1 : 0;
#pragma unroll
        for (int e = 0; e < EE; e++) if (e != i1 && p[e] > p[i2]) i2 = e;

        float w1 = p[i1], w2 = p[i2], inv = 1.0f / (w1 + w2);
        g_ti[t * 2]     = i1;  g_tw[t * 2]     = w1 * inv;
        g_ti[t * 2 + 1] = i2;  g_tw[t * 2 + 1] = w2 * inv;
        atomicAdd(&g_cnt[i1], 1);
        atomicAdd(&g_cnt[i2], 1);
    }
}

__global__ void offsets_kernel() {
    if (threadIdx.x == 0) {
        int o = 0;
        for (int e = 0; e < EE; e++) { g_off[e] = o; o += g_cnt[e]; }
    }
}

__global__ void scatter_kernel() {
    int t = blockIdx.x * 256 + threadIdx.x;
    if (t >= TT) return;
#pragma unroll
    for (int s = 0; s < 2; s++) {
        int e = g_ti[t * 2 + s];
        int pos = atomicAdd(&g_cur[e], 1);
        int r = g_off[e] + pos;
        g_etok[r] = t;
        g_ew[r] = g_tw[t * 2 + s];
    }
}

// ================= host launcher =============================================
#define HG_SMEM 65536

extern "C" void kernel_launch(void* const* d_in, const int* in_sizes, int n_in,
                              void* d_out, int out_size) {
    const float* X        = (const float*)d_in[0];
    const float* Wq       = (const float*)d_in[1];
    const float* bq       = (const float*)d_in[2];
    const float* Wk       = (const float*)d_in[3];
    const float* bk       = (const float*)d_in[4];
    const float* Wv       = (const float*)d_in[5];
    const float* bv       = (const float*)d_in[6];
    const float* Wo       = (const float*)d_in[7];
    const float* bo       = (const float*)d_in[8];
    const float* ln_ag    = (const float*)d_in[9];
    const float* ln_ab    = (const float*)d_in[10];
    const float* ln_fg    = (const float*)d_in[11];
    const float* ln_fb    = (const float*)d_in[12];
    const float* Wr       = (const float*)d_in[13];
    const float* br       = (const float*)d_in[14];
    const float* W_up     = (const float*)d_in[15];
    const float* b_up     = (const float*)d_in[16];
    const float* W_new    = (const float*)d_in[17];
    const float* b_new    = (const float*)d_in[18];
    const float* W_down   = (const float*)d_in[19];
    const float* b_down   = (const float*)d_in[20];

    float* out    = (float*)d_out;                    // layer_output [T, H]
    float* logits = out + (size_t)TT * HH;            // router_logits [T, E]

    static cudaStream_t s1;
    static cudaEvent_t evFork, evQKVW, evFFNW;
    static int once = 0;
    if (!once) {
        cudaFuncSetAttribute(hgemm<0>, cudaFuncAttributeMaxDynamicSharedMemorySize, HG_SMEM);
        cudaFuncSetAttribute(hgemm<1>, cudaFuncAttributeMaxDynamicSharedMemorySize, HG_SMEM);
        cudaFuncSetAttribute(hgemm<2>, cudaFuncAttributeMaxDynamicSharedMemorySize, HG_SMEM);
        cudaFuncSetAttribute(ffn_upgate, cudaFuncAttributeMaxDynamicSharedMemorySize, UPG_SMEM);
        cudaFuncSetAttribute(flash_attn, cudaFuncAttributeMaxDynamicSharedMemorySize, FL_SMEM);
        cudaStreamCreateWithFlags(&s1, cudaStreamNonBlocking);
        cudaEventCreateWithFlags(&evFork, cudaEventDisableTiming);
        cudaEventCreateWithFlags(&evQKVW, cudaEventDisableTiming);
        cudaEventCreateWithFlags(&evFFNW, cudaEventDisableTiming);
        once = 1;
    }

    __half *wqkvh, *wqkvl, *woh, *wol, *wuh, *wul, *wnh, *wnl, *wdh, *wdl, *xsh, *xsl;
    cudaGetSymbolAddress((void**)&wqkvh, g_wqkvh);
    cudaGetSymbolAddress((void**)&wqkvl, g_wqkvl);
    cudaGetSymbolAddress((void**)&woh, g_woh);
    cudaGetSymbolAddress((void**)&wol, g_wol);
    cudaGetSymbolAddress((void**)&wuh, g_wuh);
    cudaGetSymbolAddress((void**)&wul, g_wul);
    cudaGetSymbolAddress((void**)&wnh, g_wnh);
    cudaGetSymbolAddress((void**)&wnl, g_wnl);
    cudaGetSymbolAddress((void**)&wdh, g_wdh);
    cudaGetSymbolAddress((void**)&wdl, g_wdl);
    cudaGetSymbolAddress((void**)&xsh, g_xsh);
    cudaGetSymbolAddress((void**)&xsl, g_xsl);

    // ---- fork side stream for weight prep (fp16 hi/lo splits, no transpose) ----
    cudaEventRecord(evFork, 0);
    cudaStreamWaitEvent(s1, evFork, 0);

    // qkv/wo weight splits first (needed early by hgemm<0>/<1>)
    fsplit<<<HH * HH / 1024, 256, 0, s1>>>(Wq, wqkvh,               wqkvl);
    fsplit<<<HH * HH / 1024, 256, 0, s1>>>(Wk, wqkvh + HH * HH,     wqkvl + HH * HH);
    fsplit<<<HH * HH / 1024, 256, 0, s1>>>(Wv, wqkvh + 2 * HH * HH, wqkvl + 2 * HH * HH);
    fsplit<<<HH * HH / 1024, 256, 0, s1>>>(Wo, woh, wol);
    cudaEventRecord(evQKVW, s1);
    // big FFN weight splits overlap with the whole attention phase
    fsplit<<<EE * HH * II / 1024, 256, 0, s1>>>(W_up,  wuh, wul);
    fsplit<<<EE * HH * II / 1024, 256, 0, s1>>>(W_new, wnh, wnl);
    fsplit<<<EE * II * HH / 1024, 256, 0, s1>>>(W_down, wdh, wdl);
    cudaEventRecord(evFFNW, s1);

    // ---- main stream: activation prep + attention chain ----
    init_kernel<<<1, 32>>>();
    fsplit<<<TT * HH / 1024, 256>>>(X, xsh, xsl);

    cudaStreamWaitEvent(0, evQKVW, 0);
    hgemm<0><<<dim3(3 * HH / 128, TT / 128), 256, HG_SMEM>>>(bq, bk, bv, nullptr);
    flash_attn<<<dim3(SS / 128, BB * NHH), 256, FL_SMEM>>>();
    hgemm<1><<<dim3(HH / 128, TT / 128), 256, HG_SMEM>>>(bo, X, nullptr, nullptr);

    ln_kernel<<<TT, 256>>>(ln_ag, ln_ab, out, 0);
    ln_kernel<<<TT, 256>>>(ln_fg, ln_fb, out, 1);
    router_kernel<<<TT / 8, 256>>>(Wr, br, logits);
    offsets_kernel<<<1, 32>>>();
    scatter_kernel<<<(TT + 255) / 256, 256>>>();

    // ---- join: FFN weights must be split before the MoE GEMMs ----
    cudaStreamWaitEvent(0, evFFNW, 0);
    ffn_upgate<<<dim3(32, EE * 24), 256, UPG_SMEM>>>(b_up, b_new);
    hgemm<2><<<dim3(32, EE * 6), 256, HG_SMEM>>>(b_down, nullptr, nullptr, out);
}

// round 9
// speedup vs baseline: 3.7356x; 1.2375x over previous
#include <cuda_runtime.h>
#include <cuda_fp16.h>
#include <math.h>
#include <stdint.h>

#define TT  4096   // B*S
#define HH  768
#define SS  512
#define BB  8
#define NHH 12
#define DHH 64
#define II  3072
#define EE  8
#define ENT 8192   // TT * TOPK

// ---------------- scratch (static device allocations; no cudaMalloc) --------
__device__ float g_preln[TT * HH];
__device__ float g_attnout[TT * HH];
__device__ float g_xl[TT * HH];
__device__ __half g_xlh[TT * HH];           // xl split
__device__ __half g_xll[TT * HH];
__device__ __half g_xsh[TT * HH];           // X split
__device__ __half g_xsl[TT * HH];
__device__ __half g_qh[TT * HH];            // Q split, [B*NH][S][DH]
__device__ __half g_ql[TT * HH];
__device__ __half g_kh[TT * HH];
__device__ __half g_kl[TT * HH];
__device__ __half g_vh[TT * HH];
__device__ __half g_vl[TT * HH];
__device__ __half g_ch[TT * HH];            // ctx split [T][H]
__device__ __half g_cl[TT * HH];
__device__ __half g_hh[(size_t)ENT * II];   // FFN hidden h = gelu(u)*gate, hi
__device__ __half g_hl[(size_t)ENT * II];   // lo
__device__ __half g_wqkvh[3 * HH * HH];     // [Wq;Wk;Wv] each [768 k][768 n]
__device__ __half g_wqkvl[3 * HH * HH];
__device__ __half g_woh[HH * HH];           // Wo [768 k][768 n]
__device__ __half g_wol[HH * HH];
__device__ __half g_wuh[(size_t)EE * HH * II];  // W_up  fp16 [E][H k][I n]
__device__ __half g_wnh[(size_t)EE * HH * II];  // W_new fp16
__device__ __half g_wdh[(size_t)EE * II * HH];  // W_down fp16 [E][I k][H n]
__device__ int   g_cnt[EE];
__device__ int   g_off[EE];
__device__ int   g_cur[EE];
__device__ int   g_etok[ENT];
__device__ float g_ew[ENT];
__device__ int   g_ti[TT * 2];
__device__ float g_tw[TT * 2];

// ======================= asm helpers (portable sm_80+) =======================
__device__ __forceinline__ uint32_t smem_u32(const void* p) {
    uint32_t a;
    asm("{ .reg .u64 t; cvta.to.shared.u64 t, %1; cvt.u32.u64 %0, t; }" : "=r"(a) : "l"(p));
    return a;
}
__device__ __forceinline__ void ldsm4(uint32_t& r0, uint32_t& r1, uint32_t& r2, uint32_t& r3,
                                      uint32_t addr) {
    asm volatile("ldmatrix.sync.aligned.m8n8.x4.shared.b16 {%0,%1,%2,%3}, [%4];"
                 : "=r"(r0), "=r"(r1), "=r"(r2), "=r"(r3) : "r"(addr));
}
__device__ __forceinline__ void ldsm4t(uint32_t& r0, uint32_t& r1, uint32_t& r2, uint32_t& r3,
                                       uint32_t addr) {
    asm volatile("ldmatrix.sync.aligned.m8n8.x4.trans.shared.b16 {%0,%1,%2,%3}, [%4];"
                 : "=r"(r0), "=r"(r1), "=r"(r2), "=r"(r3) : "r"(addr));
}
__device__ __forceinline__ void mma16816(float* c, const uint32_t* a, const uint32_t* b) {
    asm volatile(
        "mma.sync.aligned.m16n8k16.row.col.f32.f16.f16.f32 "
        "{%0,%1,%2,%3}, {%4,%5,%6,%7}, {%8,%9}, {%0,%1,%2,%3};"
        : "+f"(c[0]), "+f"(c[1]), "+f"(c[2]), "+f"(c[3])
        : "r"(a[0]), "r"(a[1]), "r"(a[2]), "r"(a[3]), "r"(b[0]), "r"(b[1]));
}
__device__ __forceinline__ void cpasync16(uint32_t saddr, const void* gaddr) {
    asm volatile("cp.async.cg.shared.global [%0], [%1], 16;" :: "r"(saddr), "l"(gaddr));
}
#define CP_COMMIT() asm volatile("cp.async.commit_group;" ::: "memory")
#define CP_WAIT1()  asm volatile("cp.async.wait_group 1;" ::: "memory")
#define CP_WAIT0()  asm volatile("cp.async.wait_group 0;" ::: "memory")

// xor-swizzled smem byte offset for a [rows x 32 halves] tile (row = 64B)
__device__ __forceinline__ uint32_t swoff(int m, int kg) {
    return (uint32_t)(m * 64 + ((kg ^ ((m >> 1) & 3)) << 4));
}
// xor-swizzled smem byte offset for a [rows x 64 halves] tile (row = 128B, 8 chunks)
__device__ __forceinline__ uint32_t fswz(int m, int c) {
    return (uint32_t)(m * 128 + ((c ^ (m & 7)) << 4));
}
// xor-swizzled smem byte offset for a [32 k x 128 halves] B tile (row = 256B, 16 chunks)
__device__ __forceinline__ uint32_t bswz(int k, int c) {
    return (uint32_t)(k * 256 + ((c ^ (k & 7)) << 4));
}
__device__ __forceinline__ uint32_t packsplit(float v0, float v1, uint32_t& lo) {
    __half h0 = __float2half_rn(v0), h1 = __float2half_rn(v1);
    __half2 l = __halves2half2(__float2half_rn(v0 - __half2float(h0)),
                               __float2half_rn(v1 - __half2float(h1)));
    lo = *(uint32_t*)&l;
    __half2 h = __halves2half2(h0, h1);
    return *(uint32_t*)&h;
}

// ============ elementwise fp32 -> fp16 hi/lo split (pure streaming) ==========
__global__ void fsplit(const float* __restrict__ src, __half* __restrict__ h,
                       __half* __restrict__ l) {
    size_t i = ((size_t)blockIdx.x * 256 + threadIdx.x) * 4;
    float4 v = *(const float4*)(src + i);
    uint32_t lo0, lo1;
    uint32_t h0 = packsplit(v.x, v.y, lo0);
    uint32_t h1 = packsplit(v.z, v.w, lo1);
    *(uint32_t*)(h + i)     = h0;
    *(uint32_t*)(h + i + 2) = h1;
    *(uint32_t*)(l + i)     = lo0;
    *(uint32_t*)(l + i + 2) = lo1;
}

// ============ elementwise fp32 -> fp16 convert (FFN weights, no lo) ==========
__global__ void fconv(const float* __restrict__ src, __half* __restrict__ h) {
    size_t i = ((size_t)blockIdx.x * 256 + threadIdx.x) * 4;
    float4 v = *(const float4*)(src + i);
    __half2 a = __halves2half2(__float2half_rn(v.x), __float2half_rn(v.y));
    __half2 b = __halves2half2(__float2half_rn(v.z), __float2half_rn(v.w));
    *(uint32_t*)(h + i)     = *(uint32_t*)&a;
    *(uint32_t*)(h + i + 2) = *(uint32_t*)&b;
}

// ================= unified fp16 pipelined HMMA GEMM ==========================
// B operand is [K][N] row-major, loaded via ldsm4t.
// MODE 0: QKV   (3-term: B hi/lo)  -> g_qh..g_vl split
// MODE 1: PROJ  (3-term: B hi/lo)  -> g_preln (+bo+X)
// MODE 2: DOWN  (2-term: B fp16)   A=g_hh/l, B=g_wdh -> atomicAdd out
template<int MODE>
__global__ void __launch_bounds__(256, 2) hgemm(
    const float* __restrict__ p0, const float* __restrict__ p1,
    const float* __restrict__ p2, float* __restrict__ pout) {

    constexpr int KD = (MODE == 2) ? II : HH;   // A K-dim
    constexpr int NS = KD / 32;
    constexpr bool BLO = (MODE != 2);           // B has lo correction?

    int e = 0, base = 0, end = 0, m0 = 0, n0;
    if (MODE == 2) {
        e = blockIdx.y / 6;
        n0 = (blockIdx.y % 6) * 128;
        base = g_off[e] + blockIdx.x * 128;
        end  = g_off[e] + g_cnt[e];
        if (base >= end) return;
    } else {
        m0 = blockIdx.y * 128;
        n0 = blockIdx.x * 128;
    }

    extern __shared__ char dyn[];
    __shared__ int   s_tok[128];
    __shared__ float s_w[128];

    int tid = threadIdx.x, lane = tid & 31, wid = tid >> 5;
    int wm = wid & 1, wn = wid >> 1;

    if (MODE == 2 && tid < 128) {
        int r = min(base + tid, end - 1);
        s_tok[tid] = g_etok[r];
        s_w[tid]   = g_ew[r];
    }
    __syncthreads();

    const __half *Bh, *Bl = nullptr, *Ah, *Al;
    int nb;
    if (MODE == 0) {
        int which = n0 / HH;
        Bh = g_wqkvh + (size_t)which * HH * HH;
        Bl = g_wqkvl + (size_t)which * HH * HH;
        Ah = g_xsh; Al = g_xsl;
        nb = n0 - which * HH;
    } else if (MODE == 1) {
        Bh = g_woh; Bl = g_wol; Ah = g_ch; Al = g_cl; nb = n0;
    } else {
        Bh = g_wdh + (size_t)e * II * HH;
        Ah = g_hh;  Al = g_hl; nb = n0;
    }

    uint32_t sbase = smem_u32(dyn);

    auto issue = [&](int slab, int st) {
        int k0 = slab * 32;
        uint32_t sb = sbase + st * 32768;
#pragma unroll
        for (int i = 0; i < 2; i++) {
            int c = tid + i * 256;
            {
                int m = c >> 2, kc = c & 3;
                uint32_t so = sb + swoff(m, kc);
                int koff = k0 + kc * 8;
                size_t aoff;
                if (MODE < 2) aoff = (size_t)(m0 + m) * KD;
                else          aoff = (size_t)min(base + m, end - 1) * KD;
                cpasync16(so,        Ah + aoff + koff);
                cpasync16(so + 8192, Al + aoff + koff);
            }
            {
                int k = c >> 4, cb = c & 15;
                uint32_t bo = sb + 16384 + bswz(k, cb);
                size_t go = (size_t)(k0 + k) * HH + nb + cb * 8;
                cpasync16(bo, Bh + go);
                if (BLO) cpasync16(bo + 8192, Bl + go);
            }
        }
    };

    int j = lane >> 3, rr = lane & 7;
    int amRow = wm * 64 + (j & 1) * 8 + rr;
    int akSel = j >> 1;
    float C[4][4][4] = {};

    issue(0, 0);
    CP_COMMIT();
    for (int s = 0; s < NS; s++) {
        int st = s & 1;
        if (s + 1 < NS) {
            issue(s + 1, st ^ 1);
            CP_COMMIT();
            CP_WAIT1();
        } else {
            CP_WAIT0();
        }
        __syncthreads();
        uint32_t aH = sbase + st * 32768, aL = aH + 8192;
        uint32_t bH = aH + 16384, bL = aH + 24576;
#pragma unroll
        for (int kk = 0; kk < 2; kk++) {
            uint32_t bh[4][2], bl[4][2];
#pragma unroll
            for (int f16 = 0; f16 < 2; f16++) {
                int krow = kk * 16 + (j & 1) * 8 + rr;
                int cc = wn * 4 + f16 * 2 + (j >> 1);
                uint32_t o = bswz(krow, cc);
                ldsm4t(bh[f16 * 2][0], bh[f16 * 2][1], bh[f16 * 2 + 1][0], bh[f16 * 2 + 1][1], bH + o);
                if (BLO)
                    ldsm4t(bl[f16 * 2][0], bl[f16 * 2][1], bl[f16 * 2 + 1][0], bl[f16 * 2 + 1][1], bL + o);
            }
#pragma unroll
            for (int fm = 0; fm < 4; fm++) {
                int m = amRow + fm * 16;
                int kg = kk * 2 + akSel;
                uint32_t o = (uint32_t)(m * 64 + ((kg ^ ((m >> 1) & 3)) << 4));
                uint32_t ah[4], al[4];
                ldsm4(ah[0], ah[1], ah[2], ah[3], aH + o);
                ldsm4(al[0], al[1], al[2], al[3], aL + o);
#pragma unroll
                for (int fn = 0; fn < 4; fn++) {
                    mma16816(C[fm][fn], ah, bh[fn]);
                    mma16816(C[fm][fn], al, bh[fn]);
                    if (BLO) mma16816(C[fm][fn], ah, bl[fn]);
                }
            }
        }
        __syncthreads();
    }

    int g = lane >> 2, tig = lane & 3;

    __half *qh_out = nullptr, *ql_out = nullptr;
    const float* mbias = nullptr;
    int hcol0 = 0;
    if (MODE == 0) {
        int which = n0 / HH;
        qh_out = (which == 0) ? g_qh : (which == 1) ? g_kh : g_vh;
        ql_out = (which == 0) ? g_ql : (which == 1) ? g_kl : g_vl;
        mbias  = (which == 0) ? p0 : (which == 1) ? p1 : p2;
        hcol0  = n0 - which * HH;
    }

#pragma unroll
    for (int fm = 0; fm < 4; fm++) {
        int rowl0 = wm * 64 + fm * 16 + g;
#pragma unroll
        for (int fn = 0; fn < 4; fn++) {
            int coll = wn * 32 + fn * 8 + tig * 2;
#pragma unroll
            for (int hf = 0; hf < 2; hf++) {
                int ml = rowl0 + hf * 8;
                float c0 = C[fm][fn][hf * 2], c1 = C[fm][fn][hf * 2 + 1];
                if (MODE == 0) {
                    int t = m0 + ml;
                    int hcol = hcol0 + coll;
                    int h = hcol >> 6, d = hcol & 63;
                    int b = t >> 9, sI = t & 511;
                    size_t o = (((size_t)(b * NHH + h)) * SS + sI) * DHH + d;
                    uint32_t lo;
                    uint32_t hi = packsplit(c0 + mbias[hcol], c1 + mbias[hcol + 1], lo);
                    *(uint32_t*)(qh_out + o) = hi;
                    *(uint32_t*)(ql_out + o) = lo;
                } else if (MODE == 1) {
                    size_t t = m0 + ml;
                    int col = n0 + coll;
                    float2 xr = *(const float2*)(p1 + t * HH + col);
                    float2 v = {c0 + p0[col] + xr.x, c1 + p0[col + 1] + xr.y};
                    *(float2*)(g_preln + t * HH + col) = v;
                } else {
                    if (base + ml < end) {
                        int col = n0 + coll;
                        int t = s_tok[ml];
                        float w = s_w[ml];
                        const float* eb = p0 + (size_t)e * HH;
                        atomicAdd(pout + (size_t)t * HH + col,     (c0 + eb[col]) * w);
                        atomicAdd(pout + (size_t)t * HH + col + 1, (c1 + eb[col + 1]) * w);
                    }
                }
            }
        }
    }
}

// ============ fused up+gate pipelined HMMA grouped GEMM (2-term) =============
// h[r, i] = gelu(xl@Wu + bu) * (xl@Wn + bn) -> g_hh/g_hl (fp16 split)
// A = xl hi/lo (exact), B = fp16 weights (single copy).
#define UPG_SMEM (2 * 32768)
__global__ void __launch_bounds__(256, 1) ffn_upgate(
    const float* __restrict__ bu_, const float* __restrict__ bn_) {
    int e = blockIdx.y / 24;
    int n0 = (blockIdx.y % 24) * 128;
    int base = g_off[e] + blockIdx.x * 128;
    int end  = g_off[e] + g_cnt[e];
    if (base >= end) return;

    extern __shared__ char dyn[];
    __shared__ int s_tok[128];

    int tid = threadIdx.x, lane = tid & 31, wid = tid >> 5;
    int wm = wid & 1, wn = wid >> 1;

    if (tid < 128) s_tok[tid] = g_etok[min(base + tid, end - 1)];
    __syncthreads();

    const __half* Buh = g_wuh + (size_t)e * HH * II;
    const __half* Bnh = g_wnh + (size_t)e * HH * II;
    uint32_t sbase = smem_u32(dyn);

    auto issue = [&](int slab, int st) {
        int k0 = slab * 32;
        uint32_t sb = sbase + st * 32768;
#pragma unroll
        for (int i = 0; i < 2; i++) {
            int c = tid + i * 256;
            {
                int m = c >> 2, kc = c & 3;
                uint32_t so = sb + swoff(m, kc);
                size_t aoff = (size_t)s_tok[m] * HH + k0 + kc * 8;
                cpasync16(so,        g_xlh + aoff);
                cpasync16(so + 8192, g_xll + aoff);
            }
            {
                int k = c >> 4, cb = c & 15;
                uint32_t bo = sb + 16384 + bswz(k, cb);
                size_t go = (size_t)(k0 + k) * II + n0 + cb * 8;
                cpasync16(bo,        Buh + go);
                cpasync16(bo + 8192, Bnh + go);
            }
        }
    };

    int j = lane >> 3, rr = lane & 7;
    int amRow = wm * 64 + (j & 1) * 8 + rr;
    int akSel = j >> 1;
    float Cu[4][4][4] = {}, Cn[4][4][4] = {};

    issue(0, 0);
    CP_COMMIT();
    for (int s = 0; s < HH / 32; s++) {
        int st = s & 1;
        if (s + 1 < HH / 32) {
            issue(s + 1, st ^ 1);
            CP_COMMIT();
            CP_WAIT1();
        } else {
            CP_WAIT0();
        }
        __syncthreads();
        uint32_t aH = sbase + st * 32768, aL = aH + 8192;
        uint32_t uH = aH + 16384, nH = aH + 24576;
#pragma unroll
        for (int kk = 0; kk < 2; kk++) {
            uint32_t buh[4][2], bnh[4][2];
#pragma unroll
            for (int f16 = 0; f16 < 2; f16++) {
                int krow = kk * 16 + (j & 1) * 8 + rr;
                int cc = wn * 4 + f16 * 2 + (j >> 1);
                uint32_t o = bswz(krow, cc);
                ldsm4t(buh[f16 * 2][0], buh[f16 * 2][1], buh[f16 * 2 + 1][0], buh[f16 * 2 + 1][1], uH + o);
                ldsm4t(bnh[f16 * 2][0], bnh[f16 * 2][1], bnh[f16 * 2 + 1][0], bnh[f16 * 2 + 1][1], nH + o);
            }
#pragma unroll
            for (int fm = 0; fm < 4; fm++) {
                int m = amRow + fm * 16;
                int kg = kk * 2 + akSel;
                uint32_t o = (uint32_t)(m * 64 + ((kg ^ ((m >> 1) & 3)) << 4));
                uint32_t ah[4], al[4];
                ldsm4(ah[0], ah[1], ah[2], ah[3], aH + o);
                ldsm4(al[0], al[1], al[2], al[3], aL + o);
#pragma unroll
                for (int fn = 0; fn < 4; fn++) {
                    mma16816(Cu[fm][fn], ah, buh[fn]);
                    mma16816(Cu[fm][fn], al, buh[fn]);
                    mma16816(Cn[fm][fn], ah, bnh[fn]);
                    mma16816(Cn[fm][fn], al, bnh[fn]);
                }
            }
        }
        __syncthreads();
    }

    int g = lane >> 2, tig = lane & 3;
    const float* bu = bu_ + (size_t)e * II;
    const float* bn = bn_ + (size_t)e * II;
#pragma unroll
    for (int fm = 0; fm < 4; fm++) {
        int rowl0 = wm * 64 + fm * 16 + g;
#pragma unroll
        for (int fn = 0; fn < 4; fn++) {
            int col = n0 + wn * 32 + fn * 8 + tig * 2;
            float bu0 = bu[col], bu1 = bu[col + 1];
            float bn0 = bn[col], bn1 = bn[col + 1];
#pragma unroll
            for (int hf = 0; hf < 2; hf++) {
                int r = base + rowl0 + hf * 8;
                if (r < end) {
                    float u0 = Cu[fm][fn][hf * 2] + bu0, u1 = Cu[fm][fn][hf * 2 + 1] + bu1;
                    float h0 = u0 * normcdff(u0) * (Cn[fm][fn][hf * 2] + bn0);
                    float h1 = u1 * normcdff(u1) * (Cn[fm][fn][hf * 2 + 1] + bn1);
                    uint32_t lo;
                    uint32_t hi = packsplit(h0, h1, lo);
                    *(uint32_t*)(g_hh + (size_t)r * II + col) = hi;
                    *(uint32_t*)(g_hl + (size_t)r * II + col) = lo;
                }
            }
        }
    }
}

// ================= flash attention (fp16x3 HMMA, online softmax) =============
#define FL_SMEM (32768 + 2 * 65536)
__global__ void __launch_bounds__(256, 1) flash_attn() {
    int q0 = blockIdx.x * 128;
    int head = blockIdx.y;
    int b = head / NHH, h_ = head % NHH;

    extern __shared__ char dyn[];
    uint32_t sb = smem_u32(dyn);
    const uint32_t QH = 0, QL = 16384;

    const __half* Qh = g_qh + (size_t)head * SS * DHH;
    const __half* Ql = g_ql + (size_t)head * SS * DHH;
    const __half* Kh = g_kh + (size_t)head * SS * DHH;
    const __half* Kl = g_kl + (size_t)head * SS * DHH;
    const __half* Vh = g_vh + (size_t)head * SS * DHH;
    const __half* Vl = g_vl + (size_t)head * SS * DHH;

    int tid = threadIdx.x, lane = tid & 31, wid = tid >> 5;
    int j = lane >> 3, rr = lane & 7;
    int g = lane >> 2, tig = lane & 3;

    auto load_tile = [&](uint32_t dst, const __half* src, int row0) {
#pragma unroll
        for (int i = 0; i < 4; i++) {
            int idx = tid + i * 256;
            int m = idx >> 3, c = idx & 7;
            cpasync16(sb + dst + fswz(m, c), src + (size_t)(row0 + m) * DHH + c * 8);
        }
    };

    load_tile(QH, Qh, q0);
    load_tile(QL, Ql, q0);
    load_tile(32768, Kh, 0);
    load_tile(32768 + 16384, Kl, 0);
    load_tile(32768 + 32768, Vh, 0);
    load_tile(32768 + 49152, Vl, 0);
    CP_COMMIT();

    float O[8][4] = {};
    float rm0 = -1e30f, rm1 = -1e30f, l0 = 0.0f, l1 = 0.0f;

    for (int kt = 0; kt < 4; kt++) {
        int st = kt & 1;
        if (kt + 1 < 4) {
            uint32_t nb = 32768 + (st ^ 1) * 65536;
            load_tile(nb,         Kh, (kt + 1) * 128);
            load_tile(nb + 16384, Kl, (kt + 1) * 128);
            load_tile(nb + 32768, Vh, (kt + 1) * 128);
            load_tile(nb + 49152, Vl, (kt + 1) * 128);
            CP_COMMIT();
            CP_WAIT1();
        } else {
            CP_WAIT0();
        }
        __syncthreads();

        uint32_t kH = sb + 32768 + st * 65536, kL = kH + 16384;
        uint32_t vH = kH + 32768, vL = kH + 49152;
        uint32_t qHb = sb + QH, qLb = sb + QL;

        float S[16][4] = {};
#pragma unroll
        for (int ks = 0; ks < 4; ks++) {
            int am = wid * 16 + (j & 1) * 8 + rr;
            int ac = 2 * ks + (j >> 1);
            uint32_t ah[4], al[4];
            ldsm4(ah[0], ah[1], ah[2], ah[3], qHb + fswz(am, ac));
            ldsm4(al[0], al[1], al[2], al[3], qLb + fswz(am, ac));
#pragma unroll
            for (int fnp = 0; fnp < 8; fnp++) {
                int bn = fnp * 16 + (j >> 1) * 8 + rr;
                int bc = 2 * ks + (j & 1);
                uint32_t bo = fswz(bn, bc);
                uint32_t bh[4], bl[4];
                ldsm4(bh[0], bh[1], bh[2], bh[3], kH + bo);
                ldsm4(bl[0], bl[1], bl[2], bl[3], kL + bo);
                mma16816(S[2 * fnp],     ah, bh);
                mma16816(S[2 * fnp],     ah, bl);
                mma16816(S[2 * fnp],     al, bh);
                mma16816(S[2 * fnp + 1], ah, bh + 2);
                mma16816(S[2 * fnp + 1], ah, bl + 2);
                mma16816(S[2 * fnp + 1], al, bh + 2);
            }
        }

        float mx0 = -1e30f, mx1 = -1e30f;
#pragma unroll
        for (int fn = 0; fn < 16; fn++) {
            mx0 = fmaxf(mx0, fmaxf(S[fn][0], S[fn][1]));
            mx1 = fmaxf(mx1, fmaxf(S[fn][2], S[fn][3]));
        }
        mx0 = fmaxf(mx0, __shfl_xor_sync(~0u, mx0, 1));
        mx0 = fmaxf(mx0, __shfl_xor_sync(~0u, mx0, 2));
        mx1 = fmaxf(mx1, __shfl_xor_sync(~0u, mx1, 1));
        mx1 = fmaxf(mx1, __shfl_xor_sync(~0u, mx1, 2));
        float nm0 = fmaxf(rm0, mx0 * 0.125f);
        float nm1 = fmaxf(rm1, mx1 * 0.125f);
        float al0 = __expf(rm0 - nm0);
        float al1 = __expf(rm1 - nm1);
        rm0 = nm0; rm1 = nm1;
        float sum0 = 0.0f, sum1 = 0.0f;
#pragma unroll
        for (int fn = 0; fn < 16; fn++) {
            float p0 = __expf(fmaf(S[fn][0], 0.125f, -nm0));
            float p1 = __expf(fmaf(S[fn][1], 0.125f, -nm0));
            float p2 = __expf(fmaf(S[fn][2], 0.125f, -nm1));
            float p3 = __expf(fmaf(S[fn][3], 0.125f, -nm1));
            S[fn][0] = p0; S[fn][1] = p1; S[fn][2] = p2; S[fn][3] = p3;
            sum0 += p0 + p1; sum1 += p2 + p3;
        }
        sum0 += __shfl_xor_sync(~0u, sum0, 1);
        sum0 += __shfl_xor_sync(~0u, sum0, 2);
        sum1 += __shfl_xor_sync(~0u, sum1, 1);
        sum1 += __shfl_xor_sync(~0u, sum1, 2);
        l0 = l0 * al0 + sum0;
        l1 = l1 * al1 + sum1;
#pragma unroll
        for (int fo = 0; fo < 8; fo++) {
            O[fo][0] *= al0; O[fo][1] *= al0;
            O[fo][2] *= al1; O[fo][3] *= al1;
        }

#pragma unroll
        for (int kp = 0; kp < 8; kp++) {
            uint32_t aph[4], apl[4];
            aph[0] = packsplit(S[2 * kp][0],     S[2 * kp][1],     apl[0]);
            aph[1] = packsplit(S[2 * kp][2],     S[2 * kp][3],     apl[1]);
            aph[2] = packsplit(S[2 * kp + 1][0], S[2 * kp + 1][1], apl[2]);
            aph[3] = packsplit(S[2 * kp + 1][2], S[2 * kp + 1][3], apl[3]);
#pragma unroll
            for (int dg = 0; dg < 4; dg++) {
                int vrow = kp * 16 + (j & 1) * 8 + rr;
                int vc = dg * 2 + (j >> 1);
                uint32_t vo = fswz(vrow, vc);
                uint32_t vh[4], vl[4];
                ldsm4t(vh[0], vh[1], vh[2], vh[3], vH + vo);
                ldsm4t(vl[0], vl[1], vl[2], vl[3], vL + vo);
#pragma unroll
                for (int hg = 0; hg < 2; hg++) {
                    int fo = dg * 2 + hg;
                    mma16816(O[fo], aph, vh + hg * 2);
                    mma16816(O[fo], apl, vh + hg * 2);
                    mma16816(O[fo], aph, vl + hg * 2);
                }
            }
        }
        __syncthreads();
    }

    float inv0 = 1.0f / l0, inv1 = 1.0f / l1;
    int qr0 = q0 + wid * 16 + g;
    size_t t0 = (size_t)b * SS + qr0;
    size_t t1 = t0 + 8;
#pragma unroll
    for (int fo = 0; fo < 8; fo++) {
        int d = fo * 8 + tig * 2;
        int col = h_ * 64 + d;
        uint32_t lo;
        uint32_t hi = packsplit(O[fo][0] * inv0, O[fo][1] * inv0, lo);
        *(uint32_t*)(g_ch + t0 * HH + col) = hi;
        *(uint32_t*)(g_cl + t0 * HH + col) = lo;
        hi = packsplit(O[fo][2] * inv1, O[fo][3] * inv1, lo);
        *(uint32_t*)(g_ch + t1 * HH + col) = hi;
        *(uint32_t*)(g_cl + t1 * HH + col) = lo;
    }
}

// ================= LayerNorm ==================================================
__global__ void ln_kernel(const float* __restrict__ gamma, const float* __restrict__ beta,
                          float* __restrict__ dout, int mode) {
    size_t row = blockIdx.x;
    const float* in = (mode == 0) ? (g_preln + row * HH) : (g_attnout + row * HH);
    int tid = threadIdx.x;
    float x0 = in[tid], x1 = in[tid + 256], x2 = in[tid + 512];

    __shared__ float red[256];
    red[tid] = x0 + x1 + x2;
    __syncthreads();
    for (int s = 128; s > 0; s >>= 1) {
        if (tid < s) red[tid] += red[tid + s];
        __syncthreads();
    }
    float mean = red[0] * (1.0f / HH);
    __syncthreads();

    float c0 = x0 - mean, c1 = x1 - mean, c2 = x2 - mean;
    red[tid] = c0 * c0 + c1 * c1 + c2 * c2;
    __syncthreads();
    for (int s = 128; s > 0; s >>= 1) {
        if (tid < s) red[tid] += red[tid + s];
        __syncthreads();
    }
    float inv = 1.0f / sqrtf(red[0] * (1.0f / HH) + 1e-12f);

    float y0 = c0 * inv * gamma[tid]       + beta[tid];
    float y1 = c1 * inv * gamma[tid + 256] + beta[tid + 256];
    float y2 = c2 * inv * gamma[tid + 512] + beta[tid + 512];
    if (mode == 0) {
        g_attnout[row * HH + tid]       = y0;
        g_attnout[row * HH + tid + 256] = y1;
        g_attnout[row * HH + tid + 512] = y2;
        dout[row * HH + tid]       = y0;
        dout[row * HH + tid + 256] = y1;
        dout[row * HH + tid + 512] = y2;
    } else {
        g_xl[row * HH + tid]       = y0;
        g_xl[row * HH + tid + 256] = y1;
        g_xl[row * HH + tid + 512] = y2;
        __half h0 = __float2half_rn(y0), h1 = __float2half_rn(y1), h2 = __float2half_rn(y2);
        g_xlh[row * HH + tid]       = h0;
        g_xlh[row * HH + tid + 256] = h1;
        g_xlh[row * HH + tid + 512] = h2;
        g_xll[row * HH + tid]       = __float2half_rn(y0 - __half2float(h0));
        g_xll[row * HH + tid + 256] = __float2half_rn(y1 - __half2float(h1));
        g_xll[row * HH + tid + 512] = __float2half_rn(y2 - __half2float(h2));
    }
}

// ================= counters / router / scatter ===============================
__global__ void init_kernel() {
    int i = threadIdx.x;
    if (i < EE) { g_cnt[i] = 0; g_cur[i] = 0; }
}

__global__ void router_kernel(const float* __restrict__ Wr, const float* __restrict__ br,
                              float* __restrict__ logits_out) {
    int warp = threadIdx.x >> 5, lane = threadIdx.x & 31;
    int t = blockIdx.x * 8 + warp;
    const float* x = g_xl + (size_t)t * HH;

    float acc[EE] = {};
    for (int h = lane; h < HH; h += 32) {
        float xv = x[h];
        const float* w = Wr + (size_t)h * EE;
#pragma unroll
        for (int e = 0; e < EE; e++) acc[e] = fmaf(xv, w[e], acc[e]);
    }
#pragma unroll
    for (int e = 0; e < EE; e++)
        for (int o = 16; o > 0; o >>= 1) acc[e] += __shfl_down_sync(0xffffffffu, acc[e], o);

    if (lane == 0) {
        float lg[EE], mx = -1e30f;
#pragma unroll
        for (int e = 0; e < EE; e++) {
            lg[e] = acc[e] + br[e];
            logits_out[(size_t)t * EE + e] = lg[e];
            mx = fmaxf(mx, lg[e]);
        }
        float p[EE], s = 0.0f;
#pragma unroll
        for (int e = 0; e < EE; e++) { p[e] = expf(lg[e] - mx); s += p[e]; }
        float invs = 1.0f / s;
#pragma unroll
        for (int e = 0; e < EE; e++) p[e] *= invs;

        int i1 = 0;
#pragma unroll
        for (int e = 1; e < EE; e++) if (p[e] > p[i1]) i1 = e;
        int i2 = (i1 == 0) ? 1 : 0;
#pragma unroll
        for (int e = 0; e < EE; e++) if (e != i1 && p[e] > p[i2]) i2 = e;

        float w1 = p[i1], w2 = p[i2], inv = 1.0f / (w1 + w2);
        g_ti[t * 2]     = i1;  g_tw[t * 2]     = w1 * inv;
        g_ti[t * 2 + 1] = i2;  g_tw[t * 2 + 1] = w2 * inv;
        atomicAdd(&g_cnt[i1], 1);
        atomicAdd(&g_cnt[i2], 1);
    }
}

__global__ void offsets_kernel() {
    if (threadIdx.x == 0) {
        int o = 0;
        for (int e = 0; e < EE; e++) { g_off[e] = o; o += g_cnt[e]; }
    }
}

__global__ void scatter_kernel() {
    int t = blockIdx.x * 256 + threadIdx.x;
    if (t >= TT) return;
#pragma unroll
    for (int s = 0; s < 2; s++) {
        int e = g_ti[t * 2 + s];
        int pos = atomicAdd(&g_cur[e], 1);
        int r = g_off[e] + pos;
        g_etok[r] = t;
        g_ew[r] = g_tw[t * 2 + s];
    }
}

// ================= host launcher =============================================
#define HG_SMEM 65536

extern "C" void kernel_launch(void* const* d_in, const int* in_sizes, int n_in,
                              void* d_out, int out_size) {
    const float* X        = (const float*)d_in[0];
    const float* Wq       = (const float*)d_in[1];
    const float* bq       = (const float*)d_in[2];
    const float* Wk       = (const float*)d_in[3];
    const float* bk       = (const float*)d_in[4];
    const float* Wv       = (const float*)d_in[5];
    const float* bv       = (const float*)d_in[6];
    const float* Wo       = (const float*)d_in[7];
    const float* bo       = (const float*)d_in[8];
    const float* ln_ag    = (const float*)d_in[9];
    const float* ln_ab    = (const float*)d_in[10];
    const float* ln_fg    = (const float*)d_in[11];
    const float* ln_fb    = (const float*)d_in[12];
    const float* Wr       = (const float*)d_in[13];
    const float* br       = (const float*)d_in[14];
    const float* W_up     = (const float*)d_in[15];
    const float* b_up     = (const float*)d_in[16];
    const float* W_new    = (const float*)d_in[17];
    const float* b_new    = (const float*)d_in[18];
    const float* W_down   = (const float*)d_in[19];
    const float* b_down   = (const float*)d_in[20];

    float* out    = (float*)d_out;                    // layer_output [T, H]
    float* logits = out + (size_t)TT * HH;            // router_logits [T, E]

    static cudaStream_t s1;
    static cudaEvent_t evFork, evQKVW, evFFNW;
    static int once = 0;
    if (!once) {
        cudaFuncSetAttribute(hgemm<0>, cudaFuncAttributeMaxDynamicSharedMemorySize, HG_SMEM);
        cudaFuncSetAttribute(hgemm<1>, cudaFuncAttributeMaxDynamicSharedMemorySize, HG_SMEM);
        cudaFuncSetAttribute(hgemm<2>, cudaFuncAttributeMaxDynamicSharedMemorySize, HG_SMEM);
        cudaFuncSetAttribute(ffn_upgate, cudaFuncAttributeMaxDynamicSharedMemorySize, UPG_SMEM);
        cudaFuncSetAttribute(flash_attn, cudaFuncAttributeMaxDynamicSharedMemorySize, FL_SMEM);
        cudaStreamCreateWithFlags(&s1, cudaStreamNonBlocking);
        cudaEventCreateWithFlags(&evFork, cudaEventDisableTiming);
        cudaEventCreateWithFlags(&evQKVW, cudaEventDisableTiming);
        cudaEventCreateWithFlags(&evFFNW, cudaEventDisableTiming);
        once = 1;
    }

    __half *wqkvh, *wqkvl, *woh, *wol, *wuh, *wnh, *wdh, *xsh, *xsl;
    cudaGetSymbolAddress((void**)&wqkvh, g_wqkvh);
    cudaGetSymbolAddress((void**)&wqkvl, g_wqkvl);
    cudaGetSymbolAddress((void**)&woh, g_woh);
    cudaGetSymbolAddress((void**)&wol, g_wol);
    cudaGetSymbolAddress((void**)&wuh, g_wuh);
    cudaGetSymbolAddress((void**)&wnh, g_wnh);
    cudaGetSymbolAddress((void**)&wdh, g_wdh);
    cudaGetSymbolAddress((void**)&xsh, g_xsh);
    cudaGetSymbolAddress((void**)&xsl, g_xsl);

    // ---- fork side stream for weight prep ----
    cudaEventRecord(evFork, 0);
    cudaStreamWaitEvent(s1, evFork, 0);

    fsplit<<<HH * HH / 1024, 256, 0, s1>>>(Wq, wqkvh,               wqkvl);
    fsplit<<<HH * HH / 1024, 256, 0, s1>>>(Wk, wqkvh + HH * HH,     wqkvl + HH * HH);
    fsplit<<<HH * HH / 1024, 256, 0, s1>>>(Wv, wqkvh + 2 * HH * HH, wqkvl + 2 * HH * HH);
    fsplit<<<HH * HH / 1024, 256, 0, s1>>>(Wo, woh, wol);
    cudaEventRecord(evQKVW, s1);
    // FFN weights: plain fp16 convert (2-term GEMM needs no lo copy)
    fconv<<<EE * HH * II / 1024, 256, 0, s1>>>(W_up,  wuh);
    fconv<<<EE * HH * II / 1024, 256, 0, s1>>>(W_new, wnh);
    fconv<<<EE * II * HH / 1024, 256, 0, s1>>>(W_down, wdh);
    cudaEventRecord(evFFNW, s1);

    // ---- main stream: activation prep + attention chain ----
    init_kernel<<<1, 32>>>();
    fsplit<<<TT * HH / 1024, 256>>>(X, xsh, xsl);

    cudaStreamWaitEvent(0, evQKVW, 0);
    hgemm<0><<<dim3(3 * HH / 128, TT / 128), 256, HG_SMEM>>>(bq, bk, bv, nullptr);
    flash_attn<<<dim3(SS / 128, BB * NHH), 256, FL_SMEM>>>();
    hgemm<1><<<dim3(HH / 128, TT / 128), 256, HG_SMEM>>>(bo, X, nullptr, nullptr);

    ln_kernel<<<TT, 256>>>(ln_ag, ln_ab, out, 0);
    ln_kernel<<<TT, 256>>>(ln_fg, ln_fb, out, 1);
    router_kernel<<<TT / 8, 256>>>(Wr, br, logits);
    offsets_kernel<<<1, 32>>>();
    scatter_kernel<<<(TT + 255) / 256, 256>>>();

    // ---- join: FFN weights ready before the MoE GEMMs ----
    cudaStreamWaitEvent(0, evFFNW, 0);
    ffn_upgate<<<dim3(32, EE * 24), 256, UPG_SMEM>>>(b_up, b_new);
    hgemm<2><<<dim3(32, EE * 6), 256, HG_SMEM>>>(b_down, nullptr, nullptr, out);
}

// round 10
// speedup vs baseline: 4.8741x; 1.3048x over previous
#include <cuda_runtime.h>
#include <cuda_fp16.h>
#include <math.h>
#include <stdint.h>

#define TT  4096   // B*S
#define HH  768
#define SS  512
#define BB  8
#define NHH 12
#define DHH 64
#define II  3072
#define EE  8
#define ENT 8192   // TT * TOPK

// ---------------- scratch (static device allocations; no cudaMalloc) --------
__device__ float g_preln[TT * HH];
__device__ float g_attnout[TT * HH];
__device__ float g_xl[TT * HH];
__device__ __half g_xlh[TT * HH];           // xl fp16 (FFN A operand)
__device__ __half g_xsh[TT * HH];           // X split
__device__ __half g_xsl[TT * HH];
__device__ __half g_qh[TT * HH];            // Q split, [B*NH][S][DH]
__device__ __half g_ql[TT * HH];
__device__ __half g_kh[TT * HH];
__device__ __half g_kl[TT * HH];
__device__ __half g_vh[TT * HH];
__device__ __half g_vl[TT * HH];
__device__ __half g_ch[TT * HH];            // ctx split [T][H]
__device__ __half g_cl[TT * HH];
__device__ __half g_hh[(size_t)ENT * II];   // FFN hidden h = gelu(u)*gate, fp16
__device__ __half g_wqkvh[3 * HH * HH];     // [Wq;Wk;Wv] each [768 k][768 n]
__device__ __half g_wqkvl[3 * HH * HH];
__device__ __half g_woh[HH * HH];           // Wo [768 k][768 n]
__device__ __half g_wol[HH * HH];
__device__ __half g_wuh[(size_t)EE * HH * II];  // W_up  fp16 [E][H k][I n]
__device__ __half g_wnh[(size_t)EE * HH * II];  // W_new fp16
__device__ __half g_wdh[(size_t)EE * II * HH];  // W_down fp16 [E][I k][H n]
__device__ int   g_cnt[EE];
__device__ int   g_off[EE];
__device__ int   g_cur[EE];
__device__ int   g_etok[ENT];
__device__ float g_ew[ENT];
__device__ int   g_ti[TT * 2];
__device__ float g_tw[TT * 2];

// ======================= asm helpers (portable sm_80+) =======================
__device__ __forceinline__ uint32_t smem_u32(const void* p) {
    uint32_t a;
    asm("{ .reg .u64 t; cvta.to.shared.u64 t, %1; cvt.u32.u64 %0, t; }" : "=r"(a) : "l"(p));
    return a;
}
__device__ __forceinline__ void ldsm4(uint32_t& r0, uint32_t& r1, uint32_t& r2, uint32_t& r3,
                                      uint32_t addr) {
    asm volatile("ldmatrix.sync.aligned.m8n8.x4.shared.b16 {%0,%1,%2,%3}, [%4];"
                 : "=r"(r0), "=r"(r1), "=r"(r2), "=r"(r3) : "r"(addr));
}
__device__ __forceinline__ void ldsm4t(uint32_t& r0, uint32_t& r1, uint32_t& r2, uint32_t& r3,
                                       uint32_t addr) {
    asm volatile("ldmatrix.sync.aligned.m8n8.x4.trans.shared.b16 {%0,%1,%2,%3}, [%4];"
                 : "=r"(r0), "=r"(r1), "=r"(r2), "=r"(r3) : "r"(addr));
}
__device__ __forceinline__ void mma16816(float* c, const uint32_t* a, const uint32_t* b) {
    asm volatile(
        "mma.sync.aligned.m16n8k16.row.col.f32.f16.f16.f32 "
        "{%0,%1,%2,%3}, {%4,%5,%6,%7}, {%8,%9}, {%0,%1,%2,%3};"
        : "+f"(c[0]), "+f"(c[1]), "+f"(c[2]), "+f"(c[3])
        : "r"(a[0]), "r"(a[1]), "r"(a[2]), "r"(a[3]), "r"(b[0]), "r"(b[1]));
}
__device__ __forceinline__ void cpasync16(uint32_t saddr, const void* gaddr) {
    asm volatile("cp.async.cg.shared.global [%0], [%1], 16;" :: "r"(saddr), "l"(gaddr));
}
#define CP_COMMIT() asm volatile("cp.async.commit_group;" ::: "memory")
#define CP_WAIT1()  asm volatile("cp.async.wait_group 1;" ::: "memory")
#define CP_WAIT0()  asm volatile("cp.async.wait_group 0;" ::: "memory")

// xor-swizzled smem byte offset for a [rows x 32 halves] tile (row = 64B)
__device__ __forceinline__ uint32_t swoff(int m, int kg) {
    return (uint32_t)(m * 64 + ((kg ^ ((m >> 1) & 3)) << 4));
}
// xor-swizzled smem byte offset for a [rows x 64 halves] tile (row = 128B, 8 chunks)
__device__ __forceinline__ uint32_t fswz(int m, int c) {
    return (uint32_t)(m * 128 + ((c ^ (m & 7)) << 4));
}
// xor-swizzled smem byte offset for a [32 k x 128 halves] B tile (row = 256B, 16 chunks)
__device__ __forceinline__ uint32_t bswz(int k, int c) {
    return (uint32_t)(k * 256 + ((c ^ (k & 7)) << 4));
}
__device__ __forceinline__ uint32_t packsplit(float v0, float v1, uint32_t& lo) {
    __half h0 = __float2half_rn(v0), h1 = __float2half_rn(v1);
    __half2 l = __halves2half2(__float2half_rn(v0 - __half2float(h0)),
                               __float2half_rn(v1 - __half2float(h1)));
    lo = *(uint32_t*)&l;
    __half2 h = __halves2half2(h0, h1);
    return *(uint32_t*)&h;
}

// ============ elementwise fp32 -> fp16 hi/lo split (pure streaming) ==========
__global__ void fsplit(const float* __restrict__ src, __half* __restrict__ h,
                       __half* __restrict__ l) {
    size_t i = ((size_t)blockIdx.x * 256 + threadIdx.x) * 4;
    float4 v = *(const float4*)(src + i);
    uint32_t lo0, lo1;
    uint32_t h0 = packsplit(v.x, v.y, lo0);
    uint32_t h1 = packsplit(v.z, v.w, lo1);
    *(uint32_t*)(h + i)     = h0;
    *(uint32_t*)(h + i + 2) = h1;
    *(uint32_t*)(l + i)     = lo0;
    *(uint32_t*)(l + i + 2) = lo1;
}

// ============ elementwise fp32 -> fp16 convert (FFN weights, no lo) ==========
__global__ void fconv(const float* __restrict__ src, __half* __restrict__ h) {
    size_t i = ((size_t)blockIdx.x * 256 + threadIdx.x) * 4;
    float4 v = *(const float4*)(src + i);
    __half2 a = __halves2half2(__float2half_rn(v.x), __float2half_rn(v.y));
    __half2 b = __halves2half2(__float2half_rn(v.z), __float2half_rn(v.w));
    *(uint32_t*)(h + i)     = *(uint32_t*)&a;
    *(uint32_t*)(h + i + 2) = *(uint32_t*)&b;
}

// ================= unified fp16 pipelined HMMA GEMM ==========================
// B operand is [K][N] row-major, loaded via ldsm4t.
// MODE 0: QKV   (3-term: A+B hi/lo) -> g_qh..g_vl split
// MODE 1: PROJ  (3-term: A+B hi/lo) -> g_preln (+bo+X)
// MODE 2: DOWN  (1-term: plain fp16) A=g_hh, B=g_wdh -> atomicAdd out
template<int MODE>
__global__ void __launch_bounds__(256, 2) hgemm(
    const float* __restrict__ p0, const float* __restrict__ p1,
    const float* __restrict__ p2, float* __restrict__ pout) {

    constexpr int KD = (MODE == 2) ? II : HH;   // A K-dim
    constexpr int NS = KD / 32;
    constexpr bool LO = (MODE != 2);            // hi/lo corrections?
    constexpr uint32_t AHOF = 0;
    constexpr uint32_t ALOF = 8192;
    constexpr uint32_t BHOF = LO ? 16384 : 8192;
    constexpr uint32_t BLOF = LO ? 24576 : 0;
    constexpr uint32_t STG  = LO ? 32768 : 16384;

    int e = 0, base = 0, end = 0, m0 = 0, n0;
    if (MODE == 2) {
        e = blockIdx.y / 6;
        n0 = (blockIdx.y % 6) * 128;
        base = g_off[e] + blockIdx.x * 128;
        end  = g_off[e] + g_cnt[e];
        if (base >= end) return;
    } else {
        m0 = blockIdx.y * 128;
        n0 = blockIdx.x * 128;
    }

    extern __shared__ char dyn[];
    __shared__ int   s_tok[128];
    __shared__ float s_w[128];

    int tid = threadIdx.x, lane = tid & 31, wid = tid >> 5;
    int wm = wid & 1, wn = wid >> 1;

    if (MODE == 2 && tid < 128) {
        int r = min(base + tid, end - 1);
        s_tok[tid] = g_etok[r];
        s_w[tid]   = g_ew[r];
    }
    __syncthreads();

    const __half *Bh, *Bl = nullptr, *Ah, *Al = nullptr;
    int nb;
    if (MODE == 0) {
        int which = n0 / HH;
        Bh = g_wqkvh + (size_t)which * HH * HH;
        Bl = g_wqkvl + (size_t)which * HH * HH;
        Ah = g_xsh; Al = g_xsl;
        nb = n0 - which * HH;
    } else if (MODE == 1) {
        Bh = g_woh; Bl = g_wol; Ah = g_ch; Al = g_cl; nb = n0;
    } else {
        Bh = g_wdh + (size_t)e * II * HH;
        Ah = g_hh;  nb = n0;
    }

    uint32_t sbase = smem_u32(dyn);

    auto issue = [&](int slab, int st) {
        int k0 = slab * 32;
        uint32_t sb = sbase + st * STG;
#pragma unroll
        for (int i = 0; i < 2; i++) {
            int c = tid + i * 256;
            {
                int m = c >> 2, kc = c & 3;
                uint32_t so = sb + swoff(m, kc);
                int koff = k0 + kc * 8;
                size_t aoff;
                if (MODE < 2) aoff = (size_t)(m0 + m) * KD;
                else          aoff = (size_t)min(base + m, end - 1) * KD;
                cpasync16(so + AHOF, Ah + aoff + koff);
                if (LO) cpasync16(so + ALOF, Al + aoff + koff);
            }
            {
                int k = c >> 4, cb = c & 15;
                uint32_t bo = sb + bswz(k, cb);
                size_t go = (size_t)(k0 + k) * HH + nb + cb * 8;
                cpasync16(bo + BHOF, Bh + go);
                if (LO) cpasync16(bo + BLOF, Bl + go);
            }
        }
    };

    int j = lane >> 3, rr = lane & 7;
    int amRow = wm * 64 + (j & 1) * 8 + rr;
    int akSel = j >> 1;
    float C[4][4][4] = {};

    issue(0, 0);
    CP_COMMIT();
    for (int s = 0; s < NS; s++) {
        int st = s & 1;
        if (s + 1 < NS) {
            issue(s + 1, st ^ 1);
            CP_COMMIT();
            CP_WAIT1();
        } else {
            CP_WAIT0();
        }
        __syncthreads();
        uint32_t aH = sbase + st * STG + AHOF, aL = sbase + st * STG + ALOF;
        uint32_t bH = sbase + st * STG + BHOF, bL = sbase + st * STG + BLOF;
#pragma unroll
        for (int kk = 0; kk < 2; kk++) {
            uint32_t bh[4][2], bl[4][2];
#pragma unroll
            for (int f16 = 0; f16 < 2; f16++) {
                int krow = kk * 16 + (j & 1) * 8 + rr;
                int cc = wn * 4 + f16 * 2 + (j >> 1);
                uint32_t o = bswz(krow, cc);
                ldsm4t(bh[f16 * 2][0], bh[f16 * 2][1], bh[f16 * 2 + 1][0], bh[f16 * 2 + 1][1], bH + o);
                if (LO)
                    ldsm4t(bl[f16 * 2][0], bl[f16 * 2][1], bl[f16 * 2 + 1][0], bl[f16 * 2 + 1][1], bL + o);
            }
#pragma unroll
            for (int fm = 0; fm < 4; fm++) {
                int m = amRow + fm * 16;
                int kg = kk * 2 + akSel;
                uint32_t o = (uint32_t)(m * 64 + ((kg ^ ((m >> 1) & 3)) << 4));
                uint32_t ah[4], al[4];
                ldsm4(ah[0], ah[1], ah[2], ah[3], aH + o);
                if (LO) ldsm4(al[0], al[1], al[2], al[3], aL + o);
#pragma unroll
                for (int fn = 0; fn < 4; fn++) {
                    mma16816(C[fm][fn], ah, bh[fn]);
                    if (LO) {
                        mma16816(C[fm][fn], al, bh[fn]);
                        mma16816(C[fm][fn], ah, bl[fn]);
                    }
                }
            }
        }
        __syncthreads();
    }

    int g = lane >> 2, tig = lane & 3;

    __half *qh_out = nullptr, *ql_out = nullptr;
    const float* mbias = nullptr;
    int hcol0 = 0;
    if (MODE == 0) {
        int which = n0 / HH;
        qh_out = (which == 0) ? g_qh : (which == 1) ? g_kh : g_vh;
        ql_out = (which == 0) ? g_ql : (which == 1) ? g_kl : g_vl;
        mbias  = (which == 0) ? p0 : (which == 1) ? p1 : p2;
        hcol0  = n0 - which * HH;
    }

#pragma unroll
    for (int fm = 0; fm < 4; fm++) {
        int rowl0 = wm * 64 + fm * 16 + g;
#pragma unroll
        for (int fn = 0; fn < 4; fn++) {
            int coll = wn * 32 + fn * 8 + tig * 2;
#pragma unroll
            for (int hf = 0; hf < 2; hf++) {
                int ml = rowl0 + hf * 8;
                float c0 = C[fm][fn][hf * 2], c1 = C[fm][fn][hf * 2 + 1];
                if (MODE == 0) {
                    int t = m0 + ml;
                    int hcol = hcol0 + coll;
                    int h = hcol >> 6, d = hcol & 63;
                    int b = t >> 9, sI = t & 511;
                    size_t o = (((size_t)(b * NHH + h)) * SS + sI) * DHH + d;
                    uint32_t lo;
                    uint32_t hi = packsplit(c0 + mbias[hcol], c1 + mbias[hcol + 1], lo);
                    *(uint32_t*)(qh_out + o) = hi;
                    *(uint32_t*)(ql_out + o) = lo;
                } else if (MODE == 1) {
                    size_t t = m0 + ml;
                    int col = n0 + coll;
                    float2 xr = *(const float2*)(p1 + t * HH + col);
                    float2 v = {c0 + p0[col] + xr.x, c1 + p0[col + 1] + xr.y};
                    *(float2*)(g_preln + t * HH + col) = v;
                } else {
                    if (base + ml < end) {
                        int col = n0 + coll;
                        int t = s_tok[ml];
                        float w = s_w[ml];
                        const float* eb = p0 + (size_t)e * HH;
                        atomicAdd(pout + (size_t)t * HH + col,     (c0 + eb[col]) * w);
                        atomicAdd(pout + (size_t)t * HH + col + 1, (c1 + eb[col + 1]) * w);
                    }
                }
            }
        }
    }
}

// ============ fused up+gate pipelined HMMA grouped GEMM (1-term fp16) ========
// h[r, i] = gelu(xl@Wu + bu) * (xl@Wn + bn) -> g_hh (fp16)
#define UPG_SMEM (2 * 24576)
__global__ void __launch_bounds__(256, 1) ffn_upgate(
    const float* __restrict__ bu_, const float* __restrict__ bn_) {
    int e = blockIdx.y / 24;
    int n0 = (blockIdx.y % 24) * 128;
    int base = g_off[e] + blockIdx.x * 128;
    int end  = g_off[e] + g_cnt[e];
    if (base >= end) return;

    extern __shared__ char dyn[];
    __shared__ int s_tok[128];

    int tid = threadIdx.x, lane = tid & 31, wid = tid >> 5;
    int wm = wid & 1, wn = wid >> 1;

    if (tid < 128) s_tok[tid] = g_etok[min(base + tid, end - 1)];
    __syncthreads();

    const __half* Buh = g_wuh + (size_t)e * HH * II;
    const __half* Bnh = g_wnh + (size_t)e * HH * II;
    uint32_t sbase = smem_u32(dyn);

    auto issue = [&](int slab, int st) {
        int k0 = slab * 32;
        uint32_t sb = sbase + st * 24576;
#pragma unroll
        for (int i = 0; i < 2; i++) {
            int c = tid + i * 256;
            {
                int m = c >> 2, kc = c & 3;
                uint32_t so = sb + swoff(m, kc);
                size_t aoff = (size_t)s_tok[m] * HH + k0 + kc * 8;
                cpasync16(so, g_xlh + aoff);
            }
            {
                int k = c >> 4, cb = c & 15;
                uint32_t bo = sb + 8192 + bswz(k, cb);
                size_t go = (size_t)(k0 + k) * II + n0 + cb * 8;
                cpasync16(bo,        Buh + go);
                cpasync16(bo + 8192, Bnh + go);
            }
        }
    };

    int j = lane >> 3, rr = lane & 7;
    int amRow = wm * 64 + (j & 1) * 8 + rr;
    int akSel = j >> 1;
    float Cu[4][4][4] = {}, Cn[4][4][4] = {};

    issue(0, 0);
    CP_COMMIT();
    for (int s = 0; s < HH / 32; s++) {
        int st = s & 1;
        if (s + 1 < HH / 32) {
            issue(s + 1, st ^ 1);
            CP_COMMIT();
            CP_WAIT1();
        } else {
            CP_WAIT0();
        }
        __syncthreads();
        uint32_t aH = sbase + st * 24576;
        uint32_t uH = aH + 8192, nH = aH + 16384;
#pragma unroll
        for (int kk = 0; kk < 2; kk++) {
            uint32_t buh[4][2], bnh[4][2];
#pragma unroll
            for (int f16 = 0; f16 < 2; f16++) {
                int krow = kk * 16 + (j & 1) * 8 + rr;
                int cc = wn * 4 + f16 * 2 + (j >> 1);
                uint32_t o = bswz(krow, cc);
                ldsm4t(buh[f16 * 2][0], buh[f16 * 2][1], buh[f16 * 2 + 1][0], buh[f16 * 2 + 1][1], uH + o);
                ldsm4t(bnh[f16 * 2][0], bnh[f16 * 2][1], bnh[f16 * 2 + 1][0], bnh[f16 * 2 + 1][1], nH + o);
            }
#pragma unroll
            for (int fm = 0; fm < 4; fm++) {
                int m = amRow + fm * 16;
                int kg = kk * 2 + akSel;
                uint32_t o = (uint32_t)(m * 64 + ((kg ^ ((m >> 1) & 3)) << 4));
                uint32_t ah[4];
                ldsm4(ah[0], ah[1], ah[2], ah[3], aH + o);
#pragma unroll
                for (int fn = 0; fn < 4; fn++) {
                    mma16816(Cu[fm][fn], ah, buh[fn]);
                    mma16816(Cn[fm][fn], ah, bnh[fn]);
                }
            }
        }
        __syncthreads();
    }

    int g = lane >> 2, tig = lane & 3;
    const float* bu = bu_ + (size_t)e * II;
    const float* bn = bn_ + (size_t)e * II;
#pragma unroll
    for (int fm = 0; fm < 4; fm++) {
        int rowl0 = wm * 64 + fm * 16 + g;
#pragma unroll
        for (int fn = 0; fn < 4; fn++) {
            int col = n0 + wn * 32 + fn * 8 + tig * 2;
            float bu0 = bu[col], bu1 = bu[col + 1];
            float bn0 = bn[col], bn1 = bn[col + 1];
#pragma unroll
            for (int hf = 0; hf < 2; hf++) {
                int r = base + rowl0 + hf * 8;
                if (r < end) {
                    float u0 = Cu[fm][fn][hf * 2] + bu0, u1 = Cu[fm][fn][hf * 2 + 1] + bu1;
                    float h0 = u0 * normcdff(u0) * (Cn[fm][fn][hf * 2] + bn0);
                    float h1 = u1 * normcdff(u1) * (Cn[fm][fn][hf * 2 + 1] + bn1);
                    __half2 hv = __halves2half2(__float2half_rn(h0), __float2half_rn(h1));
                    *(uint32_t*)(g_hh + (size_t)r * II + col) = *(uint32_t*)&hv;
                }
            }
        }
    }
}

// ================= flash attention (fp16x3 HMMA, online softmax) =============
#define FL_SMEM (32768 + 2 * 65536)
__global__ void __launch_bounds__(256, 1) flash_attn() {
    int q0 = blockIdx.x * 128;
    int head = blockIdx.y;
    int b = head / NHH, h_ = head % NHH;

    extern __shared__ char dyn[];
    uint32_t sb = smem_u32(dyn);
    const uint32_t QH = 0, QL = 16384;

    const __half* Qh = g_qh + (size_t)head * SS * DHH;
    const __half* Ql = g_ql + (size_t)head * SS * DHH;
    const __half* Kh = g_kh + (size_t)head * SS * DHH;
    const __half* Kl = g_kl + (size_t)head * SS * DHH;
    const __half* Vh = g_vh + (size_t)head * SS * DHH;
    const __half* Vl = g_vl + (size_t)head * SS * DHH;

    int tid = threadIdx.x, lane = tid & 31, wid = tid >> 5;
    int j = lane >> 3, rr = lane & 7;
    int g = lane >> 2, tig = lane & 3;

    auto load_tile = [&](uint32_t dst, const __half* src, int row0) {
#pragma unroll
        for (int i = 0; i < 4; i++) {
            int idx = tid + i * 256;
            int m = idx >> 3, c = idx & 7;
            cpasync16(sb + dst + fswz(m, c), src + (size_t)(row0 + m) * DHH + c * 8);
        }
    };

    load_tile(QH, Qh, q0);
    load_tile(QL, Ql, q0);
    load_tile(32768, Kh, 0);
    load_tile(32768 + 16384, Kl, 0);
    load_tile(32768 + 32768, Vh, 0);
    load_tile(32768 + 49152, Vl, 0);
    CP_COMMIT();

    float O[8][4] = {};
    float rm0 = -1e30f, rm1 = -1e30f, l0 = 0.0f, l1 = 0.0f;

    for (int kt = 0; kt < 4; kt++) {
        int st = kt & 1;
        if (kt + 1 < 4) {
            uint32_t nb = 32768 + (st ^ 1) * 65536;
            load_tile(nb,         Kh, (kt + 1) * 128);
            load_tile(nb + 16384, Kl, (kt + 1) * 128);
            load_tile(nb + 32768, Vh, (kt + 1) * 128);
            load_tile(nb + 49152, Vl, (kt + 1) * 128);
            CP_COMMIT();
            CP_WAIT1();
        } else {
            CP_WAIT0();
        }
        __syncthreads();

        uint32_t kH = sb + 32768 + st * 65536, kL = kH + 16384;
        uint32_t vH = kH + 32768, vL = kH + 49152;
        uint32_t qHb = sb + QH, qLb = sb + QL;

        float S[16][4] = {};
#pragma unroll
        for (int ks = 0; ks < 4; ks++) {
            int am = wid * 16 + (j & 1) * 8 + rr;
            int ac = 2 * ks + (j >> 1);
            uint32_t ah[4], al[4];
            ldsm4(ah[0], ah[1], ah[2], ah[3], qHb + fswz(am, ac));
            ldsm4(al[0], al[1], al[2], al[3], qLb + fswz(am, ac));
#pragma unroll
            for (int fnp = 0; fnp < 8; fnp++) {
                int bn = fnp * 16 + (j >> 1) * 8 + rr;
                int bc = 2 * ks + (j & 1);
                uint32_t bo = fswz(bn, bc);
                uint32_t bh[4], bl[4];
                ldsm4(bh[0], bh[1], bh[2], bh[3], kH + bo);
                ldsm4(bl[0], bl[1], bl[2], bl[3], kL + bo);
                mma16816(S[2 * fnp],     ah, bh);
                mma16816(S[2 * fnp],     ah, bl);
                mma16816(S[2 * fnp],     al, bh);
                mma16816(S[2 * fnp + 1], ah, bh + 2);
                mma16816(S[2 * fnp + 1], ah, bl + 2);
                mma16816(S[2 * fnp + 1], al, bh + 2);
            }
        }

        float mx0 = -1e30f, mx1 = -1e30f;
#pragma unroll
        for (int fn = 0; fn < 16; fn++) {
            mx0 = fmaxf(mx0, fmaxf(S[fn][0], S[fn][1]));
            mx1 = fmaxf(mx1, fmaxf(S[fn][2], S[fn][3]));
        }
        mx0 = fmaxf(mx0, __shfl_xor_sync(~0u, mx0, 1));
        mx0 = fmaxf(mx0, __shfl_xor_sync(~0u, mx0, 2));
        mx1 = fmaxf(mx1, __shfl_xor_sync(~0u, mx1, 1));
        mx1 = fmaxf(mx1, __shfl_xor_sync(~0u, mx1, 2));
        float nm0 = fmaxf(rm0, mx0 * 0.125f);
        float nm1 = fmaxf(rm1, mx1 * 0.125f);
        float al0 = __expf(rm0 - nm0);
        float al1 = __expf(rm1 - nm1);
        rm0 = nm0; rm1 = nm1;
        float sum0 = 0.0f, sum1 = 0.0f;
#pragma unroll
        for (int fn = 0; fn < 16; fn++) {
            float p0 = __expf(fmaf(S[fn][0], 0.125f, -nm0));
            float p1 = __expf(fmaf(S[fn][1], 0.125f, -nm0));
            float p2 = __expf(fmaf(S[fn][2], 0.125f, -nm1));
            float p3 = __expf(fmaf(S[fn][3], 0.125f, -nm1));
            S[fn][0] = p0; S[fn][1] = p1; S[fn][2] = p2; S[fn][3] = p3;
            sum0 += p0 + p1; sum1 += p2 + p3;
        }
        sum0 += __shfl_xor_sync(~0u, sum0, 1);
        sum0 += __shfl_xor_sync(~0u, sum0, 2);
        sum1 += __shfl_xor_sync(~0u, sum1, 1);
        sum1 += __shfl_xor_sync(~0u, sum1, 2);
        l0 = l0 * al0 + sum0;
        l1 = l1 * al1 + sum1;
#pragma unroll
        for (int fo = 0; fo < 8; fo++) {
            O[fo][0] *= al0; O[fo][1] *= al0;
            O[fo][2] *= al1; O[fo][3] *= al1;
        }

#pragma unroll
        for (int kp = 0; kp < 8; kp++) {
            uint32_t aph[4], apl[4];
            aph[0] = packsplit(S[2 * kp][0],     S[2 * kp][1],     apl[0]);
            aph[1] = packsplit(S[2 * kp][2],     S[2 * kp][3],     apl[1]);
            aph[2] = packsplit(S[2 * kp + 1][0], S[2 * kp + 1][1], apl[2]);
            aph[3] = packsplit(S[2 * kp + 1][2], S[2 * kp + 1][3], apl[3]);
#pragma unroll
            for (int dg = 0; dg < 4; dg++) {
                int vrow = kp * 16 + (j & 1) * 8 + rr;
                int vc = dg * 2 + (j >> 1);
                uint32_t vo = fswz(vrow, vc);
                uint32_t vh[4], vl[4];
                ldsm4t(vh[0], vh[1], vh[2], vh[3], vH + vo);
                ldsm4t(vl[0], vl[1], vl[2], vl[3], vL + vo);
#pragma unroll
                for (int hg = 0; hg < 2; hg++) {
                    int fo = dg * 2 + hg;
                    mma16816(O[fo], aph, vh + hg * 2);
                    mma16816(O[fo], apl, vh + hg * 2);
                    mma16816(O[fo], aph, vl + hg * 2);
                }
            }
        }
        __syncthreads();
    }

    float inv0 = 1.0f / l0, inv1 = 1.0f / l1;
    int qr0 = q0 + wid * 16 + g;
    size_t t0 = (size_t)b * SS + qr0;
    size_t t1 = t0 + 8;
#pragma unroll
    for (int fo = 0; fo < 8; fo++) {
        int d = fo * 8 + tig * 2;
        int col = h_ * 64 + d;
        uint32_t lo;
        uint32_t hi = packsplit(O[fo][0] * inv0, O[fo][1] * inv0, lo);
        *(uint32_t*)(g_ch + t0 * HH + col) = hi;
        *(uint32_t*)(g_cl + t0 * HH + col) = lo;
        hi = packsplit(O[fo][2] * inv1, O[fo][3] * inv1, lo);
        *(uint32_t*)(g_ch + t1 * HH + col) = hi;
        *(uint32_t*)(g_cl + t1 * HH + col) = lo;
    }
}

// ================= LayerNorm ==================================================
__global__ void ln_kernel(const float* __restrict__ gamma, const float* __restrict__ beta,
                          float* __restrict__ dout, int mode) {
    size_t row = blockIdx.x;
    const float* in = (mode == 0) ? (g_preln + row * HH) : (g_attnout + row * HH);
    int tid = threadIdx.x;
    float x0 = in[tid], x1 = in[tid + 256], x2 = in[tid + 512];

    __shared__ float red[256];
    red[tid] = x0 + x1 + x2;
    __syncthreads();
    for (int s = 128; s > 0; s >>= 1) {
        if (tid < s) red[tid] += red[tid + s];
        __syncthreads();
    }
    float mean = red[0] * (1.0f / HH);
    __syncthreads();

    float c0 = x0 - mean, c1 = x1 - mean, c2 = x2 - mean;
    red[tid] = c0 * c0 + c1 * c1 + c2 * c2;
    __syncthreads();
    for (int s = 128; s > 0; s >>= 1) {
        if (tid < s) red[tid] += red[tid + s];
        __syncthreads();
    }
    float inv = 1.0f / sqrtf(red[0] * (1.0f / HH) + 1e-12f);

    float y0 = c0 * inv * gamma[tid]       + beta[tid];
    float y1 = c1 * inv * gamma[tid + 256] + beta[tid + 256];
    float y2 = c2 * inv * gamma[tid + 512] + beta[tid + 512];
    if (mode == 0) {
        g_attnout[row * HH + tid]       = y0;
        g_attnout[row * HH + tid + 256] = y1;
        g_attnout[row * HH + tid + 512] = y2;
        dout[row * HH + tid]       = y0;
        dout[row * HH + tid + 256] = y1;
        dout[row * HH + tid + 512] = y2;
    } else {
        g_xl[row * HH + tid]       = y0;
        g_xl[row * HH + tid + 256] = y1;
        g_xl[row * HH + tid + 512] = y2;
        g_xlh[row * HH + tid]       = __float2half_rn(y0);
        g_xlh[row * HH + tid + 256] = __float2half_rn(y1);
        g_xlh[row * HH + tid + 512] = __float2half_rn(y2);
    }
}

// ================= counters / router / scatter ===============================
__global__ void init_kernel() {
    int i = threadIdx.x;
    if (i < EE) { g_cnt[i] = 0; g_cur[i] = 0; }
}

__global__ void router_kernel(const float* __restrict__ Wr, const float* __restrict__ br,
                              float* __restrict__ logits_out) {
    int warp = threadIdx.x >> 5, lane = threadIdx.x & 31;
    int t = blockIdx.x * 8 + warp;
    const float* x = g_xl + (size_t)t * HH;

    float acc[EE] = {};
    for (int h = lane; h < HH; h += 32) {
        float xv = x[h];
        const float* w = Wr + (size_t)h * EE;
#pragma unroll
        for (int e = 0; e < EE; e++) acc[e] = fmaf(xv, w[e], acc[e]);
    }
#pragma unroll
    for (int e = 0; e < EE; e++)
        for (int o = 16; o > 0; o >>= 1) acc[e] += __shfl_down_sync(0xffffffffu, acc[e], o);

    if (lane == 0) {
        float lg[EE], mx = -1e30f;
#pragma unroll
        for (int e = 0; e < EE; e++) {
            lg[e] = acc[e] + br[e];
            logits_out[(size_t)t * EE + e] = lg[e];
            mx = fmaxf(mx, lg[e]);
        }
        float p[EE], s = 0.0f;
#pragma unroll
        for (int e = 0; e < EE; e++) { p[e] = expf(lg[e] - mx); s += p[e]; }
        float invs = 1.0f / s;
#pragma unroll
        for (int e = 0; e < EE; e++) p[e] *= invs;

        int i1 = 0;
#pragma unroll
        for (int e = 1; e < EE; e++) if (p[e] > p[i1]) i1 = e;
        int i2 = (i1 == 0) ? 1 : 0;
#pragma unroll
        for (int e = 0; e < EE; e++) if (e != i1 && p[e] > p[i2]) i2 = e;

        float w1 = p[i1], w2 = p[i2], inv = 1.0f / (w1 + w2);
        g_ti[t * 2]     = i1;  g_tw[t * 2]     = w1 * inv;
        g_ti[t * 2 + 1] = i2;  g_tw[t * 2 + 1] = w2 * inv;
        atomicAdd(&g_cnt[i1], 1);
        atomicAdd(&g_cnt[i2], 1);
    }
}

__global__ void offsets_kernel() {
    if (threadIdx.x == 0) {
        int o = 0;
        for (int e = 0; e < EE; e++) { g_off[e] = o; o += g_cnt[e]; }
    }
}

__global__ void scatter_kernel() {
    int t = blockIdx.x * 256 + threadIdx.x;
    if (t >= TT) return;
#pragma unroll
    for (int s = 0; s < 2; s++) {
        int e = g_ti[t * 2 + s];
        int pos = atomicAdd(&g_cur[e], 1);
        int r = g_off[e] + pos;
        g_etok[r] = t;
        g_ew[r] = g_tw[t * 2 + s];
    }
}

// ================= host launcher =============================================
#define HG_SMEM 65536
#define DWN_SMEM 32768

extern "C" void kernel_launch(void* const* d_in, const int* in_sizes, int n_in,
                              void* d_out, int out_size) {
    const float* X        = (const float*)d_in[0];
    const float* Wq       = (const float*)d_in[1];
    const float* bq       = (const float*)d_in[2];
    const float* Wk       = (const float*)d_in[3];
    const float* bk       = (const float*)d_in[4];
    const float* Wv       = (const float*)d_in[5];
    const float* bv       = (const float*)d_in[6];
    const float* Wo       = (const float*)d_in[7];
    const float* bo       = (const float*)d_in[8];
    const float* ln_ag    = (const float*)d_in[9];
    const float* ln_ab    = (const float*)d_in[10];
    const float* ln_fg    = (const float*)d_in[11];
    const float* ln_fb    = (const float*)d_in[12];
    const float* Wr       = (const float*)d_in[13];
    const float* br       = (const float*)d_in[14];
    const float* W_up     = (const float*)d_in[15];
    const float* b_up     = (const float*)d_in[16];
    const float* W_new    = (const float*)d_in[17];
    const float* b_new    = (const float*)d_in[18];
    const float* W_down   = (const float*)d_in[19];
    const float* b_down   = (const float*)d_in[20];

    float* out    = (float*)d_out;                    // layer_output [T, H]
    float* logits = out + (size_t)TT * HH;            // router_logits [T, E]

    static cudaStream_t s1;
    static cudaEvent_t evFork, evQKVW, evFFNW;
    static int once = 0;
    if (!once) {
        cudaFuncSetAttribute(hgemm<0>, cudaFuncAttributeMaxDynamicSharedMemorySize, HG_SMEM);
        cudaFuncSetAttribute(hgemm<1>, cudaFuncAttributeMaxDynamicSharedMemorySize, HG_SMEM);
        cudaFuncSetAttribute(hgemm<2>, cudaFuncAttributeMaxDynamicSharedMemorySize, DWN_SMEM);
        cudaFuncSetAttribute(ffn_upgate, cudaFuncAttributeMaxDynamicSharedMemorySize, UPG_SMEM);
        cudaFuncSetAttribute(flash_attn, cudaFuncAttributeMaxDynamicSharedMemorySize, FL_SMEM);
        cudaStreamCreateWithFlags(&s1, cudaStreamNonBlocking);
        cudaEventCreateWithFlags(&evFork, cudaEventDisableTiming);
        cudaEventCreateWithFlags(&evQKVW, cudaEventDisableTiming);
        cudaEventCreateWithFlags(&evFFNW, cudaEventDisableTiming);
        once = 1;
    }

    __half *wqkvh, *wqkvl, *woh, *wol, *wuh, *wnh, *wdh, *xsh, *xsl;
    cudaGetSymbolAddress((void**)&wqkvh, g_wqkvh);
    cudaGetSymbolAddress((void**)&wqkvl, g_wqkvl);
    cudaGetSymbolAddress((void**)&woh, g_woh);
    cudaGetSymbolAddress((void**)&wol, g_wol);
    cudaGetSymbolAddress((void**)&wuh, g_wuh);
    cudaGetSymbolAddress((void**)&wnh, g_wnh);
    cudaGetSymbolAddress((void**)&wdh, g_wdh);
    cudaGetSymbolAddress((void**)&xsh, g_xsh);
    cudaGetSymbolAddress((void**)&xsl, g_xsl);

    // ---- fork side stream for weight prep ----
    cudaEventRecord(evFork, 0);
    cudaStreamWaitEvent(s1, evFork, 0);

    fsplit<<<HH * HH / 1024, 256, 0, s1>>>(Wq, wqkvh,               wqkvl);
    fsplit<<<HH * HH / 1024, 256, 0, s1>>>(Wk, wqkvh + HH * HH,     wqkvl + HH * HH);
    fsplit<<<HH * HH / 1024, 256, 0, s1>>>(Wv, wqkvh + 2 * HH * HH, wqkvl + 2 * HH * HH);
    fsplit<<<HH * HH / 1024, 256, 0, s1>>>(Wo, woh, wol);
    cudaEventRecord(evQKVW, s1);
    fconv<<<EE * HH * II / 1024, 256, 0, s1>>>(W_up,  wuh);
    fconv<<<EE * HH * II / 1024, 256, 0, s1>>>(W_new, wnh);
    fconv<<<EE * II * HH / 1024, 256, 0, s1>>>(W_down, wdh);
    cudaEventRecord(evFFNW, s1);

    // ---- main stream: activation prep + attention chain ----
    init_kernel<<<1, 32>>>();
    fsplit<<<TT * HH / 1024, 256>>>(X, xsh, xsl);

    cudaStreamWaitEvent(0, evQKVW, 0);
    hgemm<0><<<dim3(3 * HH / 128, TT / 128), 256, HG_SMEM>>>(bq, bk, bv, nullptr);
    flash_attn<<<dim3(SS / 128, BB * NHH), 256, FL_SMEM>>>();
    hgemm<1><<<dim3(HH / 128, TT / 128), 256, HG_SMEM>>>(bo, X, nullptr, nullptr);

    ln_kernel<<<TT, 256>>>(ln_ag, ln_ab, out, 0);
    ln_kernel<<<TT, 256>>>(ln_fg, ln_fb, out, 1);
    router_kernel<<<TT / 8, 256>>>(Wr, br, logits);
    offsets_kernel<<<1, 32>>>();
    scatter_kernel<<<(TT + 255) / 256, 256>>>();

    // ---- join: FFN weights ready before the MoE GEMMs ----
    cudaStreamWaitEvent(0, evFFNW, 0);
    ffn_upgate<<<dim3(32, EE * 24), 256, UPG_SMEM>>>(b_up, b_new);
    hgemm<2><<<dim3(32, EE * 6), 256, DWN_SMEM>>>(b_down, nullptr, nullptr, out);
}

// round 11
// speedup vs baseline: 5.2123x; 1.0694x over previous
#include <cuda_runtime.h>
#include <cuda_fp16.h>
#include <math.h>
#include <stdint.h>

#define TT  4096   // B*S
#define HH  768
#define SS  512
#define BB  8
#define NHH 12
#define DHH 64
#define II  3072
#define EE  8
#define ENT 8192   // TT * TOPK

// ---------------- scratch (static device allocations; no cudaMalloc) --------
__device__ float g_preln[TT * HH];
__device__ float g_attnout[TT * HH];
__device__ float g_xl[TT * HH];
__device__ __half g_xlh[TT * HH];           // xl fp16 (FFN A operand)
__device__ __half g_xsh[TT * HH];           // X split (QKV A operand, exact)
__device__ __half g_xsl[TT * HH];
__device__ __half g_qh[TT * HH];            // Q split, [B*NH][S][DH]
__device__ __half g_ql[TT * HH];
__device__ __half g_kh[TT * HH];            // K fp16
__device__ __half g_vh[TT * HH];            // V fp16
__device__ __half g_ch[TT * HH];            // ctx split [T][H] (proj A, exact)
__device__ __half g_cl[TT * HH];
__device__ __half g_hh[(size_t)ENT * II];   // FFN hidden h = gelu(u)*gate, fp16
__device__ __half g_wqkvh[3 * HH * HH];     // [Wq;Wk;Wv] fp16, each [768 k][768 n]
__device__ __half g_woh[HH * HH];           // Wo fp16 [768 k][768 n]
__device__ __half g_wuh[(size_t)EE * HH * II];  // W_up  fp16 [E][H k][I n]
__device__ __half g_wnh[(size_t)EE * HH * II];  // W_new fp16
__device__ __half g_wdh[(size_t)EE * II * HH];  // W_down fp16 [E][I k][H n]
__device__ int   g_cnt[EE];
__device__ int   g_off[EE];
__device__ int   g_cur[EE];
__device__ int   g_etok[ENT];
__device__ float g_ew[ENT];
__device__ int   g_ti[TT * 2];
__device__ float g_tw[TT * 2];

// ======================= asm helpers (portable sm_80+) =======================
__device__ __forceinline__ uint32_t smem_u32(const void* p) {
    uint32_t a;
    asm("{ .reg .u64 t; cvta.to.shared.u64 t, %1; cvt.u32.u64 %0, t; }" : "=r"(a) : "l"(p));
    return a;
}
__device__ __forceinline__ void ldsm4(uint32_t& r0, uint32_t& r1, uint32_t& r2, uint32_t& r3,
                                      uint32_t addr) {
    asm volatile("ldmatrix.sync.aligned.m8n8.x4.shared.b16 {%0,%1,%2,%3}, [%4];"
                 : "=r"(r0), "=r"(r1), "=r"(r2), "=r"(r3) : "r"(addr));
}
__device__ __forceinline__ void ldsm4t(uint32_t& r0, uint32_t& r1, uint32_t& r2, uint32_t& r3,
                                       uint32_t addr) {
    asm volatile("ldmatrix.sync.aligned.m8n8.x4.trans.shared.b16 {%0,%1,%2,%3}, [%4];"
                 : "=r"(r0), "=r"(r1), "=r"(r2), "=r"(r3) : "r"(addr));
}
__device__ __forceinline__ void mma16816(float* c, const uint32_t* a, const uint32_t* b) {
    asm volatile(
        "mma.sync.aligned.m16n8k16.row.col.f32.f16.f16.f32 "
        "{%0,%1,%2,%3}, {%4,%5,%6,%7}, {%8,%9}, {%0,%1,%2,%3};"
        : "+f"(c[0]), "+f"(c[1]), "+f"(c[2]), "+f"(c[3])
        : "r"(a[0]), "r"(a[1]), "r"(a[2]), "r"(a[3]), "r"(b[0]), "r"(b[1]));
}
__device__ __forceinline__ void cpasync16(uint32_t saddr, const void* gaddr) {
    asm volatile("cp.async.cg.shared.global [%0], [%1], 16;" :: "r"(saddr), "l"(gaddr));
}
#define CP_COMMIT() asm volatile("cp.async.commit_group;" ::: "memory")
#define CP_WAIT1()  asm volatile("cp.async.wait_group 1;" ::: "memory")
#define CP_WAIT0()  asm volatile("cp.async.wait_group 0;" ::: "memory")

// xor-swizzled smem byte offset for a [rows x 32 halves] tile (row = 64B)
__device__ __forceinline__ uint32_t swoff(int m, int kg) {
    return (uint32_t)(m * 64 + ((kg ^ ((m >> 1) & 3)) << 4));
}
// xor-swizzled smem byte offset for a [rows x 64 halves] tile (row = 128B, 8 chunks)
__device__ __forceinline__ uint32_t fswz(int m, int c) {
    return (uint32_t)(m * 128 + ((c ^ (m & 7)) << 4));
}
// xor-swizzled smem byte offset for a [32 k x 128 halves] B tile (row = 256B, 16 chunks)
__device__ __forceinline__ uint32_t bswz(int k, int c) {
    return (uint32_t)(k * 256 + ((c ^ (k & 7)) << 4));
}
__device__ __forceinline__ uint32_t packsplit(float v0, float v1, uint32_t& lo) {
    __half h0 = __float2half_rn(v0), h1 = __float2half_rn(v1);
    __half2 l = __halves2half2(__float2half_rn(v0 - __half2float(h0)),
                               __float2half_rn(v1 - __half2float(h1)));
    lo = *(uint32_t*)&l;
    __half2 h = __halves2half2(h0, h1);
    return *(uint32_t*)&h;
}
__device__ __forceinline__ uint32_t pack2(float v0, float v1) {
    __half2 h = __halves2half2(__float2half_rn(v0), __float2half_rn(v1));
    return *(uint32_t*)&h;
}

// ============ elementwise fp32 -> fp16 hi/lo split (pure streaming) ==========
__global__ void fsplit(const float* __restrict__ src, __half* __restrict__ h,
                       __half* __restrict__ l) {
    size_t i = ((size_t)blockIdx.x * 256 + threadIdx.x) * 4;
    float4 v = *(const float4*)(src + i);
    uint32_t lo0, lo1;
    uint32_t h0 = packsplit(v.x, v.y, lo0);
    uint32_t h1 = packsplit(v.z, v.w, lo1);
    *(uint32_t*)(h + i)     = h0;
    *(uint32_t*)(h + i + 2) = h1;
    *(uint32_t*)(l + i)     = lo0;
    *(uint32_t*)(l + i + 2) = lo1;
}

// ============ elementwise fp32 -> fp16 convert (weights, no lo) ==============
__global__ void fconv(const float* __restrict__ src, __half* __restrict__ h) {
    size_t i = ((size_t)blockIdx.x * 256 + threadIdx.x) * 4;
    float4 v = *(const float4*)(src + i);
    *(uint32_t*)(h + i)     = pack2(v.x, v.y);
    *(uint32_t*)(h + i + 2) = pack2(v.z, v.w);
}

// ================= unified fp16 pipelined HMMA GEMM ==========================
// B operand is [K][N] row-major fp16, loaded via ldsm4t.
// MODE 0: QKV  (2-term: A hi/lo) -> Q split hi/lo, K/V fp16
// MODE 1: PROJ (2-term: A hi/lo) -> g_preln (+bo+X)
// MODE 2: DOWN (1-term)          -> atomicAdd out
template<int MODE>
__global__ void __launch_bounds__(256, 2) hgemm(
    const float* __restrict__ p0, const float* __restrict__ p1,
    const float* __restrict__ p2, float* __restrict__ pout) {

    constexpr int KD = (MODE == 2) ? II : HH;   // A K-dim
    constexpr int NS = KD / 32;
    constexpr bool ALO = (MODE != 2);
    constexpr uint32_t AHOF = 0;
    constexpr uint32_t ALOF = 8192;
    constexpr uint32_t BHOF = ALO ? 16384 : 8192;
    constexpr uint32_t STG  = ALO ? 24576 : 16384;

    int e = 0, base = 0, end = 0, m0 = 0, n0;
    if (MODE == 2) {
        e = blockIdx.y / 6;
        n0 = (blockIdx.y % 6) * 128;
        base = g_off[e] + blockIdx.x * 128;
        end  = g_off[e] + g_cnt[e];
        if (base >= end) return;
    } else {
        m0 = blockIdx.y * 128;
        n0 = blockIdx.x * 128;
    }

    extern __shared__ char dyn[];
    __shared__ int   s_tok[128];
    __shared__ float s_w[128];

    int tid = threadIdx.x, lane = tid & 31, wid = tid >> 5;
    int wm = wid & 1, wn = wid >> 1;

    if (MODE == 2 && tid < 128) {
        int r = min(base + tid, end - 1);
        s_tok[tid] = g_etok[r];
        s_w[tid]   = g_ew[r];
    }
    __syncthreads();

    const __half *Bh, *Ah, *Al = nullptr;
    int nb;
    if (MODE == 0) {
        int which = n0 / HH;
        Bh = g_wqkvh + (size_t)which * HH * HH;
        Ah = g_xsh; Al = g_xsl;
        nb = n0 - which * HH;
    } else if (MODE == 1) {
        Bh = g_woh; Ah = g_ch; Al = g_cl; nb = n0;
    } else {
        Bh = g_wdh + (size_t)e * II * HH;
        Ah = g_hh;  nb = n0;
    }

    uint32_t sbase = smem_u32(dyn);

    auto issue = [&](int slab, int st) {
        int k0 = slab * 32;
        uint32_t sb = sbase + st * STG;
#pragma unroll
        for (int i = 0; i < 2; i++) {
            int c = tid + i * 256;
            {
                int m = c >> 2, kc = c & 3;
                uint32_t so = sb + swoff(m, kc);
                int koff = k0 + kc * 8;
                size_t aoff;
                if (MODE < 2) aoff = (size_t)(m0 + m) * KD;
                else          aoff = (size_t)min(base + m, end - 1) * KD;
                cpasync16(so + AHOF, Ah + aoff + koff);
                if (ALO) cpasync16(so + ALOF, Al + aoff + koff);
            }
            {
                int k = c >> 4, cb = c & 15;
                uint32_t bo = sb + bswz(k, cb);
                size_t go = (size_t)(k0 + k) * HH + nb + cb * 8;
                cpasync16(bo + BHOF, Bh + go);
            }
        }
    };

    int j = lane >> 3, rr = lane & 7;
    int amRow = wm * 64 + (j & 1) * 8 + rr;
    int akSel = j >> 1;
    float C[4][4][4] = {};

    issue(0, 0);
    CP_COMMIT();
    for (int s = 0; s < NS; s++) {
        int st = s & 1;
        if (s + 1 < NS) {
            issue(s + 1, st ^ 1);
            CP_COMMIT();
            CP_WAIT1();
        } else {
            CP_WAIT0();
        }
        __syncthreads();
        uint32_t aH = sbase + st * STG + AHOF, aL = sbase + st * STG + ALOF;
        uint32_t bH = sbase + st * STG + BHOF;
#pragma unroll
        for (int kk = 0; kk < 2; kk++) {
            uint32_t bh[4][2];
#pragma unroll
            for (int f16 = 0; f16 < 2; f16++) {
                int krow = kk * 16 + (j & 1) * 8 + rr;
                int cc = wn * 4 + f16 * 2 + (j >> 1);
                uint32_t o = bswz(krow, cc);
                ldsm4t(bh[f16 * 2][0], bh[f16 * 2][1], bh[f16 * 2 + 1][0], bh[f16 * 2 + 1][1], bH + o);
            }
#pragma unroll
            for (int fm = 0; fm < 4; fm++) {
                int m = amRow + fm * 16;
                int kg = kk * 2 + akSel;
                uint32_t o = (uint32_t)(m * 64 + ((kg ^ ((m >> 1) & 3)) << 4));
                uint32_t ah[4], al[4];
                ldsm4(ah[0], ah[1], ah[2], ah[3], aH + o);
                if (ALO) ldsm4(al[0], al[1], al[2], al[3], aL + o);
#pragma unroll
                for (int fn = 0; fn < 4; fn++) {
                    mma16816(C[fm][fn], ah, bh[fn]);
                    if (ALO) mma16816(C[fm][fn], al, bh[fn]);
                }
            }
        }
        __syncthreads();
    }

    int g = lane >> 2, tig = lane & 3;

    __half *qh_out = nullptr, *ql_out = nullptr;
    const float* mbias = nullptr;
    int hcol0 = 0, which = 0;
    if (MODE == 0) {
        which = n0 / HH;
        qh_out = (which == 0) ? g_qh : (which == 1) ? g_kh : g_vh;
        ql_out = g_ql;   // only used when which==0
        mbias  = (which == 0) ? p0 : (which == 1) ? p1 : p2;
        hcol0  = n0 - which * HH;
    }

#pragma unroll
    for (int fm = 0; fm < 4; fm++) {
        int rowl0 = wm * 64 + fm * 16 + g;
#pragma unroll
        for (int fn = 0; fn < 4; fn++) {
            int coll = wn * 32 + fn * 8 + tig * 2;
#pragma unroll
            for (int hf = 0; hf < 2; hf++) {
                int ml = rowl0 + hf * 8;
                float c0 = C[fm][fn][hf * 2], c1 = C[fm][fn][hf * 2 + 1];
                if (MODE == 0) {
                    int t = m0 + ml;
                    int hcol = hcol0 + coll;
                    int h = hcol >> 6, d = hcol & 63;
                    int b = t >> 9, sI = t & 511;
                    size_t o = (((size_t)(b * NHH + h)) * SS + sI) * DHH + d;
                    float v0 = c0 + mbias[hcol], v1 = c1 + mbias[hcol + 1];
                    if (which == 0) {
                        uint32_t lo;
                        uint32_t hi = packsplit(v0, v1, lo);
                        *(uint32_t*)(qh_out + o) = hi;
                        *(uint32_t*)(ql_out + o) = lo;
                    } else {
                        *(uint32_t*)(qh_out + o) = pack2(v0, v1);
                    }
                } else if (MODE == 1) {
                    size_t t = m0 + ml;
                    int col = n0 + coll;
                    float2 xr = *(const float2*)(p1 + t * HH + col);
                    float2 v = {c0 + p0[col] + xr.x, c1 + p0[col + 1] + xr.y};
                    *(float2*)(g_preln + t * HH + col) = v;
                } else {
                    if (base + ml < end) {
                        int col = n0 + coll;
                        int t = s_tok[ml];
                        float w = s_w[ml];
                        const float* eb = p0 + (size_t)e * HH;
                        atomicAdd(pout + (size_t)t * HH + col,     (c0 + eb[col]) * w);
                        atomicAdd(pout + (size_t)t * HH + col + 1, (c1 + eb[col + 1]) * w);
                    }
                }
            }
        }
    }
}

// ============ fused up+gate pipelined HMMA grouped GEMM (1-term fp16) ========
#define UPG_SMEM (2 * 24576)
__global__ void __launch_bounds__(256, 1) ffn_upgate(
    const float* __restrict__ bu_, const float* __restrict__ bn_) {
    int e = blockIdx.y / 24;
    int n0 = (blockIdx.y % 24) * 128;
    int base = g_off[e] + blockIdx.x * 128;
    int end  = g_off[e] + g_cnt[e];
    if (base >= end) return;

    extern __shared__ char dyn[];
    __shared__ int s_tok[128];

    int tid = threadIdx.x, lane = tid & 31, wid = tid >> 5;
    int wm = wid & 1, wn = wid >> 1;

    if (tid < 128) s_tok[tid] = g_etok[min(base + tid, end - 1)];
    __syncthreads();

    const __half* Buh = g_wuh + (size_t)e * HH * II;
    const __half* Bnh = g_wnh + (size_t)e * HH * II;
    uint32_t sbase = smem_u32(dyn);

    auto issue = [&](int slab, int st) {
        int k0 = slab * 32;
        uint32_t sb = sbase + st * 24576;
#pragma unroll
        for (int i = 0; i < 2; i++) {
            int c = tid + i * 256;
            {
                int m = c >> 2, kc = c & 3;
                uint32_t so = sb + swoff(m, kc);
                size_t aoff = (size_t)s_tok[m] * HH + k0 + kc * 8;
                cpasync16(so, g_xlh + aoff);
            }
            {
                int k = c >> 4, cb = c & 15;
                uint32_t bo = sb + 8192 + bswz(k, cb);
                size_t go = (size_t)(k0 + k) * II + n0 + cb * 8;
                cpasync16(bo,        Buh + go);
                cpasync16(bo + 8192, Bnh + go);
            }
        }
    };

    int j = lane >> 3, rr = lane & 7;
    int amRow = wm * 64 + (j & 1) * 8 + rr;
    int akSel = j >> 1;
    float Cu[4][4][4] = {}, Cn[4][4][4] = {};

    issue(0, 0);
    CP_COMMIT();
    for (int s = 0; s < HH / 32; s++) {
        int st = s & 1;
        if (s + 1 < HH / 32) {
            issue(s + 1, st ^ 1);
            CP_COMMIT();
            CP_WAIT1();
        } else {
            CP_WAIT0();
        }
        __syncthreads();
        uint32_t aH = sbase + st * 24576;
        uint32_t uH = aH + 8192, nH = aH + 16384;
#pragma unroll
        for (int kk = 0; kk < 2; kk++) {
            uint32_t buh[4][2], bnh[4][2];
#pragma unroll
            for (int f16 = 0; f16 < 2; f16++) {
                int krow = kk * 16 + (j & 1) * 8 + rr;
                int cc = wn * 4 + f16 * 2 + (j >> 1);
                uint32_t o = bswz(krow, cc);
                ldsm4t(buh[f16 * 2][0], buh[f16 * 2][1], buh[f16 * 2 + 1][0], buh[f16 * 2 + 1][1], uH + o);
                ldsm4t(bnh[f16 * 2][0], bnh[f16 * 2][1], bnh[f16 * 2 + 1][0], bnh[f16 * 2 + 1][1], nH + o);
            }
#pragma unroll
            for (int fm = 0; fm < 4; fm++) {
                int m = amRow + fm * 16;
                int kg = kk * 2 + akSel;
                uint32_t o = (uint32_t)(m * 64 + ((kg ^ ((m >> 1) & 3)) << 4));
                uint32_t ah[4];
                ldsm4(ah[0], ah[1], ah[2], ah[3], aH + o);
#pragma unroll
                for (int fn = 0; fn < 4; fn++) {
                    mma16816(Cu[fm][fn], ah, buh[fn]);
                    mma16816(Cn[fm][fn], ah, bnh[fn]);
                }
            }
        }
        __syncthreads();
    }

    int g = lane >> 2, tig = lane & 3;
    const float* bu = bu_ + (size_t)e * II;
    const float* bn = bn_ + (size_t)e * II;
#pragma unroll
    for (int fm = 0; fm < 4; fm++) {
        int rowl0 = wm * 64 + fm * 16 + g;
#pragma unroll
        for (int fn = 0; fn < 4; fn++) {
            int col = n0 + wn * 32 + fn * 8 + tig * 2;
            float bu0 = bu[col], bu1 = bu[col + 1];
            float bn0 = bn[col], bn1 = bn[col + 1];
#pragma unroll
            for (int hf = 0; hf < 2; hf++) {
                int r = base + rowl0 + hf * 8;
                if (r < end) {
                    float u0 = Cu[fm][fn][hf * 2] + bu0, u1 = Cu[fm][fn][hf * 2 + 1] + bu1;
                    float h0 = u0 * normcdff(u0) * (Cn[fm][fn][hf * 2] + bn0);
                    float h1 = u1 * normcdff(u1) * (Cn[fm][fn][hf * 2 + 1] + bn1);
                    *(uint32_t*)(g_hh + (size_t)r * II + col) = pack2(h0, h1);
                }
            }
        }
    }
}

// ================= flash attention (2-term HMMA, online softmax) =============
// Q/P hi+lo (exact), K/V fp16.
#define FL_SMEM (32768 + 2 * 32768)
__global__ void __launch_bounds__(256, 1) flash_attn() {
    int q0 = blockIdx.x * 128;
    int head = blockIdx.y;
    int b = head / NHH, h_ = head % NHH;

    extern __shared__ char dyn[];
    uint32_t sb = smem_u32(dyn);
    const uint32_t QH = 0, QL = 16384;

    const __half* Qh = g_qh + (size_t)head * SS * DHH;
    const __half* Ql = g_ql + (size_t)head * SS * DHH;
    const __half* Kh = g_kh + (size_t)head * SS * DHH;
    const __half* Vh = g_vh + (size_t)head * SS * DHH;

    int tid = threadIdx.x, lane = tid & 31, wid = tid >> 5;
    int j = lane >> 3, rr = lane & 7;
    int g = lane >> 2, tig = lane & 3;

    auto load_tile = [&](uint32_t dst, const __half* src, int row0) {
#pragma unroll
        for (int i = 0; i < 4; i++) {
            int idx = tid + i * 256;
            int m = idx >> 3, c = idx & 7;
            cpasync16(sb + dst + fswz(m, c), src + (size_t)(row0 + m) * DHH + c * 8);
        }
    };

    load_tile(QH, Qh, q0);
    load_tile(QL, Ql, q0);
    load_tile(32768,         Kh, 0);
    load_tile(32768 + 16384, Vh, 0);
    CP_COMMIT();

    float O[8][4] = {};
    float rm0 = -1e30f, rm1 = -1e30f, l0 = 0.0f, l1 = 0.0f;

    for (int kt = 0; kt < 4; kt++) {
        int st = kt & 1;
        if (kt + 1 < 4) {
            uint32_t nb = 32768 + (st ^ 1) * 32768;
            load_tile(nb,         Kh, (kt + 1) * 128);
            load_tile(nb + 16384, Vh, (kt + 1) * 128);
            CP_COMMIT();
            CP_WAIT1();
        } else {
            CP_WAIT0();
        }
        __syncthreads();

        uint32_t kH = sb + 32768 + st * 32768;
        uint32_t vH = kH + 16384;
        uint32_t qHb = sb + QH, qLb = sb + QL;

        float S[16][4] = {};
#pragma unroll
        for (int ks = 0; ks < 4; ks++) {
            int am = wid * 16 + (j & 1) * 8 + rr;
            int ac = 2 * ks + (j >> 1);
            uint32_t ah[4], al[4];
            ldsm4(ah[0], ah[1], ah[2], ah[3], qHb + fswz(am, ac));
            ldsm4(al[0], al[1], al[2], al[3], qLb + fswz(am, ac));
#pragma unroll
            for (int fnp = 0; fnp < 8; fnp++) {
                int bn = fnp * 16 + (j >> 1) * 8 + rr;
                int bc = 2 * ks + (j & 1);
                uint32_t bo = fswz(bn, bc);
                uint32_t bh[4];
                ldsm4(bh[0], bh[1], bh[2], bh[3], kH + bo);
                mma16816(S[2 * fnp],     ah, bh);
                mma16816(S[2 * fnp],     al, bh);
                mma16816(S[2 * fnp + 1], ah, bh + 2);
                mma16816(S[2 * fnp + 1], al, bh + 2);
            }
        }

        float mx0 = -1e30f, mx1 = -1e30f;
#pragma unroll
        for (int fn = 0; fn < 16; fn++) {
            mx0 = fmaxf(mx0, fmaxf(S[fn][0], S[fn][1]));
            mx1 = fmaxf(mx1, fmaxf(S[fn][2], S[fn][3]));
        }
        mx0 = fmaxf(mx0, __shfl_xor_sync(~0u, mx0, 1));
        mx0 = fmaxf(mx0, __shfl_xor_sync(~0u, mx0, 2));
        mx1 = fmaxf(mx1, __shfl_xor_sync(~0u, mx1, 1));
        mx1 = fmaxf(mx1, __shfl_xor_sync(~0u, mx1, 2));
        float nm0 = fmaxf(rm0, mx0 * 0.125f);
        float nm1 = fmaxf(rm1, mx1 * 0.125f);
        float al0 = __expf(rm0 - nm0);
        float al1 = __expf(rm1 - nm1);
        rm0 = nm0; rm1 = nm1;
        float sum0 = 0.0f, sum1 = 0.0f;
#pragma unroll
        for (int fn = 0; fn < 16; fn++) {
            float p0 = __expf(fmaf(S[fn][0], 0.125f, -nm0));
            float p1 = __expf(fmaf(S[fn][1], 0.125f, -nm0));
            float p2 = __expf(fmaf(S[fn][2], 0.125f, -nm1));
            float p3 = __expf(fmaf(S[fn][3], 0.125f, -nm1));
            S[fn][0] = p0; S[fn][1] = p1; S[fn][2] = p2; S[fn][3] = p3;
            sum0 += p0 + p1; sum1 += p2 + p3;
        }
        sum0 += __shfl_xor_sync(~0u, sum0, 1);
        sum0 += __shfl_xor_sync(~0u, sum0, 2);
        sum1 += __shfl_xor_sync(~0u, sum1, 1);
        sum1 += __shfl_xor_sync(~0u, sum1, 2);
        l0 = l0 * al0 + sum0;
        l1 = l1 * al1 + sum1;
#pragma unroll
        for (int fo = 0; fo < 8; fo++) {
            O[fo][0] *= al0; O[fo][1] *= al0;
            O[fo][2] *= al1; O[fo][3] *= al1;
        }

#pragma unroll
        for (int kp = 0; kp < 8; kp++) {
            uint32_t aph[4], apl[4];
            aph[0] = packsplit(S[2 * kp][0],     S[2 * kp][1],     apl[0]);
            aph[1] = packsplit(S[2 * kp][2],     S[2 * kp][3],     apl[1]);
            aph[2] = packsplit(S[2 * kp + 1][0], S[2 * kp + 1][1], apl[2]);
            aph[3] = packsplit(S[2 * kp + 1][2], S[2 * kp + 1][3], apl[3]);
#pragma unroll
            for (int dg = 0; dg < 4; dg++) {
                int vrow = kp * 16 + (j & 1) * 8 + rr;
                int vc = dg * 2 + (j >> 1);
                uint32_t vo = fswz(vrow, vc);
                uint32_t vh[4];
                ldsm4t(vh[0], vh[1], vh[2], vh[3], vH + vo);
#pragma unroll
                for (int hg = 0; hg < 2; hg++) {
                    int fo = dg * 2 + hg;
                    mma16816(O[fo], aph, vh + hg * 2);
                    mma16816(O[fo], apl, vh + hg * 2);
                }
            }
        }
        __syncthreads();
    }

    float inv0 = 1.0f / l0, inv1 = 1.0f / l1;
    int qr0 = q0 + wid * 16 + g;
    size_t t0 = (size_t)b * SS + qr0;
    size_t t1 = t0 + 8;
#pragma unroll
    for (int fo = 0; fo < 8; fo++) {
        int d = fo * 8 + tig * 2;
        int col = h_ * 64 + d;
        uint32_t lo;
        uint32_t hi = packsplit(O[fo][0] * inv0, O[fo][1] * inv0, lo);
        *(uint32_t*)(g_ch + t0 * HH + col) = hi;
        *(uint32_t*)(g_cl + t0 * HH + col) = lo;
        hi = packsplit(O[fo][2] * inv1, O[fo][3] * inv1, lo);
        *(uint32_t*)(g_ch + t1 * HH + col) = hi;
        *(uint32_t*)(g_cl + t1 * HH + col) = lo;
    }
}

// ================= LayerNorm ==================================================
__global__ void ln_kernel(const float* __restrict__ gamma, const float* __restrict__ beta,
                          float* __restrict__ dout, int mode) {
    size_t row = blockIdx.x;
    const float* in = (mode == 0) ? (g_preln + row * HH) : (g_attnout + row * HH);
    int tid = threadIdx.x;
    float x0 = in[tid], x1 = in[tid + 256], x2 = in[tid + 512];

    __shared__ float red[256];
    red[tid] = x0 + x1 + x2;
    __syncthreads();
    for (int s = 128; s > 0; s >>= 1) {
        if (tid < s) red[tid] += red[tid + s];
        __syncthreads();
    }
    float mean = red[0] * (1.0f / HH);
    __syncthreads();

    float c0 = x0 - mean, c1 = x1 - mean, c2 = x2 - mean;
    red[tid] = c0 * c0 + c1 * c1 + c2 * c2;
    __syncthreads();
    for (int s = 128; s > 0; s >>= 1) {
        if (tid < s) red[tid] += red[tid + s];
        __syncthreads();
    }
    float inv = 1.0f / sqrtf(red[0] * (1.0f / HH) + 1e-12f);

    float y0 = c0 * inv * gamma[tid]       + beta[tid];
    float y1 = c1 * inv * gamma[tid + 256] + beta[tid + 256];
    float y2 = c2 * inv * gamma[tid + 512] + beta[tid + 512];
    if (mode == 0) {
        g_attnout[row * HH + tid]       = y0;
        g_attnout[row * HH + tid + 256] = y1;
        g_attnout[row * HH + tid + 512] = y2;
        dout[row * HH + tid]       = y0;
        dout[row * HH + tid + 256] = y1;
        dout[row * HH + tid + 512] = y2;
    } else {
        g_xl[row * HH + tid]       = y0;
        g_xl[row * HH + tid + 256] = y1;
        g_xl[row * HH + tid + 512] = y2;
        g_xlh[row * HH + tid]       = __float2half_rn(y0);
        g_xlh[row * HH + tid + 256] = __float2half_rn(y1);
        g_xlh[row * HH + tid + 512] = __float2half_rn(y2);
    }
}

// ================= counters / router / scatter ===============================
__global__ void init_kernel() {
    int i = threadIdx.x;
    if (i < EE) { g_cnt[i] = 0; g_cur[i] = 0; }
}

__global__ void router_kernel(const float* __restrict__ Wr, const float* __restrict__ br,
                              float* __restrict__ logits_out) {
    int warp = threadIdx.x >> 5, lane = threadIdx.x & 31;
    int t = blockIdx.x * 8 + warp;
    const float* x = g_xl + (size_t)t * HH;

    float acc[EE] = {};
    for (int h = lane; h < HH; h += 32) {
        float xv = x[h];
        const float* w = Wr + (size_t)h * EE;
#pragma unroll
        for (int e = 0; e < EE; e++) acc[e] = fmaf(xv, w[e], acc[e]);
    }
#pragma unroll
    for (int e = 0; e < EE; e++)
        for (int o = 16; o > 0; o >>= 1) acc[e] += __shfl_down_sync(0xffffffffu, acc[e], o);

    if (lane == 0) {
        float lg[EE], mx = -1e30f;
#pragma unroll
        for (int e = 0; e < EE; e++) {
            lg[e] = acc[e] + br[e];
            logits_out[(size_t)t * EE + e] = lg[e];
            mx = fmaxf(mx, lg[e]);
        }
        float p[EE], s = 0.0f;
#pragma unroll
        for (int e = 0; e < EE; e++) { p[e] = expf(lg[e] - mx); s += p[e]; }
        float invs = 1.0f / s;
#pragma unroll
        for (int e = 0; e < EE; e++) p[e] *= invs;

        int i1 = 0;
#pragma unroll
        for (int e = 1; e < EE; e++) if (p[e] > p[i1]) i1 = e;
        int i2 = (i1 == 0) ? 1 : 0;
#pragma unroll
        for (int e = 0; e < EE; e++) if (e != i1 && p[e] > p[i2]) i2 = e;

        float w1 = p[i1], w2 = p[i2], inv = 1.0f / (w1 + w2);
        g_ti[t * 2]     = i1;  g_tw[t * 2]     = w1 * inv;
        g_ti[t * 2 + 1] = i2;  g_tw[t * 2 + 1] = w2 * inv;
        atomicAdd(&g_cnt[i1], 1);
        atomicAdd(&g_cnt[i2], 1);
    }
}

__global__ void offsets_kernel() {
    if (threadIdx.x == 0) {
        int o = 0;
        for (int e = 0; e < EE; e++) { g_off[e] = o; o += g_cnt[e]; }
    }
}

__global__ void scatter_kernel() {
    int t = blockIdx.x * 256 + threadIdx.x;
    if (t >= TT) return;
#pragma unroll
    for (int s = 0; s < 2; s++) {
        int e = g_ti[t * 2 + s];
        int pos = atomicAdd(&g_cur[e], 1);
        int r = g_off[e] + pos;
        g_etok[r] = t;
        g_ew[r] = g_tw[t * 2 + s];
    }
}

// ================= host launcher =============================================
#define HG_SMEM  49152
#define DWN_SMEM 32768

extern "C" void kernel_launch(void* const* d_in, const int* in_sizes, int n_in,
                              void* d_out, int out_size) {
    const float* X        = (const float*)d_in[0];
    const float* Wq       = (const float*)d_in[1];
    const float* bq       = (const float*)d_in[2];
    const float* Wk       = (const float*)d_in[3];
    const float* bk       = (const float*)d_in[4];
    const float* Wv       = (const float*)d_in[5];
    const float* bv       = (const float*)d_in[6];
    const float* Wo       = (const float*)d_in[7];
    const float* bo       = (const float*)d_in[8];
    const float* ln_ag    = (const float*)d_in[9];
    const float* ln_ab    = (const float*)d_in[10];
    const float* ln_fg    = (const float*)d_in[11];
    const float* ln_fb    = (const float*)d_in[12];
    const float* Wr       = (const float*)d_in[13];
    const float* br       = (const float*)d_in[14];
    const float* W_up     = (const float*)d_in[15];
    const float* b_up     = (const float*)d_in[16];
    const float* W_new    = (const float*)d_in[17];
    const float* b_new    = (const float*)d_in[18];
    const float* W_down   = (const float*)d_in[19];
    const float* b_down   = (const float*)d_in[20];

    float* out    = (float*)d_out;                    // layer_output [T, H]
    float* logits = out + (size_t)TT * HH;            // router_logits [T, E]

    static cudaStream_t s1;
    static cudaEvent_t evFork, evQKVW, evFFNW;
    static int once = 0;
    if (!once) {
        cudaFuncSetAttribute(hgemm<0>, cudaFuncAttributeMaxDynamicSharedMemorySize, HG_SMEM);
        cudaFuncSetAttribute(hgemm<1>, cudaFuncAttributeMaxDynamicSharedMemorySize, HG_SMEM);
        cudaFuncSetAttribute(hgemm<2>, cudaFuncAttributeMaxDynamicSharedMemorySize, DWN_SMEM);
        cudaFuncSetAttribute(ffn_upgate, cudaFuncAttributeMaxDynamicSharedMemorySize, UPG_SMEM);
        cudaFuncSetAttribute(flash_attn, cudaFuncAttributeMaxDynamicSharedMemorySize, FL_SMEM);
        cudaStreamCreateWithFlags(&s1, cudaStreamNonBlocking);
        cudaEventCreateWithFlags(&evFork, cudaEventDisableTiming);
        cudaEventCreateWithFlags(&evQKVW, cudaEventDisableTiming);
        cudaEventCreateWithFlags(&evFFNW, cudaEventDisableTiming);
        once = 1;
    }

    __half *wqkvh, *woh, *wuh, *wnh, *wdh, *xsh, *xsl;
    cudaGetSymbolAddress((void**)&wqkvh, g_wqkvh);
    cudaGetSymbolAddress((void**)&woh, g_woh);
    cudaGetSymbolAddress((void**)&wuh, g_wuh);
    cudaGetSymbolAddress((void**)&wnh, g_wnh);
    cudaGetSymbolAddress((void**)&wdh, g_wdh);
    cudaGetSymbolAddress((void**)&xsh, g_xsh);
    cudaGetSymbolAddress((void**)&xsl, g_xsl);

    // ---- fork side stream for weight prep ----
    cudaEventRecord(evFork, 0);
    cudaStreamWaitEvent(s1, evFork, 0);

    fconv<<<HH * HH / 1024, 256, 0, s1>>>(Wq, wqkvh);
    fconv<<<HH * HH / 1024, 256, 0, s1>>>(Wk, wqkvh + HH * HH);
    fconv<<<HH * HH / 1024, 256, 0, s1>>>(Wv, wqkvh + 2 * HH * HH);
    fconv<<<HH * HH / 1024, 256, 0, s1>>>(Wo, woh);
    cudaEventRecord(evQKVW, s1);
    fconv<<<EE * HH * II / 1024, 256, 0, s1>>>(W_up,  wuh);
    fconv<<<EE * HH * II / 1024, 256, 0, s1>>>(W_new, wnh);
    fconv<<<EE * II * HH / 1024, 256, 0, s1>>>(W_down, wdh);
    cudaEventRecord(evFFNW, s1);

    // ---- main stream: activation prep + attention chain ----
    init_kernel<<<1, 32>>>();
    fsplit<<<TT * HH / 1024, 256>>>(X, xsh, xsl);

    cudaStreamWaitEvent(0, evQKVW, 0);
    hgemm<0><<<dim3(3 * HH / 128, TT / 128), 256, HG_SMEM>>>(bq, bk, bv, nullptr);
    flash_attn<<<dim3(SS / 128, BB * NHH), 256, FL_SMEM>>>();
    hgemm<1><<<dim3(HH / 128, TT / 128), 256, HG_SMEM>>>(bo, X, nullptr, nullptr);

    ln_kernel<<<TT, 256>>>(ln_ag, ln_ab, out, 0);
    ln_kernel<<<TT, 256>>>(ln_fg, ln_fb, out, 1);
    router_kernel<<<TT / 8, 256>>>(Wr, br, logits);
    offsets_kernel<<<1, 32>>>();
    scatter_kernel<<<(TT + 255) / 256, 256>>>();

    // ---- join: FFN weights ready before the MoE GEMMs ----
    cudaStreamWaitEvent(0, evFFNW, 0);
    ffn_upgate<<<dim3(32, EE * 24), 256, UPG_SMEM>>>(b_up, b_new);
    hgemm<2><<<dim3(32, EE * 6), 256, DWN_SMEM>>>(b_down, nullptr, nullptr, out);
}

// round 12
// speedup vs baseline: 5.7748x; 1.1079x over previous
#include <cuda_runtime.h>
#include <cuda_fp16.h>
#include <math.h>
#include <stdint.h>

#define TT  4096   // B*S
#define HH  768
#define SS  512
#define BB  8
#define NHH 12
#define DHH 64
#define II  3072
#define EE  8
#define ENT 8192   // TT * TOPK

// ---------------- scratch (static device allocations; no cudaMalloc) --------
__device__ float g_preln[TT * HH];
__device__ float g_attnout[TT * HH];
__device__ float g_xl[TT * HH];
__device__ __half g_xlh[TT * HH];           // xl fp16 (FFN A operand)
__device__ __half g_xsh[TT * HH];           // X fp16 (QKV A operand)
__device__ __half g_qh[TT * HH];            // Q fp16, [B*NH][S][DH]
__device__ __half g_kh[TT * HH];            // K fp16
__device__ __half g_vh[TT * HH];            // V fp16
__device__ __half g_ch[TT * HH];            // ctx fp16 [T][H] (proj A)
__device__ __half g_hh[(size_t)ENT * II];   // FFN hidden h = gelu(u)*gate, fp16
__device__ __half g_wqkvh[3 * HH * HH];     // [Wq;Wk;Wv] fp16, each [768 k][768 n]
__device__ __half g_woh[HH * HH];           // Wo fp16 [768 k][768 n]
__device__ __half g_wuh[(size_t)EE * HH * II];  // W_up  fp16 [E][H k][I n]
__device__ __half g_wnh[(size_t)EE * HH * II];  // W_new fp16
__device__ __half g_wdh[(size_t)EE * II * HH];  // W_down fp16 [E][I k][H n]
__device__ int   g_cnt[EE];
__device__ int   g_off[EE];
__device__ int   g_cur[EE];
__device__ int   g_etok[ENT];
__device__ float g_ew[ENT];
__device__ int   g_ti[TT * 2];
__device__ float g_tw[TT * 2];

// ======================= asm helpers (portable sm_80+) =======================
__device__ __forceinline__ uint32_t smem_u32(const void* p) {
    uint32_t a;
    asm("{ .reg .u64 t; cvta.to.shared.u64 t, %1; cvt.u32.u64 %0, t; }" : "=r"(a) : "l"(p));
    return a;
}
__device__ __forceinline__ void ldsm4(uint32_t& r0, uint32_t& r1, uint32_t& r2, uint32_t& r3,
                                      uint32_t addr) {
    asm volatile("ldmatrix.sync.aligned.m8n8.x4.shared.b16 {%0,%1,%2,%3}, [%4];"
                 : "=r"(r0), "=r"(r1), "=r"(r2), "=r"(r3) : "r"(addr));
}
__device__ __forceinline__ void ldsm4t(uint32_t& r0, uint32_t& r1, uint32_t& r2, uint32_t& r3,
                                       uint32_t addr) {
    asm volatile("ldmatrix.sync.aligned.m8n8.x4.trans.shared.b16 {%0,%1,%2,%3}, [%4];"
                 : "=r"(r0), "=r"(r1), "=r"(r2), "=r"(r3) : "r"(addr));
}
__device__ __forceinline__ void mma16816(float* c, const uint32_t* a, const uint32_t* b) {
    asm volatile(
        "mma.sync.aligned.m16n8k16.row.col.f32.f16.f16.f32 "
        "{%0,%1,%2,%3}, {%4,%5,%6,%7}, {%8,%9}, {%0,%1,%2,%3};"
        : "+f"(c[0]), "+f"(c[1]), "+f"(c[2]), "+f"(c[3])
        : "r"(a[0]), "r"(a[1]), "r"(a[2]), "r"(a[3]), "r"(b[0]), "r"(b[1]));
}
__device__ __forceinline__ void cpasync16(uint32_t saddr, const void* gaddr) {
    asm volatile("cp.async.cg.shared.global [%0], [%1], 16;" :: "r"(saddr), "l"(gaddr));
}
#define CP_COMMIT() asm volatile("cp.async.commit_group;" ::: "memory")
#define CP_WAIT1()  asm volatile("cp.async.wait_group 1;" ::: "memory")
#define CP_WAIT0()  asm volatile("cp.async.wait_group 0;" ::: "memory")

// xor-swizzled smem byte offset for a [rows x 32 halves] tile (row = 64B)
__device__ __forceinline__ uint32_t swoff(int m, int kg) {
    return (uint32_t)(m * 64 + ((kg ^ ((m >> 1) & 3)) << 4));
}
// xor-swizzled smem byte offset for a [rows x 64 halves] tile (row = 128B, 8 chunks)
__device__ __forceinline__ uint32_t fswz(int m, int c) {
    return (uint32_t)(m * 128 + ((c ^ (m & 7)) << 4));
}
// xor-swizzled smem byte offset for a [32 k x 128 halves] B tile (row = 256B, 16 chunks)
__device__ __forceinline__ uint32_t bswz(int k, int c) {
    return (uint32_t)(k * 256 + ((c ^ (k & 7)) << 4));
}
__device__ __forceinline__ uint32_t pack2(float v0, float v1) {
    __half2 h = __halves2half2(__float2half_rn(v0), __float2half_rn(v1));
    return *(uint32_t*)&h;
}

// ============ elementwise fp32 -> fp16 convert (pure streaming) ==============
__global__ void fconv(const float* __restrict__ src, __half* __restrict__ h) {
    size_t i = ((size_t)blockIdx.x * 256 + threadIdx.x) * 4;
    float4 v = *(const float4*)(src + i);
    *(uint32_t*)(h + i)     = pack2(v.x, v.y);
    *(uint32_t*)(h + i + 2) = pack2(v.z, v.w);
}

// ================= unified fp16 pipelined HMMA GEMM ==========================
// B operand is [K][N] row-major fp16, loaded via ldsm4t. All 1-term fp16.
// MODE 0: QKV  -> Q/K/V fp16
// MODE 1: PROJ -> g_preln (+bo+X)
// MODE 2: DOWN -> atomicAdd out
template<int MODE>
__global__ void __launch_bounds__(256, 2) hgemm(
    const float* __restrict__ p0, const float* __restrict__ p1,
    const float* __restrict__ p2, float* __restrict__ pout) {

    constexpr int KD = (MODE == 2) ? II : HH;   // A K-dim
    constexpr int NS = KD / 32;
    constexpr uint32_t STG = 16384;             // A 8K + B 8K per stage

    int e = 0, base = 0, end = 0, m0 = 0, n0;
    if (MODE == 2) {
        e = blockIdx.y / 6;
        n0 = (blockIdx.y % 6) * 128;
        base = g_off[e] + blockIdx.x * 128;
        end  = g_off[e] + g_cnt[e];
        if (base >= end) return;
    } else {
        m0 = blockIdx.y * 128;
        n0 = blockIdx.x * 128;
    }

    extern __shared__ char dyn[];
    __shared__ int   s_tok[128];
    __shared__ float s_w[128];

    int tid = threadIdx.x, lane = tid & 31, wid = tid >> 5;
    int wm = wid & 1, wn = wid >> 1;

    if (MODE == 2 && tid < 128) {
        int r = min(base + tid, end - 1);
        s_tok[tid] = g_etok[r];
        s_w[tid]   = g_ew[r];
    }
    __syncthreads();

    const __half *Bh, *Ah;
    int nb;
    if (MODE == 0) {
        int which = n0 / HH;
        Bh = g_wqkvh + (size_t)which * HH * HH;
        Ah = g_xsh;
        nb = n0 - which * HH;
    } else if (MODE == 1) {
        Bh = g_woh; Ah = g_ch; nb = n0;
    } else {
        Bh = g_wdh + (size_t)e * II * HH;
        Ah = g_hh;  nb = n0;
    }

    uint32_t sbase = smem_u32(dyn);

    auto issue = [&](int slab, int st) {
        int k0 = slab * 32;
        uint32_t sb = sbase + st * STG;
#pragma unroll
        for (int i = 0; i < 2; i++) {
            int c = tid + i * 256;
            {
                int m = c >> 2, kc = c & 3;
                uint32_t so = sb + swoff(m, kc);
                int koff = k0 + kc * 8;
                size_t aoff;
                if (MODE < 2) aoff = (size_t)(m0 + m) * KD;
                else          aoff = (size_t)min(base + m, end - 1) * KD;
                cpasync16(so, Ah + aoff + koff);
            }
            {
                int k = c >> 4, cb = c & 15;
                uint32_t bo = sb + 8192 + bswz(k, cb);
                size_t go = (size_t)(k0 + k) * HH + nb + cb * 8;
                cpasync16(bo, Bh + go);
            }
        }
    };

    int j = lane >> 3, rr = lane & 7;
    int amRow = wm * 64 + (j & 1) * 8 + rr;
    int akSel = j >> 1;
    float C[4][4][4] = {};

    issue(0, 0);
    CP_COMMIT();
    for (int s = 0; s < NS; s++) {
        int st = s & 1;
        if (s + 1 < NS) {
            issue(s + 1, st ^ 1);
            CP_COMMIT();
            CP_WAIT1();
        } else {
            CP_WAIT0();
        }
        __syncthreads();
        uint32_t aH = sbase + st * STG;
        uint32_t bH = aH + 8192;
#pragma unroll
        for (int kk = 0; kk < 2; kk++) {
            uint32_t bh[4][2];
#pragma unroll
            for (int f16 = 0; f16 < 2; f16++) {
                int krow = kk * 16 + (j & 1) * 8 + rr;
                int cc = wn * 4 + f16 * 2 + (j >> 1);
                uint32_t o = bswz(krow, cc);
                ldsm4t(bh[f16 * 2][0], bh[f16 * 2][1], bh[f16 * 2 + 1][0], bh[f16 * 2 + 1][1], bH + o);
            }
#pragma unroll
            for (int fm = 0; fm < 4; fm++) {
                int m = amRow + fm * 16;
                int kg = kk * 2 + akSel;
                uint32_t o = (uint32_t)(m * 64 + ((kg ^ ((m >> 1) & 3)) << 4));
                uint32_t ah[4];
                ldsm4(ah[0], ah[1], ah[2], ah[3], aH + o);
#pragma unroll
                for (int fn = 0; fn < 4; fn++)
                    mma16816(C[fm][fn], ah, bh[fn]);
            }
        }
        __syncthreads();
    }

    int g = lane >> 2, tig = lane & 3;

    __half* qkv_out = nullptr;
    const float* mbias = nullptr;
    int hcol0 = 0;
    if (MODE == 0) {
        int which = n0 / HH;
        qkv_out = (which == 0) ? g_qh : (which == 1) ? g_kh : g_vh;
        mbias   = (which == 0) ? p0 : (which == 1) ? p1 : p2;
        hcol0   = n0 - which * HH;
    }

#pragma unroll
    for (int fm = 0; fm < 4; fm++) {
        int rowl0 = wm * 64 + fm * 16 + g;
#pragma unroll
        for (int fn = 0; fn < 4; fn++) {
            int coll = wn * 32 + fn * 8 + tig * 2;
#pragma unroll
            for (int hf = 0; hf < 2; hf++) {
                int ml = rowl0 + hf * 8;
                float c0 = C[fm][fn][hf * 2], c1 = C[fm][fn][hf * 2 + 1];
                if (MODE == 0) {
                    int t = m0 + ml;
                    int hcol = hcol0 + coll;
                    int h = hcol >> 6, d = hcol & 63;
                    int b = t >> 9, sI = t & 511;
                    size_t o = (((size_t)(b * NHH + h)) * SS + sI) * DHH + d;
                    *(uint32_t*)(qkv_out + o) = pack2(c0 + mbias[hcol], c1 + mbias[hcol + 1]);
                } else if (MODE == 1) {
                    size_t t = m0 + ml;
                    int col = n0 + coll;
                    float2 xr = *(const float2*)(p1 + t * HH + col);
                    float2 v = {c0 + p0[col] + xr.x, c1 + p0[col + 1] + xr.y};
                    *(float2*)(g_preln + t * HH + col) = v;
                } else {
                    if (base + ml < end) {
                        int col = n0 + coll;
                        int t = s_tok[ml];
                        float w = s_w[ml];
                        const float* eb = p0 + (size_t)e * HH;
                        atomicAdd(pout + (size_t)t * HH + col,     (c0 + eb[col]) * w);
                        atomicAdd(pout + (size_t)t * HH + col + 1, (c1 + eb[col + 1]) * w);
                    }
                }
            }
        }
    }
}

// ============ fused up+gate pipelined HMMA grouped GEMM (fp16) ===============
#define UPG_SMEM (2 * 24576)
__global__ void __launch_bounds__(256, 1) ffn_upgate(
    const float* __restrict__ bu_, const float* __restrict__ bn_) {
    int e = blockIdx.y / 24;
    int n0 = (blockIdx.y % 24) * 128;
    int base = g_off[e] + blockIdx.x * 128;
    int end  = g_off[e] + g_cnt[e];
    if (base >= end) return;

    extern __shared__ char dyn[];
    __shared__ int s_tok[128];

    int tid = threadIdx.x, lane = tid & 31, wid = tid >> 5;
    int wm = wid & 1, wn = wid >> 1;

    if (tid < 128) s_tok[tid] = g_etok[min(base + tid, end - 1)];
    __syncthreads();

    const __half* Buh = g_wuh + (size_t)e * HH * II;
    const __half* Bnh = g_wnh + (size_t)e * HH * II;
    uint32_t sbase = smem_u32(dyn);

    auto issue = [&](int slab, int st) {
        int k0 = slab * 32;
        uint32_t sb = sbase + st * 24576;
#pragma unroll
        for (int i = 0; i < 2; i++) {
            int c = tid + i * 256;
            {
                int m = c >> 2, kc = c & 3;
                uint32_t so = sb + swoff(m, kc);
                size_t aoff = (size_t)s_tok[m] * HH + k0 + kc * 8;
                cpasync16(so, g_xlh + aoff);
            }
            {
                int k = c >> 4, cb = c & 15;
                uint32_t bo = sb + 8192 + bswz(k, cb);
                size_t go = (size_t)(k0 + k) * II + n0 + cb * 8;
                cpasync16(bo,        Buh + go);
                cpasync16(bo + 8192, Bnh + go);
            }
        }
    };

    int j = lane >> 3, rr = lane & 7;
    int amRow = wm * 64 + (j & 1) * 8 + rr;
    int akSel = j >> 1;
    float Cu[4][4][4] = {}, Cn[4][4][4] = {};

    issue(0, 0);
    CP_COMMIT();
    for (int s = 0; s < HH / 32; s++) {
        int st = s & 1;
        if (s + 1 < HH / 32) {
            issue(s + 1, st ^ 1);
            CP_COMMIT();
            CP_WAIT1();
        } else {
            CP_WAIT0();
        }
        __syncthreads();
        uint32_t aH = sbase + st * 24576;
        uint32_t uH = aH + 8192, nH = aH + 16384;
#pragma unroll
        for (int kk = 0; kk < 2; kk++) {
            uint32_t buh[4][2], bnh[4][2];
#pragma unroll
            for (int f16 = 0; f16 < 2; f16++) {
                int krow = kk * 16 + (j & 1) * 8 + rr;
                int cc = wn * 4 + f16 * 2 + (j >> 1);
                uint32_t o = bswz(krow, cc);
                ldsm4t(buh[f16 * 2][0], buh[f16 * 2][1], buh[f16 * 2 + 1][0], buh[f16 * 2 + 1][1], uH + o);
                ldsm4t(bnh[f16 * 2][0], bnh[f16 * 2][1], bnh[f16 * 2 + 1][0], bnh[f16 * 2 + 1][1], nH + o);
            }
#pragma unroll
            for (int fm = 0; fm < 4; fm++) {
                int m = amRow + fm * 16;
                int kg = kk * 2 + akSel;
                uint32_t o = (uint32_t)(m * 64 + ((kg ^ ((m >> 1) & 3)) << 4));
                uint32_t ah[4];
                ldsm4(ah[0], ah[1], ah[2], ah[3], aH + o);
#pragma unroll
                for (int fn = 0; fn < 4; fn++) {
                    mma16816(Cu[fm][fn], ah, buh[fn]);
                    mma16816(Cn[fm][fn], ah, bnh[fn]);
                }
            }
        }
        __syncthreads();
    }

    int g = lane >> 2, tig = lane & 3;
    const float* bu = bu_ + (size_t)e * II;
    const float* bn = bn_ + (size_t)e * II;
#pragma unroll
    for (int fm = 0; fm < 4; fm++) {
        int rowl0 = wm * 64 + fm * 16 + g;
#pragma unroll
        for (int fn = 0; fn < 4; fn++) {
            int col = n0 + wn * 32 + fn * 8 + tig * 2;
            float bu0 = bu[col], bu1 = bu[col + 1];
            float bn0 = bn[col], bn1 = bn[col + 1];
#pragma unroll
            for (int hf = 0; hf < 2; hf++) {
                int r = base + rowl0 + hf * 8;
                if (r < end) {
                    float u0 = Cu[fm][fn][hf * 2] + bu0, u1 = Cu[fm][fn][hf * 2 + 1] + bu1;
                    float h0 = u0 * normcdff(u0) * (Cn[fm][fn][hf * 2] + bn0);
                    float h1 = u1 * normcdff(u1) * (Cn[fm][fn][hf * 2 + 1] + bn1);
                    *(uint32_t*)(g_hh + (size_t)r * II + col) = pack2(h0, h1);
                }
            }
        }
    }
}

// ================= flash attention (fp16 HMMA, online softmax) ===============
#define FL_SMEM (16384 + 2 * 32768)
__global__ void __launch_bounds__(256, 1) flash_attn() {
    int q0 = blockIdx.x * 128;
    int head = blockIdx.y;
    int b = head / NHH, h_ = head % NHH;

    extern __shared__ char dyn[];
    uint32_t sb = smem_u32(dyn);

    const __half* Qh = g_qh + (size_t)head * SS * DHH;
    const __half* Kh = g_kh + (size_t)head * SS * DHH;
    const __half* Vh = g_vh + (size_t)head * SS * DHH;

    int tid = threadIdx.x, lane = tid & 31, wid = tid >> 5;
    int j = lane >> 3, rr = lane & 7;
    int g = lane >> 2, tig = lane & 3;

    auto load_tile = [&](uint32_t dst, const __half* src, int row0) {
#pragma unroll
        for (int i = 0; i < 4; i++) {
            int idx = tid + i * 256;
            int m = idx >> 3, c = idx & 7;
            cpasync16(sb + dst + fswz(m, c), src + (size_t)(row0 + m) * DHH + c * 8);
        }
    };

    load_tile(0, Qh, q0);
    load_tile(16384,         Kh, 0);
    load_tile(16384 + 16384, Vh, 0);
    CP_COMMIT();

    float O[8][4] = {};
    float rm0 = -1e30f, rm1 = -1e30f, l0 = 0.0f, l1 = 0.0f;

    for (int kt = 0; kt < 4; kt++) {
        int st = kt & 1;
        if (kt + 1 < 4) {
            uint32_t nb = 16384 + (st ^ 1) * 32768;
            load_tile(nb,         Kh, (kt + 1) * 128);
            load_tile(nb + 16384, Vh, (kt + 1) * 128);
            CP_COMMIT();
            CP_WAIT1();
        } else {
            CP_WAIT0();
        }
        __syncthreads();

        uint32_t kH = sb + 16384 + st * 32768;
        uint32_t vH = kH + 16384;
        uint32_t qHb = sb;

        float S[16][4] = {};
#pragma unroll
        for (int ks = 0; ks < 4; ks++) {
            int am = wid * 16 + (j & 1) * 8 + rr;
            int ac = 2 * ks + (j >> 1);
            uint32_t ah[4];
            ldsm4(ah[0], ah[1], ah[2], ah[3], qHb + fswz(am, ac));
#pragma unroll
            for (int fnp = 0; fnp < 8; fnp++) {
                int bn = fnp * 16 + (j >> 1) * 8 + rr;
                int bc = 2 * ks + (j & 1);
                uint32_t bo = fswz(bn, bc);
                uint32_t bh[4];
                ldsm4(bh[0], bh[1], bh[2], bh[3], kH + bo);
                mma16816(S[2 * fnp],     ah, bh);
                mma16816(S[2 * fnp + 1], ah, bh + 2);
            }
        }

        float mx0 = -1e30f, mx1 = -1e30f;
#pragma unroll
        for (int fn = 0; fn < 16; fn++) {
            mx0 = fmaxf(mx0, fmaxf(S[fn][0], S[fn][1]));
            mx1 = fmaxf(mx1, fmaxf(S[fn][2], S[fn][3]));
        }
        mx0 = fmaxf(mx0, __shfl_xor_sync(~0u, mx0, 1));
        mx0 = fmaxf(mx0, __shfl_xor_sync(~0u, mx0, 2));
        mx1 = fmaxf(mx1, __shfl_xor_sync(~0u, mx1, 1));
        mx1 = fmaxf(mx1, __shfl_xor_sync(~0u, mx1, 2));
        float nm0 = fmaxf(rm0, mx0 * 0.125f);
        float nm1 = fmaxf(rm1, mx1 * 0.125f);
        float al0 = __expf(rm0 - nm0);
        float al1 = __expf(rm1 - nm1);
        rm0 = nm0; rm1 = nm1;
        float sum0 = 0.0f, sum1 = 0.0f;
#pragma unroll
        for (int fn = 0; fn < 16; fn++) {
            float p0 = __expf(fmaf(S[fn][0], 0.125f, -nm0));
            float p1 = __expf(fmaf(S[fn][1], 0.125f, -nm0));
            float p2 = __expf(fmaf(S[fn][2], 0.125f, -nm1));
            float p3 = __expf(fmaf(S[fn][3], 0.125f, -nm1));
            S[fn][0] = p0; S[fn][1] = p1; S[fn][2] = p2; S[fn][3] = p3;
            sum0 += p0 + p1; sum1 += p2 + p3;
        }
        sum0 += __shfl_xor_sync(~0u, sum0, 1);
        sum0 += __shfl_xor_sync(~0u, sum0, 2);
        sum1 += __shfl_xor_sync(~0u, sum1, 1);
        sum1 += __shfl_xor_sync(~0u, sum1, 2);
        l0 = l0 * al0 + sum0;
        l1 = l1 * al1 + sum1;
#pragma unroll
        for (int fo = 0; fo < 8; fo++) {
            O[fo][0] *= al0; O[fo][1] *= al0;
            O[fo][2] *= al1; O[fo][3] *= al1;
        }

#pragma unroll
        for (int kp = 0; kp < 8; kp++) {
            uint32_t aph[4];
            aph[0] = pack2(S[2 * kp][0],     S[2 * kp][1]);
            aph[1] = pack2(S[2 * kp][2],     S[2 * kp][3]);
            aph[2] = pack2(S[2 * kp + 1][0], S[2 * kp + 1][1]);
            aph[3] = pack2(S[2 * kp + 1][2], S[2 * kp + 1][3]);
#pragma unroll
            for (int dg = 0; dg < 4; dg++) {
                int vrow = kp * 16 + (j & 1) * 8 + rr;
                int vc = dg * 2 + (j >> 1);
                uint32_t vo = fswz(vrow, vc);
                uint32_t vh[4];
                ldsm4t(vh[0], vh[1], vh[2], vh[3], vH + vo);
#pragma unroll
                for (int hg = 0; hg < 2; hg++) {
                    int fo = dg * 2 + hg;
                    mma16816(O[fo], aph, vh + hg * 2);
                }
            }
        }
        __syncthreads();
    }

    float inv0 = 1.0f / l0, inv1 = 1.0f / l1;
    int qr0 = q0 + wid * 16 + g;
    size_t t0 = (size_t)b * SS + qr0;
    size_t t1 = t0 + 8;
#pragma unroll
    for (int fo = 0; fo < 8; fo++) {
        int d = fo * 8 + tig * 2;
        int col = h_ * 64 + d;
        *(uint32_t*)(g_ch + t0 * HH + col) = pack2(O[fo][0] * inv0, O[fo][1] * inv0);
        *(uint32_t*)(g_ch + t1 * HH + col) = pack2(O[fo][2] * inv1, O[fo][3] * inv1);
    }
}

// ================= LayerNorm ==================================================
__global__ void ln_kernel(const float* __restrict__ gamma, const float* __restrict__ beta,
                          float* __restrict__ dout, int mode) {
    size_t row = blockIdx.x;
    const float* in = (mode == 0) ? (g_preln + row * HH) : (g_attnout + row * HH);
    int tid = threadIdx.x;
    float x0 = in[tid], x1 = in[tid + 256], x2 = in[tid + 512];

    __shared__ float red[256];
    red[tid] = x0 + x1 + x2;
    __syncthreads();
    for (int s = 128; s > 0; s >>= 1) {
        if (tid < s) red[tid] += red[tid + s];
        __syncthreads();
    }
    float mean = red[0] * (1.0f / HH);
    __syncthreads();

    float c0 = x0 - mean, c1 = x1 - mean, c2 = x2 - mean;
    red[tid] = c0 * c0 + c1 * c1 + c2 * c2;
    __syncthreads();
    for (int s = 128; s > 0; s >>= 1) {
        if (tid < s) red[tid] += red[tid + s];
        __syncthreads();
    }
    float inv = 1.0f / sqrtf(red[0] * (1.0f / HH) + 1e-12f);

    float y0 = c0 * inv * gamma[tid]       + beta[tid];
    float y1 = c1 * inv * gamma[tid + 256] + beta[tid + 256];
    float y2 = c2 * inv * gamma[tid + 512] + beta[tid + 512];
    if (mode == 0) {
        g_attnout[row * HH + tid]       = y0;
        g_attnout[row * HH + tid + 256] = y1;
        g_attnout[row * HH + tid + 512] = y2;
        dout[row * HH + tid]       = y0;
        dout[row * HH + tid + 256] = y1;
        dout[row * HH + tid + 512] = y2;
    } else {
        g_xl[row * HH + tid]       = y0;
        g_xl[row * HH + tid + 256] = y1;
        g_xl[row * HH + tid + 512] = y2;
        g_xlh[row * HH + tid]       = __float2half_rn(y0);
        g_xlh[row * HH + tid + 256] = __float2half_rn(y1);
        g_xlh[row * HH + tid + 512] = __float2half_rn(y2);
    }
}

// ================= counters / router / scatter ===============================
__global__ void init_kernel() {
    int i = threadIdx.x;
    if (i < EE) { g_cnt[i] = 0; g_cur[i] = 0; }
}

__global__ void router_kernel(const float* __restrict__ Wr, const float* __restrict__ br,
                              float* __restrict__ logits_out) {
    int warp = threadIdx.x >> 5, lane = threadIdx.x & 31;
    int t = blockIdx.x * 8 + warp;
    const float* x = g_xl + (size_t)t * HH;

    float acc[EE] = {};
    for (int h = lane; h < HH; h += 32) {
        float xv = x[h];
        const float* w = Wr + (size_t)h * EE;
#pragma unroll
        for (int e = 0; e < EE; e++) acc[e] = fmaf(xv, w[e], acc[e]);
    }
#pragma unroll
    for (int e = 0; e < EE; e++)
        for (int o = 16; o > 0; o >>= 1) acc[e] += __shfl_down_sync(0xffffffffu, acc[e], o);

    if (lane == 0) {
        float lg[EE], mx = -1e30f;
#pragma unroll
        for (int e = 0; e < EE; e++) {
            lg[e] = acc[e] + br[e];
            logits_out[(size_t)t * EE + e] = lg[e];
            mx = fmaxf(mx, lg[e]);
        }
        float p[EE], s = 0.0f;
#pragma unroll
        for (int e = 0; e < EE; e++) { p[e] = expf(lg[e] - mx); s += p[e]; }
        float invs = 1.0f / s;
#pragma unroll
        for (int e = 0; e < EE; e++) p[e] *= invs;

        int i1 = 0;
#pragma unroll
        for (int e = 1; e < EE; e++) if (p[e] > p[i1]) i1 = e;
        int i2 = (i1 == 0) ? 1 : 0;
#pragma unroll
        for (int e = 0; e < EE; e++) if (e != i1 && p[e] > p[i2]) i2 = e;

        float w1 = p[i1], w2 = p[i2], inv = 1.0f / (w1 + w2);
        g_ti[t * 2]     = i1;  g_tw[t * 2]     = w1 * inv;
        g_ti[t * 2 + 1] = i2;  g_tw[t * 2 + 1] = w2 * inv;
        atomicAdd(&g_cnt[i1], 1);
        atomicAdd(&g_cnt[i2], 1);
    }
}

__global__ void offsets_kernel() {
    if (threadIdx.x == 0) {
        int o = 0;
        for (int e = 0; e < EE; e++) { g_off[e] = o; o += g_cnt[e]; }
    }
}

__global__ void scatter_kernel() {
    int t = blockIdx.x * 256 + threadIdx.x;
    if (t >= TT) return;
#pragma unroll
    for (int s = 0; s < 2; s++) {
        int e = g_ti[t * 2 + s];
        int pos = atomicAdd(&g_cur[e], 1);
        int r = g_off[e] + pos;
        g_etok[r] = t;
        g_ew[r] = g_tw[t * 2 + s];
    }
}

// ================= host launcher =============================================
#define HG_SMEM  32768
#define DWN_SMEM 32768

extern "C" void kernel_launch(void* const* d_in, const int* in_sizes, int n_in,
                              void* d_out, int out_size) {
    const float* X        = (const float*)d_in[0];
    const float* Wq       = (const float*)d_in[1];
    const float* bq       = (const float*)d_in[2];
    const float* Wk       = (const float*)d_in[3];
    const float* bk       = (const float*)d_in[4];
    const float* Wv       = (const float*)d_in[5];
    const float* bv       = (const float*)d_in[6];
    const float* Wo       = (const float*)d_in[7];
    const float* bo       = (const float*)d_in[8];
    const float* ln_ag    = (const float*)d_in[9];
    const float* ln_ab    = (const float*)d_in[10];
    const float* ln_fg    = (const float*)d_in[11];
    const float* ln_fb    = (const float*)d_in[12];
    const float* Wr       = (const float*)d_in[13];
    const float* br       = (const float*)d_in[14];
    const float* W_up     = (const float*)d_in[15];
    const float* b_up     = (const float*)d_in[16];
    const float* W_new    = (const float*)d_in[17];
    const float* b_new    = (const float*)d_in[18];
    const float* W_down   = (const float*)d_in[19];
    const float* b_down   = (const float*)d_in[20];

    float* out    = (float*)d_out;                    // layer_output [T, H]
    float* logits = out + (size_t)TT * HH;            // router_logits [T, E]

    static cudaStream_t s1;
    static cudaEvent_t evFork, evQKVW, evFFNW;
    static int once = 0;
    if (!once) {
        cudaFuncSetAttribute(hgemm<0>, cudaFuncAttributeMaxDynamicSharedMemorySize, HG_SMEM);
        cudaFuncSetAttribute(hgemm<1>, cudaFuncAttributeMaxDynamicSharedMemorySize, HG_SMEM);
        cudaFuncSetAttribute(hgemm<2>, cudaFuncAttributeMaxDynamicSharedMemorySize, DWN_SMEM);
        cudaFuncSetAttribute(ffn_upgate, cudaFuncAttributeMaxDynamicSharedMemorySize, UPG_SMEM);
        cudaFuncSetAttribute(flash_attn, cudaFuncAttributeMaxDynamicSharedMemorySize, FL_SMEM);
        cudaStreamCreateWithFlags(&s1, cudaStreamNonBlocking);
        cudaEventCreateWithFlags(&evFork, cudaEventDisableTiming);
        cudaEventCreateWithFlags(&evQKVW, cudaEventDisableTiming);
        cudaEventCreateWithFlags(&evFFNW, cudaEventDisableTiming);
        once = 1;
    }

    __half *wqkvh, *woh, *wuh, *wnh, *wdh, *xsh;
    cudaGetSymbolAddress((void**)&wqkvh, g_wqkvh);
    cudaGetSymbolAddress((void**)&woh, g_woh);
    cudaGetSymbolAddress((void**)&wuh, g_wuh);
    cudaGetSymbolAddress((void**)&wnh, g_wnh);
    cudaGetSymbolAddress((void**)&wdh, g_wdh);
    cudaGetSymbolAddress((void**)&xsh, g_xsh);

    // ---- fork side stream for weight prep ----
    cudaEventRecord(evFork, 0);
    cudaStreamWaitEvent(s1, evFork, 0);

    fconv<<<HH * HH / 1024, 256, 0, s1>>>(Wq, wqkvh);
    fconv<<<HH * HH / 1024, 256, 0, s1>>>(Wk, wqkvh + HH * HH);
    fconv<<<HH * HH / 1024, 256, 0, s1>>>(Wv, wqkvh + 2 * HH * HH);
    fconv<<<HH * HH / 1024, 256, 0, s1>>>(Wo, woh);
    cudaEventRecord(evQKVW, s1);
    fconv<<<EE * HH * II / 1024, 256, 0, s1>>>(W_up,  wuh);
    fconv<<<EE * HH * II / 1024, 256, 0, s1>>>(W_new, wnh);
    fconv<<<EE * II * HH / 1024, 256, 0, s1>>>(W_down, wdh);
    cudaEventRecord(evFFNW, s1);

    // ---- main stream: activation prep + attention chain ----
    init_kernel<<<1, 32>>>();
    fconv<<<TT * HH / 1024, 256>>>(X, xsh);

    cudaStreamWaitEvent(0, evQKVW, 0);
    hgemm<0><<<dim3(3 * HH / 128, TT / 128), 256, HG_SMEM>>>(bq, bk, bv, nullptr);
    flash_attn<<<dim3(SS / 128, BB * NHH), 256, FL_SMEM>>>();
    hgemm<1><<<dim3(HH / 128, TT / 128), 256, HG_SMEM>>>(bo, X, nullptr, nullptr);

    ln_kernel<<<TT, 256>>>(ln_ag, ln_ab, out, 0);
    ln_kernel<<<TT, 256>>>(ln_fg, ln_fb, out, 1);
    router_kernel<<<TT / 8, 256>>>(Wr, br, logits);
    offsets_kernel<<<1, 32>>>();
    scatter_kernel<<<(TT + 255) / 256, 256>>>();

    // ---- join: FFN weights ready before the MoE GEMMs ----
    cudaStreamWaitEvent(0, evFFNW, 0);
    ffn_upgate<<<dim3(32, EE * 24), 256, UPG_SMEM>>>(b_up, b_new);
    hgemm<2><<<dim3(32, EE * 6), 256, DWN_SMEM>>>(b_down, nullptr, nullptr, out);
}

// round 13
// speedup vs baseline: 5.8272x; 1.0091x over previous
#include <cuda_runtime.h>
#include <cuda_fp16.h>
#include <math.h>
#include <stdint.h>

#define TT  4096   // B*S
#define HH  768
#define SS  512
#define BB  8
#define NHH 12
#define DHH 64
#define II  3072
#define EE  8
#define ENT 8192   // TT * TOPK

// ---------------- scratch (static device allocations; no cudaMalloc) --------
__device__ float g_preln[TT * HH];
__device__ __half g_xlh[TT * HH];           // xl fp16 (FFN A operand)
__device__ __half g_xsh[TT * HH];           // X fp16 (QKV A operand)
__device__ __half g_qh[TT * HH];            // Q fp16, [B*NH][S][DH]
__device__ __half g_kh[TT * HH];            // K fp16
__device__ __half g_vh[TT * HH];            // V fp16
__device__ __half g_ch[TT * HH];            // ctx fp16 [T][H] (proj A)
__device__ __half g_hh[(size_t)ENT * II];   // FFN hidden h = gelu(u)*gate, fp16
__device__ __half g_wqkvh[3 * HH * HH];     // [Wq;Wk;Wv] fp16, each [768 k][768 n]
__device__ __half g_woh[HH * HH];           // Wo fp16 [768 k][768 n]
__device__ __half g_wuh[(size_t)EE * HH * II];  // W_up  fp16 [E][H k][I n]
__device__ __half g_wnh[(size_t)EE * HH * II];  // W_new fp16
__device__ __half g_wdh[(size_t)EE * II * HH];  // W_down fp16 [E][I k][H n]
__device__ int   g_cnt[EE];
__device__ int   g_off[EE];
__device__ int   g_cur[EE];
__device__ int   g_etok[ENT];
__device__ float g_ew[ENT];
__device__ int   g_ti[TT * 2];
__device__ float g_tw[TT * 2];

// ======================= asm helpers (portable sm_80+) =======================
__device__ __forceinline__ uint32_t smem_u32(const void* p) {
    uint32_t a;
    asm("{ .reg .u64 t; cvta.to.shared.u64 t, %1; cvt.u32.u64 %0, t; }" : "=r"(a) : "l"(p));
    return a;
}
__device__ __forceinline__ void ldsm4(uint32_t& r0, uint32_t& r1, uint32_t& r2, uint32_t& r3,
                                      uint32_t addr) {
    asm volatile("ldmatrix.sync.aligned.m8n8.x4.shared.b16 {%0,%1,%2,%3}, [%4];"
                 : "=r"(r0), "=r"(r1), "=r"(r2), "=r"(r3) : "r"(addr));
}
__device__ __forceinline__ void ldsm4t(uint32_t& r0, uint32_t& r1, uint32_t& r2, uint32_t& r3,
                                       uint32_t addr) {
    asm volatile("ldmatrix.sync.aligned.m8n8.x4.trans.shared.b16 {%0,%1,%2,%3}, [%4];"
                 : "=r"(r0), "=r"(r1), "=r"(r2), "=r"(r3) : "r"(addr));
}
__device__ __forceinline__ void mma16816(float* c, const uint32_t* a, const uint32_t* b) {
    asm volatile(
        "mma.sync.aligned.m16n8k16.row.col.f32.f16.f16.f32 "
        "{%0,%1,%2,%3}, {%4,%5,%6,%7}, {%8,%9}, {%0,%1,%2,%3};"
        : "+f"(c[0]), "+f"(c[1]), "+f"(c[2]), "+f"(c[3])
        : "r"(a[0]), "r"(a[1]), "r"(a[2]), "r"(a[3]), "r"(b[0]), "r"(b[1]));
}
__device__ __forceinline__ void cpasync16(uint32_t saddr, const void* gaddr) {
    asm volatile("cp.async.cg.shared.global [%0], [%1], 16;" :: "r"(saddr), "l"(gaddr));
}
#define CP_COMMIT() asm volatile("cp.async.commit_group;" ::: "memory")
#define CP_WAIT1()  asm volatile("cp.async.wait_group 1;" ::: "memory")
#define CP_WAIT0()  asm volatile("cp.async.wait_group 0;" ::: "memory")

// xor-swizzled smem byte offset for a [rows x 32 halves] tile (row = 64B)
__device__ __forceinline__ uint32_t swoff(int m, int kg) {
    return (uint32_t)(m * 64 + ((kg ^ ((m >> 1) & 3)) << 4));
}
// xor-swizzled smem byte offset for a [rows x 64 halves] tile (row = 128B, 8 chunks)
__device__ __forceinline__ uint32_t fswz(int m, int c) {
    return (uint32_t)(m * 128 + ((c ^ (m & 7)) << 4));
}
// xor-swizzled smem byte offset for a [32 k x 128 halves] B tile (row = 256B, 16 chunks)
__device__ __forceinline__ uint32_t bswz(int k, int c) {
    return (uint32_t)(k * 256 + ((c ^ (k & 7)) << 4));
}
__device__ __forceinline__ uint32_t pack2(float v0, float v1) {
    __half2 h = __halves2half2(__float2half_rn(v0), __float2half_rn(v1));
    return *(uint32_t*)&h;
}

// ============ elementwise fp32 -> fp16 convert (pure streaming) ==============
__global__ void fconv(const float* __restrict__ src, __half* __restrict__ h) {
    size_t i = ((size_t)blockIdx.x * 256 + threadIdx.x) * 4;
    float4 v = *(const float4*)(src + i);
    *(uint32_t*)(h + i)     = pack2(v.x, v.y);
    *(uint32_t*)(h + i + 2) = pack2(v.z, v.w);
}

// ================= unified fp16 pipelined HMMA GEMM ==========================
// B operand is [K][N] row-major fp16, loaded via ldsm4t. All 1-term fp16.
// MODE 0: QKV  -> Q/K/V fp16
// MODE 1: PROJ -> g_preln (+bo+X)
// MODE 2: DOWN -> atomicAdd out
template<int MODE>
__global__ void __launch_bounds__(256, 2) hgemm(
    const float* __restrict__ p0, const float* __restrict__ p1,
    const float* __restrict__ p2, float* __restrict__ pout) {

    constexpr int KD = (MODE == 2) ? II : HH;   // A K-dim
    constexpr int NS = KD / 32;
    constexpr uint32_t STG = 16384;             // A 8K + B 8K per stage

    int e = 0, base = 0, end = 0, m0 = 0, n0;
    if (MODE == 2) {
        e = blockIdx.y / 6;
        n0 = (blockIdx.y % 6) * 128;
        base = g_off[e] + blockIdx.x * 128;
        end  = g_off[e] + g_cnt[e];
        if (base >= end) return;
    } else {
        m0 = blockIdx.y * 128;
        n0 = blockIdx.x * 128;
    }

    extern __shared__ char dyn[];
    __shared__ int   s_tok[128];
    __shared__ float s_w[128];

    int tid = threadIdx.x, lane = tid & 31, wid = tid >> 5;
    int wm = wid & 1, wn = wid >> 1;

    if (MODE == 2 && tid < 128) {
        int r = min(base + tid, end - 1);
        s_tok[tid] = g_etok[r];
        s_w[tid]   = g_ew[r];
    }
    __syncthreads();

    const __half *Bh, *Ah;
    int nb;
    if (MODE == 0) {
        int which = n0 / HH;
        Bh = g_wqkvh + (size_t)which * HH * HH;
        Ah = g_xsh;
        nb = n0 - which * HH;
    } else if (MODE == 1) {
        Bh = g_woh; Ah = g_ch; nb = n0;
    } else {
        Bh = g_wdh + (size_t)e * II * HH;
        Ah = g_hh;  nb = n0;
    }

    uint32_t sbase = smem_u32(dyn);

    auto issue = [&](int slab, int st) {
        int k0 = slab * 32;
        uint32_t sb = sbase + st * STG;
#pragma unroll
        for (int i = 0; i < 2; i++) {
            int c = tid + i * 256;
            {
                int m = c >> 2, kc = c & 3;
                uint32_t so = sb + swoff(m, kc);
                int koff = k0 + kc * 8;
                size_t aoff;
                if (MODE < 2) aoff = (size_t)(m0 + m) * KD;
                else          aoff = (size_t)min(base + m, end - 1) * KD;
                cpasync16(so, Ah + aoff + koff);
            }
            {
                int k = c >> 4, cb = c & 15;
                uint32_t bo = sb + 8192 + bswz(k, cb);
                size_t go = (size_t)(k0 + k) * HH + nb + cb * 8;
                cpasync16(bo, Bh + go);
            }
        }
    };

    int j = lane >> 3, rr = lane & 7;
    int amRow = wm * 64 + (j & 1) * 8 + rr;
    int akSel = j >> 1;
    float C[4][4][4] = {};

    issue(0, 0);
    CP_COMMIT();
    for (int s = 0; s < NS; s++) {
        int st = s & 1;
        if (s + 1 < NS) {
            issue(s + 1, st ^ 1);
            CP_COMMIT();
            CP_WAIT1();
        } else {
            CP_WAIT0();
        }
        __syncthreads();
        uint32_t aH = sbase + st * STG;
        uint32_t bH = aH + 8192;
#pragma unroll
        for (int kk = 0; kk < 2; kk++) {
            uint32_t bh[4][2];
#pragma unroll
            for (int f16 = 0; f16 < 2; f16++) {
                int krow = kk * 16 + (j & 1) * 8 + rr;
                int cc = wn * 4 + f16 * 2 + (j >> 1);
                uint32_t o = bswz(krow, cc);
                ldsm4t(bh[f16 * 2][0], bh[f16 * 2][1], bh[f16 * 2 + 1][0], bh[f16 * 2 + 1][1], bH + o);
            }
#pragma unroll
            for (int fm = 0; fm < 4; fm++) {
                int m = amRow + fm * 16;
                int kg = kk * 2 + akSel;
                uint32_t o = (uint32_t)(m * 64 + ((kg ^ ((m >> 1) & 3)) << 4));
                uint32_t ah[4];
                ldsm4(ah[0], ah[1], ah[2], ah[3], aH + o);
#pragma unroll
                for (int fn = 0; fn < 4; fn++)
                    mma16816(C[fm][fn], ah, bh[fn]);
            }
        }
        __syncthreads();
    }

    int g = lane >> 2, tig = lane & 3;

    __half* qkv_out = nullptr;
    const float* mbias = nullptr;
    int hcol0 = 0;
    if (MODE == 0) {
        int which = n0 / HH;
        qkv_out = (which == 0) ? g_qh : (which == 1) ? g_kh : g_vh;
        mbias   = (which == 0) ? p0 : (which == 1) ? p1 : p2;
        hcol0   = n0 - which * HH;
    }

#pragma unroll
    for (int fm = 0; fm < 4; fm++) {
        int rowl0 = wm * 64 + fm * 16 + g;
#pragma unroll
        for (int fn = 0; fn < 4; fn++) {
            int coll = wn * 32 + fn * 8 + tig * 2;
#pragma unroll
            for (int hf = 0; hf < 2; hf++) {
                int ml = rowl0 + hf * 8;
                float c0 = C[fm][fn][hf * 2], c1 = C[fm][fn][hf * 2 + 1];
                if (MODE == 0) {
                    int t = m0 + ml;
                    int hcol = hcol0 + coll;
                    int h = hcol >> 6, d = hcol & 63;
                    int b = t >> 9, sI = t & 511;
                    size_t o = (((size_t)(b * NHH + h)) * SS + sI) * DHH + d;
                    *(uint32_t*)(qkv_out + o) = pack2(c0 + mbias[hcol], c1 + mbias[hcol + 1]);
                } else if (MODE == 1) {
                    size_t t = m0 + ml;
                    int col = n0 + coll;
                    float2 xr = *(const float2*)(p1 + t * HH + col);
                    float2 v = {c0 + p0[col] + xr.x, c1 + p0[col + 1] + xr.y};
                    *(float2*)(g_preln + t * HH + col) = v;
                } else {
                    if (base + ml < end) {
                        int col = n0 + coll;
                        int t = s_tok[ml];
                        float w = s_w[ml];
                        const float* eb = p0 + (size_t)e * HH;
                        atomicAdd(pout + (size_t)t * HH + col,     (c0 + eb[col]) * w);
                        atomicAdd(pout + (size_t)t * HH + col + 1, (c1 + eb[col + 1]) * w);
                    }
                }
            }
        }
    }
}

// ============ fused up+gate pipelined HMMA grouped GEMM (fp16) ===============
#define UPG_SMEM (2 * 24576)
__global__ void __launch_bounds__(256, 1) ffn_upgate(
    const float* __restrict__ bu_, const float* __restrict__ bn_) {
    int e = blockIdx.y / 24;
    int n0 = (blockIdx.y % 24) * 128;
    int base = g_off[e] + blockIdx.x * 128;
    int end  = g_off[e] + g_cnt[e];
    if (base >= end) return;

    extern __shared__ char dyn[];
    __shared__ int s_tok[128];

    int tid = threadIdx.x, lane = tid & 31, wid = tid >> 5;
    int wm = wid & 1, wn = wid >> 1;

    if (tid < 128) s_tok[tid] = g_etok[min(base + tid, end - 1)];
    __syncthreads();

    const __half* Buh = g_wuh + (size_t)e * HH * II;
    const __half* Bnh = g_wnh + (size_t)e * HH * II;
    uint32_t sbase = smem_u32(dyn);

    auto issue = [&](int slab, int st) {
        int k0 = slab * 32;
        uint32_t sb = sbase + st * 24576;
#pragma unroll
        for (int i = 0; i < 2; i++) {
            int c = tid + i * 256;
            {
                int m = c >> 2, kc = c & 3;
                uint32_t so = sb + swoff(m, kc);
                size_t aoff = (size_t)s_tok[m] * HH + k0 + kc * 8;
                cpasync16(so, g_xlh + aoff);
            }
            {
                int k = c >> 4, cb = c & 15;
                uint32_t bo = sb + 8192 + bswz(k, cb);
                size_t go = (size_t)(k0 + k) * II + n0 + cb * 8;
                cpasync16(bo,        Buh + go);
                cpasync16(bo + 8192, Bnh + go);
            }
        }
    };

    int j = lane >> 3, rr = lane & 7;
    int amRow = wm * 64 + (j & 1) * 8 + rr;
    int akSel = j >> 1;
    float Cu[4][4][4] = {}, Cn[4][4][4] = {};

    issue(0, 0);
    CP_COMMIT();
    for (int s = 0; s < HH / 32; s++) {
        int st = s & 1;
        if (s + 1 < HH / 32) {
            issue(s + 1, st ^ 1);
            CP_COMMIT();
            CP_WAIT1();
        } else {
            CP_WAIT0();
        }
        __syncthreads();
        uint32_t aH = sbase + st * 24576;
        uint32_t uH = aH + 8192, nH = aH + 16384;
#pragma unroll
        for (int kk = 0; kk < 2; kk++) {
            uint32_t buh[4][2], bnh[4][2];
#pragma unroll
            for (int f16 = 0; f16 < 2; f16++) {
                int krow = kk * 16 + (j & 1) * 8 + rr;
                int cc = wn * 4 + f16 * 2 + (j >> 1);
                uint32_t o = bswz(krow, cc);
                ldsm4t(buh[f16 * 2][0], buh[f16 * 2][1], buh[f16 * 2 + 1][0], buh[f16 * 2 + 1][1], uH + o);
                ldsm4t(bnh[f16 * 2][0], bnh[f16 * 2][1], bnh[f16 * 2 + 1][0], bnh[f16 * 2 + 1][1], nH + o);
            }
#pragma unroll
            for (int fm = 0; fm < 4; fm++) {
                int m = amRow + fm * 16;
                int kg = kk * 2 + akSel;
                uint32_t o = (uint32_t)(m * 64 + ((kg ^ ((m >> 1) & 3)) << 4));
                uint32_t ah[4];
                ldsm4(ah[0], ah[1], ah[2], ah[3], aH + o);
#pragma unroll
                for (int fn = 0; fn < 4; fn++) {
                    mma16816(Cu[fm][fn], ah, buh[fn]);
                    mma16816(Cn[fm][fn], ah, bnh[fn]);
                }
            }
        }
        __syncthreads();
    }

    int g = lane >> 2, tig = lane & 3;
    const float* bu = bu_ + (size_t)e * II;
    const float* bn = bn_ + (size_t)e * II;
#pragma unroll
    for (int fm = 0; fm < 4; fm++) {
        int rowl0 = wm * 64 + fm * 16 + g;
#pragma unroll
        for (int fn = 0; fn < 4; fn++) {
            int col = n0 + wn * 32 + fn * 8 + tig * 2;
            float bu0 = bu[col], bu1 = bu[col + 1];
            float bn0 = bn[col], bn1 = bn[col + 1];
#pragma unroll
            for (int hf = 0; hf < 2; hf++) {
                int r = base + rowl0 + hf * 8;
                if (r < end) {
                    float u0 = Cu[fm][fn][hf * 2] + bu0, u1 = Cu[fm][fn][hf * 2 + 1] + bu1;
                    float h0 = u0 * normcdff(u0) * (Cn[fm][fn][hf * 2] + bn0);
                    float h1 = u1 * normcdff(u1) * (Cn[fm][fn][hf * 2 + 1] + bn1);
                    *(uint32_t*)(g_hh + (size_t)r * II + col) = pack2(h0, h1);
                }
            }
        }
    }
}

// ================= flash attention (fp16 HMMA, online softmax) ===============
#define FL_SMEM (16384 + 2 * 32768)
__global__ void __launch_bounds__(256, 1) flash_attn() {
    int q0 = blockIdx.x * 128;
    int head = blockIdx.y;
    int b = head / NHH, h_ = head % NHH;

    extern __shared__ char dyn[];
    uint32_t sb = smem_u32(dyn);

    const __half* Qh = g_qh + (size_t)head * SS * DHH;
    const __half* Kh = g_kh + (size_t)head * SS * DHH;
    const __half* Vh = g_vh + (size_t)head * SS * DHH;

    int tid = threadIdx.x, lane = tid & 31, wid = tid >> 5;
    int j = lane >> 3, rr = lane & 7;
    int g = lane >> 2, tig = lane & 3;

    auto load_tile = [&](uint32_t dst, const __half* src, int row0) {
#pragma unroll
        for (int i = 0; i < 4; i++) {
            int idx = tid + i * 256;
            int m = idx >> 3, c = idx & 7;
            cpasync16(sb + dst + fswz(m, c), src + (size_t)(row0 + m) * DHH + c * 8);
        }
    };

    load_tile(0, Qh, q0);
    load_tile(16384,         Kh, 0);
    load_tile(16384 + 16384, Vh, 0);
    CP_COMMIT();

    float O[8][4] = {};
    float rm0 = -1e30f, rm1 = -1e30f, l0 = 0.0f, l1 = 0.0f;

    for (int kt = 0; kt < 4; kt++) {
        int st = kt & 1;
        if (kt + 1 < 4) {
            uint32_t nb = 16384 + (st ^ 1) * 32768;
            load_tile(nb,         Kh, (kt + 1) * 128);
            load_tile(nb + 16384, Vh, (kt + 1) * 128);
            CP_COMMIT();
            CP_WAIT1();
        } else {
            CP_WAIT0();
        }
        __syncthreads();

        uint32_t kH = sb + 16384 + st * 32768;
        uint32_t vH = kH + 16384;
        uint32_t qHb = sb;

        float S[16][4] = {};
#pragma unroll
        for (int ks = 0; ks < 4; ks++) {
            int am = wid * 16 + (j & 1) * 8 + rr;
            int ac = 2 * ks + (j >> 1);
            uint32_t ah[4];
            ldsm4(ah[0], ah[1], ah[2], ah[3], qHb + fswz(am, ac));
#pragma unroll
            for (int fnp = 0; fnp < 8; fnp++) {
                int bn = fnp * 16 + (j >> 1) * 8 + rr;
                int bc = 2 * ks + (j & 1);
                uint32_t bo = fswz(bn, bc);
                uint32_t bh[4];
                ldsm4(bh[0], bh[1], bh[2], bh[3], kH + bo);
                mma16816(S[2 * fnp],     ah, bh);
                mma16816(S[2 * fnp + 1], ah, bh + 2);
            }
        }

        float mx0 = -1e30f, mx1 = -1e30f;
#pragma unroll
        for (int fn = 0; fn < 16; fn++) {
            mx0 = fmaxf(mx0, fmaxf(S[fn][0], S[fn][1]));
            mx1 = fmaxf(mx1, fmaxf(S[fn][2], S[fn][3]));
        }
        mx0 = fmaxf(mx0, __shfl_xor_sync(~0u, mx0, 1));
        mx0 = fmaxf(mx0, __shfl_xor_sync(~0u, mx0, 2));
        mx1 = fmaxf(mx1, __shfl_xor_sync(~0u, mx1, 1));
        mx1 = fmaxf(mx1, __shfl_xor_sync(~0u, mx1, 2));
        float nm0 = fmaxf(rm0, mx0 * 0.125f);
        float nm1 = fmaxf(rm1, mx1 * 0.125f);
        float al0 = __expf(rm0 - nm0);
        float al1 = __expf(rm1 - nm1);
        rm0 = nm0; rm1 = nm1;
        float sum0 = 0.0f, sum1 = 0.0f;
#pragma unroll
        for (int fn = 0; fn < 16; fn++) {
            float p0 = __expf(fmaf(S[fn][0], 0.125f, -nm0));
            float p1 = __expf(fmaf(S[fn][1], 0.125f, -nm0));
            float p2 = __expf(fmaf(S[fn][2], 0.125f, -nm1));
            float p3 = __expf(fmaf(S[fn][3], 0.125f, -nm1));
            S[fn][0] = p0; S[fn][1] = p1; S[fn][2] = p2; S[fn][3] = p3;
            sum0 += p0 + p1; sum1 += p2 + p3;
        }
        sum0 += __shfl_xor_sync(~0u, sum0, 1);
        sum0 += __shfl_xor_sync(~0u, sum0, 2);
        sum1 += __shfl_xor_sync(~0u, sum1, 1);
        sum1 += __shfl_xor_sync(~0u, sum1, 2);
        l0 = l0 * al0 + sum0;
        l1 = l1 * al1 + sum1;
#pragma unroll
        for (int fo = 0; fo < 8; fo++) {
            O[fo][0] *= al0; O[fo][1] *= al0;
            O[fo][2] *= al1; O[fo][3] *= al1;
        }

#pragma unroll
        for (int kp = 0; kp < 8; kp++) {
            uint32_t aph[4];
            aph[0] = pack2(S[2 * kp][0],     S[2 * kp][1]);
            aph[1] = pack2(S[2 * kp][2],     S[2 * kp][3]);
            aph[2] = pack2(S[2 * kp + 1][0], S[2 * kp + 1][1]);
            aph[3] = pack2(S[2 * kp + 1][2], S[2 * kp + 1][3]);
#pragma unroll
            for (int dg = 0; dg < 4; dg++) {
                int vrow = kp * 16 + (j & 1) * 8 + rr;
                int vc = dg * 2 + (j >> 1);
                uint32_t vo = fswz(vrow, vc);
                uint32_t vh[4];
                ldsm4t(vh[0], vh[1], vh[2], vh[3], vH + vo);
#pragma unroll
                for (int hg = 0; hg < 2; hg++) {
                    int fo = dg * 2 + hg;
                    mma16816(O[fo], aph, vh + hg * 2);
                }
            }
        }
        __syncthreads();
    }

    float inv0 = 1.0f / l0, inv1 = 1.0f / l1;
    int qr0 = q0 + wid * 16 + g;
    size_t t0 = (size_t)b * SS + qr0;
    size_t t1 = t0 + 8;
#pragma unroll
    for (int fo = 0; fo < 8; fo++) {
        int d = fo * 8 + tig * 2;
        int col = h_ * 64 + d;
        *(uint32_t*)(g_ch + t0 * HH + col) = pack2(O[fo][0] * inv0, O[fo][1] * inv0);
        *(uint32_t*)(g_ch + t1 * HH + col) = pack2(O[fo][2] * inv1, O[fo][3] * inv1);
    }
}

// ====== fused: LN(attn) -> out ; LN(ffn) -> xlh ; router+top2 (one pass) =====
__global__ void lnrouter_kernel(const float* __restrict__ g1, const float* __restrict__ b1,
                                const float* __restrict__ g2, const float* __restrict__ b2,
                                const float* __restrict__ Wr, const float* __restrict__ br,
                                float* __restrict__ dout, float* __restrict__ logits_out) {
    size_t row = blockIdx.x;
    const float* in = g_preln + row * HH;
    int tid = threadIdx.x, lane = tid & 31, wid = tid >> 5;
    float x0 = in[tid], x1 = in[tid + 256], x2 = in[tid + 512];

    __shared__ float red[256];
    __shared__ float racc[8][EE];

    // ---- LN 1 (attention output) ----
    red[tid] = x0 + x1 + x2;
    __syncthreads();
    for (int s = 128; s > 0; s >>= 1) {
        if (tid < s) red[tid] += red[tid + s];
        __syncthreads();
    }
    float mean = red[0] * (1.0f / HH);
    __syncthreads();
    float c0 = x0 - mean, c1 = x1 - mean, c2 = x2 - mean;
    red[tid] = c0 * c0 + c1 * c1 + c2 * c2;
    __syncthreads();
    for (int s = 128; s > 0; s >>= 1) {
        if (tid < s) red[tid] += red[tid + s];
        __syncthreads();
    }
    float inv = 1.0f / sqrtf(red[0] * (1.0f / HH) + 1e-12f);
    __syncthreads();

    float y0 = c0 * inv * g1[tid]       + b1[tid];
    float y1 = c1 * inv * g1[tid + 256] + b1[tid + 256];
    float y2 = c2 * inv * g1[tid + 512] + b1[tid + 512];
    dout[row * HH + tid]       = y0;
    dout[row * HH + tid + 256] = y1;
    dout[row * HH + tid + 512] = y2;

    // ---- LN 2 (FFN input) ----
    red[tid] = y0 + y1 + y2;
    __syncthreads();
    for (int s = 128; s > 0; s >>= 1) {
        if (tid < s) red[tid] += red[tid + s];
        __syncthreads();
    }
    float mean2 = red[0] * (1.0f / HH);
    __syncthreads();
    float d0 = y0 - mean2, d1 = y1 - mean2, d2 = y2 - mean2;
    red[tid] = d0 * d0 + d1 * d1 + d2 * d2;
    __syncthreads();
    for (int s = 128; s > 0; s >>= 1) {
        if (tid < s) red[tid] += red[tid + s];
        __syncthreads();
    }
    float inv2 = 1.0f / sqrtf(red[0] * (1.0f / HH) + 1e-12f);

    float z0 = d0 * inv2 * g2[tid]       + b2[tid];
    float z1 = d1 * inv2 * g2[tid + 256] + b2[tid + 256];
    float z2 = d2 * inv2 * g2[tid + 512] + b2[tid + 512];
    g_xlh[row * HH + tid]       = __float2half_rn(z0);
    g_xlh[row * HH + tid + 256] = __float2half_rn(z1);
    g_xlh[row * HH + tid + 512] = __float2half_rn(z2);

    // ---- router: logits[e] = sum_h z[h] * Wr[h][e] + br[e] ----
    float acc[EE];
#pragma unroll
    for (int e = 0; e < EE; e++) {
        acc[e] = z0 * Wr[(size_t)tid * EE + e]
               + z1 * Wr[(size_t)(tid + 256) * EE + e]
               + z2 * Wr[(size_t)(tid + 512) * EE + e];
    }
#pragma unroll
    for (int e = 0; e < EE; e++)
        for (int o = 16; o > 0; o >>= 1) acc[e] += __shfl_down_sync(~0u, acc[e], o);
    if (lane == 0)
#pragma unroll
        for (int e = 0; e < EE; e++) racc[wid][e] = acc[e];
    __syncthreads();

    if (tid == 0) {
        float lg[EE], mx = -1e30f;
#pragma unroll
        for (int e = 0; e < EE; e++) {
            float v = br[e];
#pragma unroll
            for (int w = 0; w < 8; w++) v += racc[w][e];
            lg[e] = v;
            logits_out[row * EE + e] = v;
            mx = fmaxf(mx, v);
        }
        float p[EE], s = 0.0f;
#pragma unroll
        for (int e = 0; e < EE; e++) { p[e] = expf(lg[e] - mx); s += p[e]; }
        float invs = 1.0f / s;
#pragma unroll
        for (int e = 0; e < EE; e++) p[e] *= invs;

        int i1 = 0;
#pragma unroll
        for (int e = 1; e < EE; e++) if (p[e] > p[i1]) i1 = e;
        int i2 = (i1 == 0) ? 1 : 0;
#pragma unroll
        for (int e = 0; e < EE; e++) if (e != i1 && p[e] > p[i2]) i2 = e;

        float w1 = p[i1], w2 = p[i2], invw = 1.0f / (w1 + w2);
        g_ti[row * 2]     = i1;  g_tw[row * 2]     = w1 * invw;
        g_ti[row * 2 + 1] = i2;  g_tw[row * 2 + 1] = w2 * invw;
        atomicAdd(&g_cnt[i1], 1);
        atomicAdd(&g_cnt[i2], 1);
    }
}

// ================= counters / offsets / scatter ==============================
__global__ void init_kernel() {
    int i = threadIdx.x;
    if (i < EE) { g_cnt[i] = 0; g_cur[i] = 0; }
}

__global__ void offsets_kernel() {
    if (threadIdx.x == 0) {
        int o = 0;
        for (int e = 0; e < EE; e++) { g_off[e] = o; o += g_cnt[e]; }
    }
}

__global__ void scatter_kernel() {
    int t = blockIdx.x * 256 + threadIdx.x;
    if (t >= TT) return;
#pragma unroll
    for (int s = 0; s < 2; s++) {
        int e = g_ti[t * 2 + s];
        int pos = atomicAdd(&g_cur[e], 1);
        int r = g_off[e] + pos;
        g_etok[r] = t;
        g_ew[r] = g_tw[t * 2 + s];
    }
}

// ================= host launcher =============================================
#define HG_SMEM  32768
#define DWN_SMEM 32768

extern "C" void kernel_launch(void* const* d_in, const int* in_sizes, int n_in,
                              void* d_out, int out_size) {
    const float* X        = (const float*)d_in[0];
    const float* Wq       = (const float*)d_in[1];
    const float* bq       = (const float*)d_in[2];
    const float* Wk       = (const float*)d_in[3];
    const float* bk       = (const float*)d_in[4];
    const float* Wv       = (const float*)d_in[5];
    const float* bv       = (const float*)d_in[6];
    const float* Wo       = (const float*)d_in[7];
    const float* bo       = (const float*)d_in[8];
    const float* ln_ag    = (const float*)d_in[9];
    const float* ln_ab    = (const float*)d_in[10];
    const float* ln_fg    = (const float*)d_in[11];
    const float* ln_fb    = (const float*)d_in[12];
    const float* Wr       = (const float*)d_in[13];
    const float* br       = (const float*)d_in[14];
    const float* W_up     = (const float*)d_in[15];
    const float* b_up     = (const float*)d_in[16];
    const float* W_new    = (const float*)d_in[17];
    const float* b_new    = (const float*)d_in[18];
    const float* W_down   = (const float*)d_in[19];
    const float* b_down   = (const float*)d_in[20];

    float* out    = (float*)d_out;                    // layer_output [T, H]
    float* logits = out + (size_t)TT * HH;            // router_logits [T, E]

    static cudaStream_t s1;
    static cudaEvent_t evFork, evQKVW, evFFNW;
    static int once = 0;
    if (!once) {
        cudaFuncSetAttribute(hgemm<0>, cudaFuncAttributeMaxDynamicSharedMemorySize, HG_SMEM);
        cudaFuncSetAttribute(hgemm<1>, cudaFuncAttributeMaxDynamicSharedMemorySize, HG_SMEM);
        cudaFuncSetAttribute(hgemm<2>, cudaFuncAttributeMaxDynamicSharedMemorySize, DWN_SMEM);
        cudaFuncSetAttribute(ffn_upgate, cudaFuncAttributeMaxDynamicSharedMemorySize, UPG_SMEM);
        cudaFuncSetAttribute(flash_attn, cudaFuncAttributeMaxDynamicSharedMemorySize, FL_SMEM);
        cudaStreamCreateWithFlags(&s1, cudaStreamNonBlocking);
        cudaEventCreateWithFlags(&evFork, cudaEventDisableTiming);
        cudaEventCreateWithFlags(&evQKVW, cudaEventDisableTiming);
        cudaEventCreateWithFlags(&evFFNW, cudaEventDisableTiming);
        once = 1;
    }

    __half *wqkvh, *woh, *wuh, *wnh, *wdh, *xsh;
    cudaGetSymbolAddress((void**)&wqkvh, g_wqkvh);
    cudaGetSymbolAddress((void**)&woh, g_woh);
    cudaGetSymbolAddress((void**)&wuh, g_wuh);
    cudaGetSymbolAddress((void**)&wnh, g_wnh);
    cudaGetSymbolAddress((void**)&wdh, g_wdh);
    cudaGetSymbolAddress((void**)&xsh, g_xsh);

    // ---- fork side stream for weight prep ----
    cudaEventRecord(evFork, 0);
    cudaStreamWaitEvent(s1, evFork, 0);

    fconv<<<HH * HH / 1024, 256, 0, s1>>>(Wq, wqkvh);
    fconv<<<HH * HH / 1024, 256, 0, s1>>>(Wk, wqkvh + HH * HH);
    fconv<<<HH * HH / 1024, 256, 0, s1>>>(Wv, wqkvh + 2 * HH * HH);
    fconv<<<HH * HH / 1024, 256, 0, s1>>>(Wo, woh);
    cudaEventRecord(evQKVW, s1);
    fconv<<<EE * HH * II / 1024, 256, 0, s1>>>(W_up,  wuh);
    fconv<<<EE * HH * II / 1024, 256, 0, s1>>>(W_new, wnh);
    fconv<<<EE * II * HH / 1024, 256, 0, s1>>>(W_down, wdh);
    cudaEventRecord(evFFNW, s1);

    // ---- main stream: activation prep + attention chain ----
    init_kernel<<<1, 32>>>();
    fconv<<<TT * HH / 1024, 256>>>(X, xsh);

    cudaStreamWaitEvent(0, evQKVW, 0);
    hgemm<0><<<dim3(3 * HH / 128, TT / 128), 256, HG_SMEM>>>(bq, bk, bv, nullptr);
    flash_attn<<<dim3(SS / 128, BB * NHH), 256, FL_SMEM>>>();
    hgemm<1><<<dim3(HH / 128, TT / 128), 256, HG_SMEM>>>(bo, X, nullptr, nullptr);

    lnrouter_kernel<<<TT, 256>>>(ln_ag, ln_ab, ln_fg, ln_fb, Wr, br, out, logits);
    offsets_kernel<<<1, 32>>>();
    scatter_kernel<<<(TT + 255) / 256, 256>>>();

    // ---- join: FFN weights ready before the MoE GEMMs ----
    cudaStreamWaitEvent(0, evFFNW, 0);
    ffn_upgate<<<dim3(32, EE * 24), 256, UPG_SMEM>>>(b_up, b_new);
    hgemm<2><<<dim3(32, EE * 6), 256, DWN_SMEM>>>(b_down, nullptr, nullptr, out);
}

// round 14
// speedup vs baseline: 6.2967x; 1.0806x over previous
#include <cuda_runtime.h>
#include <cuda_fp16.h>
#include <math.h>
#include <stdint.h>

#define TT  4096   // B*S
#define HH  768
#define SS  512
#define BB  8
#define NHH 12
#define DHH 64
#define II  3072
#define EE  8
#define ENT 8192   // TT * TOPK

// ---------------- scratch (static device allocations; no cudaMalloc) --------
__device__ float g_preln[TT * HH];
__device__ __half g_xlh[TT * HH];           // xl fp16 (FFN A operand)
__device__ __half g_xsh[TT * HH];           // X fp16 (QKV A operand)
__device__ __half g_qh[TT * HH];            // Q fp16, [B*NH][S][DH]
__device__ __half g_kh[TT * HH];            // K fp16
__device__ __half g_vh[TT * HH];            // V fp16
__device__ __half g_ch[TT * HH];            // ctx fp16 [T][H] (proj A)
__device__ __half g_hh[(size_t)ENT * II];   // FFN hidden h = gelu(u)*gate, fp16
__device__ __half g_wqkvh[3 * HH * HH];     // [Wq;Wk;Wv] fp16, each [768 k][768 n]
__device__ __half g_woh[HH * HH];           // Wo fp16 [768 k][768 n]
__device__ __half g_wuh[(size_t)EE * HH * II];  // W_up  fp16 [E][H k][I n]
__device__ __half g_wnh[(size_t)EE * HH * II];  // W_new fp16
__device__ __half g_wdh[(size_t)EE * II * HH];  // W_down fp16 [E][I k][H n]
__device__ int   g_cnt[EE];
__device__ int   g_off[EE];
__device__ int   g_cur[EE];
__device__ int   g_etok[ENT];
__device__ float g_ew[ENT];
__device__ int   g_ti[TT * 2];
__device__ float g_tw[TT * 2];

// ======================= asm helpers (portable sm_80+) =======================
__device__ __forceinline__ uint32_t smem_u32(const void* p) {
    uint32_t a;
    asm("{ .reg .u64 t; cvta.to.shared.u64 t, %1; cvt.u32.u64 %0, t; }" : "=r"(a) : "l"(p));
    return a;
}
__device__ __forceinline__ void ldsm4(uint32_t& r0, uint32_t& r1, uint32_t& r2, uint32_t& r3,
                                      uint32_t addr) {
    asm volatile("ldmatrix.sync.aligned.m8n8.x4.shared.b16 {%0,%1,%2,%3}, [%4];"
                 : "=r"(r0), "=r"(r1), "=r"(r2), "=r"(r3) : "r"(addr));
}
__device__ __forceinline__ void ldsm4t(uint32_t& r0, uint32_t& r1, uint32_t& r2, uint32_t& r3,
                                       uint32_t addr) {
    asm volatile("ldmatrix.sync.aligned.m8n8.x4.trans.shared.b16 {%0,%1,%2,%3}, [%4];"
                 : "=r"(r0), "=r"(r1), "=r"(r2), "=r"(r3) : "r"(addr));
}
__device__ __forceinline__ void mma16816(float* c, const uint32_t* a, const uint32_t* b) {
    asm volatile(
        "mma.sync.aligned.m16n8k16.row.col.f32.f16.f16.f32 "
        "{%0,%1,%2,%3}, {%4,%5,%6,%7}, {%8,%9}, {%0,%1,%2,%3};"
        : "+f"(c[0]), "+f"(c[1]), "+f"(c[2]), "+f"(c[3])
        : "r"(a[0]), "r"(a[1]), "r"(a[2]), "r"(a[3]), "r"(b[0]), "r"(b[1]));
}
__device__ __forceinline__ void cpasync16(uint32_t saddr, const void* gaddr) {
    asm volatile("cp.async.cg.shared.global [%0], [%1], 16;" :: "r"(saddr), "l"(gaddr));
}
#define CP_COMMIT() asm volatile("cp.async.commit_group;" ::: "memory")
#define CP_WAIT1()  asm volatile("cp.async.wait_group 1;" ::: "memory")
#define CP_WAIT0()  asm volatile("cp.async.wait_group 0;" ::: "memory")

// xor-swizzled smem byte offset for a [rows x 64 halves] tile (row = 128B, 8 chunks)
__device__ __forceinline__ uint32_t fswz(int m, int c) {
    return (uint32_t)(m * 128 + ((c ^ (m & 7)) << 4));
}
// xor-swizzled smem byte offset for a [k x 128 halves] B tile (row = 256B, 16 chunks)
__device__ __forceinline__ uint32_t bswz(int k, int c) {
    return (uint32_t)(k * 256 + ((c ^ (k & 7)) << 4));
}
__device__ __forceinline__ uint32_t pack2(float v0, float v1) {
    __half2 h = __halves2half2(__float2half_rn(v0), __float2half_rn(v1));
    return *(uint32_t*)&h;
}

// ============ elementwise fp32 -> fp16 convert (pure streaming) ==============
__global__ void fconv(const float* __restrict__ src, __half* __restrict__ h) {
    size_t i = ((size_t)blockIdx.x * 256 + threadIdx.x) * 4;
    float4 v = *(const float4*)(src + i);
    *(uint32_t*)(h + i)     = pack2(v.x, v.y);
    *(uint32_t*)(h + i + 2) = pack2(v.z, v.w);
}

// ================= unified fp16 pipelined HMMA GEMM (K-slab 64) ==============
// B operand is [K][N] row-major fp16, loaded via ldsm4t. All 1-term fp16.
// MODE 0: QKV  -> Q/K/V fp16
// MODE 1: PROJ -> g_preln (+bo+X)
// MODE 2: DOWN -> atomicAdd out
template<int MODE>
__global__ void __launch_bounds__(256, 2) hgemm(
    const float* __restrict__ p0, const float* __restrict__ p1,
    const float* __restrict__ p2, float* __restrict__ pout) {

    constexpr int KD = (MODE == 2) ? II : HH;   // A K-dim
    constexpr int NS = KD / 64;
    constexpr uint32_t STG = 32768;             // A 16K + B 16K per stage

    int e = 0, base = 0, end = 0, m0 = 0, n0;
    if (MODE == 2) {
        e = blockIdx.y / 6;
        n0 = (blockIdx.y % 6) * 128;
        base = g_off[e] + blockIdx.x * 128;
        end  = g_off[e] + g_cnt[e];
        if (base >= end) return;
    } else {
        m0 = blockIdx.y * 128;
        n0 = blockIdx.x * 128;
    }

    extern __shared__ char dyn[];
    __shared__ int   s_tok[128];
    __shared__ float s_w[128];

    int tid = threadIdx.x, lane = tid & 31, wid = tid >> 5;
    int wm = wid & 1, wn = wid >> 1;

    if (MODE == 2 && tid < 128) {
        int r = min(base + tid, end - 1);
        s_tok[tid] = g_etok[r];
        s_w[tid]   = g_ew[r];
    }
    __syncthreads();

    const __half *Bh, *Ah;
    int nb;
    if (MODE == 0) {
        int which = n0 / HH;
        Bh = g_wqkvh + (size_t)which * HH * HH;
        Ah = g_xsh;
        nb = n0 - which * HH;
    } else if (MODE == 1) {
        Bh = g_woh; Ah = g_ch; nb = n0;
    } else {
        Bh = g_wdh + (size_t)e * II * HH;
        Ah = g_hh;  nb = n0;
    }

    uint32_t sbase = smem_u32(dyn);

    auto issue = [&](int slab, int st) {
        int k0 = slab * 64;
        uint32_t sb = sbase + st * STG;
#pragma unroll
        for (int i = 0; i < 4; i++) {
            int c = tid + i * 256;
            {   // A tile [128 m][64 k]
                int m = c >> 3, kc = c & 7;
                uint32_t so = sb + fswz(m, kc);
                int koff = k0 + kc * 8;
                size_t aoff;
                if (MODE < 2) aoff = (size_t)(m0 + m) * KD;
                else          aoff = (size_t)min(base + m, end - 1) * KD;
                cpasync16(so, Ah + aoff + koff);
            }
            {   // B tile [64 k][128 n]
                int k = c >> 4, cb = c & 15;
                uint32_t bo = sb + 16384 + bswz(k, cb);
                size_t go = (size_t)(k0 + k) * HH + nb + cb * 8;
                cpasync16(bo, Bh + go);
            }
        }
    };

    int j = lane >> 3, rr = lane & 7;
    int amRow = wm * 64 + (j & 1) * 8 + rr;
    int akSel = j >> 1;
    float C[4][4][4] = {};

    issue(0, 0);
    CP_COMMIT();
    for (int s = 0; s < NS; s++) {
        int st = s & 1;
        if (s + 1 < NS) {
            issue(s + 1, st ^ 1);
            CP_COMMIT();
            CP_WAIT1();
        } else {
            CP_WAIT0();
        }
        __syncthreads();
        uint32_t aH = sbase + st * STG;
        uint32_t bH = aH + 16384;
#pragma unroll
        for (int kk = 0; kk < 4; kk++) {
            uint32_t bh[4][2];
#pragma unroll
            for (int f16 = 0; f16 < 2; f16++) {
                int krow = kk * 16 + (j & 1) * 8 + rr;
                int cc = wn * 4 + f16 * 2 + (j >> 1);
                uint32_t o = bswz(krow, cc);
                ldsm4t(bh[f16 * 2][0], bh[f16 * 2][1], bh[f16 * 2 + 1][0], bh[f16 * 2 + 1][1], bH + o);
            }
#pragma unroll
            for (int fm = 0; fm < 4; fm++) {
                int m = amRow + fm * 16;
                int kg = kk * 2 + akSel;
                uint32_t ah[4];
                ldsm4(ah[0], ah[1], ah[2], ah[3], aH + fswz(m, kg));
#pragma unroll
                for (int fn = 0; fn < 4; fn++)
                    mma16816(C[fm][fn], ah, bh[fn]);
            }
        }
        __syncthreads();
    }

    int g = lane >> 2, tig = lane & 3;

    __half* qkv_out = nullptr;
    const float* mbias = nullptr;
    int hcol0 = 0;
    if (MODE == 0) {
        int which = n0 / HH;
        qkv_out = (which == 0) ? g_qh : (which == 1) ? g_kh : g_vh;
        mbias   = (which == 0) ? p0 : (which == 1) ? p1 : p2;
        hcol0   = n0 - which * HH;
    }

#pragma unroll
    for (int fm = 0; fm < 4; fm++) {
        int rowl0 = wm * 64 + fm * 16 + g;
#pragma unroll
        for (int fn = 0; fn < 4; fn++) {
            int coll = wn * 32 + fn * 8 + tig * 2;
#pragma unroll
            for (int hf = 0; hf < 2; hf++) {
                int ml = rowl0 + hf * 8;
                float c0 = C[fm][fn][hf * 2], c1 = C[fm][fn][hf * 2 + 1];
                if (MODE == 0) {
                    int t = m0 + ml;
                    int hcol = hcol0 + coll;
                    int h = hcol >> 6, d = hcol & 63;
                    int b = t >> 9, sI = t & 511;
                    size_t o = (((size_t)(b * NHH + h)) * SS + sI) * DHH + d;
                    *(uint32_t*)(qkv_out + o) = pack2(c0 + mbias[hcol], c1 + mbias[hcol + 1]);
                } else if (MODE == 1) {
                    size_t t = m0 + ml;
                    int col = n0 + coll;
                    float2 xr = *(const float2*)(p1 + t * HH + col);
                    float2 v = {c0 + p0[col] + xr.x, c1 + p0[col + 1] + xr.y};
                    *(float2*)(g_preln + t * HH + col) = v;
                } else {
                    if (base + ml < end) {
                        int col = n0 + coll;
                        int t = s_tok[ml];
                        float w = s_w[ml];
                        const float* eb = p0 + (size_t)e * HH;
                        atomicAdd(pout + (size_t)t * HH + col,     (c0 + eb[col]) * w);
                        atomicAdd(pout + (size_t)t * HH + col + 1, (c1 + eb[col + 1]) * w);
                    }
                }
            }
        }
    }
}

// ============ fused up+gate pipelined HMMA grouped GEMM (K-slab 64) ==========
#define UPG_SMEM (2 * 49152)
__global__ void __launch_bounds__(256, 1) ffn_upgate(
    const float* __restrict__ bu_, const float* __restrict__ bn_) {
    int e = blockIdx.y / 24;
    int n0 = (blockIdx.y % 24) * 128;
    int base = g_off[e] + blockIdx.x * 128;
    int end  = g_off[e] + g_cnt[e];
    if (base >= end) return;

    extern __shared__ char dyn[];
    __shared__ int s_tok[128];

    int tid = threadIdx.x, lane = tid & 31, wid = tid >> 5;
    int wm = wid & 1, wn = wid >> 1;

    if (tid < 128) s_tok[tid] = g_etok[min(base + tid, end - 1)];
    __syncthreads();

    const __half* Buh = g_wuh + (size_t)e * HH * II;
    const __half* Bnh = g_wnh + (size_t)e * HH * II;
    uint32_t sbase = smem_u32(dyn);

    auto issue = [&](int slab, int st) {
        int k0 = slab * 64;
        uint32_t sb = sbase + st * 49152;
#pragma unroll
        for (int i = 0; i < 4; i++) {
            int c = tid + i * 256;
            {   // A tile [128 m][64 k]
                int m = c >> 3, kc = c & 7;
                uint32_t so = sb + fswz(m, kc);
                size_t aoff = (size_t)s_tok[m] * HH + k0 + kc * 8;
                cpasync16(so, g_xlh + aoff);
            }
            {   // B tiles [64 k][128 n]
                int k = c >> 4, cb = c & 15;
                uint32_t bo = sb + 16384 + bswz(k, cb);
                size_t go = (size_t)(k0 + k) * II + n0 + cb * 8;
                cpasync16(bo,         Buh + go);
                cpasync16(bo + 16384, Bnh + go);
            }
        }
    };

    int j = lane >> 3, rr = lane & 7;
    int amRow = wm * 64 + (j & 1) * 8 + rr;
    int akSel = j >> 1;
    float Cu[4][4][4] = {}, Cn[4][4][4] = {};

    issue(0, 0);
    CP_COMMIT();
    for (int s = 0; s < HH / 64; s++) {
        int st = s & 1;
        if (s + 1 < HH / 64) {
            issue(s + 1, st ^ 1);
            CP_COMMIT();
            CP_WAIT1();
        } else {
            CP_WAIT0();
        }
        __syncthreads();
        uint32_t aH = sbase + st * 49152;
        uint32_t uH = aH + 16384, nH = aH + 32768;
#pragma unroll
        for (int kk = 0; kk < 4; kk++) {
            uint32_t buh[4][2], bnh[4][2];
#pragma unroll
            for (int f16 = 0; f16 < 2; f16++) {
                int krow = kk * 16 + (j & 1) * 8 + rr;
                int cc = wn * 4 + f16 * 2 + (j >> 1);
                uint32_t o = bswz(krow, cc);
                ldsm4t(buh[f16 * 2][0], buh[f16 * 2][1], buh[f16 * 2 + 1][0], buh[f16 * 2 + 1][1], uH + o);
                ldsm4t(bnh[f16 * 2][0], bnh[f16 * 2][1], bnh[f16 * 2 + 1][0], bnh[f16 * 2 + 1][1], nH + o);
            }
#pragma unroll
            for (int fm = 0; fm < 4; fm++) {
                int m = amRow + fm * 16;
                int kg = kk * 2 + akSel;
                uint32_t ah[4];
                ldsm4(ah[0], ah[1], ah[2], ah[3], aH + fswz(m, kg));
#pragma unroll
                for (int fn = 0; fn < 4; fn++) {
                    mma16816(Cu[fm][fn], ah, buh[fn]);
                    mma16816(Cn[fm][fn], ah, bnh[fn]);
                }
            }
        }
        __syncthreads();
    }

    int g = lane >> 2, tig = lane & 3;
    const float* bu = bu_ + (size_t)e * II;
    const float* bn = bn_ + (size_t)e * II;
#pragma unroll
    for (int fm = 0; fm < 4; fm++) {
        int rowl0 = wm * 64 + fm * 16 + g;
#pragma unroll
        for (int fn = 0; fn < 4; fn++) {
            int col = n0 + wn * 32 + fn * 8 + tig * 2;
            float bu0 = bu[col], bu1 = bu[col + 1];
            float bn0 = bn[col], bn1 = bn[col + 1];
#pragma unroll
            for (int hf = 0; hf < 2; hf++) {
                int r = base + rowl0 + hf * 8;
                if (r < end) {
                    float u0 = Cu[fm][fn][hf * 2] + bu0, u1 = Cu[fm][fn][hf * 2 + 1] + bu1;
                    float h0 = u0 * normcdff(u0) * (Cn[fm][fn][hf * 2] + bn0);
                    float h1 = u1 * normcdff(u1) * (Cn[fm][fn][hf * 2 + 1] + bn1);
                    *(uint32_t*)(g_hh + (size_t)r * II + col) = pack2(h0, h1);
                }
            }
        }
    }
}

// ================= flash attention (fp16 HMMA, online softmax) ===============
#define FL_SMEM (16384 + 2 * 32768)
__global__ void __launch_bounds__(256, 1) flash_attn() {
    int q0 = blockIdx.x * 128;
    int head = blockIdx.y;
    int b = head / NHH, h_ = head % NHH;

    extern __shared__ char dyn[];
    uint32_t sb = smem_u32(dyn);

    const __half* Qh = g_qh + (size_t)head * SS * DHH;
    const __half* Kh = g_kh + (size_t)head * SS * DHH;
    const __half* Vh = g_vh + (size_t)head * SS * DHH;

    int tid = threadIdx.x, lane = tid & 31, wid = tid >> 5;
    int j = lane >> 3, rr = lane & 7;
    int g = lane >> 2, tig = lane & 3;

    auto load_tile = [&](uint32_t dst, const __half* src, int row0) {
#pragma unroll
        for (int i = 0; i < 4; i++) {
            int idx = tid + i * 256;
            int m = idx >> 3, c = idx & 7;
            cpasync16(sb + dst + fswz(m, c), src + (size_t)(row0 + m) * DHH + c * 8);
        }
    };

    load_tile(0, Qh, q0);
    load_tile(16384,         Kh, 0);
    load_tile(16384 + 16384, Vh, 0);
    CP_COMMIT();

    float O[8][4] = {};
    float rm0 = -1e30f, rm1 = -1e30f, l0 = 0.0f, l1 = 0.0f;

    for (int kt = 0; kt < 4; kt++) {
        int st = kt & 1;
        if (kt + 1 < 4) {
            uint32_t nb = 16384 + (st ^ 1) * 32768;
            load_tile(nb,         Kh, (kt + 1) * 128);
            load_tile(nb + 16384, Vh, (kt + 1) * 128);
            CP_COMMIT();
            CP_WAIT1();
        } else {
            CP_WAIT0();
        }
        __syncthreads();

        uint32_t kH = sb + 16384 + st * 32768;
        uint32_t vH = kH + 16384;
        uint32_t qHb = sb;

        float S[16][4] = {};
#pragma unroll
        for (int ks = 0; ks < 4; ks++) {
            int am = wid * 16 + (j & 1) * 8 + rr;
            int ac = 2 * ks + (j >> 1);
            uint32_t ah[4];
            ldsm4(ah[0], ah[1], ah[2], ah[3], qHb + fswz(am, ac));
#pragma unroll
            for (int fnp = 0; fnp < 8; fnp++) {
                int bn = fnp * 16 + (j >> 1) * 8 + rr;
                int bc = 2 * ks + (j & 1);
                uint32_t bo = fswz(bn, bc);
                uint32_t bh[4];
                ldsm4(bh[0], bh[1], bh[2], bh[3], kH + bo);
                mma16816(S[2 * fnp],     ah, bh);
                mma16816(S[2 * fnp + 1], ah, bh + 2);
            }
        }

        float mx0 = -1e30f, mx1 = -1e30f;
#pragma unroll
        for (int fn = 0; fn < 16; fn++) {
            mx0 = fmaxf(mx0, fmaxf(S[fn][0], S[fn][1]));
            mx1 = fmaxf(mx1, fmaxf(S[fn][2], S[fn][3]));
        }
        mx0 = fmaxf(mx0, __shfl_xor_sync(~0u, mx0, 1));
        mx0 = fmaxf(mx0, __shfl_xor_sync(~0u, mx0, 2));
        mx1 = fmaxf(mx1, __shfl_xor_sync(~0u, mx1, 1));
        mx1 = fmaxf(mx1, __shfl_xor_sync(~0u, mx1, 2));
        float nm0 = fmaxf(rm0, mx0 * 0.125f);
        float nm1 = fmaxf(rm1, mx1 * 0.125f);
        float al0 = __expf(rm0 - nm0);
        float al1 = __expf(rm1 - nm1);
        rm0 = nm0; rm1 = nm1;
        float sum0 = 0.0f, sum1 = 0.0f;
#pragma unroll
        for (int fn = 0; fn < 16; fn++) {
            float p0 = __expf(fmaf(S[fn][0], 0.125f, -nm0));
            float p1 = __expf(fmaf(S[fn][1], 0.125f, -nm0));
            float p2 = __expf(fmaf(S[fn][2], 0.125f, -nm1));
            float p3 = __expf(fmaf(S[fn][3], 0.125f, -nm1));
            S[fn][0] = p0; S[fn][1] = p1; S[fn][2] = p2; S[fn][3] = p3;
            sum0 += p0 + p1; sum1 += p2 + p3;
        }
        sum0 += __shfl_xor_sync(~0u, sum0, 1);
        sum0 += __shfl_xor_sync(~0u, sum0, 2);
        sum1 += __shfl_xor_sync(~0u, sum1, 1);
        sum1 += __shfl_xor_sync(~0u, sum1, 2);
        l0 = l0 * al0 + sum0;
        l1 = l1 * al1 + sum1;
#pragma unroll
        for (int fo = 0; fo < 8; fo++) {
            O[fo][0] *= al0; O[fo][1] *= al0;
            O[fo][2] *= al1; O[fo][3] *= al1;
        }

#pragma unroll
        for (int kp = 0; kp < 8; kp++) {
            uint32_t aph[4];
            aph[0] = pack2(S[2 * kp][0],     S[2 * kp][1]);
            aph[1] = pack2(S[2 * kp][2],     S[2 * kp][3]);
            aph[2] = pack2(S[2 * kp + 1][0], S[2 * kp + 1][1]);
            aph[3] = pack2(S[2 * kp + 1][2], S[2 * kp + 1][3]);
#pragma unroll
            for (int dg = 0; dg < 4; dg++) {
                int vrow = kp * 16 + (j & 1) * 8 + rr;
                int vc = dg * 2 + (j >> 1);
                uint32_t vo = fswz(vrow, vc);
                uint32_t vh[4];
                ldsm4t(vh[0], vh[1], vh[2], vh[3], vH + vo);
#pragma unroll
                for (int hg = 0; hg < 2; hg++) {
                    int fo = dg * 2 + hg;
                    mma16816(O[fo], aph, vh + hg * 2);
                }
            }
        }
        __syncthreads();
    }

    float inv0 = 1.0f / l0, inv1 = 1.0f / l1;
    int qr0 = q0 + wid * 16 + g;
    size_t t0 = (size_t)b * SS + qr0;
    size_t t1 = t0 + 8;
#pragma unroll
    for (int fo = 0; fo < 8; fo++) {
        int d = fo * 8 + tig * 2;
        int col = h_ * 64 + d;
        *(uint32_t*)(g_ch + t0 * HH + col) = pack2(O[fo][0] * inv0, O[fo][1] * inv0);
        *(uint32_t*)(g_ch + t1 * HH + col) = pack2(O[fo][2] * inv1, O[fo][3] * inv1);
    }
}

// ====== fused: LN(attn) -> out ; LN(ffn) -> xlh ; router+top2 (one pass) =====
__global__ void lnrouter_kernel(const float* __restrict__ g1, const float* __restrict__ b1,
                                const float* __restrict__ g2, const float* __restrict__ b2,
                                const float* __restrict__ Wr, const float* __restrict__ br,
                                float* __restrict__ dout, float* __restrict__ logits_out) {
    size_t row = blockIdx.x;
    const float* in = g_preln + row * HH;
    int tid = threadIdx.x, lane = tid & 31, wid = tid >> 5;
    float x0 = in[tid], x1 = in[tid + 256], x2 = in[tid + 512];

    __shared__ float red[256];
    __shared__ float racc[8][EE];

    red[tid] = x0 + x1 + x2;
    __syncthreads();
    for (int s = 128; s > 0; s >>= 1) {
        if (tid < s) red[tid] += red[tid + s];
        __syncthreads();
    }
    float mean = red[0] * (1.0f / HH);
    __syncthreads();
    float c0 = x0 - mean, c1 = x1 - mean, c2 = x2 - mean;
    red[tid] = c0 * c0 + c1 * c1 + c2 * c2;
    __syncthreads();
    for (int s = 128; s > 0; s >>= 1) {
        if (tid < s) red[tid] += red[tid + s];
        __syncthreads();
    }
    float inv = 1.0f / sqrtf(red[0] * (1.0f / HH) + 1e-12f);
    __syncthreads();

    float y0 = c0 * inv * g1[tid]       + b1[tid];
    float y1 = c1 * inv * g1[tid + 256] + b1[tid + 256];
    float y2 = c2 * inv * g1[tid + 512] + b1[tid + 512];
    dout[row * HH + tid]       = y0;
    dout[row * HH + tid + 256] = y1;
    dout[row * HH + tid + 512] = y2;

    red[tid] = y0 + y1 + y2;
    __syncthreads();
    for (int s = 128; s > 0; s >>= 1) {
        if (tid < s) red[tid] += red[tid + s];
        __syncthreads();
    }
    float mean2 = red[0] * (1.0f / HH);
    __syncthreads();
    float d0 = y0 - mean2, d1 = y1 - mean2, d2 = y2 - mean2;
    red[tid] = d0 * d0 + d1 * d1 + d2 * d2;
    __syncthreads();
    for (int s = 128; s > 0; s >>= 1) {
        if (tid < s) red[tid] += red[tid + s];
        __syncthreads();
    }
    float inv2 = 1.0f / sqrtf(red[0] * (1.0f / HH) + 1e-12f);

    float z0 = d0 * inv2 * g2[tid]       + b2[tid];
    float z1 = d1 * inv2 * g2[tid + 256] + b2[tid + 256];
    float z2 = d2 * inv2 * g2[tid + 512] + b2[tid + 512];
    g_xlh[row * HH + tid]       = __float2half_rn(z0);
    g_xlh[row * HH + tid + 256] = __float2half_rn(z1);
    g_xlh[row * HH + tid + 512] = __float2half_rn(z2);

    float acc[EE];
#pragma unroll
    for (int e = 0; e < EE; e++) {
        acc[e] = z0 * Wr[(size_t)tid * EE + e]
               + z1 * Wr[(size_t)(tid + 256) * EE + e]
               + z2 * Wr[(size_t)(tid + 512) * EE + e];
    }
#pragma unroll
    for (int e = 0; e < EE; e++)
        for (int o = 16; o > 0; o >>= 1) acc[e] += __shfl_down_sync(~0u, acc[e], o);
    if (lane == 0)
#pragma unroll
        for (int e = 0; e < EE; e++) racc[wid][e] = acc[e];
    __syncthreads();

    if (tid == 0) {
        float lg[EE], mx = -1e30f;
#pragma unroll
        for (int e = 0; e < EE; e++) {
            float v = br[e];
#pragma unroll
            for (int w = 0; w < 8; w++) v += racc[w][e];
            lg[e] = v;
            logits_out[row * EE + e] = v;
            mx = fmaxf(mx, v);
        }
        float p[EE], s = 0.0f;
#pragma unroll
        for (int e = 0; e < EE; e++) { p[e] = expf(lg[e] - mx); s += p[e]; }
        float invs = 1.0f / s;
#pragma unroll
        for (int e = 0; e < EE; e++) p[e] *= invs;

        int i1 = 0;
#pragma unroll
        for (int e = 1; e < EE; e++) if (p[e] > p[i1]) i1 = e;
        int i2 = (i1 == 0) ? 1 : 0;
#pragma unroll
        for (int e = 0; e < EE; e++) if (e != i1 && p[e] > p[i2]) i2 = e;

        float w1 = p[i1], w2 = p[i2], invw = 1.0f / (w1 + w2);
        g_ti[row * 2]     = i1;  g_tw[row * 2]     = w1 * invw;
        g_ti[row * 2 + 1] = i2;  g_tw[row * 2 + 1] = w2 * invw;
        atomicAdd(&g_cnt[i1], 1);
        atomicAdd(&g_cnt[i2], 1);
    }
}

// ================= counters / offsets / scatter ==============================
__global__ void init_kernel() {
    int i = threadIdx.x;
    if (i < EE) { g_cnt[i] = 0; g_cur[i] = 0; }
}

__global__ void offsets_kernel() {
    if (threadIdx.x == 0) {
        int o = 0;
        for (int e = 0; e < EE; e++) { g_off[e] = o; o += g_cnt[e]; }
    }
}

__global__ void scatter_kernel() {
    int t = blockIdx.x * 256 + threadIdx.x;
    if (t >= TT) return;
#pragma unroll
    for (int s = 0; s < 2; s++) {
        int e = g_ti[t * 2 + s];
        int pos = atomicAdd(&g_cur[e], 1);
        int r = g_off[e] + pos;
        g_etok[r] = t;
        g_ew[r] = g_tw[t * 2 + s];
    }
}

// ================= host launcher =============================================
#define HG_SMEM  65536
#define DWN_SMEM 65536

extern "C" void kernel_launch(void* const* d_in, const int* in_sizes, int n_in,
                              void* d_out, int out_size) {
    const float* X        = (const float*)d_in[0];
    const float* Wq       = (const float*)d_in[1];
    const float* bq       = (const float*)d_in[2];
    const float* Wk       = (const float*)d_in[3];
    const float* bk       = (const float*)d_in[4];
    const float* Wv       = (const float*)d_in[5];
    const float* bv       = (const float*)d_in[6];
    const float* Wo       = (const float*)d_in[7];
    const float* bo       = (const float*)d_in[8];
    const float* ln_ag    = (const float*)d_in[9];
    const float* ln_ab    = (const float*)d_in[10];
    const float* ln_fg    = (const float*)d_in[11];
    const float* ln_fb    = (const float*)d_in[12];
    const float* Wr       = (const float*)d_in[13];
    const float* br       = (const float*)d_in[14];
    const float* W_up     = (const float*)d_in[15];
    const float* b_up     = (const float*)d_in[16];
    const float* W_new    = (const float*)d_in[17];
    const float* b_new    = (const float*)d_in[18];
    const float* W_down   = (const float*)d_in[19];
    const float* b_down   = (const float*)d_in[20];

    float* out    = (float*)d_out;                    // layer_output [T, H]
    float* logits = out + (size_t)TT * HH;            // router_logits [T, E]

    static cudaStream_t s1;
    static cudaEvent_t evFork, evQKVW, evFFNW;
    static int once = 0;
    if (!once) {
        cudaFuncSetAttribute(hgemm<0>, cudaFuncAttributeMaxDynamicSharedMemorySize, HG_SMEM);
        cudaFuncSetAttribute(hgemm<1>, cudaFuncAttributeMaxDynamicSharedMemorySize, HG_SMEM);
        cudaFuncSetAttribute(hgemm<2>, cudaFuncAttributeMaxDynamicSharedMemorySize, DWN_SMEM);
        cudaFuncSetAttribute(ffn_upgate, cudaFuncAttributeMaxDynamicSharedMemorySize, UPG_SMEM);
        cudaFuncSetAttribute(flash_attn, cudaFuncAttributeMaxDynamicSharedMemorySize, FL_SMEM);
        cudaStreamCreateWithFlags(&s1, cudaStreamNonBlocking);
        cudaEventCreateWithFlags(&evFork, cudaEventDisableTiming);
        cudaEventCreateWithFlags(&evQKVW, cudaEventDisableTiming);
        cudaEventCreateWithFlags(&evFFNW, cudaEventDisableTiming);
        once = 1;
    }

    __half *wqkvh, *woh, *wuh, *wnh, *wdh, *xsh;
    cudaGetSymbolAddress((void**)&wqkvh, g_wqkvh);
    cudaGetSymbolAddress((void**)&woh, g_woh);
    cudaGetSymbolAddress((void**)&wuh, g_wuh);
    cudaGetSymbolAddress((void**)&wnh, g_wnh);
    cudaGetSymbolAddress((void**)&wdh, g_wdh);
    cudaGetSymbolAddress((void**)&xsh, g_xsh);

    // ---- fork side stream for weight prep ----
    cudaEventRecord(evFork, 0);
    cudaStreamWaitEvent(s1, evFork, 0);

    fconv<<<HH * HH / 1024, 256, 0, s1>>>(Wq, wqkvh);
    fconv<<<HH * HH / 1024, 256, 0, s1>>>(Wk, wqkvh + HH * HH);
    fconv<<<HH * HH / 1024, 256, 0, s1>>>(Wv, wqkvh + 2 * HH * HH);
    fconv<<<HH * HH / 1024, 256, 0, s1>>>(Wo, woh);
    cudaEventRecord(evQKVW, s1);
    fconv<<<EE * HH * II / 1024, 256, 0, s1>>>(W_up,  wuh);
    fconv<<<EE * HH * II / 1024, 256, 0, s1>>>(W_new, wnh);
    fconv<<<EE * II * HH / 1024, 256, 0, s1>>>(W_down, wdh);
    cudaEventRecord(evFFNW, s1);

    // ---- main stream: activation prep + attention chain ----
    init_kernel<<<1, 32>>>();
    fconv<<<TT * HH / 1024, 256>>>(X, xsh);

    cudaStreamWaitEvent(0, evQKVW, 0);
    hgemm<0><<<dim3(3 * HH / 128, TT / 128), 256, HG_SMEM>>>(bq, bk, bv, nullptr);
    flash_attn<<<dim3(SS / 128, BB * NHH), 256, FL_SMEM>>>();
    hgemm<1><<<dim3(HH / 128, TT / 128), 256, HG_SMEM>>>(bo, X, nullptr, nullptr);

    lnrouter_kernel<<<TT, 256>>>(ln_ag, ln_ab, ln_fg, ln_fb, Wr, br, out, logits);
    offsets_kernel<<<1, 32>>>();
    scatter_kernel<<<(TT + 255) / 256, 256>>>();

    // ---- join: FFN weights ready before the MoE GEMMs ----
    cudaStreamWaitEvent(0, evFFNW, 0);
    ffn_upgate<<<dim3(32, EE * 24), 256, UPG_SMEM>>>(b_up, b_new);
    hgemm<2><<<dim3(32, EE * 6), 256, DWN_SMEM>>>(b_down, nullptr, nullptr, out);
}